// round 5
// baseline (speedup 1.0000x reference)
#include <cuda_runtime.h>
#include <math.h>
#include <stdint.h>

#define T_DIM 256
#define N_DIM 1024
#define H_DIM 256
#define L_DIM 16
#define NL_DIM 32
#define C_DIM 64
#define NA_DIM 16
#define ROW_OUT 278
#define G3 768
#define LN (L_DIM*N_DIM)          /* 16384 */
#define TN (T_DIM*N_DIM)          /* 262144 */

// ---------------- scratch ----------------
__device__ float g_giF[NL_DIM*G3];
__device__ float g_giB[NL_DIM*G3];
__device__ float g_Hf[2][(size_t)LN*H_DIM];
__device__ float g_Hb[2][(size_t)LN*H_DIM];
__device__ float g_Rproj[(size_t)LN*H_DIM];
__device__ float g_A0[(size_t)TN*H_DIM];
__device__ float g_A1[(size_t)TN*H_DIM];
__device__ float g_GI[(size_t)TN*G3];
__device__ float g_hm[2][N_DIM*H_DIM];

// ---------------- helpers ----------------
__device__ __forceinline__ uint32_t f2tf(float x){
    uint32_t r; asm("cvt.rna.tf32.f32 %0, %1;" : "=r"(r) : "f"(x)); return r;
}
__device__ __forceinline__ void mma8(float* c, const uint32_t* a, const uint32_t* b){
    asm volatile("mma.sync.aligned.m16n8k8.row.col.f32.tf32.tf32.f32 "
        "{%0,%1,%2,%3},{%4,%5,%6,%7},{%8,%9},{%0,%1,%2,%3};"
        : "+f"(c[0]), "+f"(c[1]), "+f"(c[2]), "+f"(c[3])
        : "r"(a[0]), "r"(a[1]), "r"(a[2]), "r"(a[3]), "r"(b[0]), "r"(b[1]));
}
__device__ __forceinline__ float sigm(float x){ return 1.f/(1.f+expf(-x)); }
__device__ __forceinline__ void cp16(void* smem_dst, const void* gsrc){
    uint32_t s = (uint32_t)__cvta_generic_to_shared(smem_dst);
    asm volatile("cp.async.cg.shared.global [%0], [%1], 16;" :: "r"(s), "l"(gsrc));
}
__device__ __forceinline__ void cp_commit(){ asm volatile("cp.async.commit_group;"); }
template<int N> __device__ __forceinline__ void cp_wait(){
    asm volatile("cp.async.wait_group %0;" :: "n"(N));
}
__device__ __forceinline__ void cluster_sync_(){
    asm volatile("barrier.cluster.arrive.aligned;" ::: "memory");
    asm volatile("barrier.cluster.wait.aligned;" ::: "memory");
}

// ---------------- gi tables ----------------
__global__ void gi_tables(const float* __restrict__ embed,
                          const float* __restrict__ wihF, const float* __restrict__ bihF,
                          const float* __restrict__ wihB, const float* __restrict__ bihB)
{
    int idx = blockIdx.x*blockDim.x + threadIdx.x;
    if (idx >= 2*NL_DIM*G3) return;
    int dir = idx / (NL_DIM*G3);
    int rem = idx % (NL_DIM*G3);
    int e = rem / G3, j = rem % G3;
    const float* wih = dir ? wihB : wihF;
    const float* bih = dir ? bihB : bihF;
    float s = bih[j];
    const float* em = embed + e*H_DIM;
    const float* w  = wih + (size_t)j*H_DIM;
    #pragma unroll 8
    for (int k = 0; k < H_DIM; k++) s += em[k]*w[k];
    (dir ? g_giB : g_giF)[rem] = s;
}

// ---------------- init ----------------
__global__ void init_state(const float* __restrict__ h0)
{
    size_t stride = (size_t)gridDim.x*blockDim.x;
    size_t i0 = (size_t)blockIdx.x*blockDim.x + threadIdx.x;
    size_t HS = (size_t)LN*H_DIM;
    for (size_t p = i0; p < HS; p += stride){ g_Hf[0][p] = 0.f; g_Hb[0][p] = 0.f; }
    for (size_t p = i0; p < (size_t)N_DIM*H_DIM; p += stride) g_hm[0][p] = h0[p];
}

// ---------------- plain tf32 GEMM (Rproj + layer0) ----------------
template<int ALOAD, int EPI>
__global__ void __launch_bounds__(256)
gemm_plain(const float* __restrict__ A, const float* __restrict__ B, int ldb,
           const float* __restrict__ bias, float* __restrict__ out,
           int K, int NC, const int* __restrict__ active)
{
    __shared__ float As[128][20];
    __shared__ float Bs[64][20];
    const int tid = threadIdx.x, lane = tid & 31, wid = tid >> 5;
    const int wm = wid >> 1, wn = wid & 1;
    const int brow = blockIdx.y, bcol = blockIdx.x;
    float acc[2][4][4];
    #pragma unroll
    for (int a = 0; a < 2; a++)
        #pragma unroll
        for (int b = 0; b < 4; b++)
            #pragma unroll
            for (int c = 0; c < 4; c++) acc[a][b][c] = 0.f;

    for (int k0 = 0; k0 < K; k0 += 16){
        #pragma unroll
        for (int i = tid; i < 2048; i += 256){
            int r = i >> 4, c = i & 15;
            int row = brow*128 + r; int k = k0 + c;
            float v;
            if (ALOAD == 0) v = A[(size_t)row*K + k];
            else v = (k < H_DIM) ? g_Hf[0][(size_t)row*H_DIM + k]
                                 : g_Hb[0][(size_t)row*H_DIM + (k - H_DIM)];
            As[r][c] = __uint_as_float(f2tf(v));
        }
        #pragma unroll
        for (int i = tid; i < 1024; i += 256){
            int n = i >> 4, c = i & 15;
            Bs[n][c] = __uint_as_float(f2tf(B[(size_t)(bcol*64 + n)*ldb + k0 + c]));
        }
        __syncthreads();
        #pragma unroll
        for (int kk = 0; kk < 16; kk += 8){
            uint32_t af[2][4], bf[4][2];
            #pragma unroll
            for (int mt = 0; mt < 2; mt++){
                int r0 = wm*32 + mt*16 + (lane >> 2);
                int c0 = kk + (lane & 3);
                af[mt][0] = __float_as_uint(As[r0][c0]);
                af[mt][1] = __float_as_uint(As[r0+8][c0]);
                af[mt][2] = __float_as_uint(As[r0][c0+4]);
                af[mt][3] = __float_as_uint(As[r0+8][c0+4]);
            }
            #pragma unroll
            for (int nt = 0; nt < 4; nt++){
                int n0 = wn*32 + nt*8 + (lane >> 2);
                bf[nt][0] = __float_as_uint(Bs[n0][kk + (lane & 3)]);
                bf[nt][1] = __float_as_uint(Bs[n0][kk + 4 + (lane & 3)]);
            }
            #pragma unroll
            for (int mt = 0; mt < 2; mt++)
                #pragma unroll
                for (int nt = 0; nt < 4; nt++)
                    mma8(acc[mt][nt], af[mt], bf[nt]);
        }
        __syncthreads();
    }
    #pragma unroll
    for (int mt = 0; mt < 2; mt++){
        #pragma unroll
        for (int nt = 0; nt < 4; nt++){
            int rbase = brow*128 + wm*32 + mt*16 + (lane >> 2);
            int cbase = bcol*64 + wn*32 + nt*8 + (lane & 3)*2;
            #pragma unroll
            for (int dr = 0; dr < 2; dr++){
                #pragma unroll
                for (int dc = 0; dc < 2; dc++){
                    int rr = rbase + dr*8, cc = cbase + dc;
                    float v = acc[mt][nt][dr*2 + dc];
                    if (EPI == 3){
                        int n = rr & (N_DIM - 1);
                        int w = active[rr];
                        v += bias[cc];
                        v += g_Rproj[(size_t)(w*N_DIM + n)*H_DIM + cc];
                        v = fmaxf(v, 0.f);
                    }
                    out[(size_t)rr*NC + cc] = v;
                }
            }
        }
    }
}

// ---------------- persistent encoder v3: cluster sync + single-sync pipeline -------
// grid (8 bcol, 16 slab), cluster (8,1,1), 512 thr. slab<8: fwd (Hf), else bwd (Hb).
#define ENC_W_FLOATS (3*32*260)            /* 24960 */
#define ENC_A_FLOATS (2*256*36)            /* 18432 */
#define ENC_SMEM_BYTES ((ENC_W_FLOATS + ENC_A_FLOATS)*4)

__global__ void __launch_bounds__(512, 1) __cluster_dims__(8, 1, 1)
enc_v3(const float* __restrict__ whF, const float* __restrict__ bhF,
       const float* __restrict__ whB, const float* __restrict__ bhB,
       const int* __restrict__ lines)
{
    extern __shared__ float sm[];
    float* Ws = sm;
    float* As = sm + ENC_W_FLOATS;
    const int tid = threadIdx.x, lane = tid & 31, wid = tid >> 5;
    const int wm = wid >> 1, wn = wid & 1;
    const int bcol = blockIdx.x;                // 0..7
    const int slab = blockIdx.y;                // 0..15
    const bool dirF = (slab < 8);
    const float* __restrict__ W  = dirF ? whF : whB;
    const float* __restrict__ bh = dirF ? bhF : bhB;
    const float* __restrict__ giT = dirF ? g_giF : g_giB;
    const int lrow0 = (dirF ? slab : slab - 8) * 2048;

    for (int i = tid; i < 3*32*H_DIM; i += 512){
        int g = i >> 13, rem = i & 8191;
        int c = rem >> 8, k = rem & 255;
        Ws[(g*32 + c)*260 + k] =
            __uint_as_float(f2tf(W[(size_t)(g*H_DIM + bcol*32 + c)*H_DIM + k]));
    }
    __syncthreads();

    for (int t = 0; t < L_DIM; t++){
        const float* __restrict__ hsrc = dirF ? g_Hf[t & 1] : g_Hb[t & 1];
        float* __restrict__ hdst = dirF ? g_Hf[(t + 1) & 1] : g_Hb[(t + 1) & 1];

        auto stage = [&](int p){
            int chunk = p >> 3, kb = p & 7, buf = p & 1;
            const float* src = hsrc + (size_t)(lrow0 + chunk*256)*H_DIM + kb*32;
            float* dst = As + buf*256*36;
            #pragma unroll
            for (int i = tid; i < 2048; i += 512){
                int r = i >> 3, q = (i & 7)*4;
                cp16(&dst[r*36 + q], src + (size_t)r*H_DIM + q);
            }
            cp_commit();
        };

        float acc[3][2][2][4];
        stage(0);
        for (int p = 0; p < 64; p++){
            cp_wait<0>();
            __syncthreads();
            if (p + 1 < 64) stage(p + 1);
            const int kb = p & 7;
            if (kb == 0){
                #pragma unroll
                for (int g = 0; g < 3; g++)
                    #pragma unroll
                    for (int a = 0; a < 2; a++)
                        #pragma unroll
                        for (int b = 0; b < 2; b++)
                            #pragma unroll
                            for (int c = 0; c < 4; c++) acc[g][a][b][c] = 0.f;
            }
            const float* Ab = As + (p & 1)*256*36;
            const int kbase = kb*32;
            #pragma unroll
            for (int kk = 0; kk < 32; kk += 8){
                uint32_t af[2][4];
                #pragma unroll
                for (int mt = 0; mt < 2; mt++){
                    int r0 = wm*32 + mt*16 + (lane >> 2);
                    int c0 = kk + (lane & 3);
                    af[mt][0] = f2tf(Ab[r0*36 + c0]);
                    af[mt][1] = f2tf(Ab[(r0+8)*36 + c0]);
                    af[mt][2] = f2tf(Ab[r0*36 + c0 + 4]);
                    af[mt][3] = f2tf(Ab[(r0+8)*36 + c0 + 4]);
                }
                uint32_t bf[3][2][2];
                #pragma unroll
                for (int g = 0; g < 3; g++)
                    #pragma unroll
                    for (int nt = 0; nt < 2; nt++){
                        int n0 = wn*16 + nt*8 + (lane >> 2);
                        bf[g][nt][0] = __float_as_uint(Ws[(g*32 + n0)*260 + kbase + kk + (lane & 3)]);
                        bf[g][nt][1] = __float_as_uint(Ws[(g*32 + n0)*260 + kbase + kk + 4 + (lane & 3)]);
                    }
                #pragma unroll
                for (int g = 0; g < 3; g++)
                    #pragma unroll
                    for (int mt = 0; mt < 2; mt++)
                        #pragma unroll
                        for (int nt = 0; nt < 2; nt++)
                            mma8(acc[g][mt][nt], af[mt], bf[g][nt]);
            }

            if (kb == 7){
                const int base = lrow0 + (p >> 3)*256;
                #pragma unroll
                for (int mt = 0; mt < 2; mt++){
                    #pragma unroll
                    for (int nt = 0; nt < 2; nt++){
                        #pragma unroll
                        for (int dr = 0; dr < 2; dr++){
                            int lr = base + wm*32 + mt*16 + (lane >> 2) + dr*8;
                            int iroll = lr >> 10;
                            int nb = lr & (N_DIM - 1);
                            int l = dirF ? ((iroll + t) & 15) : ((iroll + 15 - t) & 15);
                            const float* gi = giT + __ldg(&lines[nb*L_DIM + l])*G3;
                            #pragma unroll
                            for (int dc = 0; dc < 2; dc++){
                                int hc = bcol*32 + wn*16 + nt*8 + (lane & 3)*2 + dc;
                                float gr = acc[0][mt][nt][dr*2+dc] + bh[hc];
                                float gz = acc[1][mt][nt][dr*2+dc] + bh[H_DIM + hc];
                                float gn = acc[2][mt][nt][dr*2+dc] + bh[2*H_DIM + hc];
                                float r  = sigm(__ldg(&gi[hc]) + gr);
                                float z  = sigm(__ldg(&gi[H_DIM + hc]) + gz);
                                float nn = tanhf(__ldg(&gi[2*H_DIM + hc]) + r*gn);
                                float hold = __ldcg(&hsrc[(size_t)lr*H_DIM + hc]);
                                float hnew = (1.f - z)*nn + z*hold;
                                __stcg(&hdst[(size_t)lr*H_DIM + hc], hnew);
                            }
                        }
                    }
                }
            }
        }
        cluster_sync_();
    }
}

// ---------------- feed-forward GEMM v3: single-sync pipeline ----------
#define FF_W_FLOATS (64*260)               /* 16640 */
#define FF_A_FLOATS (2*256*36)             /* 18432 */
#define FF_SMEM_BYTES ((FF_W_FLOATS + FF_A_FLOATS)*4)

template<int EPI>
__global__ void __launch_bounds__(512, 1)
gemm_ff2(const float* __restrict__ A, const float* __restrict__ W,
         const float* __restrict__ bias, float* __restrict__ out,
         int NC, int nrt)
{
    extern __shared__ float sm[];
    float* Ws = sm;
    float* As = sm + FF_W_FLOATS;
    const int tid = threadIdx.x, lane = tid & 31, wid = tid >> 5;
    const int wm = wid >> 1, wn = wid & 1;
    const int bcol = blockIdx.x;

    for (int i = tid; i < 64*H_DIM; i += 512){
        int c = i >> 8, k = i & 255;
        Ws[c*260 + k] = __uint_as_float(f2tf(W[(size_t)(bcol*64 + c)*H_DIM + k]));
    }
    __syncthreads();

    const int nch = (nrt - (int)blockIdx.y + (int)gridDim.y - 1) / (int)gridDim.y;
    if (nch <= 0) return;
    const int total = nch*8;

    auto stage = [&](int p){
        int ci = p >> 3, kb = p & 7, buf = p & 1;
        int rt = blockIdx.y + ci*gridDim.y;
        const float* src = A + (size_t)rt*256*H_DIM + kb*32;
        float* dst = As + buf*256*36;
        #pragma unroll
        for (int i = tid; i < 2048; i += 512){
            int r = i >> 3, q = (i & 7)*4;
            cp16(&dst[r*36 + q], src + (size_t)r*H_DIM + q);
        }
        cp_commit();
    };

    float acc[2][4][4];
    stage(0);
    for (int p = 0; p < total; p++){
        cp_wait<0>();
        __syncthreads();
        if (p + 1 < total) stage(p + 1);
        const int kb = p & 7;
        if (kb == 0){
            #pragma unroll
            for (int a = 0; a < 2; a++)
                #pragma unroll
                for (int b = 0; b < 4; b++)
                    #pragma unroll
                    for (int c = 0; c < 4; c++) acc[a][b][c] = 0.f;
        }
        const float* Ab = As + (p & 1)*256*36;
        const int kbase = kb*32;
        #pragma unroll
        for (int kk = 0; kk < 32; kk += 8){
            uint32_t af[2][4];
            #pragma unroll
            for (int mt = 0; mt < 2; mt++){
                int r0 = wm*32 + mt*16 + (lane >> 2);
                int c0 = kk + (lane & 3);
                af[mt][0] = f2tf(Ab[r0*36 + c0]);
                af[mt][1] = f2tf(Ab[(r0+8)*36 + c0]);
                af[mt][2] = f2tf(Ab[r0*36 + c0 + 4]);
                af[mt][3] = f2tf(Ab[(r0+8)*36 + c0 + 4]);
            }
            uint32_t bf[4][2];
            #pragma unroll
            for (int nt = 0; nt < 4; nt++){
                int n0 = wn*32 + nt*8 + (lane >> 2);
                bf[nt][0] = __float_as_uint(Ws[n0*260 + kbase + kk + (lane & 3)]);
                bf[nt][1] = __float_as_uint(Ws[n0*260 + kbase + kk + 4 + (lane & 3)]);
            }
            #pragma unroll
            for (int mt = 0; mt < 2; mt++)
                #pragma unroll
                for (int nt = 0; nt < 4; nt++)
                    mma8(acc[mt][nt], af[mt], bf[nt]);
        }

        if (kb == 7){
            int rt = blockIdx.y + (p >> 3)*gridDim.y;
            #pragma unroll
            for (int mt = 0; mt < 2; mt++){
                #pragma unroll
                for (int nt = 0; nt < 4; nt++){
                    #pragma unroll
                    for (int dr = 0; dr < 2; dr++){
                        int rr = rt*256 + wm*32 + mt*16 + (lane >> 2) + dr*8;
                        #pragma unroll
                        for (int dc = 0; dc < 2; dc++){
                            int cc = bcol*64 + wn*32 + nt*8 + (lane & 3)*2 + dc;
                            float v = acc[mt][nt][dr*2 + dc] + bias[cc];
                            if (EPI == 1) v = fmaxf(v, 0.f);
                            out[(size_t)rr*NC + cc] = v;
                        }
                    }
                }
            }
        }
    }
}

// ---------------- persistent main-loop GRU v4: cluster sync ----------------
// grid (8 bcol, 16 brow), cluster (8,1,1), 256 thr.
// CTA: 64 rows x 32 cols x 3 gates; weights resident.
#define MAIN_W_FLOATS (3*32*260)           /* 24960 */
#define MAIN_A_FLOATS (2*64*36)            /* 4608  */
#define MAIN_SMEM_BYTES ((MAIN_W_FLOATS + MAIN_A_FLOATS)*4)

__global__ void __launch_bounds__(256, 1) __cluster_dims__(8, 1, 1)
main_gru_v4(const float* __restrict__ whh, const float* __restrict__ bhh,
            float* __restrict__ out)
{
    extern __shared__ float sm[];
    float* Ws = sm;
    float* As = sm + MAIN_W_FLOATS;
    const int tid = threadIdx.x, lane = tid & 31, wid = tid >> 5;
    const int wm = wid >> 1, wn = wid & 1;      // wm 0..3 (16-row tiles), wn 0..1
    const int bcol = blockIdx.x;                // 0..7  (32 cols)
    const int row0 = blockIdx.y*64;             // 0..15 *64

    for (int i = tid; i < 3*32*H_DIM; i += 256){
        int g = i >> 13, rem = i & 8191;
        int c = rem >> 8, k = rem & 255;
        Ws[(g*32 + c)*260 + k] =
            __uint_as_float(f2tf(whh[(size_t)(g*H_DIM + bcol*32 + c)*H_DIM + k]));
    }
    // bias regs: 4 cols per thread (nt 0..1, dc 0..1)
    float bR[2][2], bZ[2][2], bN[2][2];
    #pragma unroll
    for (int nt = 0; nt < 2; nt++)
        #pragma unroll
        for (int dc = 0; dc < 2; dc++){
            int c = bcol*32 + wn*16 + nt*8 + (lane & 3)*2 + dc;
            bR[nt][dc] = bhh[c];
            bZ[nt][dc] = bhh[H_DIM + c];
            bN[nt][dc] = bhh[2*H_DIM + c];
        }
    __syncthreads();

    for (int t = 0; t < T_DIM; t++){
        const float* __restrict__ hsrc = g_hm[t & 1];
        float* __restrict__ hdst = g_hm[(t + 1) & 1];

        auto stage = [&](int p){
            int kb = p & 7, buf = p & 1;
            const float* src = hsrc + (size_t)row0*H_DIM + kb*32;
            float* dst = As + buf*64*36;
            #pragma unroll
            for (int i = tid; i < 512; i += 256){
                int r = i >> 3, q = (i & 7)*4;
                cp16(&dst[r*36 + q], src + (size_t)r*H_DIM + q);
            }
            cp_commit();
        };

        float acc[3][2][4];
        #pragma unroll
        for (int g = 0; g < 3; g++)
            #pragma unroll
            for (int n = 0; n < 2; n++)
                #pragma unroll
                for (int c = 0; c < 4; c++) acc[g][n][c] = 0.f;

        stage(0);
        for (int p = 0; p < 8; p++){
            cp_wait<0>();
            __syncthreads();
            if (p + 1 < 8) stage(p + 1);
            const float* Ab = As + (p & 1)*64*36;
            const int kbase = p*32;
            #pragma unroll
            for (int kk = 0; kk < 32; kk += 8){
                uint32_t af[4];
                {
                    int r0 = wm*16 + (lane >> 2);
                    int c0 = kk + (lane & 3);
                    af[0] = f2tf(Ab[r0*36 + c0]);
                    af[1] = f2tf(Ab[(r0+8)*36 + c0]);
                    af[2] = f2tf(Ab[r0*36 + c0 + 4]);
                    af[3] = f2tf(Ab[(r0+8)*36 + c0 + 4]);
                }
                uint32_t bf[3][2][2];
                #pragma unroll
                for (int g = 0; g < 3; g++)
                    #pragma unroll
                    for (int nt = 0; nt < 2; nt++){
                        int n0 = wn*16 + nt*8 + (lane >> 2);
                        bf[g][nt][0] = __float_as_uint(Ws[(g*32 + n0)*260 + kbase + kk + (lane & 3)]);
                        bf[g][nt][1] = __float_as_uint(Ws[(g*32 + n0)*260 + kbase + kk + 4 + (lane & 3)]);
                    }
                #pragma unroll
                for (int g = 0; g < 3; g++)
                    #pragma unroll
                    for (int nt = 0; nt < 2; nt++)
                        mma8(acc[g][nt], af, bf[g][nt]);
            }
        }

        const float* __restrict__ gi_t = g_GI + (size_t)t*N_DIM*G3;
        float* __restrict__ out_t = out + ((size_t)t*N_DIM)*ROW_OUT;
        #pragma unroll
        for (int dr = 0; dr < 2; dr++){
            int row = row0 + wm*16 + (lane >> 2) + dr*8;
            const float* gi = gi_t + (size_t)row*G3;
            #pragma unroll
            for (int nt = 0; nt < 2; nt++){
                #pragma unroll
                for (int dc = 0; dc < 2; dc++){
                    int c = bcol*32 + wn*16 + nt*8 + (lane & 3)*2 + dc;
                    float gr = acc[0][nt][dr*2+dc] + bR[nt][dc];
                    float gz = acc[1][nt][dr*2+dc] + bZ[nt][dc];
                    float gn = acc[2][nt][dr*2+dc] + bN[nt][dc];
                    float r  = sigm(__ldg(&gi[c]) + gr);
                    float z  = sigm(__ldg(&gi[H_DIM + c]) + gz);
                    float nn = tanhf(__ldg(&gi[2*H_DIM + c]) + r*gn);
                    float hold = __ldcg(&hsrc[(size_t)row*H_DIM + c]);
                    float hnew = (1.f - z)*nn + z*hold;
                    __stcg(&hdst[(size_t)row*H_DIM + c], hnew);
                    out_t[(size_t)row*ROW_OUT + 4 + c] = hnew;
                }
            }
        }
        cluster_sync_();
    }
}

// ---------------- heads ----------------
__global__ void __launch_bounds__(256)
heads_kernel(float* __restrict__ out, const int* __restrict__ actions,
             const int* __restrict__ active, const float* __restrict__ p0,
             const float* __restrict__ pp0,
             const float* __restrict__ w_actor, const float* __restrict__ b_actor,
             const float* __restrict__ w_critic, const float* __restrict__ b_critic)
{
    int wid = threadIdx.x >> 5, lane = threadIdx.x & 31;
    size_t row = (size_t)blockIdx.x*8 + wid;
    float* orow = out + row*ROW_OUT;
    float hv[8];
    #pragma unroll
    for (int i = 0; i < 8; i++) hv[i] = orow[4 + lane + 32*i];

    float lg = 0.f;
    #pragma unroll
    for (int a = 0; a < NA_DIM; a++){
        float s = 0.f;
        #pragma unroll
        for (int i = 0; i < 8; i++) s += hv[i]*w_actor[a*H_DIM + lane + 32*i];
        #pragma unroll
        for (int o = 16; o > 0; o >>= 1) s += __shfl_xor_sync(0xffffffffu, s, o);
        if (lane == a) lg = s + b_actor[a];
    }
    float m = (lane < NA_DIM) ? lg : -1e30f;
    #pragma unroll
    for (int o = 16; o > 0; o >>= 1) m = fmaxf(m, __shfl_xor_sync(0xffffffffu, m, o));
    float e = (lane < NA_DIM) ? expf(lg - m) : 0.f;
    float den = e;
    #pragma unroll
    for (int o = 16; o > 0; o >>= 1) den += __shfl_xor_sync(0xffffffffu, den, o);
    if (lane < NA_DIM) orow[260 + lane] = e/den;

    float s = 0.f;
    #pragma unroll
    for (int i = 0; i < 8; i++) s += hv[i]*w_critic[lane + 32*i];
    #pragma unroll
    for (int o = 16; o > 0; o >>= 1) s += __shfl_xor_sync(0xffffffffu, s, o);

    int n = (int)(row & (N_DIM - 1));
    if (lane == 0)  orow[3]   = s + b_critic[0];
    if (lane == 16) orow[0]   = (float)actions[row];
    if (lane == 17) orow[1]   = p0[n];
    if (lane == 18) orow[2]   = (float)active[row];
    if (lane == 19) orow[276] = pp0[n*2];
    if (lane == 20) orow[277] = pp0[n*2 + 1];
}

// ---------------- launch ----------------
extern "C" void kernel_launch(void* const* d_in, const int* in_sizes, int n_in,
                              void* d_out, int out_size)
{
    (void)in_sizes; (void)n_in; (void)out_size;
    const float* condition = (const float*)d_in[0];
    const int*   active    = (const int*)d_in[1];
    const int*   lines     = (const int*)d_in[2];
    const int*   actions   = (const int*)d_in[3];
    const float* h0        = (const float*)d_in[4];
    const float* p0        = (const float*)d_in[5];
    const float* pp0       = (const float*)d_in[6];
    const float* embed     = (const float*)d_in[7];
    const float* wih_f = (const float*)d_in[8],  *whh_f = (const float*)d_in[9];
    const float* bih_f = (const float*)d_in[10], *bhh_f = (const float*)d_in[11];
    const float* wih_b = (const float*)d_in[12], *whh_b = (const float*)d_in[13];
    const float* bih_b = (const float*)d_in[14], *bhh_b = (const float*)d_in[15];
    const float* f_w0 = (const float*)d_in[16], *f_b0 = (const float*)d_in[17];
    const float* f_w1 = (const float*)d_in[18], *f_b1 = (const float*)d_in[19];
    const float* f_w2 = (const float*)d_in[20], *f_b2 = (const float*)d_in[21];
    const float* c_wih = (const float*)d_in[22], *c_whh = (const float*)d_in[23];
    const float* c_bih = (const float*)d_in[24], *c_bhh = (const float*)d_in[25];
    const float* w_critic = (const float*)d_in[26], *b_critic = (const float*)d_in[27];
    const float* w_actor  = (const float*)d_in[28], *b_actor  = (const float*)d_in[29];
    float* out = (float*)d_out;

    float *A0p, *A1p, *Rp, *GIp;
    cudaGetSymbolAddress((void**)&A0p, g_A0);
    cudaGetSymbolAddress((void**)&A1p, g_A1);
    cudaGetSymbolAddress((void**)&Rp,  g_Rproj);
    cudaGetSymbolAddress((void**)&GIp, g_GI);

    cudaFuncSetAttribute(enc_v3,
                         cudaFuncAttributeMaxDynamicSharedMemorySize, ENC_SMEM_BYTES);
    cudaFuncSetAttribute(main_gru_v4,
                         cudaFuncAttributeMaxDynamicSharedMemorySize, MAIN_SMEM_BYTES);
    cudaFuncSetAttribute(gemm_ff2<1>,
                         cudaFuncAttributeMaxDynamicSharedMemorySize, FF_SMEM_BYTES);
    cudaFuncSetAttribute(gemm_ff2<2>,
                         cudaFuncAttributeMaxDynamicSharedMemorySize, FF_SMEM_BYTES);

    // 0) gi tables + state init
    gi_tables<<<(2*NL_DIM*G3 + 255)/256, 256>>>(embed, wih_f, bih_f, wih_b, bih_b);
    init_state<<<4096, 256>>>(h0);

    // 1) persistent bidirectional encoder (clustered)
    enc_v3<<<dim3(8, 16), 512, ENC_SMEM_BYTES>>>(whh_f, bhh_f, whh_b, bhh_b, lines);

    // 2) Rproj = Hmem @ W0r^T (dedup over (w,n))
    gemm_plain<1, 0><<<dim3(4, 128), 256>>>(nullptr, f_w0 + 64, 576, nullptr, Rp, 512, 256, nullptr);
    // 3) A0 = relu(cond @ W0c^T + Rproj[active] + b0)
    gemm_plain<0, 3><<<dim3(4, 2048), 256>>>(condition, f_w0, 576, f_b0, A0p, 64, 256, active);
    // 4) A1 = relu(A0 @ w1^T + b1); A0 = relu(A1 @ w2^T + b2)
    gemm_ff2<1><<<dim3(4, 33), 512, FF_SMEM_BYTES>>>(A0p, f_w1, f_b1, A1p, 256, 1024);
    gemm_ff2<1><<<dim3(4, 33), 512, FF_SMEM_BYTES>>>(A1p, f_w2, f_b2, A0p, 256, 1024);
    // 5) GI = A0 @ c_wih^T + c_bih
    gemm_ff2<2><<<dim3(12, 11), 512, FF_SMEM_BYTES>>>(A0p, c_wih, c_bih, GIp, 768, 1024);

    // 6) persistent main GRU (clustered, no grid barrier)
    main_gru_v4<<<dim3(8, 16), 256, MAIN_SMEM_BYTES>>>(c_whh, c_bhh, out);

    // 7) heads + scalar fields
    heads_kernel<<<TN/8, 256>>>(out, actions, active, p0, pp0,
                                w_actor, b_actor, w_critic, b_critic);
}

// round 6
// speedup vs baseline: 1.5024x; 1.5024x over previous
#include <cuda_runtime.h>
#include <math.h>
#include <stdint.h>

#define T_DIM 256
#define N_DIM 1024
#define H_DIM 256
#define L_DIM 16
#define NL_DIM 32
#define C_DIM 64
#define NA_DIM 16
#define ROW_OUT 278
#define G3 768
#define LN (L_DIM*N_DIM)          /* 16384 */
#define TN (T_DIM*N_DIM)          /* 262144 */

// ---------------- scratch ----------------
__device__ float g_giF[NL_DIM*G3];
__device__ float g_giB[NL_DIM*G3];
__device__ float g_Hf[2][(size_t)LN*H_DIM];
__device__ float g_Hb[2][(size_t)LN*H_DIM];
__device__ float g_Rproj[(size_t)LN*H_DIM];
__device__ float g_A0[(size_t)TN*H_DIM];
__device__ float g_A1[(size_t)TN*H_DIM];
__device__ float g_GI[(size_t)TN*G3];
__device__ float g_hm[2][N_DIM*H_DIM];
__device__ unsigned g_slabc[16][32];   // per-slab counters, 128B apart
__device__ unsigned g_slabg[16][32];   // per-slab generations

// ---------------- helpers ----------------
__device__ __forceinline__ uint32_t f2tf(float x){
    uint32_t r; asm("cvt.rna.tf32.f32 %0, %1;" : "=r"(r) : "f"(x)); return r;
}
__device__ __forceinline__ void mma8(float* c, const uint32_t* a, const uint32_t* b){
    asm volatile("mma.sync.aligned.m16n8k8.row.col.f32.tf32.tf32.f32 "
        "{%0,%1,%2,%3},{%4,%5,%6,%7},{%8,%9},{%0,%1,%2,%3};"
        : "+f"(c[0]), "+f"(c[1]), "+f"(c[2]), "+f"(c[3])
        : "r"(a[0]), "r"(a[1]), "r"(a[2]), "r"(a[3]), "r"(b[0]), "r"(b[1]));
}
__device__ __forceinline__ float sigm(float x){ return 1.f/(1.f+expf(-x)); }
__device__ __forceinline__ void cp16(void* smem_dst, const void* gsrc){
    uint32_t s = (uint32_t)__cvta_generic_to_shared(smem_dst);
    asm volatile("cp.async.cg.shared.global [%0], [%1], 16;" :: "r"(s), "l"(gsrc));
}
__device__ __forceinline__ void cp_commit(){ asm volatile("cp.async.commit_group;"); }
template<int N> __device__ __forceinline__ void cp_wait(){
    asm volatile("cp.async.wait_group %0;" :: "n"(N));
}

// per-slab software barrier: only the CTAs sharing rows synchronize
__device__ __forceinline__ void slab_sync(int slab, unsigned nb){
    __syncthreads();
    if (threadIdx.x == 0){
        volatile unsigned* genp = &g_slabg[slab][0];
        unsigned old = *genp;
        __threadfence();
        if (atomicAdd(&g_slabc[slab][0], 1u) == nb - 1u){
            g_slabc[slab][0] = 0u;
            __threadfence();
            *genp = old + 1u;
        } else {
            while (*genp == old) { }
            __threadfence();
        }
    }
    __syncthreads();
}

// ---------------- gi tables ----------------
__global__ void gi_tables(const float* __restrict__ embed,
                          const float* __restrict__ wihF, const float* __restrict__ bihF,
                          const float* __restrict__ wihB, const float* __restrict__ bihB)
{
    int idx = blockIdx.x*blockDim.x + threadIdx.x;
    if (idx >= 2*NL_DIM*G3) return;
    int dir = idx / (NL_DIM*G3);
    int rem = idx % (NL_DIM*G3);
    int e = rem / G3, j = rem % G3;
    const float* wih = dir ? wihB : wihF;
    const float* bih = dir ? bihB : bihF;
    float s = bih[j];
    const float* em = embed + e*H_DIM;
    const float* w  = wih + (size_t)j*H_DIM;
    #pragma unroll 8
    for (int k = 0; k < H_DIM; k++) s += em[k]*w[k];
    (dir ? g_giB : g_giF)[rem] = s;
}

// ---------------- init ----------------
__global__ void init_state(const float* __restrict__ h0)
{
    size_t stride = (size_t)gridDim.x*blockDim.x;
    size_t i0 = (size_t)blockIdx.x*blockDim.x + threadIdx.x;
    size_t HS = (size_t)LN*H_DIM;
    for (size_t p = i0; p < HS; p += stride){ g_Hf[0][p] = 0.f; g_Hb[0][p] = 0.f; }
    for (size_t p = i0; p < (size_t)N_DIM*H_DIM; p += stride) g_hm[0][p] = h0[p];
}

// ---------------- plain tf32 GEMM (Rproj + layer0) ----------------
template<int ALOAD, int EPI>
__global__ void __launch_bounds__(256)
gemm_plain(const float* __restrict__ A, const float* __restrict__ B, int ldb,
           const float* __restrict__ bias, float* __restrict__ out,
           int K, int NC, const int* __restrict__ active)
{
    __shared__ float As[128][20];
    __shared__ float Bs[64][20];
    const int tid = threadIdx.x, lane = tid & 31, wid = tid >> 5;
    const int wm = wid >> 1, wn = wid & 1;
    const int brow = blockIdx.y, bcol = blockIdx.x;
    float acc[2][4][4];
    #pragma unroll
    for (int a = 0; a < 2; a++)
        #pragma unroll
        for (int b = 0; b < 4; b++)
            #pragma unroll
            for (int c = 0; c < 4; c++) acc[a][b][c] = 0.f;

    for (int k0 = 0; k0 < K; k0 += 16){
        #pragma unroll
        for (int i = tid; i < 2048; i += 256){
            int r = i >> 4, c = i & 15;
            int row = brow*128 + r; int k = k0 + c;
            float v;
            if (ALOAD == 0) v = A[(size_t)row*K + k];
            else v = (k < H_DIM) ? g_Hf[0][(size_t)row*H_DIM + k]
                                 : g_Hb[0][(size_t)row*H_DIM + (k - H_DIM)];
            As[r][c] = __uint_as_float(f2tf(v));
        }
        #pragma unroll
        for (int i = tid; i < 1024; i += 256){
            int n = i >> 4, c = i & 15;
            Bs[n][c] = __uint_as_float(f2tf(B[(size_t)(bcol*64 + n)*ldb + k0 + c]));
        }
        __syncthreads();
        #pragma unroll
        for (int kk = 0; kk < 16; kk += 8){
            uint32_t af[2][4], bf[4][2];
            #pragma unroll
            for (int mt = 0; mt < 2; mt++){
                int r0 = wm*32 + mt*16 + (lane >> 2);
                int c0 = kk + (lane & 3);
                af[mt][0] = __float_as_uint(As[r0][c0]);
                af[mt][1] = __float_as_uint(As[r0+8][c0]);
                af[mt][2] = __float_as_uint(As[r0][c0+4]);
                af[mt][3] = __float_as_uint(As[r0+8][c0+4]);
            }
            #pragma unroll
            for (int nt = 0; nt < 4; nt++){
                int n0 = wn*32 + nt*8 + (lane >> 2);
                bf[nt][0] = __float_as_uint(Bs[n0][kk + (lane & 3)]);
                bf[nt][1] = __float_as_uint(Bs[n0][kk + 4 + (lane & 3)]);
            }
            #pragma unroll
            for (int mt = 0; mt < 2; mt++)
                #pragma unroll
                for (int nt = 0; nt < 4; nt++)
                    mma8(acc[mt][nt], af[mt], bf[nt]);
        }
        __syncthreads();
    }
    #pragma unroll
    for (int mt = 0; mt < 2; mt++){
        #pragma unroll
        for (int nt = 0; nt < 4; nt++){
            int rbase = brow*128 + wm*32 + mt*16 + (lane >> 2);
            int cbase = bcol*64 + wn*32 + nt*8 + (lane & 3)*2;
            #pragma unroll
            for (int dr = 0; dr < 2; dr++){
                #pragma unroll
                for (int dc = 0; dc < 2; dc++){
                    int rr = rbase + dr*8, cc = cbase + dc;
                    float v = acc[mt][nt][dr*2 + dc];
                    if (EPI == 3){
                        int n = rr & (N_DIM - 1);
                        int w = active[rr];
                        v += bias[cc];
                        v += g_Rproj[(size_t)(w*N_DIM + n)*H_DIM + cc];
                        v = fmaxf(v, 0.f);
                    }
                    out[(size_t)rr*NC + cc] = v;
                }
            }
        }
    }
}

// ---------------- persistent encoder (round-4 structure, per-slab barrier) ---------
// grid (8 bcol, 16 slab), 512 thr. slab<8: fwd (Hf), else bwd (Hb).
#define ENC_W_FLOATS (3*32*260)            /* 24960 */
#define ENC_A_FLOATS (2*256*36)            /* 18432 */
#define ENC_SMEM_BYTES ((ENC_W_FLOATS + ENC_A_FLOATS)*4)

__global__ void __launch_bounds__(512, 1)
enc_v2(const float* __restrict__ whF, const float* __restrict__ bhF,
       const float* __restrict__ whB, const float* __restrict__ bhB,
       const int* __restrict__ lines)
{
    extern __shared__ float sm[];
    float* Ws = sm;
    float* As = sm + ENC_W_FLOATS;
    const int tid = threadIdx.x, lane = tid & 31, wid = tid >> 5;
    const int wm = wid >> 1, wn = wid & 1;
    const int bcol = blockIdx.x;                // 0..7
    const int slab = blockIdx.y;                // 0..15
    const bool dirF = (slab < 8);
    const float* __restrict__ W  = dirF ? whF : whB;
    const float* __restrict__ bh = dirF ? bhF : bhB;
    const float* __restrict__ giT = dirF ? g_giF : g_giB;
    const int lrow0 = (dirF ? slab : slab - 8) * 2048;

    for (int i = tid; i < 3*32*H_DIM; i += 512){
        int g = i >> 13, rem = i & 8191;
        int c = rem >> 8, k = rem & 255;
        Ws[(g*32 + c)*260 + k] =
            __uint_as_float(f2tf(W[(size_t)(g*H_DIM + bcol*32 + c)*H_DIM + k]));
    }
    __syncthreads();

    for (int t = 0; t < L_DIM; t++){
        const float* __restrict__ hsrc = dirF ? g_Hf[t & 1] : g_Hb[t & 1];
        float* __restrict__ hdst = dirF ? g_Hf[(t + 1) & 1] : g_Hb[(t + 1) & 1];

        auto stage = [&](int p){
            int chunk = p >> 3, kb = p & 7, buf = p & 1;
            const float* src = hsrc + (size_t)(lrow0 + chunk*256)*H_DIM + kb*32;
            float* dst = As + buf*256*36;
            #pragma unroll
            for (int i = tid; i < 2048; i += 512){
                int r = i >> 3, q = (i & 7)*4;
                cp16(&dst[r*36 + q], src + (size_t)r*H_DIM + q);
            }
            cp_commit();
        };

        float acc[3][2][2][4];
        stage(0);
        for (int p = 0; p < 64; p++){
            if (p + 1 < 64){ stage(p + 1); cp_wait<1>(); }
            else cp_wait<0>();
            __syncthreads();
            const int kb = p & 7;
            if (kb == 0){
                #pragma unroll
                for (int g = 0; g < 3; g++)
                    #pragma unroll
                    for (int a = 0; a < 2; a++)
                        #pragma unroll
                        for (int b = 0; b < 2; b++)
                            #pragma unroll
                            for (int c = 0; c < 4; c++) acc[g][a][b][c] = 0.f;
            }
            const float* Ab = As + (p & 1)*256*36;
            const int kbase = kb*32;
            #pragma unroll
            for (int kk = 0; kk < 32; kk += 8){
                uint32_t af[2][4];
                #pragma unroll
                for (int mt = 0; mt < 2; mt++){
                    int r0 = wm*32 + mt*16 + (lane >> 2);
                    int c0 = kk + (lane & 3);
                    af[mt][0] = f2tf(Ab[r0*36 + c0]);
                    af[mt][1] = f2tf(Ab[(r0+8)*36 + c0]);
                    af[mt][2] = f2tf(Ab[r0*36 + c0 + 4]);
                    af[mt][3] = f2tf(Ab[(r0+8)*36 + c0 + 4]);
                }
                uint32_t bf[3][2][2];
                #pragma unroll
                for (int g = 0; g < 3; g++)
                    #pragma unroll
                    for (int nt = 0; nt < 2; nt++){
                        int n0 = wn*16 + nt*8 + (lane >> 2);
                        bf[g][nt][0] = __float_as_uint(Ws[(g*32 + n0)*260 + kbase + kk + (lane & 3)]);
                        bf[g][nt][1] = __float_as_uint(Ws[(g*32 + n0)*260 + kbase + kk + 4 + (lane & 3)]);
                    }
                #pragma unroll
                for (int g = 0; g < 3; g++)
                    #pragma unroll
                    for (int mt = 0; mt < 2; mt++)
                        #pragma unroll
                        for (int nt = 0; nt < 2; nt++)
                            mma8(acc[g][mt][nt], af[mt], bf[g][nt]);
            }
            __syncthreads();

            if (kb == 7){
                const int base = lrow0 + (p >> 3)*256;
                #pragma unroll
                for (int mt = 0; mt < 2; mt++){
                    #pragma unroll
                    for (int nt = 0; nt < 2; nt++){
                        #pragma unroll
                        for (int dr = 0; dr < 2; dr++){
                            int lr = base + wm*32 + mt*16 + (lane >> 2) + dr*8;
                            int iroll = lr >> 10;
                            int nb = lr & (N_DIM - 1);
                            int l = dirF ? ((iroll + t) & 15) : ((iroll + 15 - t) & 15);
                            const float* gi = giT + __ldg(&lines[nb*L_DIM + l])*G3;
                            #pragma unroll
                            for (int dc = 0; dc < 2; dc++){
                                int hc = bcol*32 + wn*16 + nt*8 + (lane & 3)*2 + dc;
                                float gr = acc[0][mt][nt][dr*2+dc] + bh[hc];
                                float gz = acc[1][mt][nt][dr*2+dc] + bh[H_DIM + hc];
                                float gn = acc[2][mt][nt][dr*2+dc] + bh[2*H_DIM + hc];
                                float r  = sigm(__ldg(&gi[hc]) + gr);
                                float z  = sigm(__ldg(&gi[H_DIM + hc]) + gz);
                                float nn = tanhf(__ldg(&gi[2*H_DIM + hc]) + r*gn);
                                float hold = __ldcg(&hsrc[(size_t)lr*H_DIM + hc]);
                                float hnew = (1.f - z)*nn + z*hold;
                                __stcg(&hdst[(size_t)lr*H_DIM + hc], hnew);
                            }
                        }
                    }
                }
            }
        }
        slab_sync(slab, 8);
    }
}

// ---------------- feed-forward GEMM: K-chunk 64 (fewer stage syncs) ----------
#define FF_W_FLOATS (64*260)               /* 16640 */
#define FF_A_FLOATS (2*256*68)             /* 34816 */
#define FF_SMEM_BYTES ((FF_W_FLOATS + FF_A_FLOATS)*4)

template<int EPI>
__global__ void __launch_bounds__(512, 1)
gemm_ff2(const float* __restrict__ A, const float* __restrict__ W,
         const float* __restrict__ bias, float* __restrict__ out,
         int NC, int nrt)
{
    extern __shared__ float sm[];
    float* Ws = sm;
    float* As = sm + FF_W_FLOATS;
    const int tid = threadIdx.x, lane = tid & 31, wid = tid >> 5;
    const int wm = wid >> 1, wn = wid & 1;
    const int bcol = blockIdx.x;

    for (int i = tid; i < 64*H_DIM; i += 512){
        int c = i >> 8, k = i & 255;
        Ws[c*260 + k] = __uint_as_float(f2tf(W[(size_t)(bcol*64 + c)*H_DIM + k]));
    }
    __syncthreads();

    const int nch = (nrt - (int)blockIdx.y + (int)gridDim.y - 1) / (int)gridDim.y;
    if (nch <= 0) return;
    const int total = nch*4;                 // 4 K-stages of 64 per row tile

    auto stage = [&](int p){
        int ci = p >> 2, kb = p & 3, buf = p & 1;
        int rt = blockIdx.y + ci*gridDim.y;
        const float* src = A + (size_t)rt*256*H_DIM + kb*64;
        float* dst = As + buf*256*68;
        #pragma unroll
        for (int i = tid; i < 4096; i += 512){
            int r = i >> 4, q = (i & 15)*4;
            cp16(&dst[r*68 + q], src + (size_t)r*H_DIM + q);
        }
        cp_commit();
    };

    float acc[2][4][4];
    stage(0);
    for (int p = 0; p < total; p++){
        if (p + 1 < total){ stage(p + 1); cp_wait<1>(); }
        else cp_wait<0>();
        __syncthreads();
        const int kb = p & 3;
        if (kb == 0){
            #pragma unroll
            for (int a = 0; a < 2; a++)
                #pragma unroll
                for (int b = 0; b < 4; b++)
                    #pragma unroll
                    for (int c = 0; c < 4; c++) acc[a][b][c] = 0.f;
        }
        const float* Ab = As + (p & 1)*256*68;
        const int kbase = kb*64;
        #pragma unroll
        for (int kk = 0; kk < 64; kk += 8){
            uint32_t af[2][4];
            #pragma unroll
            for (int mt = 0; mt < 2; mt++){
                int r0 = wm*32 + mt*16 + (lane >> 2);
                int c0 = kk + (lane & 3);
                af[mt][0] = f2tf(Ab[r0*68 + c0]);
                af[mt][1] = f2tf(Ab[(r0+8)*68 + c0]);
                af[mt][2] = f2tf(Ab[r0*68 + c0 + 4]);
                af[mt][3] = f2tf(Ab[(r0+8)*68 + c0 + 4]);
            }
            uint32_t bf[4][2];
            #pragma unroll
            for (int nt = 0; nt < 4; nt++){
                int n0 = wn*32 + nt*8 + (lane >> 2);
                bf[nt][0] = __float_as_uint(Ws[n0*260 + kbase + kk + (lane & 3)]);
                bf[nt][1] = __float_as_uint(Ws[n0*260 + kbase + kk + 4 + (lane & 3)]);
            }
            #pragma unroll
            for (int mt = 0; mt < 2; mt++)
                #pragma unroll
                for (int nt = 0; nt < 4; nt++)
                    mma8(acc[mt][nt], af[mt], bf[nt]);
        }
        __syncthreads();

        if (kb == 3){
            int rt = blockIdx.y + (p >> 2)*gridDim.y;
            #pragma unroll
            for (int mt = 0; mt < 2; mt++){
                #pragma unroll
                for (int nt = 0; nt < 4; nt++){
                    #pragma unroll
                    for (int dr = 0; dr < 2; dr++){
                        int rr = rt*256 + wm*32 + mt*16 + (lane >> 2) + dr*8;
                        #pragma unroll
                        for (int dc = 0; dc < 2; dc++){
                            int cc = bcol*64 + wn*32 + nt*8 + (lane & 3)*2 + dc;
                            float v = acc[mt][nt][dr*2 + dc] + bias[cc];
                            if (EPI == 1) v = fmaxf(v, 0.f);
                            out[(size_t)rr*NC + cc] = v;
                        }
                    }
                }
            }
        }
    }
}

// ---------------- persistent main GRU (round-4 structure, K-chunk 64, slab sync) ----
// grid (16 bcol, 8 brow), 256 thr. CTA: 128 rows x 16 cols x 3 gates.
#define MAIN_W_FLOATS (3*16*260)           /* 12480 */
#define MAIN_A_FLOATS (2*128*68)           /* 17408 */
#define MAIN_SMEM_BYTES ((MAIN_W_FLOATS + MAIN_A_FLOATS)*4)

__global__ void __launch_bounds__(256, 1)
main_gru_v5(const float* __restrict__ whh, const float* __restrict__ bhh,
            float* __restrict__ out)
{
    extern __shared__ float sm[];
    float* Ws = sm;
    float* As = sm + MAIN_W_FLOATS;
    const int tid = threadIdx.x, lane = tid & 31, wid = tid >> 5;
    const int wm = wid >> 1, wn = wid & 1;
    const int bcol = blockIdx.x;          // 0..15
    const int slab = blockIdx.y;          // 0..7
    const int row0 = slab*128;

    for (int i = tid; i < 3*16*H_DIM; i += 256){
        int g = i >> 12, rem = i & 4095;
        int c = rem >> 8, k = rem & 255;
        Ws[(g*16 + c)*260 + k] =
            __uint_as_float(f2tf(whh[(size_t)(g*H_DIM + bcol*16 + c)*H_DIM + k]));
    }
    const int cb0 = bcol*16 + wn*8 + (lane & 3)*2;
    float bR0 = bhh[cb0],           bR1 = bhh[cb0 + 1];
    float bZ0 = bhh[H_DIM + cb0],   bZ1 = bhh[H_DIM + cb0 + 1];
    float bN0 = bhh[2*H_DIM + cb0], bN1 = bhh[2*H_DIM + cb0 + 1];
    __syncthreads();

    for (int t = 0; t < T_DIM; t++){
        const float* __restrict__ hsrc = g_hm[t & 1];
        float* __restrict__ hdst = g_hm[(t + 1) & 1];

        auto stage = [&](int p){
            int kb = p & 3, buf = p & 1;
            const float* src = hsrc + (size_t)row0*H_DIM + kb*64;
            float* dst = As + buf*128*68;
            #pragma unroll
            for (int i = tid; i < 2048; i += 256){
                int r = i >> 4, q = (i & 15)*4;
                cp16(&dst[r*68 + q], src + (size_t)r*H_DIM + q);
            }
            cp_commit();
        };

        float acc[3][2][4];
        #pragma unroll
        for (int g = 0; g < 3; g++)
            #pragma unroll
            for (int m = 0; m < 2; m++)
                #pragma unroll
                for (int c = 0; c < 4; c++) acc[g][m][c] = 0.f;

        stage(0);
        for (int p = 0; p < 4; p++){
            if (p + 1 < 4){ stage(p + 1); cp_wait<1>(); }
            else cp_wait<0>();
            __syncthreads();
            const float* Ab = As + (p & 1)*128*68;
            const int kbase = p*64;
            #pragma unroll
            for (int kk = 0; kk < 64; kk += 8){
                uint32_t af[2][4];
                #pragma unroll
                for (int mt = 0; mt < 2; mt++){
                    int r0 = wm*32 + mt*16 + (lane >> 2);
                    int c0 = kk + (lane & 3);
                    af[mt][0] = f2tf(Ab[r0*68 + c0]);
                    af[mt][1] = f2tf(Ab[(r0+8)*68 + c0]);
                    af[mt][2] = f2tf(Ab[r0*68 + c0 + 4]);
                    af[mt][3] = f2tf(Ab[(r0+8)*68 + c0 + 4]);
                }
                uint32_t bf[3][2];
                int n0 = wn*8 + (lane >> 2);
                #pragma unroll
                for (int g = 0; g < 3; g++){
                    bf[g][0] = __float_as_uint(Ws[(g*16 + n0)*260 + kbase + kk + (lane & 3)]);
                    bf[g][1] = __float_as_uint(Ws[(g*16 + n0)*260 + kbase + kk + 4 + (lane & 3)]);
                }
                #pragma unroll
                for (int g = 0; g < 3; g++)
                    #pragma unroll
                    for (int mt = 0; mt < 2; mt++)
                        mma8(acc[g][mt], af[mt], bf[g]);
            }
            __syncthreads();
        }

        const float* __restrict__ gi_t = g_GI + (size_t)t*N_DIM*G3;
        float* __restrict__ out_t = out + ((size_t)t*N_DIM)*ROW_OUT;
        #pragma unroll
        for (int mt = 0; mt < 2; mt++){
            #pragma unroll
            for (int dr = 0; dr < 2; dr++){
                int row = row0 + wm*32 + mt*16 + (lane >> 2) + dr*8;
                const float* gi = gi_t + (size_t)row*G3;
                #pragma unroll
                for (int dc = 0; dc < 2; dc++){
                    int c = cb0 + dc;
                    float gr = acc[0][mt][dr*2+dc] + (dc ? bR1 : bR0);
                    float gz = acc[1][mt][dr*2+dc] + (dc ? bZ1 : bZ0);
                    float gn = acc[2][mt][dr*2+dc] + (dc ? bN1 : bN0);
                    float r  = sigm(__ldg(&gi[c]) + gr);
                    float z  = sigm(__ldg(&gi[H_DIM + c]) + gz);
                    float nn = tanhf(__ldg(&gi[2*H_DIM + c]) + r*gn);
                    float hold = __ldcg(&hsrc[(size_t)row*H_DIM + c]);
                    float hnew = (1.f - z)*nn + z*hold;
                    __stcg(&hdst[(size_t)row*H_DIM + c], hnew);
                    out_t[(size_t)row*ROW_OUT + 4 + c] = hnew;
                }
            }
        }
        slab_sync(slab, 16);
    }
}

// ---------------- heads ----------------
__global__ void __launch_bounds__(256)
heads_kernel(float* __restrict__ out, const int* __restrict__ actions,
             const int* __restrict__ active, const float* __restrict__ p0,
             const float* __restrict__ pp0,
             const float* __restrict__ w_actor, const float* __restrict__ b_actor,
             const float* __restrict__ w_critic, const float* __restrict__ b_critic)
{
    int wid = threadIdx.x >> 5, lane = threadIdx.x & 31;
    size_t row = (size_t)blockIdx.x*8 + wid;
    float* orow = out + row*ROW_OUT;
    float hv[8];
    #pragma unroll
    for (int i = 0; i < 8; i++) hv[i] = orow[4 + lane + 32*i];

    float lg = 0.f;
    #pragma unroll
    for (int a = 0; a < NA_DIM; a++){
        float s = 0.f;
        #pragma unroll
        for (int i = 0; i < 8; i++) s += hv[i]*w_actor[a*H_DIM + lane + 32*i];
        #pragma unroll
        for (int o = 16; o > 0; o >>= 1) s += __shfl_xor_sync(0xffffffffu, s, o);
        if (lane == a) lg = s + b_actor[a];
    }
    float m = (lane < NA_DIM) ? lg : -1e30f;
    #pragma unroll
    for (int o = 16; o > 0; o >>= 1) m = fmaxf(m, __shfl_xor_sync(0xffffffffu, m, o));
    float e = (lane < NA_DIM) ? expf(lg - m) : 0.f;
    float den = e;
    #pragma unroll
    for (int o = 16; o > 0; o >>= 1) den += __shfl_xor_sync(0xffffffffu, den, o);
    if (lane < NA_DIM) orow[260 + lane] = e/den;

    float s = 0.f;
    #pragma unroll
    for (int i = 0; i < 8; i++) s += hv[i]*w_critic[lane + 32*i];
    #pragma unroll
    for (int o = 16; o > 0; o >>= 1) s += __shfl_xor_sync(0xffffffffu, s, o);

    int n = (int)(row & (N_DIM - 1));
    if (lane == 0)  orow[3]   = s + b_critic[0];
    if (lane == 16) orow[0]   = (float)actions[row];
    if (lane == 17) orow[1]   = p0[n];
    if (lane == 18) orow[2]   = (float)active[row];
    if (lane == 19) orow[276] = pp0[n*2];
    if (lane == 20) orow[277] = pp0[n*2 + 1];
}

// ---------------- launch ----------------
extern "C" void kernel_launch(void* const* d_in, const int* in_sizes, int n_in,
                              void* d_out, int out_size)
{
    (void)in_sizes; (void)n_in; (void)out_size;
    const float* condition = (const float*)d_in[0];
    const int*   active    = (const int*)d_in[1];
    const int*   lines     = (const int*)d_in[2];
    const int*   actions   = (const int*)d_in[3];
    const float* h0        = (const float*)d_in[4];
    const float* p0        = (const float*)d_in[5];
    const float* pp0       = (const float*)d_in[6];
    const float* embed     = (const float*)d_in[7];
    const float* wih_f = (const float*)d_in[8],  *whh_f = (const float*)d_in[9];
    const float* bih_f = (const float*)d_in[10], *bhh_f = (const float*)d_in[11];
    const float* wih_b = (const float*)d_in[12], *whh_b = (const float*)d_in[13];
    const float* bih_b = (const float*)d_in[14], *bhh_b = (const float*)d_in[15];
    const float* f_w0 = (const float*)d_in[16], *f_b0 = (const float*)d_in[17];
    const float* f_w1 = (const float*)d_in[18], *f_b1 = (const float*)d_in[19];
    const float* f_w2 = (const float*)d_in[20], *f_b2 = (const float*)d_in[21];
    const float* c_wih = (const float*)d_in[22], *c_whh = (const float*)d_in[23];
    const float* c_bih = (const float*)d_in[24], *c_bhh = (const float*)d_in[25];
    const float* w_critic = (const float*)d_in[26], *b_critic = (const float*)d_in[27];
    const float* w_actor  = (const float*)d_in[28], *b_actor  = (const float*)d_in[29];
    float* out = (float*)d_out;

    float *A0p, *A1p, *Rp, *GIp;
    cudaGetSymbolAddress((void**)&A0p, g_A0);
    cudaGetSymbolAddress((void**)&A1p, g_A1);
    cudaGetSymbolAddress((void**)&Rp,  g_Rproj);
    cudaGetSymbolAddress((void**)&GIp, g_GI);

    cudaFuncSetAttribute(enc_v2,
                         cudaFuncAttributeMaxDynamicSharedMemorySize, ENC_SMEM_BYTES);
    cudaFuncSetAttribute(main_gru_v5,
                         cudaFuncAttributeMaxDynamicSharedMemorySize, MAIN_SMEM_BYTES);
    cudaFuncSetAttribute(gemm_ff2<1>,
                         cudaFuncAttributeMaxDynamicSharedMemorySize, FF_SMEM_BYTES);
    cudaFuncSetAttribute(gemm_ff2<2>,
                         cudaFuncAttributeMaxDynamicSharedMemorySize, FF_SMEM_BYTES);

    // 0) gi tables + state init
    gi_tables<<<(2*NL_DIM*G3 + 255)/256, 256>>>(embed, wih_f, bih_f, wih_b, bih_b);
    init_state<<<4096, 256>>>(h0);

    // 1) persistent bidirectional encoder (per-slab barriers)
    enc_v2<<<dim3(8, 16), 512, ENC_SMEM_BYTES>>>(whh_f, bhh_f, whh_b, bhh_b, lines);

    // 2) Rproj = Hmem @ W0r^T (dedup over (w,n))
    gemm_plain<1, 0><<<dim3(4, 128), 256>>>(nullptr, f_w0 + 64, 576, nullptr, Rp, 512, 256, nullptr);
    // 3) A0 = relu(cond @ W0c^T + Rproj[active] + b0)
    gemm_plain<0, 3><<<dim3(4, 2048), 256>>>(condition, f_w0, 576, f_b0, A0p, 64, 256, active);
    // 4) A1 = relu(A0 @ w1^T + b1); A0 = relu(A1 @ w2^T + b2)
    gemm_ff2<1><<<dim3(4, 33), 512, FF_SMEM_BYTES>>>(A0p, f_w1, f_b1, A1p, 256, 1024);
    gemm_ff2<1><<<dim3(4, 33), 512, FF_SMEM_BYTES>>>(A1p, f_w2, f_b2, A0p, 256, 1024);
    // 5) GI = A0 @ c_wih^T + c_bih
    gemm_ff2<2><<<dim3(12, 11), 512, FF_SMEM_BYTES>>>(A0p, c_wih, c_bih, GIp, 768, 1024);

    // 6) persistent main GRU (per-slab barriers)
    main_gru_v5<<<dim3(16, 8), 256, MAIN_SMEM_BYTES>>>(c_whh, c_bhh, out);

    // 7) heads + scalar fields
    heads_kernel<<<TN/8, 256>>>(out, actions, active, p0, pp0,
                                w_actor, b_actor, w_critic, b_critic);
}

// round 7
// speedup vs baseline: 1.9549x; 1.3012x over previous
#include <cuda_runtime.h>
#include <math.h>
#include <stdint.h>

#define T_DIM 256
#define N_DIM 1024
#define H_DIM 256
#define L_DIM 16
#define NL_DIM 32
#define C_DIM 64
#define NA_DIM 16
#define ROW_OUT 278
#define G3 768
#define LN (L_DIM*N_DIM)          /* 16384 */
#define TN (T_DIM*N_DIM)          /* 262144 */

// ---------------- scratch ----------------
__device__ float g_giF[NL_DIM*G3];
__device__ float g_giB[NL_DIM*G3];
__device__ float g_Hf[2][(size_t)LN*H_DIM];
__device__ float g_Hb[2][(size_t)LN*H_DIM];
__device__ float g_Rproj[(size_t)LN*H_DIM];
__device__ float g_A0[(size_t)TN*H_DIM];
__device__ float g_A1[(size_t)TN*H_DIM];
__device__ float g_GI[(size_t)TN*G3];
__device__ float g_hm[2][N_DIM*H_DIM];
__device__ unsigned g_slabc[16][32];
__device__ unsigned g_slabg[16][32];

// ---------------- helpers ----------------
__device__ __forceinline__ uint32_t f2tf(float x){
    uint32_t r; asm("cvt.rna.tf32.f32 %0, %1;" : "=r"(r) : "f"(x)); return r;
}
__device__ __forceinline__ void mma8(float* c, const uint32_t* a, const uint32_t* b){
    asm volatile("mma.sync.aligned.m16n8k8.row.col.f32.tf32.tf32.f32 "
        "{%0,%1,%2,%3},{%4,%5,%6,%7},{%8,%9},{%0,%1,%2,%3};"
        : "+f"(c[0]), "+f"(c[1]), "+f"(c[2]), "+f"(c[3])
        : "r"(a[0]), "r"(a[1]), "r"(a[2]), "r"(a[3]), "r"(b[0]), "r"(b[1]));
}
__device__ __forceinline__ float sigm(float x){ return 1.f/(1.f+expf(-x)); }
__device__ __forceinline__ void cp16(void* smem_dst, const void* gsrc){
    uint32_t s = (uint32_t)__cvta_generic_to_shared(smem_dst);
    asm volatile("cp.async.cg.shared.global [%0], [%1], 16;" :: "r"(s), "l"(gsrc));
}
__device__ __forceinline__ void cp_commit(){ asm volatile("cp.async.commit_group;"); }
template<int N> __device__ __forceinline__ void cp_wait(){
    asm volatile("cp.async.wait_group %0;" :: "n"(N));
}

__device__ __forceinline__ void slab_sync(int slab, unsigned nb){
    __syncthreads();
    if (threadIdx.x == 0){
        volatile unsigned* genp = &g_slabg[slab][0];
        unsigned old = *genp;
        __threadfence();
        if (atomicAdd(&g_slabc[slab][0], 1u) == nb - 1u){
            g_slabc[slab][0] = 0u;
            __threadfence();
            *genp = old + 1u;
        } else {
            while (*genp == old) { }
            __threadfence();
        }
    }
    __syncthreads();
}

// ---------------- gi tables ----------------
__global__ void gi_tables(const float* __restrict__ embed,
                          const float* __restrict__ wihF, const float* __restrict__ bihF,
                          const float* __restrict__ wihB, const float* __restrict__ bihB)
{
    int idx = blockIdx.x*blockDim.x + threadIdx.x;
    if (idx >= 2*NL_DIM*G3) return;
    int dir = idx / (NL_DIM*G3);
    int rem = idx % (NL_DIM*G3);
    int e = rem / G3, j = rem % G3;
    const float* wih = dir ? wihB : wihF;
    const float* bih = dir ? bihB : bihF;
    float s = bih[j];
    const float* em = embed + e*H_DIM;
    const float* w  = wih + (size_t)j*H_DIM;
    #pragma unroll 8
    for (int k = 0; k < H_DIM; k++) s += em[k]*w[k];
    (dir ? g_giB : g_giF)[rem] = s;
}

// ---------------- init ----------------
__global__ void init_state(const float* __restrict__ h0)
{
    size_t stride = (size_t)gridDim.x*blockDim.x;
    size_t i0 = (size_t)blockIdx.x*blockDim.x + threadIdx.x;
    size_t HS = (size_t)LN*H_DIM;
    for (size_t p = i0; p < HS; p += stride){ g_Hf[0][p] = 0.f; g_Hb[0][p] = 0.f; }
    for (size_t p = i0; p < (size_t)N_DIM*H_DIM; p += stride) g_hm[0][p] = h0[p];
}

// ---------------- plain tf32 GEMM (Rproj + layer0) ----------------
template<int ALOAD, int EPI>
__global__ void __launch_bounds__(256)
gemm_plain(const float* __restrict__ A, const float* __restrict__ B, int ldb,
           const float* __restrict__ bias, float* __restrict__ out,
           int K, int NC, const int* __restrict__ active)
{
    __shared__ float As[128][20];
    __shared__ float Bs[64][20];
    const int tid = threadIdx.x, lane = tid & 31, wid = tid >> 5;
    const int wm = wid >> 1, wn = wid & 1;
    const int brow = blockIdx.y, bcol = blockIdx.x;
    float acc[2][4][4];
    #pragma unroll
    for (int a = 0; a < 2; a++)
        #pragma unroll
        for (int b = 0; b < 4; b++)
            #pragma unroll
            for (int c = 0; c < 4; c++) acc[a][b][c] = 0.f;

    for (int k0 = 0; k0 < K; k0 += 16){
        #pragma unroll
        for (int i = tid; i < 2048; i += 256){
            int r = i >> 4, c = i & 15;
            int row = brow*128 + r; int k = k0 + c;
            float v;
            if (ALOAD == 0) v = A[(size_t)row*K + k];
            else v = (k < H_DIM) ? g_Hf[0][(size_t)row*H_DIM + k]
                                 : g_Hb[0][(size_t)row*H_DIM + (k - H_DIM)];
            As[r][c] = __uint_as_float(f2tf(v));
        }
        #pragma unroll
        for (int i = tid; i < 1024; i += 256){
            int n = i >> 4, c = i & 15;
            Bs[n][c] = __uint_as_float(f2tf(B[(size_t)(bcol*64 + n)*ldb + k0 + c]));
        }
        __syncthreads();
        #pragma unroll
        for (int kk = 0; kk < 16; kk += 8){
            uint32_t af[2][4], bf[4][2];
            #pragma unroll
            for (int mt = 0; mt < 2; mt++){
                int r0 = wm*32 + mt*16 + (lane >> 2);
                int c0 = kk + (lane & 3);
                af[mt][0] = __float_as_uint(As[r0][c0]);
                af[mt][1] = __float_as_uint(As[r0+8][c0]);
                af[mt][2] = __float_as_uint(As[r0][c0+4]);
                af[mt][3] = __float_as_uint(As[r0+8][c0+4]);
            }
            #pragma unroll
            for (int nt = 0; nt < 4; nt++){
                int n0 = wn*32 + nt*8 + (lane >> 2);
                bf[nt][0] = __float_as_uint(Bs[n0][kk + (lane & 3)]);
                bf[nt][1] = __float_as_uint(Bs[n0][kk + 4 + (lane & 3)]);
            }
            #pragma unroll
            for (int mt = 0; mt < 2; mt++)
                #pragma unroll
                for (int nt = 0; nt < 4; nt++)
                    mma8(acc[mt][nt], af[mt], bf[nt]);
        }
        __syncthreads();
    }
    #pragma unroll
    for (int mt = 0; mt < 2; mt++){
        #pragma unroll
        for (int nt = 0; nt < 4; nt++){
            int rbase = brow*128 + wm*32 + mt*16 + (lane >> 2);
            int cbase = bcol*64 + wn*32 + nt*8 + (lane & 3)*2;
            #pragma unroll
            for (int dr = 0; dr < 2; dr++){
                #pragma unroll
                for (int dc = 0; dc < 2; dc++){
                    int rr = rbase + dr*8, cc = cbase + dc;
                    float v = acc[mt][nt][dr*2 + dc];
                    if (EPI == 3){
                        int n = rr & (N_DIM - 1);
                        int w = active[rr];
                        v += bias[cc];
                        v += g_Rproj[(size_t)(w*N_DIM + n)*H_DIM + cc];
                        v = fmaxf(v, 0.f);
                    }
                    out[(size_t)rr*NC + cc] = v;
                }
            }
        }
    }
}

// ---------------- persistent encoder v4: single-sync pipeline, per-slab barrier -----
#define ENC_W_FLOATS (3*32*260)            /* 24960 */
#define ENC_A_FLOATS (2*256*36)            /* 18432 */
#define ENC_SMEM_BYTES ((ENC_W_FLOATS + ENC_A_FLOATS)*4)

__global__ void __launch_bounds__(512, 1)
enc_v4(const float* __restrict__ whF, const float* __restrict__ bhF,
       const float* __restrict__ whB, const float* __restrict__ bhB,
       const int* __restrict__ lines)
{
    extern __shared__ float sm[];
    float* Ws = sm;
    float* As = sm + ENC_W_FLOATS;
    const int tid = threadIdx.x, lane = tid & 31, wid = tid >> 5;
    const int wm = wid >> 1, wn = wid & 1;
    const int bcol = blockIdx.x;                // 0..7
    const int slab = blockIdx.y;                // 0..15
    const bool dirF = (slab < 8);
    const float* __restrict__ W  = dirF ? whF : whB;
    const float* __restrict__ bh = dirF ? bhF : bhB;
    const float* __restrict__ giT = dirF ? g_giF : g_giB;
    const int lrow0 = (dirF ? slab : slab - 8) * 2048;

    for (int i = tid; i < 3*32*H_DIM; i += 512){
        int g = i >> 13, rem = i & 8191;
        int c = rem >> 8, k = rem & 255;
        Ws[(g*32 + c)*260 + k] =
            __uint_as_float(f2tf(W[(size_t)(g*H_DIM + bcol*32 + c)*H_DIM + k]));
    }
    __syncthreads();

    for (int t = 0; t < L_DIM; t++){
        const float* __restrict__ hsrc = dirF ? g_Hf[t & 1] : g_Hb[t & 1];
        float* __restrict__ hdst = dirF ? g_Hf[(t + 1) & 1] : g_Hb[(t + 1) & 1];

        auto stage = [&](int p){
            int chunk = p >> 3, kb = p & 7, buf = p & 1;
            const float* src = hsrc + (size_t)(lrow0 + chunk*256)*H_DIM + kb*32;
            float* dst = As + buf*256*36;
            #pragma unroll
            for (int i = tid; i < 2048; i += 512){
                int r = i >> 3, q = (i & 7)*4;
                cp16(&dst[r*36 + q], src + (size_t)r*H_DIM + q);
            }
            cp_commit();
        };

        float acc[3][2][2][4];
        stage(0);
        for (int p = 0; p < 64; p++){
            cp_wait<0>();
            __syncthreads();
            if (p + 1 < 64) stage(p + 1);
            const int kb = p & 7;
            if (kb == 0){
                #pragma unroll
                for (int g = 0; g < 3; g++)
                    #pragma unroll
                    for (int a = 0; a < 2; a++)
                        #pragma unroll
                        for (int b = 0; b < 2; b++)
                            #pragma unroll
                            for (int c = 0; c < 4; c++) acc[g][a][b][c] = 0.f;
            }
            const float* Ab = As + (p & 1)*256*36;
            const int kbase = kb*32;
            #pragma unroll
            for (int kk = 0; kk < 32; kk += 8){
                uint32_t af[2][4];
                #pragma unroll
                for (int mt = 0; mt < 2; mt++){
                    int r0 = wm*32 + mt*16 + (lane >> 2);
                    int c0 = kk + (lane & 3);
                    af[mt][0] = f2tf(Ab[r0*36 + c0]);
                    af[mt][1] = f2tf(Ab[(r0+8)*36 + c0]);
                    af[mt][2] = f2tf(Ab[r0*36 + c0 + 4]);
                    af[mt][3] = f2tf(Ab[(r0+8)*36 + c0 + 4]);
                }
                uint32_t bf[3][2][2];
                #pragma unroll
                for (int g = 0; g < 3; g++)
                    #pragma unroll
                    for (int nt = 0; nt < 2; nt++){
                        int n0 = wn*16 + nt*8 + (lane >> 2);
                        bf[g][nt][0] = __float_as_uint(Ws[(g*32 + n0)*260 + kbase + kk + (lane & 3)]);
                        bf[g][nt][1] = __float_as_uint(Ws[(g*32 + n0)*260 + kbase + kk + 4 + (lane & 3)]);
                    }
                #pragma unroll
                for (int g = 0; g < 3; g++)
                    #pragma unroll
                    for (int mt = 0; mt < 2; mt++)
                        #pragma unroll
                        for (int nt = 0; nt < 2; nt++)
                            mma8(acc[g][mt][nt], af[mt], bf[g][nt]);
            }

            if (kb == 7){
                const int base = lrow0 + (p >> 3)*256;
                #pragma unroll
                for (int mt = 0; mt < 2; mt++){
                    #pragma unroll
                    for (int nt = 0; nt < 2; nt++){
                        #pragma unroll
                        for (int dr = 0; dr < 2; dr++){
                            int lr = base + wm*32 + mt*16 + (lane >> 2) + dr*8;
                            int iroll = lr >> 10;
                            int nb = lr & (N_DIM - 1);
                            int l = dirF ? ((iroll + t) & 15) : ((iroll + 15 - t) & 15);
                            const float* gi = giT + __ldg(&lines[nb*L_DIM + l])*G3;
                            int hc0 = bcol*32 + wn*16 + nt*8 + (lane & 3)*2;
                            float2 gv0 = __ldg((const float2*)&gi[hc0]);
                            float2 gv1 = __ldg((const float2*)&gi[H_DIM + hc0]);
                            float2 gv2 = __ldg((const float2*)&gi[2*H_DIM + hc0]);
                            float2 hold = __ldcg((const float2*)&hsrc[(size_t)lr*H_DIM + hc0]);
                            float2 hout;
                            #pragma unroll
                            for (int dc = 0; dc < 2; dc++){
                                int hc = hc0 + dc;
                                float gr = acc[0][mt][nt][dr*2+dc] + bh[hc];
                                float gz = acc[1][mt][nt][dr*2+dc] + bh[H_DIM + hc];
                                float gn = acc[2][mt][nt][dr*2+dc] + bh[2*H_DIM + hc];
                                float r  = sigm((dc ? gv0.y : gv0.x) + gr);
                                float z  = sigm((dc ? gv1.y : gv1.x) + gz);
                                float nn = tanhf((dc ? gv2.y : gv2.x) + r*gn);
                                float ho = dc ? hold.y : hold.x;
                                float hnew = (1.f - z)*nn + z*ho;
                                if (dc) hout.y = hnew; else hout.x = hnew;
                            }
                            __stcg((float2*)&hdst[(size_t)lr*H_DIM + hc0], hout);
                        }
                    }
                }
            }
        }
        slab_sync(slab, 8);
    }
}

// ---------------- feed-forward GEMM: K-chunk 64, single-sync ----------
#define FF_W_FLOATS (64*260)               /* 16640 */
#define FF_A_FLOATS (2*256*68)             /* 34816 */
#define FF_SMEM_BYTES ((FF_W_FLOATS + FF_A_FLOATS)*4)

template<int EPI>
__global__ void __launch_bounds__(512, 1)
gemm_ff2(const float* __restrict__ A, const float* __restrict__ W,
         const float* __restrict__ bias, float* __restrict__ out,
         int NC, int nrt)
{
    extern __shared__ float sm[];
    float* Ws = sm;
    float* As = sm + FF_W_FLOATS;
    const int tid = threadIdx.x, lane = tid & 31, wid = tid >> 5;
    const int wm = wid >> 1, wn = wid & 1;
    const int bcol = blockIdx.x;

    for (int i = tid; i < 64*H_DIM; i += 512){
        int c = i >> 8, k = i & 255;
        Ws[c*260 + k] = __uint_as_float(f2tf(W[(size_t)(bcol*64 + c)*H_DIM + k]));
    }
    __syncthreads();

    const int nch = (nrt - (int)blockIdx.y + (int)gridDim.y - 1) / (int)gridDim.y;
    if (nch <= 0) return;
    const int total = nch*4;

    auto stage = [&](int p){
        int ci = p >> 2, kb = p & 3, buf = p & 1;
        int rt = blockIdx.y + ci*gridDim.y;
        const float* src = A + (size_t)rt*256*H_DIM + kb*64;
        float* dst = As + buf*256*68;
        #pragma unroll
        for (int i = tid; i < 4096; i += 512){
            int r = i >> 4, q = (i & 15)*4;
            cp16(&dst[r*68 + q], src + (size_t)r*H_DIM + q);
        }
        cp_commit();
    };

    float acc[2][4][4];
    stage(0);
    for (int p = 0; p < total; p++){
        cp_wait<0>();
        __syncthreads();
        if (p + 1 < total) stage(p + 1);
        const int kb = p & 3;
        if (kb == 0){
            #pragma unroll
            for (int a = 0; a < 2; a++)
                #pragma unroll
                for (int b = 0; b < 4; b++)
                    #pragma unroll
                    for (int c = 0; c < 4; c++) acc[a][b][c] = 0.f;
        }
        const float* Ab = As + (p & 1)*256*68;
        const int kbase = kb*64;
        #pragma unroll
        for (int kk = 0; kk < 64; kk += 8){
            uint32_t af[2][4];
            #pragma unroll
            for (int mt = 0; mt < 2; mt++){
                int r0 = wm*32 + mt*16 + (lane >> 2);
                int c0 = kk + (lane & 3);
                af[mt][0] = f2tf(Ab[r0*68 + c0]);
                af[mt][1] = f2tf(Ab[(r0+8)*68 + c0]);
                af[mt][2] = f2tf(Ab[r0*68 + c0 + 4]);
                af[mt][3] = f2tf(Ab[(r0+8)*68 + c0 + 4]);
            }
            uint32_t bf[4][2];
            #pragma unroll
            for (int nt = 0; nt < 4; nt++){
                int n0 = wn*32 + nt*8 + (lane >> 2);
                bf[nt][0] = __float_as_uint(Ws[n0*260 + kbase + kk + (lane & 3)]);
                bf[nt][1] = __float_as_uint(Ws[n0*260 + kbase + kk + 4 + (lane & 3)]);
            }
            #pragma unroll
            for (int mt = 0; mt < 2; mt++)
                #pragma unroll
                for (int nt = 0; nt < 4; nt++)
                    mma8(acc[mt][nt], af[mt], bf[nt]);
        }

        if (kb == 3){
            int rt = blockIdx.y + (p >> 2)*gridDim.y;
            #pragma unroll
            for (int mt = 0; mt < 2; mt++){
                #pragma unroll
                for (int nt = 0; nt < 4; nt++){
                    #pragma unroll
                    for (int dr = 0; dr < 2; dr++){
                        int rr = rt*256 + wm*32 + mt*16 + (lane >> 2) + dr*8;
                        #pragma unroll
                        for (int dc = 0; dc < 2; dc++){
                            int cc = bcol*64 + wn*32 + nt*8 + (lane & 3)*2 + dc;
                            float v = acc[mt][nt][dr*2 + dc] + bias[cc];
                            if (EPI == 1) v = fmaxf(v, 0.f);
                            out[(size_t)rr*NC + cc] = v;
                        }
                    }
                }
            }
        }
    }
}

// ---------------- persistent main GRU v6: single-stage full-K, gi prefetch ---------
// grid (16 bcol, 8 slab), 256 thr. CTA: 128 rows x 16 h-cols x 3 gates.
#define MAIN_W_FLOATS (3*16*260)           /* 12480 */
#define MAIN_A_FLOATS (128*260)            /* 33280 */
#define MAIN_G_FLOATS (128*52)             /* 6656  */
#define MAIN_SMEM_BYTES ((MAIN_W_FLOATS + MAIN_A_FLOATS + MAIN_G_FLOATS)*4)

__global__ void __launch_bounds__(256, 1)
main_gru_v6(const float* __restrict__ whh, const float* __restrict__ bhh,
            float* __restrict__ out)
{
    extern __shared__ float sm[];
    float* Ws  = sm;
    float* As  = sm + MAIN_W_FLOATS;
    float* GIs = sm + MAIN_W_FLOATS + MAIN_A_FLOATS;
    const int tid = threadIdx.x, lane = tid & 31, wid = tid >> 5;
    const int wm = wid >> 1, wn = wid & 1;
    const int bcol = blockIdx.x;          // 0..15
    const int slab = blockIdx.y;          // 0..7
    const int row0 = slab*128;

    for (int i = tid; i < 3*16*H_DIM; i += 256){
        int g = i >> 12, rem = i & 4095;
        int c = rem >> 8, k = rem & 255;
        Ws[(g*16 + c)*260 + k] =
            __uint_as_float(f2tf(whh[(size_t)(g*H_DIM + bcol*16 + c)*H_DIM + k]));
    }
    const int ccl = wn*8 + (lane & 3)*2;          // local col (0..15), even
    const int cb0 = bcol*16 + ccl;                // global h col
    float bR0 = bhh[cb0],           bR1 = bhh[cb0 + 1];
    float bZ0 = bhh[H_DIM + cb0],   bZ1 = bhh[H_DIM + cb0 + 1];
    float bN0 = bhh[2*H_DIM + cb0], bN1 = bhh[2*H_DIM + cb0 + 1];

    // prologue: stage gi(0)
    {
        const float* gsrc = g_GI + (size_t)row0*G3 + bcol*16;
        #pragma unroll
        for (int i = tid; i < 1536; i += 256){
            int r = i / 12, j = i % 12;
            int g = j >> 2, qj = j & 3;
            cp16(&GIs[r*52 + g*16 + qj*4], gsrc + (size_t)r*G3 + g*H_DIM + qj*4);
        }
        cp_commit();
    }

    slab_sync(slab, 16);   // also orders init_state writes (harmless extra)

    for (int t = 0; t < T_DIM; t++){
        const float* __restrict__ hsrc = g_hm[t & 1];
        float* __restrict__ hdst = g_hm[(t + 1) & 1];

        // stage full A tile (128 rows x 256 K)
        {
            const float* src = hsrc + (size_t)row0*H_DIM;
            #pragma unroll
            for (int i = tid; i < 8192; i += 256){
                int r = i >> 6, q = (i & 63)*4;
                cp16(&As[r*260 + q], src + (size_t)r*H_DIM + q);
            }
            cp_commit();
        }
        cp_wait<0>();
        __syncthreads();

        float acc[3][2][4];
        #pragma unroll
        for (int g = 0; g < 3; g++)
            #pragma unroll
            for (int m = 0; m < 2; m++)
                #pragma unroll
                for (int c = 0; c < 4; c++) acc[g][m][c] = 0.f;

        #pragma unroll 4
        for (int kk = 0; kk < H_DIM; kk += 8){
            uint32_t af[2][4];
            #pragma unroll
            for (int mt = 0; mt < 2; mt++){
                int r0 = wm*32 + mt*16 + (lane >> 2);
                int c0 = kk + (lane & 3);
                af[mt][0] = f2tf(As[r0*260 + c0]);
                af[mt][1] = f2tf(As[(r0+8)*260 + c0]);
                af[mt][2] = f2tf(As[r0*260 + c0 + 4]);
                af[mt][3] = f2tf(As[(r0+8)*260 + c0 + 4]);
            }
            uint32_t bf[3][2];
            int n0 = wn*8 + (lane >> 2);
            #pragma unroll
            for (int g = 0; g < 3; g++){
                bf[g][0] = __float_as_uint(Ws[(g*16 + n0)*260 + kk + (lane & 3)]);
                bf[g][1] = __float_as_uint(Ws[(g*16 + n0)*260 + kk + 4 + (lane & 3)]);
            }
            #pragma unroll
            for (int g = 0; g < 3; g++)
                #pragma unroll
                for (int mt = 0; mt < 2; mt++)
                    mma8(acc[g][mt], af[mt], bf[g]);
        }

        // epilogue: gi + hold from SMEM, float2 stores
        float* __restrict__ out_t = out + ((size_t)t*N_DIM)*ROW_OUT;
        #pragma unroll
        for (int mt = 0; mt < 2; mt++){
            #pragma unroll
            for (int dr = 0; dr < 2; dr++){
                int rl = wm*32 + mt*16 + (lane >> 2) + dr*8;
                int row = row0 + rl;
                float2 gv0 = *(const float2*)&GIs[rl*52 + ccl];
                float2 gv1 = *(const float2*)&GIs[rl*52 + 16 + ccl];
                float2 gv2 = *(const float2*)&GIs[rl*52 + 32 + ccl];
                float2 hold = *(const float2*)&As[rl*260 + cb0];
                float2 hout;
                #pragma unroll
                for (int dc = 0; dc < 2; dc++){
                    float gr = acc[0][mt][dr*2+dc] + (dc ? bR1 : bR0);
                    float gz = acc[1][mt][dr*2+dc] + (dc ? bZ1 : bZ0);
                    float gn = acc[2][mt][dr*2+dc] + (dc ? bN1 : bN0);
                    float r  = sigm((dc ? gv0.y : gv0.x) + gr);
                    float z  = sigm((dc ? gv1.y : gv1.x) + gz);
                    float nn = tanhf((dc ? gv2.y : gv2.x) + r*gn);
                    float ho = dc ? hold.y : hold.x;
                    float hnew = (1.f - z)*nn + z*ho;
                    if (dc) hout.y = hnew; else hout.x = hnew;
                }
                __stcg((float2*)&hdst[(size_t)row*H_DIM + cb0], hout);
                *(float2*)&out_t[(size_t)row*ROW_OUT + 4 + cb0] = hout;
            }
        }

        // prefetch gi(t+1) before the barrier (overlaps barrier + next A stage)
        __syncthreads();
        if (t + 1 < T_DIM){
            const float* gsrc = g_GI + ((size_t)(t + 1)*N_DIM + row0)*G3 + bcol*16;
            #pragma unroll
            for (int i = tid; i < 1536; i += 256){
                int r = i / 12, j = i % 12;
                int g = j >> 2, qj = j & 3;
                cp16(&GIs[r*52 + g*16 + qj*4], gsrc + (size_t)r*G3 + g*H_DIM + qj*4);
            }
            cp_commit();
        }
        slab_sync(slab, 16);
    }
}

// ---------------- heads ----------------
__global__ void __launch_bounds__(256)
heads_kernel(float* __restrict__ out, const int* __restrict__ actions,
             const int* __restrict__ active, const float* __restrict__ p0,
             const float* __restrict__ pp0,
             const float* __restrict__ w_actor, const float* __restrict__ b_actor,
             const float* __restrict__ w_critic, const float* __restrict__ b_critic)
{
    int wid = threadIdx.x >> 5, lane = threadIdx.x & 31;
    size_t row = (size_t)blockIdx.x*8 + wid;
    float* orow = out + row*ROW_OUT;
    float hv[8];
    #pragma unroll
    for (int i = 0; i < 8; i++) hv[i] = orow[4 + lane + 32*i];

    float lg = 0.f;
    #pragma unroll
    for (int a = 0; a < NA_DIM; a++){
        float s = 0.f;
        #pragma unroll
        for (int i = 0; i < 8; i++) s += hv[i]*w_actor[a*H_DIM + lane + 32*i];
        #pragma unroll
        for (int o = 16; o > 0; o >>= 1) s += __shfl_xor_sync(0xffffffffu, s, o);
        if (lane == a) lg = s + b_actor[a];
    }
    float m = (lane < NA_DIM) ? lg : -1e30f;
    #pragma unroll
    for (int o = 16; o > 0; o >>= 1) m = fmaxf(m, __shfl_xor_sync(0xffffffffu, m, o));
    float e = (lane < NA_DIM) ? expf(lg - m) : 0.f;
    float den = e;
    #pragma unroll
    for (int o = 16; o > 0; o >>= 1) den += __shfl_xor_sync(0xffffffffu, den, o);
    if (lane < NA_DIM) orow[260 + lane] = e/den;

    float s = 0.f;
    #pragma unroll
    for (int i = 0; i < 8; i++) s += hv[i]*w_critic[lane + 32*i];
    #pragma unroll
    for (int o = 16; o > 0; o >>= 1) s += __shfl_xor_sync(0xffffffffu, s, o);

    int n = (int)(row & (N_DIM - 1));
    if (lane == 0)  orow[3]   = s + b_critic[0];
    if (lane == 16) orow[0]   = (float)actions[row];
    if (lane == 17) orow[1]   = p0[n];
    if (lane == 18) orow[2]   = (float)active[row];
    if (lane == 19) orow[276] = pp0[n*2];
    if (lane == 20) orow[277] = pp0[n*2 + 1];
}

// ---------------- launch ----------------
extern "C" void kernel_launch(void* const* d_in, const int* in_sizes, int n_in,
                              void* d_out, int out_size)
{
    (void)in_sizes; (void)n_in; (void)out_size;
    const float* condition = (const float*)d_in[0];
    const int*   active    = (const int*)d_in[1];
    const int*   lines     = (const int*)d_in[2];
    const int*   actions   = (const int*)d_in[3];
    const float* h0        = (const float*)d_in[4];
    const float* p0        = (const float*)d_in[5];
    const float* pp0       = (const float*)d_in[6];
    const float* embed     = (const float*)d_in[7];
    const float* wih_f = (const float*)d_in[8],  *whh_f = (const float*)d_in[9];
    const float* bih_f = (const float*)d_in[10], *bhh_f = (const float*)d_in[11];
    const float* wih_b = (const float*)d_in[12], *whh_b = (const float*)d_in[13];
    const float* bih_b = (const float*)d_in[14], *bhh_b = (const float*)d_in[15];
    const float* f_w0 = (const float*)d_in[16], *f_b0 = (const float*)d_in[17];
    const float* f_w1 = (const float*)d_in[18], *f_b1 = (const float*)d_in[19];
    const float* f_w2 = (const float*)d_in[20], *f_b2 = (const float*)d_in[21];
    const float* c_wih = (const float*)d_in[22], *c_whh = (const float*)d_in[23];
    const float* c_bih = (const float*)d_in[24], *c_bhh = (const float*)d_in[25];
    const float* w_critic = (const float*)d_in[26], *b_critic = (const float*)d_in[27];
    const float* w_actor  = (const float*)d_in[28], *b_actor  = (const float*)d_in[29];
    float* out = (float*)d_out;

    float *A0p, *A1p, *Rp, *GIp;
    cudaGetSymbolAddress((void**)&A0p, g_A0);
    cudaGetSymbolAddress((void**)&A1p, g_A1);
    cudaGetSymbolAddress((void**)&Rp,  g_Rproj);
    cudaGetSymbolAddress((void**)&GIp, g_GI);

    cudaFuncSetAttribute(enc_v4,
                         cudaFuncAttributeMaxDynamicSharedMemorySize, ENC_SMEM_BYTES);
    cudaFuncSetAttribute(main_gru_v6,
                         cudaFuncAttributeMaxDynamicSharedMemorySize, MAIN_SMEM_BYTES);
    cudaFuncSetAttribute(gemm_ff2<1>,
                         cudaFuncAttributeMaxDynamicSharedMemorySize, FF_SMEM_BYTES);
    cudaFuncSetAttribute(gemm_ff2<2>,
                         cudaFuncAttributeMaxDynamicSharedMemorySize, FF_SMEM_BYTES);

    // 0) gi tables + state init
    gi_tables<<<(2*NL_DIM*G3 + 255)/256, 256>>>(embed, wih_f, bih_f, wih_b, bih_b);
    init_state<<<4096, 256>>>(h0);

    // 1) persistent bidirectional encoder (per-slab barriers)
    enc_v4<<<dim3(8, 16), 512, ENC_SMEM_BYTES>>>(whh_f, bhh_f, whh_b, bhh_b, lines);

    // 2) Rproj = Hmem @ W0r^T (dedup over (w,n))
    gemm_plain<1, 0><<<dim3(4, 128), 256>>>(nullptr, f_w0 + 64, 576, nullptr, Rp, 512, 256, nullptr);
    // 3) A0 = relu(cond @ W0c^T + Rproj[active] + b0)
    gemm_plain<0, 3><<<dim3(4, 2048), 256>>>(condition, f_w0, 576, f_b0, A0p, 64, 256, active);
    // 4) A1 = relu(A0 @ w1^T + b1); A0 = relu(A1 @ w2^T + b2)
    gemm_ff2<1><<<dim3(4, 33), 512, FF_SMEM_BYTES>>>(A0p, f_w1, f_b1, A1p, 256, 1024);
    gemm_ff2<1><<<dim3(4, 33), 512, FF_SMEM_BYTES>>>(A1p, f_w2, f_b2, A0p, 256, 1024);
    // 5) GI = A0 @ c_wih^T + c_bih
    gemm_ff2<2><<<dim3(12, 11), 512, FF_SMEM_BYTES>>>(A0p, c_wih, c_bih, GIp, 768, 1024);

    // 6) persistent main GRU (single-stage, gi prefetch, per-slab barriers)
    main_gru_v6<<<dim3(16, 8), 256, MAIN_SMEM_BYTES>>>(c_whh, c_bhh, out);

    // 7) heads + scalar fields
    heads_kernel<<<TN/8, 256>>>(out, actions, active, p0, pp0,
                                w_actor, b_actor, w_critic, b_critic);
}

// round 8
// speedup vs baseline: 2.3233x; 1.1884x over previous
#include <cuda_runtime.h>
#include <math.h>
#include <stdint.h>

#define T_DIM 256
#define N_DIM 1024
#define H_DIM 256
#define L_DIM 16
#define NL_DIM 32
#define C_DIM 64
#define NA_DIM 16
#define ROW_OUT 278
#define G3 768
#define LN (L_DIM*N_DIM)          /* 16384 */
#define TN (T_DIM*N_DIM)          /* 262144 */

// ---------------- scratch ----------------
__device__ float g_giF[NL_DIM*G3];
__device__ float g_giB[NL_DIM*G3];
__device__ float g_Hf[2][(size_t)LN*H_DIM];
__device__ float g_Hb[2][(size_t)LN*H_DIM];
__device__ float g_Rproj[(size_t)LN*H_DIM];
__device__ float g_A0[(size_t)TN*H_DIM];
__device__ float g_A1[(size_t)TN*H_DIM];
__device__ float g_GI[(size_t)TN*G3];
__device__ float g_hm[2][N_DIM*H_DIM];
__device__ unsigned g_slabc[16][32];
__device__ unsigned g_slabg[16][32];

// ---------------- helpers ----------------
__device__ __forceinline__ uint32_t f2tf(float x){
    uint32_t r; asm("cvt.rna.tf32.f32 %0, %1;" : "=r"(r) : "f"(x)); return r;
}
__device__ __forceinline__ void mma8(float* c, const uint32_t* a, const uint32_t* b){
    asm volatile("mma.sync.aligned.m16n8k8.row.col.f32.tf32.tf32.f32 "
        "{%0,%1,%2,%3},{%4,%5,%6,%7},{%8,%9},{%0,%1,%2,%3};"
        : "+f"(c[0]), "+f"(c[1]), "+f"(c[2]), "+f"(c[3])
        : "r"(a[0]), "r"(a[1]), "r"(a[2]), "r"(a[3]), "r"(b[0]), "r"(b[1]));
}
__device__ __forceinline__ float sigm(float x){ return 1.f/(1.f+expf(-x)); }
__device__ __forceinline__ void cp16(void* smem_dst, const void* gsrc){
    uint32_t s = (uint32_t)__cvta_generic_to_shared(smem_dst);
    asm volatile("cp.async.cg.shared.global [%0], [%1], 16;" :: "r"(s), "l"(gsrc));
}
__device__ __forceinline__ void cp_commit(){ asm volatile("cp.async.commit_group;"); }
template<int N> __device__ __forceinline__ void cp_wait(){
    asm volatile("cp.async.wait_group %0;" :: "n"(N));
}

__device__ __forceinline__ void slab_sync(int slab, unsigned nb){
    __syncthreads();
    if (threadIdx.x == 0){
        volatile unsigned* genp = &g_slabg[slab][0];
        unsigned old = *genp;
        __threadfence();
        if (atomicAdd(&g_slabc[slab][0], 1u) == nb - 1u){
            g_slabc[slab][0] = 0u;
            __threadfence();
            *genp = old + 1u;
        } else {
            while (*genp == old) { }
            __threadfence();
        }
    }
    __syncthreads();
}

// ---------------- gi tables ----------------
__global__ void gi_tables(const float* __restrict__ embed,
                          const float* __restrict__ wihF, const float* __restrict__ bihF,
                          const float* __restrict__ wihB, const float* __restrict__ bihB)
{
    int idx = blockIdx.x*blockDim.x + threadIdx.x;
    if (idx >= 2*NL_DIM*G3) return;
    int dir = idx / (NL_DIM*G3);
    int rem = idx % (NL_DIM*G3);
    int e = rem / G3, j = rem % G3;
    const float* wih = dir ? wihB : wihF;
    const float* bih = dir ? bihB : bihF;
    float s = bih[j];
    const float* em = embed + e*H_DIM;
    const float* w  = wih + (size_t)j*H_DIM;
    #pragma unroll 8
    for (int k = 0; k < H_DIM; k++) s += em[k]*w[k];
    (dir ? g_giB : g_giF)[rem] = s;
}

// ---------------- init ----------------
__global__ void init_state(const float* __restrict__ h0)
{
    size_t stride = (size_t)gridDim.x*blockDim.x;
    size_t i0 = (size_t)blockIdx.x*blockDim.x + threadIdx.x;
    size_t HS = (size_t)LN*H_DIM;
    for (size_t p = i0; p < HS; p += stride){ g_Hf[0][p] = 0.f; g_Hb[0][p] = 0.f; }
    for (size_t p = i0; p < (size_t)N_DIM*H_DIM; p += stride) g_hm[0][p] = h0[p];
}

// ---------------- plain tf32 GEMM (Rproj + layer0) ----------------
template<int ALOAD, int EPI>
__global__ void __launch_bounds__(256)
gemm_plain(const float* __restrict__ A, const float* __restrict__ B, int ldb,
           const float* __restrict__ bias, float* __restrict__ out,
           int K, int NC, const int* __restrict__ active)
{
    __shared__ float As[128][20];
    __shared__ float Bs[64][20];
    const int tid = threadIdx.x, lane = tid & 31, wid = tid >> 5;
    const int wm = wid >> 1, wn = wid & 1;
    const int brow = blockIdx.y, bcol = blockIdx.x;
    float acc[2][4][4];
    #pragma unroll
    for (int a = 0; a < 2; a++)
        #pragma unroll
        for (int b = 0; b < 4; b++)
            #pragma unroll
            for (int c = 0; c < 4; c++) acc[a][b][c] = 0.f;

    for (int k0 = 0; k0 < K; k0 += 16){
        #pragma unroll
        for (int i = tid; i < 2048; i += 256){
            int r = i >> 4, c = i & 15;
            int row = brow*128 + r; int k = k0 + c;
            float v;
            if (ALOAD == 0) v = A[(size_t)row*K + k];
            else v = (k < H_DIM) ? g_Hf[0][(size_t)row*H_DIM + k]
                                 : g_Hb[0][(size_t)row*H_DIM + (k - H_DIM)];
            As[r][c] = __uint_as_float(f2tf(v));
        }
        #pragma unroll
        for (int i = tid; i < 1024; i += 256){
            int n = i >> 4, c = i & 15;
            Bs[n][c] = __uint_as_float(f2tf(B[(size_t)(bcol*64 + n)*ldb + k0 + c]));
        }
        __syncthreads();
        #pragma unroll
        for (int kk = 0; kk < 16; kk += 8){
            uint32_t af[2][4], bf[4][2];
            #pragma unroll
            for (int mt = 0; mt < 2; mt++){
                int r0 = wm*32 + mt*16 + (lane >> 2);
                int c0 = kk + (lane & 3);
                af[mt][0] = __float_as_uint(As[r0][c0]);
                af[mt][1] = __float_as_uint(As[r0+8][c0]);
                af[mt][2] = __float_as_uint(As[r0][c0+4]);
                af[mt][3] = __float_as_uint(As[r0+8][c0+4]);
            }
            #pragma unroll
            for (int nt = 0; nt < 4; nt++){
                int n0 = wn*32 + nt*8 + (lane >> 2);
                bf[nt][0] = __float_as_uint(Bs[n0][kk + (lane & 3)]);
                bf[nt][1] = __float_as_uint(Bs[n0][kk + 4 + (lane & 3)]);
            }
            #pragma unroll
            for (int mt = 0; mt < 2; mt++)
                #pragma unroll
                for (int nt = 0; nt < 4; nt++)
                    mma8(acc[mt][nt], af[mt], bf[nt]);
        }
        __syncthreads();
    }
    #pragma unroll
    for (int mt = 0; mt < 2; mt++){
        #pragma unroll
        for (int nt = 0; nt < 4; nt++){
            int rbase = brow*128 + wm*32 + mt*16 + (lane >> 2);
            int cbase = bcol*64 + wn*32 + nt*8 + (lane & 3)*2;
            #pragma unroll
            for (int dr = 0; dr < 2; dr++){
                #pragma unroll
                for (int dc = 0; dc < 2; dc++){
                    int rr = rbase + dr*8, cc = cbase + dc;
                    float v = acc[mt][nt][dr*2 + dc];
                    if (EPI == 3){
                        int n = rr & (N_DIM - 1);
                        int w = active[rr];
                        v += bias[cc];
                        v += g_Rproj[(size_t)(w*N_DIM + n)*H_DIM + cc];
                        v = fmaxf(v, 0.f);
                    }
                    out[(size_t)rr*NC + cc] = v;
                }
            }
        }
    }
}

// ---------------- persistent encoder v5: SMEM gi table, hoisted bias/lines ---------
#define ENC_W_FLOATS (3*32*260)            /* 24960 */
#define ENC_A_FLOATS (2*256*36)            /* 18432 */
#define ENC_G_FLOATS (NL_DIM*100)          /* 3200  */
#define ENC_SMEM_BYTES ((ENC_W_FLOATS + ENC_A_FLOATS + ENC_G_FLOATS)*4)

__global__ void __launch_bounds__(512, 1)
enc_v5(const float* __restrict__ whF, const float* __restrict__ bhF,
       const float* __restrict__ whB, const float* __restrict__ bhB,
       const int* __restrict__ lines)
{
    extern __shared__ float sm[];
    float* Ws  = sm;
    float* As  = sm + ENC_W_FLOATS;
    float* GIe = As + ENC_A_FLOATS;
    const int tid = threadIdx.x, lane = tid & 31, wid = tid >> 5;
    const int wm = wid >> 1, wn = wid & 1;
    const int bcol = blockIdx.x;                // 0..7
    const int slab = blockIdx.y;                // 0..15
    const bool dirF = (slab < 8);
    const float* __restrict__ W  = dirF ? whF : whB;
    const float* __restrict__ bh = dirF ? bhF : bhB;
    const float* __restrict__ giT = dirF ? g_giF : g_giB;
    const int lrow0 = (dirF ? slab : slab - 8) * 2048;

    for (int i = tid; i < 3*32*H_DIM; i += 512){
        int g = i >> 13, rem = i & 8191;
        int c = rem >> 8, k = rem & 255;
        Ws[(g*32 + c)*260 + k] =
            __uint_as_float(f2tf(W[(size_t)(g*H_DIM + bcol*32 + c)*H_DIM + k]));
    }
    // gi table slice: 32 embeds x (3 gates x 32 cols), step-invariant
    for (int i = tid; i < NL_DIM*96; i += 512){
        int e = i / 96, j = i % 96;
        int g = j >> 5, c = j & 31;
        GIe[e*100 + j] = __ldg(&giT[e*G3 + g*H_DIM + bcol*32 + c]);
    }
    // bias regs (4 cols x 3 gates)
    float bR[2][2], bZ[2][2], bN[2][2];
    #pragma unroll
    for (int nt = 0; nt < 2; nt++)
        #pragma unroll
        for (int dc = 0; dc < 2; dc++){
            int c = bcol*32 + wn*16 + nt*8 + (lane & 3)*2 + dc;
            bR[nt][dc] = bh[c];
            bZ[nt][dc] = bh[H_DIM + c];
            bN[nt][dc] = bh[2*H_DIM + c];
        }
    __syncthreads();

    for (int t = 0; t < L_DIM; t++){
        const float* __restrict__ hsrc = dirF ? g_Hf[t & 1] : g_Hb[t & 1];
        float* __restrict__ hdst = dirF ? g_Hf[(t + 1) & 1] : g_Hb[(t + 1) & 1];

        auto stage = [&](int p){
            int chunk = p >> 3, kb = p & 7, buf = p & 1;
            const float* src = hsrc + (size_t)(lrow0 + chunk*256)*H_DIM + kb*32;
            float* dst = As + buf*256*36;
            #pragma unroll
            for (int i = tid; i < 2048; i += 512){
                int r = i >> 3, q = (i & 7)*4;
                cp16(&dst[r*36 + q], src + (size_t)r*H_DIM + q);
            }
            cp_commit();
        };

        float acc[3][2][2][4];
        stage(0);
        for (int p = 0; p < 64; p++){
            cp_wait<0>();
            __syncthreads();
            if (p + 1 < 64) stage(p + 1);
            const int kb = p & 7;
            if (kb == 0){
                #pragma unroll
                for (int g = 0; g < 3; g++)
                    #pragma unroll
                    for (int a = 0; a < 2; a++)
                        #pragma unroll
                        for (int b = 0; b < 2; b++)
                            #pragma unroll
                            for (int c = 0; c < 4; c++) acc[g][a][b][c] = 0.f;
            }
            const float* Ab = As + (p & 1)*256*36;
            const int kbase = kb*32;
            #pragma unroll
            for (int kk = 0; kk < 32; kk += 8){
                uint32_t af[2][4];
                #pragma unroll
                for (int mt = 0; mt < 2; mt++){
                    int r0 = wm*32 + mt*16 + (lane >> 2);
                    int c0 = kk + (lane & 3);
                    af[mt][0] = f2tf(Ab[r0*36 + c0]);
                    af[mt][1] = f2tf(Ab[(r0+8)*36 + c0]);
                    af[mt][2] = f2tf(Ab[r0*36 + c0 + 4]);
                    af[mt][3] = f2tf(Ab[(r0+8)*36 + c0 + 4]);
                }
                uint32_t bf[3][2][2];
                #pragma unroll
                for (int g = 0; g < 3; g++)
                    #pragma unroll
                    for (int nt = 0; nt < 2; nt++){
                        int n0 = wn*16 + nt*8 + (lane >> 2);
                        bf[g][nt][0] = __float_as_uint(Ws[(g*32 + n0)*260 + kbase + kk + (lane & 3)]);
                        bf[g][nt][1] = __float_as_uint(Ws[(g*32 + n0)*260 + kbase + kk + 4 + (lane & 3)]);
                    }
                #pragma unroll
                for (int g = 0; g < 3; g++)
                    #pragma unroll
                    for (int mt = 0; mt < 2; mt++)
                        #pragma unroll
                        for (int nt = 0; nt < 2; nt++)
                            mma8(acc[g][mt][nt], af[mt], bf[g][nt]);
            }

            if (kb == 7){
                const int base = lrow0 + (p >> 3)*256;
                #pragma unroll
                for (int mt = 0; mt < 2; mt++){
                    #pragma unroll
                    for (int dr = 0; dr < 2; dr++){
                        int lr = base + wm*32 + mt*16 + (lane >> 2) + dr*8;
                        int iroll = lr >> 10;
                        int nb = lr & (N_DIM - 1);
                        int l = dirF ? ((iroll + t) & 15) : ((iroll + 15 - t) & 15);
                        const float* ge = GIe + __ldg(&lines[nb*L_DIM + l])*100;
                        #pragma unroll
                        for (int nt = 0; nt < 2; nt++){
                            int hcl = wn*16 + nt*8 + (lane & 3)*2;
                            float2 gv0 = *(const float2*)&ge[hcl];
                            float2 gv1 = *(const float2*)&ge[32 + hcl];
                            float2 gv2 = *(const float2*)&ge[64 + hcl];
                            float2 hold = __ldcg((const float2*)&hsrc[(size_t)lr*H_DIM + bcol*32 + hcl]);
                            float2 hout;
                            #pragma unroll
                            for (int dc = 0; dc < 2; dc++){
                                float gr = acc[0][mt][nt][dr*2+dc] + bR[nt][dc];
                                float gz = acc[1][mt][nt][dr*2+dc] + bZ[nt][dc];
                                float gn = acc[2][mt][nt][dr*2+dc] + bN[nt][dc];
                                float r  = sigm((dc ? gv0.y : gv0.x) + gr);
                                float z  = sigm((dc ? gv1.y : gv1.x) + gz);
                                float nn = tanhf((dc ? gv2.y : gv2.x) + r*gn);
                                float ho = dc ? hold.y : hold.x;
                                float hnew = (1.f - z)*nn + z*ho;
                                if (dc) hout.y = hnew; else hout.x = hnew;
                            }
                            __stcg((float2*)&hdst[(size_t)lr*H_DIM + bcol*32 + hcl], hout);
                        }
                    }
                }
            }
        }
        slab_sync(slab, 8);
    }
}

// ---------------- feed-forward GEMM v3: 128 cols/CTA, K-chunk 32 double-buffer -----
// 512 thr, wm 0..7 (256 rows), wn 0..1 (NTN n-tiles each). EPI: 1 relu, 2 bias only.
template<int NTN, int EPI>
__global__ void __launch_bounds__(512, 1)
gemm_ff3(const float* __restrict__ A, const float* __restrict__ W,
         const float* __restrict__ bias, float* __restrict__ out,
         int NC, int nrt)
{
    constexpr int BN = NTN*16;
    extern __shared__ float sm[];
    float* Ws = sm;
    float* As = sm + BN*260;
    const int tid = threadIdx.x, lane = tid & 31, wid = tid >> 5;
    const int wm = wid >> 1, wn = wid & 1;
    const int bcol = blockIdx.x;

    for (int i = tid; i < BN*H_DIM; i += 512){
        int c = i >> 8, k = i & 255;
        Ws[c*260 + k] = __uint_as_float(f2tf(W[(size_t)(bcol*BN + c)*H_DIM + k]));
    }
    __syncthreads();

    const int nch = (nrt - (int)blockIdx.y + (int)gridDim.y - 1) / (int)gridDim.y;
    if (nch <= 0) return;
    const int total = nch*8;

    auto stage = [&](int p){
        int ci = p >> 3, kb = p & 7, buf = p & 1;
        int rt = blockIdx.y + ci*gridDim.y;
        const float* src = A + (size_t)rt*256*H_DIM + kb*32;
        float* dst = As + buf*256*36;
        #pragma unroll
        for (int i = tid; i < 2048; i += 512){
            int r = i >> 3, q = (i & 7)*4;
            cp16(&dst[r*36 + q], src + (size_t)r*H_DIM + q);
        }
        cp_commit();
    };

    float acc[2][NTN][4];
    stage(0);
    for (int p = 0; p < total; p++){
        cp_wait<0>();
        __syncthreads();
        if (p + 1 < total) stage(p + 1);
        const int kb = p & 7;
        if (kb == 0){
            #pragma unroll
            for (int a = 0; a < 2; a++)
                #pragma unroll
                for (int b = 0; b < NTN; b++)
                    #pragma unroll
                    for (int c = 0; c < 4; c++) acc[a][b][c] = 0.f;
        }
        const float* Ab = As + (p & 1)*256*36;
        const int kbase = kb*32;
        #pragma unroll
        for (int kk = 0; kk < 32; kk += 8){
            uint32_t af[2][4];
            #pragma unroll
            for (int mt = 0; mt < 2; mt++){
                int r0 = wm*32 + mt*16 + (lane >> 2);
                int c0 = kk + (lane & 3);
                af[mt][0] = f2tf(Ab[r0*36 + c0]);
                af[mt][1] = f2tf(Ab[(r0+8)*36 + c0]);
                af[mt][2] = f2tf(Ab[r0*36 + c0 + 4]);
                af[mt][3] = f2tf(Ab[(r0+8)*36 + c0 + 4]);
            }
            uint32_t bf[NTN][2];
            #pragma unroll
            for (int nt = 0; nt < NTN; nt++){
                int n0 = wn*NTN*8 + nt*8 + (lane >> 2);
                bf[nt][0] = __float_as_uint(Ws[n0*260 + kbase + kk + (lane & 3)]);
                bf[nt][1] = __float_as_uint(Ws[n0*260 + kbase + kk + 4 + (lane & 3)]);
            }
            #pragma unroll
            for (int mt = 0; mt < 2; mt++)
                #pragma unroll
                for (int nt = 0; nt < NTN; nt++)
                    mma8(acc[mt][nt], af[mt], bf[nt]);
        }

        if (kb == 7){
            int rt = blockIdx.y + (p >> 3)*gridDim.y;
            #pragma unroll
            for (int mt = 0; mt < 2; mt++){
                #pragma unroll
                for (int nt = 0; nt < NTN; nt++){
                    #pragma unroll
                    for (int dr = 0; dr < 2; dr++){
                        int rr = rt*256 + wm*32 + mt*16 + (lane >> 2) + dr*8;
                        int cc = bcol*BN + wn*NTN*8 + nt*8 + (lane & 3)*2;
                        float2 v;
                        v.x = acc[mt][nt][dr*2 + 0] + bias[cc];
                        v.y = acc[mt][nt][dr*2 + 1] + bias[cc + 1];
                        if (EPI == 1){ v.x = fmaxf(v.x, 0.f); v.y = fmaxf(v.y, 0.f); }
                        *(float2*)&out[(size_t)rr*NC + cc] = v;
                    }
                }
            }
        }
    }
}

// ---------------- persistent main GRU v7: 8x16 grid, 64 rows x 32 cols -------------
#define M7_W_FLOATS (3*32*260)             /* 24960 */
#define M7_A_FLOATS (64*260)               /* 16640 */
#define M7_G_FLOATS (64*100)               /* 6400  */
#define M7_SMEM_BYTES ((M7_W_FLOATS + M7_A_FLOATS + M7_G_FLOATS)*4)

__global__ void __launch_bounds__(256, 1)
main_gru_v7(const float* __restrict__ whh, const float* __restrict__ bhh,
            float* __restrict__ out)
{
    extern __shared__ float sm[];
    float* Ws  = sm;
    float* As  = sm + M7_W_FLOATS;
    float* GIs = As + M7_A_FLOATS;
    const int tid = threadIdx.x, lane = tid & 31, wid = tid >> 5;
    const int wm = wid >> 1, wn = wid & 1;      // wm 0..3 (16 rows each), wn 0..1
    const int bcol = blockIdx.x;                // 0..7 (32 cols)
    const int slab = blockIdx.y;                // 0..15
    const int row0 = slab*64;

    for (int i = tid; i < 3*32*H_DIM; i += 256){
        int g = i >> 13, rem = i & 8191;
        int c = rem >> 8, k = rem & 255;
        Ws[(g*32 + c)*260 + k] =
            __uint_as_float(f2tf(whh[(size_t)(g*H_DIM + bcol*32 + c)*H_DIM + k]));
    }
    float bR[2][2], bZ[2][2], bN[2][2];
    #pragma unroll
    for (int nt = 0; nt < 2; nt++)
        #pragma unroll
        for (int dc = 0; dc < 2; dc++){
            int c = bcol*32 + wn*16 + nt*8 + (lane & 3)*2 + dc;
            bR[nt][dc] = bhh[c];
            bZ[nt][dc] = bhh[H_DIM + c];
            bN[nt][dc] = bhh[2*H_DIM + c];
        }

    // prologue: stage gi(0) slice (64 rows x 3x32 cols)
    {
        const float* gsrc = g_GI + (size_t)row0*G3 + bcol*32;
        #pragma unroll
        for (int i = tid; i < 1536; i += 256){
            int r = i / 24, j = i % 24;
            int g = j >> 3, q = (j & 7)*4;
            cp16(&GIs[r*100 + g*32 + q], gsrc + (size_t)r*G3 + g*H_DIM + q);
        }
        cp_commit();
    }
    slab_sync(slab, 8);

    for (int t = 0; t < T_DIM; t++){
        const float* __restrict__ hsrc = g_hm[t & 1];
        float* __restrict__ hdst = g_hm[(t + 1) & 1];

        // stage full A tile (64 rows x 256 K)
        {
            const float* src = hsrc + (size_t)row0*H_DIM;
            #pragma unroll
            for (int i = tid; i < 4096; i += 256){
                int r = i >> 6, q = (i & 63)*4;
                cp16(&As[r*260 + q], src + (size_t)r*H_DIM + q);
            }
            cp_commit();
        }
        cp_wait<0>();
        __syncthreads();

        float acc[3][2][4];
        #pragma unroll
        for (int g = 0; g < 3; g++)
            #pragma unroll
            for (int n = 0; n < 2; n++)
                #pragma unroll
                for (int c = 0; c < 4; c++) acc[g][n][c] = 0.f;

        #pragma unroll 4
        for (int kk = 0; kk < H_DIM; kk += 8){
            uint32_t af[4];
            {
                int r0 = wm*16 + (lane >> 2);
                int c0 = kk + (lane & 3);
                af[0] = f2tf(As[r0*260 + c0]);
                af[1] = f2tf(As[(r0+8)*260 + c0]);
                af[2] = f2tf(As[r0*260 + c0 + 4]);
                af[3] = f2tf(As[(r0+8)*260 + c0 + 4]);
            }
            uint32_t bf[3][2][2];
            #pragma unroll
            for (int g = 0; g < 3; g++)
                #pragma unroll
                for (int nt = 0; nt < 2; nt++){
                    int n0 = wn*16 + nt*8 + (lane >> 2);
                    bf[g][nt][0] = __float_as_uint(Ws[(g*32 + n0)*260 + kk + (lane & 3)]);
                    bf[g][nt][1] = __float_as_uint(Ws[(g*32 + n0)*260 + kk + 4 + (lane & 3)]);
                }
            #pragma unroll
            for (int g = 0; g < 3; g++)
                #pragma unroll
                for (int nt = 0; nt < 2; nt++)
                    mma8(acc[g][nt], af, bf[g][nt]);
        }

        // epilogue: gi + hold from SMEM, float2 stores
        float* __restrict__ out_t = out + ((size_t)t*N_DIM)*ROW_OUT;
        #pragma unroll
        for (int dr = 0; dr < 2; dr++){
            int rl = wm*16 + (lane >> 2) + dr*8;
            int row = row0 + rl;
            #pragma unroll
            for (int nt = 0; nt < 2; nt++){
                int ccl = wn*16 + nt*8 + (lane & 3)*2;
                float2 gv0 = *(const float2*)&GIs[rl*100 + ccl];
                float2 gv1 = *(const float2*)&GIs[rl*100 + 32 + ccl];
                float2 gv2 = *(const float2*)&GIs[rl*100 + 64 + ccl];
                float2 hold = *(const float2*)&As[rl*260 + bcol*32 + ccl];
                float2 hout;
                #pragma unroll
                for (int dc = 0; dc < 2; dc++){
                    float gr = acc[0][nt][dr*2+dc] + bR[nt][dc];
                    float gz = acc[1][nt][dr*2+dc] + bZ[nt][dc];
                    float gn = acc[2][nt][dr*2+dc] + bN[nt][dc];
                    float r  = sigm((dc ? gv0.y : gv0.x) + gr);
                    float z  = sigm((dc ? gv1.y : gv1.x) + gz);
                    float nn = tanhf((dc ? gv2.y : gv2.x) + r*gn);
                    float ho = dc ? hold.y : hold.x;
                    float hnew = (1.f - z)*nn + z*ho;
                    if (dc) hout.y = hnew; else hout.x = hnew;
                }
                __stcg((float2*)&hdst[(size_t)row*H_DIM + bcol*32 + ccl], hout);
                *(float2*)&out_t[(size_t)row*ROW_OUT + 4 + bcol*32 + ccl] = hout;
            }
        }

        // prefetch gi(t+1) before the barrier
        __syncthreads();
        if (t + 1 < T_DIM){
            const float* gsrc = g_GI + ((size_t)(t + 1)*N_DIM + row0)*G3 + bcol*32;
            #pragma unroll
            for (int i = tid; i < 1536; i += 256){
                int r = i / 24, j = i % 24;
                int g = j >> 3, q = (j & 7)*4;
                cp16(&GIs[r*100 + g*32 + q], gsrc + (size_t)r*G3 + g*H_DIM + q);
            }
            cp_commit();
        }
        slab_sync(slab, 8);
    }
}

// ---------------- heads ----------------
__global__ void __launch_bounds__(256)
heads_kernel(float* __restrict__ out, const int* __restrict__ actions,
             const int* __restrict__ active, const float* __restrict__ p0,
             const float* __restrict__ pp0,
             const float* __restrict__ w_actor, const float* __restrict__ b_actor,
             const float* __restrict__ w_critic, const float* __restrict__ b_critic)
{
    int wid = threadIdx.x >> 5, lane = threadIdx.x & 31;
    size_t row = (size_t)blockIdx.x*8 + wid;
    float* orow = out + row*ROW_OUT;
    float hv[8];
    #pragma unroll
    for (int i = 0; i < 8; i++) hv[i] = orow[4 + lane + 32*i];

    float lg = 0.f;
    #pragma unroll
    for (int a = 0; a < NA_DIM; a++){
        float s = 0.f;
        #pragma unroll
        for (int i = 0; i < 8; i++) s += hv[i]*w_actor[a*H_DIM + lane + 32*i];
        #pragma unroll
        for (int o = 16; o > 0; o >>= 1) s += __shfl_xor_sync(0xffffffffu, s, o);
        if (lane == a) lg = s + b_actor[a];
    }
    float m = (lane < NA_DIM) ? lg : -1e30f;
    #pragma unroll
    for (int o = 16; o > 0; o >>= 1) m = fmaxf(m, __shfl_xor_sync(0xffffffffu, m, o));
    float e = (lane < NA_DIM) ? expf(lg - m) : 0.f;
    float den = e;
    #pragma unroll
    for (int o = 16; o > 0; o >>= 1) den += __shfl_xor_sync(0xffffffffu, den, o);
    if (lane < NA_DIM) orow[260 + lane] = e/den;

    float s = 0.f;
    #pragma unroll
    for (int i = 0; i < 8; i++) s += hv[i]*w_critic[lane + 32*i];
    #pragma unroll
    for (int o = 16; o > 0; o >>= 1) s += __shfl_xor_sync(0xffffffffu, s, o);

    int n = (int)(row & (N_DIM - 1));
    if (lane == 0)  orow[3]   = s + b_critic[0];
    if (lane == 16) orow[0]   = (float)actions[row];
    if (lane == 17) orow[1]   = p0[n];
    if (lane == 18) orow[2]   = (float)active[row];
    if (lane == 19) orow[276] = pp0[n*2];
    if (lane == 20) orow[277] = pp0[n*2 + 1];
}

// ---------------- launch ----------------
extern "C" void kernel_launch(void* const* d_in, const int* in_sizes, int n_in,
                              void* d_out, int out_size)
{
    (void)in_sizes; (void)n_in; (void)out_size;
    const float* condition = (const float*)d_in[0];
    const int*   active    = (const int*)d_in[1];
    const int*   lines     = (const int*)d_in[2];
    const int*   actions   = (const int*)d_in[3];
    const float* h0        = (const float*)d_in[4];
    const float* p0        = (const float*)d_in[5];
    const float* pp0       = (const float*)d_in[6];
    const float* embed     = (const float*)d_in[7];
    const float* wih_f = (const float*)d_in[8],  *whh_f = (const float*)d_in[9];
    const float* bih_f = (const float*)d_in[10], *bhh_f = (const float*)d_in[11];
    const float* wih_b = (const float*)d_in[12], *whh_b = (const float*)d_in[13];
    const float* bih_b = (const float*)d_in[14], *bhh_b = (const float*)d_in[15];
    const float* f_w0 = (const float*)d_in[16], *f_b0 = (const float*)d_in[17];
    const float* f_w1 = (const float*)d_in[18], *f_b1 = (const float*)d_in[19];
    const float* f_w2 = (const float*)d_in[20], *f_b2 = (const float*)d_in[21];
    const float* c_wih = (const float*)d_in[22], *c_whh = (const float*)d_in[23];
    const float* c_bih = (const float*)d_in[24], *c_bhh = (const float*)d_in[25];
    const float* w_critic = (const float*)d_in[26], *b_critic = (const float*)d_in[27];
    const float* w_actor  = (const float*)d_in[28], *b_actor  = (const float*)d_in[29];
    float* out = (float*)d_out;

    float *A0p, *A1p, *Rp, *GIp;
    cudaGetSymbolAddress((void**)&A0p, g_A0);
    cudaGetSymbolAddress((void**)&A1p, g_A1);
    cudaGetSymbolAddress((void**)&Rp,  g_Rproj);
    cudaGetSymbolAddress((void**)&GIp, g_GI);

    const int FF3_SMEM = (128*260 + 2*256*36)*4;
    cudaFuncSetAttribute(enc_v5,
                         cudaFuncAttributeMaxDynamicSharedMemorySize, ENC_SMEM_BYTES);
    cudaFuncSetAttribute(main_gru_v7,
                         cudaFuncAttributeMaxDynamicSharedMemorySize, M7_SMEM_BYTES);
    cudaFuncSetAttribute(gemm_ff3<8,1>,
                         cudaFuncAttributeMaxDynamicSharedMemorySize, FF3_SMEM);
    cudaFuncSetAttribute(gemm_ff3<8,2>,
                         cudaFuncAttributeMaxDynamicSharedMemorySize, FF3_SMEM);

    // 0) gi tables + state init
    gi_tables<<<(2*NL_DIM*G3 + 255)/256, 256>>>(embed, wih_f, bih_f, wih_b, bih_b);
    init_state<<<4096, 256>>>(h0);

    // 1) persistent bidirectional encoder (per-slab barriers, SMEM gi)
    enc_v5<<<dim3(8, 16), 512, ENC_SMEM_BYTES>>>(whh_f, bhh_f, whh_b, bhh_b, lines);

    // 2) Rproj = Hmem @ W0r^T (dedup over (w,n))
    gemm_plain<1, 0><<<dim3(4, 128), 256>>>(nullptr, f_w0 + 64, 576, nullptr, Rp, 512, 256, nullptr);
    // 3) A0 = relu(cond @ W0c^T + Rproj[active] + b0)
    gemm_plain<0, 3><<<dim3(4, 2048), 256>>>(condition, f_w0, 576, f_b0, A0p, 64, 256, active);
    // 4) A1 = relu(A0 @ w1^T + b1); A0 = relu(A1 @ w2^T + b2)  (128 cols/CTA)
    gemm_ff3<8, 1><<<dim3(2, 74), 512, FF3_SMEM>>>(A0p, f_w1, f_b1, A1p, 256, 1024);
    gemm_ff3<8, 1><<<dim3(2, 74), 512, FF3_SMEM>>>(A1p, f_w2, f_b2, A0p, 256, 1024);
    // 5) GI = A0 @ c_wih^T + c_bih  (128 cols/CTA, 6 col-tiles)
    gemm_ff3<8, 2><<<dim3(6, 24), 512, FF3_SMEM>>>(A0p, c_wih, c_bih, GIp, 768, 1024);

    // 6) persistent main GRU v7 (8x16, 64 rows x 32 cols, per-slab barriers)
    main_gru_v7<<<dim3(8, 16), 256, M7_SMEM_BYTES>>>(c_whh, c_bhh, out);

    // 7) heads + scalar fields
    heads_kernel<<<TN/8, 256>>>(out, actions, active, p0, pp0,
                                w_actor, b_actor, w_critic, b_critic);
}

// round 9
// speedup vs baseline: 2.5333x; 1.0904x over previous
#include <cuda_runtime.h>
#include <math.h>
#include <stdint.h>

#define T_DIM 256
#define N_DIM 1024
#define H_DIM 256
#define L_DIM 16
#define NL_DIM 32
#define C_DIM 64
#define NA_DIM 16
#define ROW_OUT 278
#define G3 768
#define LN (L_DIM*N_DIM)          /* 16384 */
#define TN (T_DIM*N_DIM)          /* 262144 */

// ---------------- scratch ----------------
__device__ float g_giF[NL_DIM*G3];
__device__ float g_giB[NL_DIM*G3];
__device__ float g_Hf[2][(size_t)LN*H_DIM];
__device__ float g_Hb[2][(size_t)LN*H_DIM];
__device__ uint16_t g_Hfb[2][(size_t)LN*H_DIM];   // bf16 shadow of Hf (MMA operand)
__device__ uint16_t g_Hbb[2][(size_t)LN*H_DIM];   // bf16 shadow of Hb
__device__ float g_Rproj[(size_t)LN*H_DIM];
__device__ float g_A0[(size_t)TN*H_DIM];
__device__ float g_A1[(size_t)TN*H_DIM];
__device__ float g_GI[(size_t)TN*G3];
__device__ float g_hm[2][N_DIM*H_DIM];
__device__ unsigned g_slabc[16][32];
__device__ unsigned g_slabg[16][32];

// ---------------- helpers ----------------
__device__ __forceinline__ uint32_t f2tf(float x){
    uint32_t r; asm("cvt.rna.tf32.f32 %0, %1;" : "=r"(r) : "f"(x)); return r;
}
__device__ __forceinline__ uint32_t packbf(float lo, float hi){
    uint32_t r; asm("cvt.rn.bf16x2.f32 %0, %1, %2;" : "=r"(r) : "f"(hi), "f"(lo)); return r;
}
__device__ __forceinline__ void mma8(float* c, const uint32_t* a, const uint32_t* b){
    asm volatile("mma.sync.aligned.m16n8k8.row.col.f32.tf32.tf32.f32 "
        "{%0,%1,%2,%3},{%4,%5,%6,%7},{%8,%9},{%0,%1,%2,%3};"
        : "+f"(c[0]), "+f"(c[1]), "+f"(c[2]), "+f"(c[3])
        : "r"(a[0]), "r"(a[1]), "r"(a[2]), "r"(a[3]), "r"(b[0]), "r"(b[1]));
}
__device__ __forceinline__ void mma16b(float* c, const uint32_t* a, const uint32_t* b){
    asm volatile("mma.sync.aligned.m16n8k16.row.col.f32.bf16.bf16.f32 "
        "{%0,%1,%2,%3},{%4,%5,%6,%7},{%8,%9},{%0,%1,%2,%3};"
        : "+f"(c[0]), "+f"(c[1]), "+f"(c[2]), "+f"(c[3])
        : "r"(a[0]), "r"(a[1]), "r"(a[2]), "r"(a[3]), "r"(b[0]), "r"(b[1]));
}
__device__ __forceinline__ float sigm(float x){ return 1.f/(1.f+expf(-x)); }
__device__ __forceinline__ void cp16(void* smem_dst, const void* gsrc){
    uint32_t s = (uint32_t)__cvta_generic_to_shared(smem_dst);
    asm volatile("cp.async.cg.shared.global [%0], [%1], 16;" :: "r"(s), "l"(gsrc));
}
__device__ __forceinline__ void cp_commit(){ asm volatile("cp.async.commit_group;"); }
template<int N> __device__ __forceinline__ void cp_wait(){
    asm volatile("cp.async.wait_group %0;" :: "n"(N));
}

__device__ __forceinline__ void slab_sync(int slab, unsigned nb){
    __syncthreads();
    if (threadIdx.x == 0){
        volatile unsigned* genp = &g_slabg[slab][0];
        unsigned old = *genp;
        __threadfence();
        if (atomicAdd(&g_slabc[slab][0], 1u) == nb - 1u){
            g_slabc[slab][0] = 0u;
            __threadfence();
            *genp = old + 1u;
        } else {
            while (*genp == old) { }
            __threadfence();
        }
    }
    __syncthreads();
}

// ---------------- gi tables ----------------
__global__ void gi_tables(const float* __restrict__ embed,
                          const float* __restrict__ wihF, const float* __restrict__ bihF,
                          const float* __restrict__ wihB, const float* __restrict__ bihB)
{
    int idx = blockIdx.x*blockDim.x + threadIdx.x;
    if (idx >= 2*NL_DIM*G3) return;
    int dir = idx / (NL_DIM*G3);
    int rem = idx % (NL_DIM*G3);
    int e = rem / G3, j = rem % G3;
    const float* wih = dir ? wihB : wihF;
    const float* bih = dir ? bihB : bihF;
    float s = bih[j];
    const float* em = embed + e*H_DIM;
    const float* w  = wih + (size_t)j*H_DIM;
    #pragma unroll 8
    for (int k = 0; k < H_DIM; k++) s += em[k]*w[k];
    (dir ? g_giB : g_giF)[rem] = s;
}

// ---------------- init ----------------
__global__ void init_state(const float* __restrict__ h0)
{
    size_t stride = (size_t)gridDim.x*blockDim.x;
    size_t i0 = (size_t)blockIdx.x*blockDim.x + threadIdx.x;
    size_t HS = (size_t)LN*H_DIM;
    for (size_t p = i0; p < HS; p += stride){
        g_Hf[0][p] = 0.f; g_Hb[0][p] = 0.f;
        g_Hfb[0][p] = 0;  g_Hbb[0][p] = 0;
    }
    for (size_t p = i0; p < (size_t)N_DIM*H_DIM; p += stride) g_hm[0][p] = h0[p];
}

// ---------------- plain tf32 GEMM (Rproj + layer0) ----------------
template<int ALOAD, int EPI>
__global__ void __launch_bounds__(256)
gemm_plain(const float* __restrict__ A, const float* __restrict__ B, int ldb,
           const float* __restrict__ bias, float* __restrict__ out,
           int K, int NC, const int* __restrict__ active)
{
    __shared__ float As[128][20];
    __shared__ float Bs[64][20];
    const int tid = threadIdx.x, lane = tid & 31, wid = tid >> 5;
    const int wm = wid >> 1, wn = wid & 1;
    const int brow = blockIdx.y, bcol = blockIdx.x;
    float acc[2][4][4];
    #pragma unroll
    for (int a = 0; a < 2; a++)
        #pragma unroll
        for (int b = 0; b < 4; b++)
            #pragma unroll
            for (int c = 0; c < 4; c++) acc[a][b][c] = 0.f;

    for (int k0 = 0; k0 < K; k0 += 16){
        #pragma unroll
        for (int i = tid; i < 2048; i += 256){
            int r = i >> 4, c = i & 15;
            int row = brow*128 + r; int k = k0 + c;
            float v;
            if (ALOAD == 0) v = A[(size_t)row*K + k];
            else v = (k < H_DIM) ? g_Hf[0][(size_t)row*H_DIM + k]
                                 : g_Hb[0][(size_t)row*H_DIM + (k - H_DIM)];
            As[r][c] = __uint_as_float(f2tf(v));
        }
        #pragma unroll
        for (int i = tid; i < 1024; i += 256){
            int n = i >> 4, c = i & 15;
            Bs[n][c] = __uint_as_float(f2tf(B[(size_t)(bcol*64 + n)*ldb + k0 + c]));
        }
        __syncthreads();
        #pragma unroll
        for (int kk = 0; kk < 16; kk += 8){
            uint32_t af[2][4], bf[4][2];
            #pragma unroll
            for (int mt = 0; mt < 2; mt++){
                int r0 = wm*32 + mt*16 + (lane >> 2);
                int c0 = kk + (lane & 3);
                af[mt][0] = __float_as_uint(As[r0][c0]);
                af[mt][1] = __float_as_uint(As[r0+8][c0]);
                af[mt][2] = __float_as_uint(As[r0][c0+4]);
                af[mt][3] = __float_as_uint(As[r0+8][c0+4]);
            }
            #pragma unroll
            for (int nt = 0; nt < 4; nt++){
                int n0 = wn*32 + nt*8 + (lane >> 2);
                bf[nt][0] = __float_as_uint(Bs[n0][kk + (lane & 3)]);
                bf[nt][1] = __float_as_uint(Bs[n0][kk + 4 + (lane & 3)]);
            }
            #pragma unroll
            for (int mt = 0; mt < 2; mt++)
                #pragma unroll
                for (int nt = 0; nt < 4; nt++)
                    mma8(acc[mt][nt], af[mt], bf[nt]);
        }
        __syncthreads();
    }
    #pragma unroll
    for (int mt = 0; mt < 2; mt++){
        #pragma unroll
        for (int nt = 0; nt < 4; nt++){
            int rbase = brow*128 + wm*32 + mt*16 + (lane >> 2);
            int cbase = bcol*64 + wn*32 + nt*8 + (lane & 3)*2;
            #pragma unroll
            for (int dr = 0; dr < 2; dr++){
                #pragma unroll
                for (int dc = 0; dc < 2; dc++){
                    int rr = rbase + dr*8, cc = cbase + dc;
                    float v = acc[mt][nt][dr*2 + dc];
                    if (EPI == 3){
                        int n = rr & (N_DIM - 1);
                        int w = active[rr];
                        v += bias[cc];
                        v += g_Rproj[(size_t)(w*N_DIM + n)*H_DIM + cc];
                        v = fmaxf(v, 0.f);
                    }
                    out[(size_t)rr*NC + cc] = v;
                }
            }
        }
    }
}

// ---------------- persistent encoder v6: bf16 m16n8k16 ----------------
// grid (8 bcol, 16 slab), 512 thr. Weights + A operand in bf16; gates/hold in f32.
#define E6_W_U32 (3*32*132)                /* 12672 u32 */
#define E6_A_U32 (2*256*20)                /* 10240 u32 */
#define E6_G_FLOATS (NL_DIM*100)           /* 3200 f32  */
#define E6_SMEM_BYTES ((E6_W_U32 + E6_A_U32 + E6_G_FLOATS)*4)

__global__ void __launch_bounds__(512, 1)
enc_v6(const float* __restrict__ whF, const float* __restrict__ bhF,
       const float* __restrict__ whB, const float* __restrict__ bhB,
       const int* __restrict__ lines)
{
    extern __shared__ uint32_t smu[];
    uint32_t* Ws2 = smu;
    uint32_t* As2 = smu + E6_W_U32;
    float* GIe = (float*)(smu + E6_W_U32 + E6_A_U32);
    const int tid = threadIdx.x, lane = tid & 31, wid = tid >> 5;
    const int wm = wid >> 1, wn = wid & 1;
    const int bcol = blockIdx.x;                // 0..7
    const int slab = blockIdx.y;                // 0..15
    const bool dirF = (slab < 8);
    const float* __restrict__ W  = dirF ? whF : whB;
    const float* __restrict__ bh = dirF ? bhF : bhB;
    const float* __restrict__ giT = dirF ? g_giF : g_giB;
    const int lrow0 = (dirF ? slab : slab - 8) * 2048;

    // pack weights to bf16 pairs: Ws2[(g*32+c)*132 + kp] = {W[2kp], W[2kp+1]}
    for (int i = tid; i < 3*32*128; i += 512){
        int g = i >> 12, rem = i & 4095;
        int c = rem >> 7, kp = rem & 127;
        const float* wr = W + (size_t)(g*H_DIM + bcol*32 + c)*H_DIM + 2*kp;
        Ws2[(g*32 + c)*132 + kp] = packbf(wr[0], wr[1]);
    }
    // gi table slice (f32, step-invariant)
    for (int i = tid; i < NL_DIM*96; i += 512){
        int e = i / 96, j = i % 96;
        int g = j >> 5, c = j & 31;
        GIe[e*100 + j] = __ldg(&giT[e*G3 + g*H_DIM + bcol*32 + c]);
    }
    float bR[2][2], bZ[2][2], bN[2][2];
    #pragma unroll
    for (int nt = 0; nt < 2; nt++)
        #pragma unroll
        for (int dc = 0; dc < 2; dc++){
            int c = bcol*32 + wn*16 + nt*8 + (lane & 3)*2 + dc;
            bR[nt][dc] = bh[c];
            bZ[nt][dc] = bh[H_DIM + c];
            bN[nt][dc] = bh[2*H_DIM + c];
        }
    __syncthreads();

    for (int t = 0; t < L_DIM; t++){
        const float* __restrict__ hsrc = dirF ? g_Hf[t & 1] : g_Hb[t & 1];
        float* __restrict__ hdst = dirF ? g_Hf[(t + 1) & 1] : g_Hb[(t + 1) & 1];
        const uint16_t* __restrict__ hsrc16 = dirF ? g_Hfb[t & 1] : g_Hbb[t & 1];
        uint16_t* __restrict__ hdst16 = dirF ? g_Hfb[(t + 1) & 1] : g_Hbb[(t + 1) & 1];

        auto stage = [&](int p){
            int chunk = p >> 3, kb = p & 7, buf = p & 1;
            const uint16_t* src = hsrc16 + (size_t)(lrow0 + chunk*256)*H_DIM + kb*32;
            uint32_t* dst = As2 + buf*256*20;
            #pragma unroll
            for (int i = tid; i < 1024; i += 512){
                int r = i >> 2, q = i & 3;
                cp16(&dst[r*20 + q*4], src + (size_t)r*H_DIM + q*8);
            }
            cp_commit();
        };

        float acc[3][2][2][4];
        stage(0);
        for (int p = 0; p < 64; p++){
            cp_wait<0>();
            __syncthreads();
            if (p + 1 < 64) stage(p + 1);
            const int kb = p & 7;
            if (kb == 0){
                #pragma unroll
                for (int g = 0; g < 3; g++)
                    #pragma unroll
                    for (int a = 0; a < 2; a++)
                        #pragma unroll
                        for (int b = 0; b < 2; b++)
                            #pragma unroll
                            for (int c = 0; c < 4; c++) acc[g][a][b][c] = 0.f;
            }
            const uint32_t* Ab2 = As2 + (p & 1)*256*20;
            #pragma unroll
            for (int kk = 0; kk < 32; kk += 16){
                uint32_t af[2][4];
                #pragma unroll
                for (int mt = 0; mt < 2; mt++){
                    int r0 = wm*32 + mt*16 + (lane >> 2);
                    int ui = r0*20 + (kk >> 1) + (lane & 3);
                    af[mt][0] = Ab2[ui];
                    af[mt][1] = Ab2[ui + 160];
                    af[mt][2] = Ab2[ui + 4];
                    af[mt][3] = Ab2[ui + 164];
                }
                uint32_t bf[3][2][2];
                #pragma unroll
                for (int g = 0; g < 3; g++)
                    #pragma unroll
                    for (int nt = 0; nt < 2; nt++){
                        int n0 = wn*16 + nt*8 + (lane >> 2);
                        int wi = (g*32 + n0)*132 + kb*16 + (kk >> 1) + (lane & 3);
                        bf[g][nt][0] = Ws2[wi];
                        bf[g][nt][1] = Ws2[wi + 4];
                    }
                #pragma unroll
                for (int g = 0; g < 3; g++)
                    #pragma unroll
                    for (int mt = 0; mt < 2; mt++)
                        #pragma unroll
                        for (int nt = 0; nt < 2; nt++)
                            mma16b(acc[g][mt][nt], af[mt], bf[g][nt]);
            }

            if (kb == 7){
                const int base = lrow0 + (p >> 3)*256;
                #pragma unroll
                for (int mt = 0; mt < 2; mt++){
                    #pragma unroll
                    for (int dr = 0; dr < 2; dr++){
                        int lr = base + wm*32 + mt*16 + (lane >> 2) + dr*8;
                        int iroll = lr >> 10;
                        int nb = lr & (N_DIM - 1);
                        int l = dirF ? ((iroll + t) & 15) : ((iroll + 15 - t) & 15);
                        const float* ge = GIe + __ldg(&lines[nb*L_DIM + l])*100;
                        #pragma unroll
                        for (int nt = 0; nt < 2; nt++){
                            int hcl = wn*16 + nt*8 + (lane & 3)*2;
                            float2 gv0 = *(const float2*)&ge[hcl];
                            float2 gv1 = *(const float2*)&ge[32 + hcl];
                            float2 gv2 = *(const float2*)&ge[64 + hcl];
                            float2 hold = __ldcg((const float2*)&hsrc[(size_t)lr*H_DIM + bcol*32 + hcl]);
                            float2 hout;
                            #pragma unroll
                            for (int dc = 0; dc < 2; dc++){
                                float gr = acc[0][mt][nt][dr*2+dc] + bR[nt][dc];
                                float gz = acc[1][mt][nt][dr*2+dc] + bZ[nt][dc];
                                float gn = acc[2][mt][nt][dr*2+dc] + bN[nt][dc];
                                float r  = sigm((dc ? gv0.y : gv0.x) + gr);
                                float z  = sigm((dc ? gv1.y : gv1.x) + gz);
                                float nn = tanhf((dc ? gv2.y : gv2.x) + r*gn);
                                float ho = dc ? hold.y : hold.x;
                                float hnew = (1.f - z)*nn + z*ho;
                                if (dc) hout.y = hnew; else hout.x = hnew;
                            }
                            __stcg((float2*)&hdst[(size_t)lr*H_DIM + bcol*32 + hcl], hout);
                            __stcg((uint32_t*)(hdst16 + (size_t)lr*H_DIM + bcol*32 + hcl),
                                   packbf(hout.x, hout.y));
                        }
                    }
                }
            }
        }
        slab_sync(slab, 8);
    }
}

// ---------------- feed-forward GEMM v3: 128 cols/CTA, K-chunk 32 double-buffer -----
template<int NTN, int EPI>
__global__ void __launch_bounds__(512, 1)
gemm_ff3(const float* __restrict__ A, const float* __restrict__ W,
         const float* __restrict__ bias, float* __restrict__ out,
         int NC, int nrt)
{
    constexpr int BN = NTN*16;
    extern __shared__ float sm[];
    float* Ws = sm;
    float* As = sm + BN*260;
    const int tid = threadIdx.x, lane = tid & 31, wid = tid >> 5;
    const int wm = wid >> 1, wn = wid & 1;
    const int bcol = blockIdx.x;

    for (int i = tid; i < BN*H_DIM; i += 512){
        int c = i >> 8, k = i & 255;
        Ws[c*260 + k] = __uint_as_float(f2tf(W[(size_t)(bcol*BN + c)*H_DIM + k]));
    }
    __syncthreads();

    const int nch = (nrt - (int)blockIdx.y + (int)gridDim.y - 1) / (int)gridDim.y;
    if (nch <= 0) return;
    const int total = nch*8;

    auto stage = [&](int p){
        int ci = p >> 3, kb = p & 7, buf = p & 1;
        int rt = blockIdx.y + ci*gridDim.y;
        const float* src = A + (size_t)rt*256*H_DIM + kb*32;
        float* dst = As + buf*256*36;
        #pragma unroll
        for (int i = tid; i < 2048; i += 512){
            int r = i >> 3, q = (i & 7)*4;
            cp16(&dst[r*36 + q], src + (size_t)r*H_DIM + q);
        }
        cp_commit();
    };

    float acc[2][NTN][4];
    stage(0);
    for (int p = 0; p < total; p++){
        cp_wait<0>();
        __syncthreads();
        if (p + 1 < total) stage(p + 1);
        const int kb = p & 7;
        if (kb == 0){
            #pragma unroll
            for (int a = 0; a < 2; a++)
                #pragma unroll
                for (int b = 0; b < NTN; b++)
                    #pragma unroll
                    for (int c = 0; c < 4; c++) acc[a][b][c] = 0.f;
        }
        const float* Ab = As + (p & 1)*256*36;
        const int kbase = kb*32;
        #pragma unroll
        for (int kk = 0; kk < 32; kk += 8){
            uint32_t af[2][4];
            #pragma unroll
            for (int mt = 0; mt < 2; mt++){
                int r0 = wm*32 + mt*16 + (lane >> 2);
                int c0 = kk + (lane & 3);
                af[mt][0] = f2tf(Ab[r0*36 + c0]);
                af[mt][1] = f2tf(Ab[(r0+8)*36 + c0]);
                af[mt][2] = f2tf(Ab[r0*36 + c0 + 4]);
                af[mt][3] = f2tf(Ab[(r0+8)*36 + c0 + 4]);
            }
            uint32_t bf[NTN][2];
            #pragma unroll
            for (int nt = 0; nt < NTN; nt++){
                int n0 = wn*NTN*8 + nt*8 + (lane >> 2);
                bf[nt][0] = __float_as_uint(Ws[n0*260 + kbase + kk + (lane & 3)]);
                bf[nt][1] = __float_as_uint(Ws[n0*260 + kbase + kk + 4 + (lane & 3)]);
            }
            #pragma unroll
            for (int mt = 0; mt < 2; mt++)
                #pragma unroll
                for (int nt = 0; nt < NTN; nt++)
                    mma8(acc[mt][nt], af[mt], bf[nt]);
        }

        if (kb == 7){
            int rt = blockIdx.y + (p >> 3)*gridDim.y;
            #pragma unroll
            for (int mt = 0; mt < 2; mt++){
                #pragma unroll
                for (int nt = 0; nt < NTN; nt++){
                    #pragma unroll
                    for (int dr = 0; dr < 2; dr++){
                        int rr = rt*256 + wm*32 + mt*16 + (lane >> 2) + dr*8;
                        int cc = bcol*BN + wn*NTN*8 + nt*8 + (lane & 3)*2;
                        float2 v;
                        v.x = acc[mt][nt][dr*2 + 0] + bias[cc];
                        v.y = acc[mt][nt][dr*2 + 1] + bias[cc + 1];
                        if (EPI == 1){ v.x = fmaxf(v.x, 0.f); v.y = fmaxf(v.y, 0.f); }
                        *(float2*)&out[(size_t)rr*NC + cc] = v;
                    }
                }
            }
        }
    }
}

// ---------------- persistent main GRU v7: 8x16 grid, 64 rows x 32 cols -------------
#define M7_W_FLOATS (3*32*260)             /* 24960 */
#define M7_A_FLOATS (64*260)               /* 16640 */
#define M7_G_FLOATS (64*100)               /* 6400  */
#define M7_SMEM_BYTES ((M7_W_FLOATS + M7_A_FLOATS + M7_G_FLOATS)*4)

__global__ void __launch_bounds__(256, 1)
main_gru_v7(const float* __restrict__ whh, const float* __restrict__ bhh,
            float* __restrict__ out)
{
    extern __shared__ float sm[];
    float* Ws  = sm;
    float* As  = sm + M7_W_FLOATS;
    float* GIs = As + M7_A_FLOATS;
    const int tid = threadIdx.x, lane = tid & 31, wid = tid >> 5;
    const int wm = wid >> 1, wn = wid & 1;
    const int bcol = blockIdx.x;                // 0..7 (32 cols)
    const int slab = blockIdx.y;                // 0..15
    const int row0 = slab*64;

    for (int i = tid; i < 3*32*H_DIM; i += 256){
        int g = i >> 13, rem = i & 8191;
        int c = rem >> 8, k = rem & 255;
        Ws[(g*32 + c)*260 + k] =
            __uint_as_float(f2tf(whh[(size_t)(g*H_DIM + bcol*32 + c)*H_DIM + k]));
    }
    float bR[2][2], bZ[2][2], bN[2][2];
    #pragma unroll
    for (int nt = 0; nt < 2; nt++)
        #pragma unroll
        for (int dc = 0; dc < 2; dc++){
            int c = bcol*32 + wn*16 + nt*8 + (lane & 3)*2 + dc;
            bR[nt][dc] = bhh[c];
            bZ[nt][dc] = bhh[H_DIM + c];
            bN[nt][dc] = bhh[2*H_DIM + c];
        }

    {
        const float* gsrc = g_GI + (size_t)row0*G3 + bcol*32;
        #pragma unroll
        for (int i = tid; i < 1536; i += 256){
            int r = i / 24, j = i % 24;
            int g = j >> 3, q = (j & 7)*4;
            cp16(&GIs[r*100 + g*32 + q], gsrc + (size_t)r*G3 + g*H_DIM + q);
        }
        cp_commit();
    }
    slab_sync(slab, 8);

    for (int t = 0; t < T_DIM; t++){
        const float* __restrict__ hsrc = g_hm[t & 1];
        float* __restrict__ hdst = g_hm[(t + 1) & 1];

        {
            const float* src = hsrc + (size_t)row0*H_DIM;
            #pragma unroll
            for (int i = tid; i < 4096; i += 256){
                int r = i >> 6, q = (i & 63)*4;
                cp16(&As[r*260 + q], src + (size_t)r*H_DIM + q);
            }
            cp_commit();
        }
        cp_wait<0>();
        __syncthreads();

        float acc[3][2][4];
        #pragma unroll
        for (int g = 0; g < 3; g++)
            #pragma unroll
            for (int n = 0; n < 2; n++)
                #pragma unroll
                for (int c = 0; c < 4; c++) acc[g][n][c] = 0.f;

        #pragma unroll 4
        for (int kk = 0; kk < H_DIM; kk += 8){
            uint32_t af[4];
            {
                int r0 = wm*16 + (lane >> 2);
                int c0 = kk + (lane & 3);
                af[0] = f2tf(As[r0*260 + c0]);
                af[1] = f2tf(As[(r0+8)*260 + c0]);
                af[2] = f2tf(As[r0*260 + c0 + 4]);
                af[3] = f2tf(As[(r0+8)*260 + c0 + 4]);
            }
            uint32_t bf[3][2][2];
            #pragma unroll
            for (int g = 0; g < 3; g++)
                #pragma unroll
                for (int nt = 0; nt < 2; nt++){
                    int n0 = wn*16 + nt*8 + (lane >> 2);
                    bf[g][nt][0] = __float_as_uint(Ws[(g*32 + n0)*260 + kk + (lane & 3)]);
                    bf[g][nt][1] = __float_as_uint(Ws[(g*32 + n0)*260 + kk + 4 + (lane & 3)]);
                }
            #pragma unroll
            for (int g = 0; g < 3; g++)
                #pragma unroll
                for (int nt = 0; nt < 2; nt++)
                    mma8(acc[g][nt], af, bf[g][nt]);
        }

        float* __restrict__ out_t = out + ((size_t)t*N_DIM)*ROW_OUT;
        #pragma unroll
        for (int dr = 0; dr < 2; dr++){
            int rl = wm*16 + (lane >> 2) + dr*8;
            int row = row0 + rl;
            #pragma unroll
            for (int nt = 0; nt < 2; nt++){
                int ccl = wn*16 + nt*8 + (lane & 3)*2;
                float2 gv0 = *(const float2*)&GIs[rl*100 + ccl];
                float2 gv1 = *(const float2*)&GIs[rl*100 + 32 + ccl];
                float2 gv2 = *(const float2*)&GIs[rl*100 + 64 + ccl];
                float2 hold = *(const float2*)&As[rl*260 + bcol*32 + ccl];
                float2 hout;
                #pragma unroll
                for (int dc = 0; dc < 2; dc++){
                    float gr = acc[0][nt][dr*2+dc] + bR[nt][dc];
                    float gz = acc[1][nt][dr*2+dc] + bZ[nt][dc];
                    float gn = acc[2][nt][dr*2+dc] + bN[nt][dc];
                    float r  = sigm((dc ? gv0.y : gv0.x) + gr);
                    float z  = sigm((dc ? gv1.y : gv1.x) + gz);
                    float nn = tanhf((dc ? gv2.y : gv2.x) + r*gn);
                    float ho = dc ? hold.y : hold.x;
                    float hnew = (1.f - z)*nn + z*ho;
                    if (dc) hout.y = hnew; else hout.x = hnew;
                }
                __stcg((float2*)&hdst[(size_t)row*H_DIM + bcol*32 + ccl], hout);
                *(float2*)&out_t[(size_t)row*ROW_OUT + 4 + bcol*32 + ccl] = hout;
            }
        }

        __syncthreads();
        if (t + 1 < T_DIM){
            const float* gsrc = g_GI + ((size_t)(t + 1)*N_DIM + row0)*G3 + bcol*32;
            #pragma unroll
            for (int i = tid; i < 1536; i += 256){
                int r = i / 24, j = i % 24;
                int g = j >> 3, q = (j & 7)*4;
                cp16(&GIs[r*100 + g*32 + q], gsrc + (size_t)r*G3 + g*H_DIM + q);
            }
            cp_commit();
        }
        slab_sync(slab, 8);
    }
}

// ---------------- heads ----------------
__global__ void __launch_bounds__(256)
heads_kernel(float* __restrict__ out, const int* __restrict__ actions,
             const int* __restrict__ active, const float* __restrict__ p0,
             const float* __restrict__ pp0,
             const float* __restrict__ w_actor, const float* __restrict__ b_actor,
             const float* __restrict__ w_critic, const float* __restrict__ b_critic)
{
    int wid = threadIdx.x >> 5, lane = threadIdx.x & 31;
    size_t row = (size_t)blockIdx.x*8 + wid;
    float* orow = out + row*ROW_OUT;
    float hv[8];
    #pragma unroll
    for (int i = 0; i < 8; i++) hv[i] = orow[4 + lane + 32*i];

    float lg = 0.f;
    #pragma unroll
    for (int a = 0; a < NA_DIM; a++){
        float s = 0.f;
        #pragma unroll
        for (int i = 0; i < 8; i++) s += hv[i]*w_actor[a*H_DIM + lane + 32*i];
        #pragma unroll
        for (int o = 16; o > 0; o >>= 1) s += __shfl_xor_sync(0xffffffffu, s, o);
        if (lane == a) lg = s + b_actor[a];
    }
    float m = (lane < NA_DIM) ? lg : -1e30f;
    #pragma unroll
    for (int o = 16; o > 0; o >>= 1) m = fmaxf(m, __shfl_xor_sync(0xffffffffu, m, o));
    float e = (lane < NA_DIM) ? expf(lg - m) : 0.f;
    float den = e;
    #pragma unroll
    for (int o = 16; o > 0; o >>= 1) den += __shfl_xor_sync(0xffffffffu, den, o);
    if (lane < NA_DIM) orow[260 + lane] = e/den;

    float s = 0.f;
    #pragma unroll
    for (int i = 0; i < 8; i++) s += hv[i]*w_critic[lane + 32*i];
    #pragma unroll
    for (int o = 16; o > 0; o >>= 1) s += __shfl_xor_sync(0xffffffffu, s, o);

    int n = (int)(row & (N_DIM - 1));
    if (lane == 0)  orow[3]   = s + b_critic[0];
    if (lane == 16) orow[0]   = (float)actions[row];
    if (lane == 17) orow[1]   = p0[n];
    if (lane == 18) orow[2]   = (float)active[row];
    if (lane == 19) orow[276] = pp0[n*2];
    if (lane == 20) orow[277] = pp0[n*2 + 1];
}

// ---------------- launch ----------------
extern "C" void kernel_launch(void* const* d_in, const int* in_sizes, int n_in,
                              void* d_out, int out_size)
{
    (void)in_sizes; (void)n_in; (void)out_size;
    const float* condition = (const float*)d_in[0];
    const int*   active    = (const int*)d_in[1];
    const int*   lines     = (const int*)d_in[2];
    const int*   actions   = (const int*)d_in[3];
    const float* h0        = (const float*)d_in[4];
    const float* p0        = (const float*)d_in[5];
    const float* pp0       = (const float*)d_in[6];
    const float* embed     = (const float*)d_in[7];
    const float* wih_f = (const float*)d_in[8],  *whh_f = (const float*)d_in[9];
    const float* bih_f = (const float*)d_in[10], *bhh_f = (const float*)d_in[11];
    const float* wih_b = (const float*)d_in[12], *whh_b = (const float*)d_in[13];
    const float* bih_b = (const float*)d_in[14], *bhh_b = (const float*)d_in[15];
    const float* f_w0 = (const float*)d_in[16], *f_b0 = (const float*)d_in[17];
    const float* f_w1 = (const float*)d_in[18], *f_b1 = (const float*)d_in[19];
    const float* f_w2 = (const float*)d_in[20], *f_b2 = (const float*)d_in[21];
    const float* c_wih = (const float*)d_in[22], *c_whh = (const float*)d_in[23];
    const float* c_bih = (const float*)d_in[24], *c_bhh = (const float*)d_in[25];
    const float* w_critic = (const float*)d_in[26], *b_critic = (const float*)d_in[27];
    const float* w_actor  = (const float*)d_in[28], *b_actor  = (const float*)d_in[29];
    float* out = (float*)d_out;

    float *A0p, *A1p, *Rp, *GIp;
    cudaGetSymbolAddress((void**)&A0p, g_A0);
    cudaGetSymbolAddress((void**)&A1p, g_A1);
    cudaGetSymbolAddress((void**)&Rp,  g_Rproj);
    cudaGetSymbolAddress((void**)&GIp, g_GI);

    const int FF3_SMEM = (128*260 + 2*256*36)*4;
    cudaFuncSetAttribute(enc_v6,
                         cudaFuncAttributeMaxDynamicSharedMemorySize, E6_SMEM_BYTES);
    cudaFuncSetAttribute(main_gru_v7,
                         cudaFuncAttributeMaxDynamicSharedMemorySize, M7_SMEM_BYTES);
    cudaFuncSetAttribute(gemm_ff3<8,1>,
                         cudaFuncAttributeMaxDynamicSharedMemorySize, FF3_SMEM);
    cudaFuncSetAttribute(gemm_ff3<8,2>,
                         cudaFuncAttributeMaxDynamicSharedMemorySize, FF3_SMEM);

    // 0) gi tables + state init
    gi_tables<<<(2*NL_DIM*G3 + 255)/256, 256>>>(embed, wih_f, bih_f, wih_b, bih_b);
    init_state<<<4096, 256>>>(h0);

    // 1) persistent bidirectional encoder (bf16 MMA)
    enc_v6<<<dim3(8, 16), 512, E6_SMEM_BYTES>>>(whh_f, bhh_f, whh_b, bhh_b, lines);

    // 2) Rproj = Hmem @ W0r^T (dedup over (w,n))
    gemm_plain<1, 0><<<dim3(4, 128), 256>>>(nullptr, f_w0 + 64, 576, nullptr, Rp, 512, 256, nullptr);
    // 3) A0 = relu(cond @ W0c^T + Rproj[active] + b0)
    gemm_plain<0, 3><<<dim3(4, 2048), 256>>>(condition, f_w0, 576, f_b0, A0p, 64, 256, active);
    // 4) A1 = relu(A0 @ w1^T + b1); A0 = relu(A1 @ w2^T + b2)  (128 cols/CTA)
    gemm_ff3<8, 1><<<dim3(2, 74), 512, FF3_SMEM>>>(A0p, f_w1, f_b1, A1p, 256, 1024);
    gemm_ff3<8, 1><<<dim3(2, 74), 512, FF3_SMEM>>>(A1p, f_w2, f_b2, A0p, 256, 1024);
    // 5) GI = A0 @ c_wih^T + c_bih  (128 cols/CTA, 6 col-tiles)
    gemm_ff3<8, 2><<<dim3(6, 24), 512, FF3_SMEM>>>(A0p, c_wih, c_bih, GIp, 768, 1024);

    // 6) persistent main GRU v7 (8x16, 64 rows x 32 cols, per-slab barriers)
    main_gru_v7<<<dim3(8, 16), 256, M7_SMEM_BYTES>>>(c_whh, c_bhh, out);

    // 7) heads + scalar fields
    heads_kernel<<<TN/8, 256>>>(out, actions, active, p0, pp0,
                                w_actor, b_actor, w_critic, b_critic);
}

// round 10
// speedup vs baseline: 2.9324x; 1.1576x over previous
#include <cuda_runtime.h>
#include <math.h>
#include <stdint.h>

#define T_DIM 256
#define N_DIM 1024
#define H_DIM 256
#define L_DIM 16
#define NL_DIM 32
#define C_DIM 64
#define NA_DIM 16
#define ROW_OUT 278
#define G3 768
#define LN (L_DIM*N_DIM)          /* 16384 */
#define TN (T_DIM*N_DIM)          /* 262144 */

// ---------------- scratch ----------------
__device__ float g_giF[NL_DIM*G3];
__device__ float g_giB[NL_DIM*G3];
__device__ float g_Hf[2][(size_t)LN*H_DIM];
__device__ float g_Hb[2][(size_t)LN*H_DIM];
__device__ uint16_t g_Hfb[2][(size_t)LN*H_DIM];   // bf16 shadow of Hf
__device__ uint16_t g_Hbb[2][(size_t)LN*H_DIM];   // bf16 shadow of Hb
__device__ float g_Rproj[(size_t)LN*H_DIM];
__device__ uint32_t g_A0b[(size_t)TN*(H_DIM/2)];  // packed bf16 intermediates
__device__ uint32_t g_A1b[(size_t)TN*(H_DIM/2)];
__device__ float g_GI[(size_t)TN*G3];             // f32 (precision-critical)
__device__ float g_hm[2][N_DIM*H_DIM];            // f32 h (recurrence)
__device__ uint16_t g_hmb[2][N_DIM*H_DIM];        // bf16 shadow of h
__device__ unsigned g_slabc[16][32];
__device__ unsigned g_slabg[16][32];

// ---------------- helpers ----------------
__device__ __forceinline__ uint32_t f2tf(float x){
    uint32_t r; asm("cvt.rna.tf32.f32 %0, %1;" : "=r"(r) : "f"(x)); return r;
}
__device__ __forceinline__ uint32_t packbf(float lo, float hi){
    uint32_t r; asm("cvt.rn.bf16x2.f32 %0, %1, %2;" : "=r"(r) : "f"(hi), "f"(lo)); return r;
}
__device__ __forceinline__ void mma8(float* c, const uint32_t* a, const uint32_t* b){
    asm volatile("mma.sync.aligned.m16n8k8.row.col.f32.tf32.tf32.f32 "
        "{%0,%1,%2,%3},{%4,%5,%6,%7},{%8,%9},{%0,%1,%2,%3};"
        : "+f"(c[0]), "+f"(c[1]), "+f"(c[2]), "+f"(c[3])
        : "r"(a[0]), "r"(a[1]), "r"(a[2]), "r"(a[3]), "r"(b[0]), "r"(b[1]));
}
__device__ __forceinline__ void mma16b(float* c, const uint32_t* a, const uint32_t* b){
    asm volatile("mma.sync.aligned.m16n8k16.row.col.f32.bf16.bf16.f32 "
        "{%0,%1,%2,%3},{%4,%5,%6,%7},{%8,%9},{%0,%1,%2,%3};"
        : "+f"(c[0]), "+f"(c[1]), "+f"(c[2]), "+f"(c[3])
        : "r"(a[0]), "r"(a[1]), "r"(a[2]), "r"(a[3]), "r"(b[0]), "r"(b[1]));
}
__device__ __forceinline__ float sigm(float x){ return 1.f/(1.f+expf(-x)); }
__device__ __forceinline__ void cp16(void* smem_dst, const void* gsrc){
    uint32_t s = (uint32_t)__cvta_generic_to_shared(smem_dst);
    asm volatile("cp.async.cg.shared.global [%0], [%1], 16;" :: "r"(s), "l"(gsrc));
}
__device__ __forceinline__ void cp_commit(){ asm volatile("cp.async.commit_group;"); }
template<int N> __device__ __forceinline__ void cp_wait(){
    asm volatile("cp.async.wait_group %0;" :: "n"(N));
}

__device__ __forceinline__ void slab_sync(int slab, unsigned nb){
    __syncthreads();
    if (threadIdx.x == 0){
        volatile unsigned* genp = &g_slabg[slab][0];
        unsigned old = *genp;
        __threadfence();
        if (atomicAdd(&g_slabc[slab][0], 1u) == nb - 1u){
            g_slabc[slab][0] = 0u;
            __threadfence();
            *genp = old + 1u;
        } else {
            while (*genp == old) { }
            __threadfence();
        }
    }
    __syncthreads();
}

// ---------------- gi tables ----------------
__global__ void gi_tables(const float* __restrict__ embed,
                          const float* __restrict__ wihF, const float* __restrict__ bihF,
                          const float* __restrict__ wihB, const float* __restrict__ bihB)
{
    int idx = blockIdx.x*blockDim.x + threadIdx.x;
    if (idx >= 2*NL_DIM*G3) return;
    int dir = idx / (NL_DIM*G3);
    int rem = idx % (NL_DIM*G3);
    int e = rem / G3, j = rem % G3;
    const float* wih = dir ? wihB : wihF;
    const float* bih = dir ? bihB : bihF;
    float s = bih[j];
    const float* em = embed + e*H_DIM;
    const float* w  = wih + (size_t)j*H_DIM;
    #pragma unroll 8
    for (int k = 0; k < H_DIM; k++) s += em[k]*w[k];
    (dir ? g_giB : g_giF)[rem] = s;
}

// ---------------- init ----------------
__global__ void init_state(const float* __restrict__ h0)
{
    size_t stride = (size_t)gridDim.x*blockDim.x;
    size_t i0 = (size_t)blockIdx.x*blockDim.x + threadIdx.x;
    size_t HS = (size_t)LN*H_DIM;
    for (size_t p = i0; p < HS; p += stride){
        g_Hf[0][p] = 0.f; g_Hb[0][p] = 0.f;
        g_Hfb[0][p] = 0;  g_Hbb[0][p] = 0;
    }
    for (size_t p = i0; p < (size_t)N_DIM*H_DIM; p += stride){
        float v = h0[p];
        g_hm[0][p] = v;
        g_hmb[0][p] = (uint16_t)(packbf(v, 0.f) & 0xffffu);
    }
}

// ---------------- plain tf32 GEMM: EPI 0 = f32 store (Rproj); EPI 4 = layer0 packed --
template<int ALOAD, int EPI>
__global__ void __launch_bounds__(256)
gemm_plain(const float* __restrict__ A, const float* __restrict__ B, int ldb,
           const float* __restrict__ bias, void* __restrict__ outv,
           int K, int NC, const int* __restrict__ active)
{
    __shared__ float As[128][20];
    __shared__ float Bs[64][20];
    const int tid = threadIdx.x, lane = tid & 31, wid = tid >> 5;
    const int wm = wid >> 1, wn = wid & 1;
    const int brow = blockIdx.y, bcol = blockIdx.x;
    float acc[2][4][4];
    #pragma unroll
    for (int a = 0; a < 2; a++)
        #pragma unroll
        for (int b = 0; b < 4; b++)
            #pragma unroll
            for (int c = 0; c < 4; c++) acc[a][b][c] = 0.f;

    for (int k0 = 0; k0 < K; k0 += 16){
        #pragma unroll
        for (int i = tid; i < 2048; i += 256){
            int r = i >> 4, c = i & 15;
            int row = brow*128 + r; int k = k0 + c;
            float v;
            if (ALOAD == 0) v = A[(size_t)row*K + k];
            else v = (k < H_DIM) ? g_Hf[0][(size_t)row*H_DIM + k]
                                 : g_Hb[0][(size_t)row*H_DIM + (k - H_DIM)];
            As[r][c] = __uint_as_float(f2tf(v));
        }
        #pragma unroll
        for (int i = tid; i < 1024; i += 256){
            int n = i >> 4, c = i & 15;
            Bs[n][c] = __uint_as_float(f2tf(B[(size_t)(bcol*64 + n)*ldb + k0 + c]));
        }
        __syncthreads();
        #pragma unroll
        for (int kk = 0; kk < 16; kk += 8){
            uint32_t af[2][4], bf[4][2];
            #pragma unroll
            for (int mt = 0; mt < 2; mt++){
                int r0 = wm*32 + mt*16 + (lane >> 2);
                int c0 = kk + (lane & 3);
                af[mt][0] = __float_as_uint(As[r0][c0]);
                af[mt][1] = __float_as_uint(As[r0+8][c0]);
                af[mt][2] = __float_as_uint(As[r0][c0+4]);
                af[mt][3] = __float_as_uint(As[r0+8][c0+4]);
            }
            #pragma unroll
            for (int nt = 0; nt < 4; nt++){
                int n0 = wn*32 + nt*8 + (lane >> 2);
                bf[nt][0] = __float_as_uint(Bs[n0][kk + (lane & 3)]);
                bf[nt][1] = __float_as_uint(Bs[n0][kk + 4 + (lane & 3)]);
            }
            #pragma unroll
            for (int mt = 0; mt < 2; mt++)
                #pragma unroll
                for (int nt = 0; nt < 4; nt++)
                    mma8(acc[mt][nt], af[mt], bf[nt]);
        }
        __syncthreads();
    }
    #pragma unroll
    for (int mt = 0; mt < 2; mt++){
        #pragma unroll
        for (int nt = 0; nt < 4; nt++){
            int rbase = brow*128 + wm*32 + mt*16 + (lane >> 2);
            int cbase = bcol*64 + wn*32 + nt*8 + (lane & 3)*2;
            #pragma unroll
            for (int dr = 0; dr < 2; dr++){
                int rr = rbase + dr*8, cc = cbase;
                float v0 = acc[mt][nt][dr*2 + 0];
                float v1 = acc[mt][nt][dr*2 + 1];
                if (EPI == 4){
                    int n = rr & (N_DIM - 1);
                    int w = active[rr];
                    const float* rp = &g_Rproj[(size_t)(w*N_DIM + n)*H_DIM + cc];
                    v0 = fmaxf(v0 + bias[cc]   + rp[0], 0.f);
                    v1 = fmaxf(v1 + bias[cc+1] + rp[1], 0.f);
                    ((uint32_t*)outv)[(size_t)rr*(H_DIM/2) + (cc >> 1)] = packbf(v0, v1);
                } else {
                    float* out = (float*)outv;
                    out[(size_t)rr*NC + cc]     = v0;
                    out[(size_t)rr*NC + cc + 1] = v1;
                }
            }
        }
    }
}

// ---------------- persistent encoder v6: bf16 m16n8k16 (unchanged) ----------------
#define E6_W_U32 (3*32*132)
#define E6_A_U32 (2*256*20)
#define E6_G_FLOATS (NL_DIM*100)
#define E6_SMEM_BYTES ((E6_W_U32 + E6_A_U32 + E6_G_FLOATS)*4)

__global__ void __launch_bounds__(512, 1)
enc_v6(const float* __restrict__ whF, const float* __restrict__ bhF,
       const float* __restrict__ whB, const float* __restrict__ bhB,
       const int* __restrict__ lines)
{
    extern __shared__ uint32_t smu[];
    uint32_t* Ws2 = smu;
    uint32_t* As2 = smu + E6_W_U32;
    float* GIe = (float*)(smu + E6_W_U32 + E6_A_U32);
    const int tid = threadIdx.x, lane = tid & 31, wid = tid >> 5;
    const int wm = wid >> 1, wn = wid & 1;
    const int bcol = blockIdx.x;
    const int slab = blockIdx.y;
    const bool dirF = (slab < 8);
    const float* __restrict__ W  = dirF ? whF : whB;
    const float* __restrict__ bh = dirF ? bhF : bhB;
    const float* __restrict__ giT = dirF ? g_giF : g_giB;
    const int lrow0 = (dirF ? slab : slab - 8) * 2048;

    for (int i = tid; i < 3*32*128; i += 512){
        int g = i >> 12, rem = i & 4095;
        int c = rem >> 7, kp = rem & 127;
        const float* wr = W + (size_t)(g*H_DIM + bcol*32 + c)*H_DIM + 2*kp;
        Ws2[(g*32 + c)*132 + kp] = packbf(wr[0], wr[1]);
    }
    for (int i = tid; i < NL_DIM*96; i += 512){
        int e = i / 96, j = i % 96;
        int g = j >> 5, c = j & 31;
        GIe[e*100 + j] = __ldg(&giT[e*G3 + g*H_DIM + bcol*32 + c]);
    }
    float bR[2][2], bZ[2][2], bN[2][2];
    #pragma unroll
    for (int nt = 0; nt < 2; nt++)
        #pragma unroll
        for (int dc = 0; dc < 2; dc++){
            int c = bcol*32 + wn*16 + nt*8 + (lane & 3)*2 + dc;
            bR[nt][dc] = bh[c];
            bZ[nt][dc] = bh[H_DIM + c];
            bN[nt][dc] = bh[2*H_DIM + c];
        }
    __syncthreads();

    for (int t = 0; t < L_DIM; t++){
        const float* __restrict__ hsrc = dirF ? g_Hf[t & 1] : g_Hb[t & 1];
        float* __restrict__ hdst = dirF ? g_Hf[(t + 1) & 1] : g_Hb[(t + 1) & 1];
        const uint16_t* __restrict__ hsrc16 = dirF ? g_Hfb[t & 1] : g_Hbb[t & 1];
        uint16_t* __restrict__ hdst16 = dirF ? g_Hfb[(t + 1) & 1] : g_Hbb[(t + 1) & 1];

        auto stage = [&](int p){
            int chunk = p >> 3, kb = p & 7, buf = p & 1;
            const uint16_t* src = hsrc16 + (size_t)(lrow0 + chunk*256)*H_DIM + kb*32;
            uint32_t* dst = As2 + buf*256*20;
            #pragma unroll
            for (int i = tid; i < 1024; i += 512){
                int r = i >> 2, q = i & 3;
                cp16(&dst[r*20 + q*4], src + (size_t)r*H_DIM + q*8);
            }
            cp_commit();
        };

        float acc[3][2][2][4];
        stage(0);
        for (int p = 0; p < 64; p++){
            cp_wait<0>();
            __syncthreads();
            if (p + 1 < 64) stage(p + 1);
            const int kb = p & 7;
            if (kb == 0){
                #pragma unroll
                for (int g = 0; g < 3; g++)
                    #pragma unroll
                    for (int a = 0; a < 2; a++)
                        #pragma unroll
                        for (int b = 0; b < 2; b++)
                            #pragma unroll
                            for (int c = 0; c < 4; c++) acc[g][a][b][c] = 0.f;
            }
            const uint32_t* Ab2 = As2 + (p & 1)*256*20;
            #pragma unroll
            for (int kk = 0; kk < 32; kk += 16){
                uint32_t af[2][4];
                #pragma unroll
                for (int mt = 0; mt < 2; mt++){
                    int r0 = wm*32 + mt*16 + (lane >> 2);
                    int ui = r0*20 + (kk >> 1) + (lane & 3);
                    af[mt][0] = Ab2[ui];
                    af[mt][1] = Ab2[ui + 160];
                    af[mt][2] = Ab2[ui + 4];
                    af[mt][3] = Ab2[ui + 164];
                }
                uint32_t bf[3][2][2];
                #pragma unroll
                for (int g = 0; g < 3; g++)
                    #pragma unroll
                    for (int nt = 0; nt < 2; nt++){
                        int n0 = wn*16 + nt*8 + (lane >> 2);
                        int wi = (g*32 + n0)*132 + kb*16 + (kk >> 1) + (lane & 3);
                        bf[g][nt][0] = Ws2[wi];
                        bf[g][nt][1] = Ws2[wi + 4];
                    }
                #pragma unroll
                for (int g = 0; g < 3; g++)
                    #pragma unroll
                    for (int mt = 0; mt < 2; mt++)
                        #pragma unroll
                        for (int nt = 0; nt < 2; nt++)
                            mma16b(acc[g][mt][nt], af[mt], bf[g][nt]);
            }

            if (kb == 7){
                const int base = lrow0 + (p >> 3)*256;
                #pragma unroll
                for (int mt = 0; mt < 2; mt++){
                    #pragma unroll
                    for (int dr = 0; dr < 2; dr++){
                        int lr = base + wm*32 + mt*16 + (lane >> 2) + dr*8;
                        int iroll = lr >> 10;
                        int nb = lr & (N_DIM - 1);
                        int l = dirF ? ((iroll + t) & 15) : ((iroll + 15 - t) & 15);
                        const float* ge = GIe + __ldg(&lines[nb*L_DIM + l])*100;
                        #pragma unroll
                        for (int nt = 0; nt < 2; nt++){
                            int hcl = wn*16 + nt*8 + (lane & 3)*2;
                            float2 gv0 = *(const float2*)&ge[hcl];
                            float2 gv1 = *(const float2*)&ge[32 + hcl];
                            float2 gv2 = *(const float2*)&ge[64 + hcl];
                            float2 hold = __ldcg((const float2*)&hsrc[(size_t)lr*H_DIM + bcol*32 + hcl]);
                            float2 hout;
                            #pragma unroll
                            for (int dc = 0; dc < 2; dc++){
                                float gr = acc[0][mt][nt][dr*2+dc] + bR[nt][dc];
                                float gz = acc[1][mt][nt][dr*2+dc] + bZ[nt][dc];
                                float gn = acc[2][mt][nt][dr*2+dc] + bN[nt][dc];
                                float r  = sigm((dc ? gv0.y : gv0.x) + gr);
                                float z  = sigm((dc ? gv1.y : gv1.x) + gz);
                                float nn = tanhf((dc ? gv2.y : gv2.x) + r*gn);
                                float ho = dc ? hold.y : hold.x;
                                float hnew = (1.f - z)*nn + z*ho;
                                if (dc) hout.y = hnew; else hout.x = hnew;
                            }
                            __stcg((float2*)&hdst[(size_t)lr*H_DIM + bcol*32 + hcl], hout);
                            __stcg((uint32_t*)(hdst16 + (size_t)lr*H_DIM + bcol*32 + hcl),
                                   packbf(hout.x, hout.y));
                        }
                    }
                }
            }
        }
        slab_sync(slab, 8);
    }
}

// ---------------- bf16 feed-forward GEMM: 128 cols/CTA, m16n8k16 -------------------
// A packed bf16 [M, 128 u32]; W f32 -> packed in SMEM. EPI 1: relu + packed bf16 out;
// EPI 2: +bias, f32 out (GI).
#define FFB_W_U32 (128*132)                /* 16896 */
#define FFB_A_U32 (2*256*36)               /* 18432 */
#define FFB_SMEM_BYTES ((FFB_W_U32 + FFB_A_U32)*4)

template<int EPI>
__global__ void __launch_bounds__(512, 1)
gemm_ffb(const uint32_t* __restrict__ A, const float* __restrict__ W,
         const float* __restrict__ bias, void* __restrict__ outv,
         int out_stride, int nrt)
{
    extern __shared__ uint32_t smu[];
    uint32_t* Ws2 = smu;
    uint32_t* As2 = smu + FFB_W_U32;
    const int tid = threadIdx.x, lane = tid & 31, wid = tid >> 5;
    const int wm = wid >> 1, wn = wid & 1;
    const int bcol = blockIdx.x;

    for (int i = tid; i < 128*128; i += 512){
        int c = i >> 7, kp = i & 127;
        const float* wr = W + (size_t)(bcol*128 + c)*H_DIM + 2*kp;
        Ws2[c*132 + kp] = packbf(wr[0], wr[1]);
    }
    __syncthreads();

    const int nch = (nrt - (int)blockIdx.y + (int)gridDim.y - 1) / (int)gridDim.y;
    if (nch <= 0) return;
    const int total = nch*4;

    auto stage = [&](int p){
        int ci = p >> 2, kb = p & 3, buf = p & 1;
        int rt = blockIdx.y + ci*gridDim.y;
        const uint32_t* src = A + (size_t)rt*256*128 + kb*32;
        uint32_t* dst = As2 + buf*256*36;
        #pragma unroll
        for (int i = tid; i < 2048; i += 512){
            int r = i >> 3, q = i & 7;
            cp16(&dst[r*36 + q*4], src + (size_t)r*128 + q*4);
        }
        cp_commit();
    };

    float acc[2][8][4];
    stage(0);
    for (int p = 0; p < total; p++){
        cp_wait<0>();
        __syncthreads();
        if (p + 1 < total) stage(p + 1);
        const int kb = p & 3;
        if (kb == 0){
            #pragma unroll
            for (int a = 0; a < 2; a++)
                #pragma unroll
                for (int b = 0; b < 8; b++)
                    #pragma unroll
                    for (int c = 0; c < 4; c++) acc[a][b][c] = 0.f;
        }
        const uint32_t* Ab2 = As2 + (p & 1)*256*36;
        #pragma unroll
        for (int kk = 0; kk < 64; kk += 16){
            uint32_t af[2][4];
            #pragma unroll
            for (int mt = 0; mt < 2; mt++){
                int r0 = wm*32 + mt*16 + (lane >> 2);
                int ui = r0*36 + (kk >> 1) + (lane & 3);
                af[mt][0] = Ab2[ui];
                af[mt][1] = Ab2[ui + 288];
                af[mt][2] = Ab2[ui + 4];
                af[mt][3] = Ab2[ui + 292];
            }
            uint32_t bf[8][2];
            #pragma unroll
            for (int nt = 0; nt < 8; nt++){
                int n0 = wn*64 + nt*8 + (lane >> 2);
                int wi = n0*132 + kb*32 + (kk >> 1) + (lane & 3);
                bf[nt][0] = Ws2[wi];
                bf[nt][1] = Ws2[wi + 4];
            }
            #pragma unroll
            for (int mt = 0; mt < 2; mt++)
                #pragma unroll
                for (int nt = 0; nt < 8; nt++)
                    mma16b(acc[mt][nt], af[mt], bf[nt]);
        }

        if (kb == 3){
            int rt = blockIdx.y + (p >> 2)*gridDim.y;
            #pragma unroll
            for (int mt = 0; mt < 2; mt++){
                #pragma unroll
                for (int nt = 0; nt < 8; nt++){
                    #pragma unroll
                    for (int dr = 0; dr < 2; dr++){
                        int rr = rt*256 + wm*32 + mt*16 + (lane >> 2) + dr*8;
                        int cc = bcol*128 + wn*64 + nt*8 + (lane & 3)*2;
                        float v0 = acc[mt][nt][dr*2 + 0] + bias[cc];
                        float v1 = acc[mt][nt][dr*2 + 1] + bias[cc + 1];
                        if (EPI == 1){
                            v0 = fmaxf(v0, 0.f); v1 = fmaxf(v1, 0.f);
                            ((uint32_t*)outv)[(size_t)rr*out_stride + (cc >> 1)] = packbf(v0, v1);
                        } else {
                            float2 v; v.x = v0; v.y = v1;
                            *(float2*)&((float*)outv)[(size_t)rr*out_stride + cc] = v;
                        }
                    }
                }
            }
        }
    }
}

// ---------------- persistent main GRU v8: bf16 MMA, f32 gates/hold -----------------
#define M8_W_U32 (3*32*132)                /* 12672 */
#define M8_A_U32 (64*132)                  /* 8448  */
#define M8_G_FLOATS (64*100)               /* 6400  */
#define M8_SMEM_BYTES ((M8_W_U32 + M8_A_U32 + M8_G_FLOATS)*4)

__global__ void __launch_bounds__(256, 1)
main_gru_v8(const float* __restrict__ whh, const float* __restrict__ bhh,
            float* __restrict__ out)
{
    extern __shared__ uint32_t smu[];
    uint32_t* Ws2 = smu;
    uint32_t* As2 = smu + M8_W_U32;
    float* GIs = (float*)(smu + M8_W_U32 + M8_A_U32);
    const int tid = threadIdx.x, lane = tid & 31, wid = tid >> 5;
    const int wm = wid >> 1, wn = wid & 1;      // wm 0..3 (16 rows), wn 0..1
    const int bcol = blockIdx.x;                // 0..7 (32 cols)
    const int slab = blockIdx.y;                // 0..15
    const int row0 = slab*64;

    for (int i = tid; i < 3*32*128; i += 256){
        int g = i >> 12, rem = i & 4095;
        int c = rem >> 7, kp = rem & 127;
        const float* wr = whh + (size_t)(g*H_DIM + bcol*32 + c)*H_DIM + 2*kp;
        Ws2[(g*32 + c)*132 + kp] = packbf(wr[0], wr[1]);
    }
    float bR[2][2], bZ[2][2], bN[2][2];
    #pragma unroll
    for (int nt = 0; nt < 2; nt++)
        #pragma unroll
        for (int dc = 0; dc < 2; dc++){
            int c = bcol*32 + wn*16 + nt*8 + (lane & 3)*2 + dc;
            bR[nt][dc] = bhh[c];
            bZ[nt][dc] = bhh[H_DIM + c];
            bN[nt][dc] = bhh[2*H_DIM + c];
        }

    {
        const float* gsrc = g_GI + (size_t)row0*G3 + bcol*32;
        #pragma unroll
        for (int i = tid; i < 1536; i += 256){
            int r = i / 24, j = i % 24;
            int g = j >> 3, q = (j & 7)*4;
            cp16(&GIs[r*100 + g*32 + q], gsrc + (size_t)r*G3 + g*H_DIM + q);
        }
        cp_commit();
    }
    slab_sync(slab, 8);

    for (int t = 0; t < T_DIM; t++){
        const float* __restrict__ hsrc = g_hm[t & 1];
        float* __restrict__ hdst = g_hm[(t + 1) & 1];
        const uint16_t* __restrict__ hsrc16 = g_hmb[t & 1];
        uint16_t* __restrict__ hdst16 = g_hmb[(t + 1) & 1];

        // stage bf16 A tile (64 rows x 256 K = 64x128 u32)
        {
            const uint16_t* src = hsrc16 + (size_t)row0*H_DIM;
            #pragma unroll
            for (int i = tid; i < 2048; i += 256){
                int r = i >> 5, q = i & 31;
                cp16(&As2[r*132 + q*4], src + (size_t)r*H_DIM + q*8);
            }
            cp_commit();
        }
        cp_wait<0>();
        __syncthreads();

        float acc[3][2][4];
        #pragma unroll
        for (int g = 0; g < 3; g++)
            #pragma unroll
            for (int n = 0; n < 2; n++)
                #pragma unroll
                for (int c = 0; c < 4; c++) acc[g][n][c] = 0.f;

        #pragma unroll 4
        for (int kk = 0; kk < H_DIM; kk += 16){
            uint32_t af[4];
            {
                int r0 = wm*16 + (lane >> 2);
                int ui = r0*132 + (kk >> 1) + (lane & 3);
                af[0] = As2[ui];
                af[1] = As2[ui + 8*132];
                af[2] = As2[ui + 4];
                af[3] = As2[ui + 8*132 + 4];
            }
            uint32_t bf[3][2][2];
            #pragma unroll
            for (int g = 0; g < 3; g++)
                #pragma unroll
                for (int nt = 0; nt < 2; nt++){
                    int n0 = wn*16 + nt*8 + (lane >> 2);
                    int wi = (g*32 + n0)*132 + (kk >> 1) + (lane & 3);
                    bf[g][nt][0] = Ws2[wi];
                    bf[g][nt][1] = Ws2[wi + 4];
                }
            #pragma unroll
            for (int g = 0; g < 3; g++)
                #pragma unroll
                for (int nt = 0; nt < 2; nt++)
                    mma16b(acc[g][nt], af, bf[g][nt]);
        }

        float* __restrict__ out_t = out + ((size_t)t*N_DIM)*ROW_OUT;
        #pragma unroll
        for (int dr = 0; dr < 2; dr++){
            int rl = wm*16 + (lane >> 2) + dr*8;
            int row = row0 + rl;
            #pragma unroll
            for (int nt = 0; nt < 2; nt++){
                int ccl = wn*16 + nt*8 + (lane & 3)*2;
                float2 gv0 = *(const float2*)&GIs[rl*100 + ccl];
                float2 gv1 = *(const float2*)&GIs[rl*100 + 32 + ccl];
                float2 gv2 = *(const float2*)&GIs[rl*100 + 64 + ccl];
                float2 hold = __ldcg((const float2*)&hsrc[(size_t)row*H_DIM + bcol*32 + ccl]);
                float2 hout;
                #pragma unroll
                for (int dc = 0; dc < 2; dc++){
                    float gr = acc[0][nt][dr*2+dc] + bR[nt][dc];
                    float gz = acc[1][nt][dr*2+dc] + bZ[nt][dc];
                    float gn = acc[2][nt][dr*2+dc] + bN[nt][dc];
                    float r  = sigm((dc ? gv0.y : gv0.x) + gr);
                    float z  = sigm((dc ? gv1.y : gv1.x) + gz);
                    float nn = tanhf((dc ? gv2.y : gv2.x) + r*gn);
                    float ho = dc ? hold.y : hold.x;
                    float hnew = (1.f - z)*nn + z*ho;
                    if (dc) hout.y = hnew; else hout.x = hnew;
                }
                __stcg((float2*)&hdst[(size_t)row*H_DIM + bcol*32 + ccl], hout);
                __stcg((uint32_t*)(hdst16 + (size_t)row*H_DIM + bcol*32 + ccl),
                       packbf(hout.x, hout.y));
                *(float2*)&out_t[(size_t)row*ROW_OUT + 4 + bcol*32 + ccl] = hout;
            }
        }

        __syncthreads();
        if (t + 1 < T_DIM){
            const float* gsrc = g_GI + ((size_t)(t + 1)*N_DIM + row0)*G3 + bcol*32;
            #pragma unroll
            for (int i = tid; i < 1536; i += 256){
                int r = i / 24, j = i % 24;
                int g = j >> 3, q = (j & 7)*4;
                cp16(&GIs[r*100 + g*32 + q], gsrc + (size_t)r*G3 + g*H_DIM + q);
            }
            cp_commit();
        }
        slab_sync(slab, 8);
    }
}

// ---------------- heads ----------------
__global__ void __launch_bounds__(256)
heads_kernel(float* __restrict__ out, const int* __restrict__ actions,
             const int* __restrict__ active, const float* __restrict__ p0,
             const float* __restrict__ pp0,
             const float* __restrict__ w_actor, const float* __restrict__ b_actor,
             const float* __restrict__ w_critic, const float* __restrict__ b_critic)
{
    int wid = threadIdx.x >> 5, lane = threadIdx.x & 31;
    size_t row = (size_t)blockIdx.x*8 + wid;
    float* orow = out + row*ROW_OUT;
    float hv[8];
    #pragma unroll
    for (int i = 0; i < 8; i++) hv[i] = orow[4 + lane + 32*i];

    float lg = 0.f;
    #pragma unroll
    for (int a = 0; a < NA_DIM; a++){
        float s = 0.f;
        #pragma unroll
        for (int i = 0; i < 8; i++) s += hv[i]*w_actor[a*H_DIM + lane + 32*i];
        #pragma unroll
        for (int o = 16; o > 0; o >>= 1) s += __shfl_xor_sync(0xffffffffu, s, o);
        if (lane == a) lg = s + b_actor[a];
    }
    float m = (lane < NA_DIM) ? lg : -1e30f;
    #pragma unroll
    for (int o = 16; o > 0; o >>= 1) m = fmaxf(m, __shfl_xor_sync(0xffffffffu, m, o));
    float e = (lane < NA_DIM) ? expf(lg - m) : 0.f;
    float den = e;
    #pragma unroll
    for (int o = 16; o > 0; o >>= 1) den += __shfl_xor_sync(0xffffffffu, den, o);
    if (lane < NA_DIM) orow[260 + lane] = e/den;

    float s = 0.f;
    #pragma unroll
    for (int i = 0; i < 8; i++) s += hv[i]*w_critic[lane + 32*i];
    #pragma unroll
    for (int o = 16; o > 0; o >>= 1) s += __shfl_xor_sync(0xffffffffu, s, o);

    int n = (int)(row & (N_DIM - 1));
    if (lane == 0)  orow[3]   = s + b_critic[0];
    if (lane == 16) orow[0]   = (float)actions[row];
    if (lane == 17) orow[1]   = p0[n];
    if (lane == 18) orow[2]   = (float)active[row];
    if (lane == 19) orow[276] = pp0[n*2];
    if (lane == 20) orow[277] = pp0[n*2 + 1];
}

// ---------------- launch ----------------
extern "C" void kernel_launch(void* const* d_in, const int* in_sizes, int n_in,
                              void* d_out, int out_size)
{
    (void)in_sizes; (void)n_in; (void)out_size;
    const float* condition = (const float*)d_in[0];
    const int*   active    = (const int*)d_in[1];
    const int*   lines     = (const int*)d_in[2];
    const int*   actions   = (const int*)d_in[3];
    const float* h0        = (const float*)d_in[4];
    const float* p0        = (const float*)d_in[5];
    const float* pp0       = (const float*)d_in[6];
    const float* embed     = (const float*)d_in[7];
    const float* wih_f = (const float*)d_in[8],  *whh_f = (const float*)d_in[9];
    const float* bih_f = (const float*)d_in[10], *bhh_f = (const float*)d_in[11];
    const float* wih_b = (const float*)d_in[12], *whh_b = (const float*)d_in[13];
    const float* bih_b = (const float*)d_in[14], *bhh_b = (const float*)d_in[15];
    const float* f_w0 = (const float*)d_in[16], *f_b0 = (const float*)d_in[17];
    const float* f_w1 = (const float*)d_in[18], *f_b1 = (const float*)d_in[19];
    const float* f_w2 = (const float*)d_in[20], *f_b2 = (const float*)d_in[21];
    const float* c_wih = (const float*)d_in[22], *c_whh = (const float*)d_in[23];
    const float* c_bih = (const float*)d_in[24], *c_bhh = (const float*)d_in[25];
    const float* w_critic = (const float*)d_in[26], *b_critic = (const float*)d_in[27];
    const float* w_actor  = (const float*)d_in[28], *b_actor  = (const float*)d_in[29];
    float* out = (float*)d_out;

    float *Rp, *GIp;
    uint32_t *A0bp, *A1bp;
    cudaGetSymbolAddress((void**)&Rp,  g_Rproj);
    cudaGetSymbolAddress((void**)&GIp, g_GI);
    cudaGetSymbolAddress((void**)&A0bp, g_A0b);
    cudaGetSymbolAddress((void**)&A1bp, g_A1b);

    cudaFuncSetAttribute(enc_v6,
                         cudaFuncAttributeMaxDynamicSharedMemorySize, E6_SMEM_BYTES);
    cudaFuncSetAttribute(main_gru_v8,
                         cudaFuncAttributeMaxDynamicSharedMemorySize, M8_SMEM_BYTES);
    cudaFuncSetAttribute(gemm_ffb<1>,
                         cudaFuncAttributeMaxDynamicSharedMemorySize, FFB_SMEM_BYTES);
    cudaFuncSetAttribute(gemm_ffb<2>,
                         cudaFuncAttributeMaxDynamicSharedMemorySize, FFB_SMEM_BYTES);

    // 0) gi tables + state init
    gi_tables<<<(2*NL_DIM*G3 + 255)/256, 256>>>(embed, wih_f, bih_f, wih_b, bih_b);
    init_state<<<4096, 256>>>(h0);

    // 1) persistent bidirectional encoder (bf16 MMA)
    enc_v6<<<dim3(8, 16), 512, E6_SMEM_BYTES>>>(whh_f, bhh_f, whh_b, bhh_b, lines);

    // 2) Rproj = Hmem @ W0r^T (f32)
    gemm_plain<1, 0><<<dim3(4, 128), 256>>>(nullptr, f_w0 + 64, 576, nullptr, Rp, 512, 256, nullptr);
    // 3) A0 = relu(cond @ W0c^T + Rproj[active] + b0)  -> packed bf16
    gemm_plain<0, 4><<<dim3(4, 2048), 256>>>(condition, f_w0, 576, f_b0, A0bp, 64, 256, active);
    // 4) A1 = relu(A0 @ w1^T + b1); A0'' = relu(A1 @ w2^T + b2)  (bf16 GEMMs)
    gemm_ffb<1><<<dim3(2, 74), 512, FFB_SMEM_BYTES>>>(A0bp, f_w1, f_b1, A1bp, 128, 1024);
    gemm_ffb<1><<<dim3(2, 74), 512, FFB_SMEM_BYTES>>>(A1bp, f_w2, f_b2, A0bp, 128, 1024);
    // 5) GI = A0'' @ c_wih^T + c_bih  (bf16 inputs, f32 output)
    gemm_ffb<2><<<dim3(6, 24), 512, FFB_SMEM_BYTES>>>(A0bp, c_wih, c_bih, GIp, 768, 1024);

    // 6) persistent main GRU v8 (bf16 MMA, f32 gates/hold)
    main_gru_v8<<<dim3(8, 16), 256, M8_SMEM_BYTES>>>(c_whh, c_bhh, out);

    // 7) heads + scalar fields
    heads_kernel<<<TN/8, 256>>>(out, actions, active, p0, pp0,
                                w_actor, b_actor, w_critic, b_critic);
}

// round 11
// speedup vs baseline: 3.0669x; 1.0458x over previous
#include <cuda_runtime.h>
#include <math.h>
#include <stdint.h>

#define T_DIM 256
#define N_DIM 1024
#define H_DIM 256
#define L_DIM 16
#define NL_DIM 32
#define C_DIM 64
#define NA_DIM 16
#define ROW_OUT 278
#define G3 768
#define LN (L_DIM*N_DIM)          /* 16384 */
#define TN (T_DIM*N_DIM)          /* 262144 */

// ---------------- scratch ----------------
__device__ float g_giF[NL_DIM*G3];
__device__ float g_giB[NL_DIM*G3];
__device__ float g_Hf[2][(size_t)LN*H_DIM];
__device__ float g_Hb[2][(size_t)LN*H_DIM];
__device__ uint16_t g_Hfb[2][(size_t)LN*H_DIM];   // bf16 shadow of Hf
__device__ uint16_t g_Hbb[2][(size_t)LN*H_DIM];   // bf16 shadow of Hb
__device__ float g_Rproj[(size_t)LN*H_DIM];
__device__ uint32_t g_A0b[(size_t)TN*(H_DIM/2)];  // packed bf16 intermediates
__device__ uint32_t g_A1b[(size_t)TN*(H_DIM/2)];
__device__ uint32_t g_GIb[(size_t)TN*(G3/2)];     // packed bf16 gi (402 MB vs 805)
__device__ float g_hm[2][N_DIM*H_DIM];            // f32 h (recurrence)
__device__ uint16_t g_hmb[2][N_DIM*H_DIM];        // bf16 shadow of h
__device__ unsigned g_slabc[16][32];
__device__ unsigned g_slabg[16][32];

// ---------------- helpers ----------------
__device__ __forceinline__ uint32_t f2tf(float x){
    uint32_t r; asm("cvt.rna.tf32.f32 %0, %1;" : "=r"(r) : "f"(x)); return r;
}
__device__ __forceinline__ uint32_t packbf(float lo, float hi){
    uint32_t r; asm("cvt.rn.bf16x2.f32 %0, %1, %2;" : "=r"(r) : "f"(hi), "f"(lo)); return r;
}
__device__ __forceinline__ float2 unpackbf(uint32_t u){
    float2 r;
    r.x = __uint_as_float(u << 16);
    r.y = __uint_as_float(u & 0xffff0000u);
    return r;
}
__device__ __forceinline__ void mma8(float* c, const uint32_t* a, const uint32_t* b){
    asm volatile("mma.sync.aligned.m16n8k8.row.col.f32.tf32.tf32.f32 "
        "{%0,%1,%2,%3},{%4,%5,%6,%7},{%8,%9},{%0,%1,%2,%3};"
        : "+f"(c[0]), "+f"(c[1]), "+f"(c[2]), "+f"(c[3])
        : "r"(a[0]), "r"(a[1]), "r"(a[2]), "r"(a[3]), "r"(b[0]), "r"(b[1]));
}
__device__ __forceinline__ void mma16b(float* c, const uint32_t* a, const uint32_t* b){
    asm volatile("mma.sync.aligned.m16n8k16.row.col.f32.bf16.bf16.f32 "
        "{%0,%1,%2,%3},{%4,%5,%6,%7},{%8,%9},{%0,%1,%2,%3};"
        : "+f"(c[0]), "+f"(c[1]), "+f"(c[2]), "+f"(c[3])
        : "r"(a[0]), "r"(a[1]), "r"(a[2]), "r"(a[3]), "r"(b[0]), "r"(b[1]));
}
__device__ __forceinline__ float sigm(float x){ return 1.f/(1.f+expf(-x)); }
__device__ __forceinline__ void cp16(void* smem_dst, const void* gsrc){
    uint32_t s = (uint32_t)__cvta_generic_to_shared(smem_dst);
    asm volatile("cp.async.cg.shared.global [%0], [%1], 16;" :: "r"(s), "l"(gsrc));
}
__device__ __forceinline__ void cp_commit(){ asm volatile("cp.async.commit_group;"); }
template<int N> __device__ __forceinline__ void cp_wait(){
    asm volatile("cp.async.wait_group %0;" :: "n"(N));
}

__device__ __forceinline__ void slab_sync(int slab, unsigned nb){
    __syncthreads();
    if (threadIdx.x == 0){
        volatile unsigned* genp = &g_slabg[slab][0];
        unsigned old = *genp;
        __threadfence();
        if (atomicAdd(&g_slabc[slab][0], 1u) == nb - 1u){
            g_slabc[slab][0] = 0u;
            __threadfence();
            *genp = old + 1u;
        } else {
            while (*genp == old) { }
            __threadfence();
        }
    }
    __syncthreads();
}

// ---------------- gi tables ----------------
__global__ void gi_tables(const float* __restrict__ embed,
                          const float* __restrict__ wihF, const float* __restrict__ bihF,
                          const float* __restrict__ wihB, const float* __restrict__ bihB)
{
    int idx = blockIdx.x*blockDim.x + threadIdx.x;
    if (idx >= 2*NL_DIM*G3) return;
    int dir = idx / (NL_DIM*G3);
    int rem = idx % (NL_DIM*G3);
    int e = rem / G3, j = rem % G3;
    const float* wih = dir ? wihB : wihF;
    const float* bih = dir ? bihB : bihF;
    float s = bih[j];
    const float* em = embed + e*H_DIM;
    const float* w  = wih + (size_t)j*H_DIM;
    #pragma unroll 8
    for (int k = 0; k < H_DIM; k++) s += em[k]*w[k];
    (dir ? g_giB : g_giF)[rem] = s;
}

// ---------------- init ----------------
__global__ void init_state(const float* __restrict__ h0)
{
    size_t stride = (size_t)gridDim.x*blockDim.x;
    size_t i0 = (size_t)blockIdx.x*blockDim.x + threadIdx.x;
    size_t HS = (size_t)LN*H_DIM;
    for (size_t p = i0; p < HS; p += stride){
        g_Hf[0][p] = 0.f; g_Hb[0][p] = 0.f;
        g_Hfb[0][p] = 0;  g_Hbb[0][p] = 0;
    }
    for (size_t p = i0; p < (size_t)N_DIM*H_DIM; p += stride){
        float v = h0[p];
        g_hm[0][p] = v;
        g_hmb[0][p] = (uint16_t)(packbf(v, 0.f) & 0xffffu);
    }
}

// ---------------- plain tf32 GEMM: EPI 0 = f32 store (Rproj); EPI 4 = layer0 packed --
template<int ALOAD, int EPI>
__global__ void __launch_bounds__(256)
gemm_plain(const float* __restrict__ A, const float* __restrict__ B, int ldb,
           const float* __restrict__ bias, void* __restrict__ outv,
           int K, int NC, const int* __restrict__ active)
{
    __shared__ float As[128][20];
    __shared__ float Bs[64][20];
    const int tid = threadIdx.x, lane = tid & 31, wid = tid >> 5;
    const int wm = wid >> 1, wn = wid & 1;
    const int brow = blockIdx.y, bcol = blockIdx.x;
    float acc[2][4][4];
    #pragma unroll
    for (int a = 0; a < 2; a++)
        #pragma unroll
        for (int b = 0; b < 4; b++)
            #pragma unroll
            for (int c = 0; c < 4; c++) acc[a][b][c] = 0.f;

    for (int k0 = 0; k0 < K; k0 += 16){
        #pragma unroll
        for (int i = tid; i < 2048; i += 256){
            int r = i >> 4, c = i & 15;
            int row = brow*128 + r; int k = k0 + c;
            float v;
            if (ALOAD == 0) v = A[(size_t)row*K + k];
            else v = (k < H_DIM) ? g_Hf[0][(size_t)row*H_DIM + k]
                                 : g_Hb[0][(size_t)row*H_DIM + (k - H_DIM)];
            As[r][c] = __uint_as_float(f2tf(v));
        }
        #pragma unroll
        for (int i = tid; i < 1024; i += 256){
            int n = i >> 4, c = i & 15;
            Bs[n][c] = __uint_as_float(f2tf(B[(size_t)(bcol*64 + n)*ldb + k0 + c]));
        }
        __syncthreads();
        #pragma unroll
        for (int kk = 0; kk < 16; kk += 8){
            uint32_t af[2][4], bf[4][2];
            #pragma unroll
            for (int mt = 0; mt < 2; mt++){
                int r0 = wm*32 + mt*16 + (lane >> 2);
                int c0 = kk + (lane & 3);
                af[mt][0] = __float_as_uint(As[r0][c0]);
                af[mt][1] = __float_as_uint(As[r0+8][c0]);
                af[mt][2] = __float_as_uint(As[r0][c0+4]);
                af[mt][3] = __float_as_uint(As[r0+8][c0+4]);
            }
            #pragma unroll
            for (int nt = 0; nt < 4; nt++){
                int n0 = wn*32 + nt*8 + (lane >> 2);
                bf[nt][0] = __float_as_uint(Bs[n0][kk + (lane & 3)]);
                bf[nt][1] = __float_as_uint(Bs[n0][kk + 4 + (lane & 3)]);
            }
            #pragma unroll
            for (int mt = 0; mt < 2; mt++)
                #pragma unroll
                for (int nt = 0; nt < 4; nt++)
                    mma8(acc[mt][nt], af[mt], bf[nt]);
        }
        __syncthreads();
    }
    #pragma unroll
    for (int mt = 0; mt < 2; mt++){
        #pragma unroll
        for (int nt = 0; nt < 4; nt++){
            int rbase = brow*128 + wm*32 + mt*16 + (lane >> 2);
            int cbase = bcol*64 + wn*32 + nt*8 + (lane & 3)*2;
            #pragma unroll
            for (int dr = 0; dr < 2; dr++){
                int rr = rbase + dr*8, cc = cbase;
                float v0 = acc[mt][nt][dr*2 + 0];
                float v1 = acc[mt][nt][dr*2 + 1];
                if (EPI == 4){
                    int n = rr & (N_DIM - 1);
                    int w = active[rr];
                    const float* rp = &g_Rproj[(size_t)(w*N_DIM + n)*H_DIM + cc];
                    v0 = fmaxf(v0 + bias[cc]   + rp[0], 0.f);
                    v1 = fmaxf(v1 + bias[cc+1] + rp[1], 0.f);
                    ((uint32_t*)outv)[(size_t)rr*(H_DIM/2) + (cc >> 1)] = packbf(v0, v1);
                } else {
                    float* out = (float*)outv;
                    out[(size_t)rr*NC + cc]     = v0;
                    out[(size_t)rr*NC + cc + 1] = v1;
                }
            }
        }
    }
}

// ---------------- persistent encoder v7: bf16, K-chunk 64 (half the stages) --------
#define E7_W_U32 (3*32*132)                /* 12672 */
#define E7_A_U32 (2*256*36)                /* 18432 */
#define E7_G_FLOATS (NL_DIM*100)           /* 3200  */
#define E7_SMEM_BYTES ((E7_W_U32 + E7_A_U32 + E7_G_FLOATS)*4)

__global__ void __launch_bounds__(512, 1)
enc_v7(const float* __restrict__ whF, const float* __restrict__ bhF,
       const float* __restrict__ whB, const float* __restrict__ bhB,
       const int* __restrict__ lines)
{
    extern __shared__ uint32_t smu[];
    uint32_t* Ws2 = smu;
    uint32_t* As2 = smu + E7_W_U32;
    float* GIe = (float*)(smu + E7_W_U32 + E7_A_U32);
    const int tid = threadIdx.x, lane = tid & 31, wid = tid >> 5;
    const int wm = wid >> 1, wn = wid & 1;
    const int bcol = blockIdx.x;
    const int slab = blockIdx.y;
    const bool dirF = (slab < 8);
    const float* __restrict__ W  = dirF ? whF : whB;
    const float* __restrict__ bh = dirF ? bhF : bhB;
    const float* __restrict__ giT = dirF ? g_giF : g_giB;
    const int lrow0 = (dirF ? slab : slab - 8) * 2048;

    for (int i = tid; i < 3*32*128; i += 512){
        int g = i >> 12, rem = i & 4095;
        int c = rem >> 7, kp = rem & 127;
        const float* wr = W + (size_t)(g*H_DIM + bcol*32 + c)*H_DIM + 2*kp;
        Ws2[(g*32 + c)*132 + kp] = packbf(wr[0], wr[1]);
    }
    for (int i = tid; i < NL_DIM*96; i += 512){
        int e = i / 96, j = i % 96;
        int g = j >> 5, c = j & 31;
        GIe[e*100 + j] = __ldg(&giT[e*G3 + g*H_DIM + bcol*32 + c]);
    }
    float bR[2][2], bZ[2][2], bN[2][2];
    #pragma unroll
    for (int nt = 0; nt < 2; nt++)
        #pragma unroll
        for (int dc = 0; dc < 2; dc++){
            int c = bcol*32 + wn*16 + nt*8 + (lane & 3)*2 + dc;
            bR[nt][dc] = bh[c];
            bZ[nt][dc] = bh[H_DIM + c];
            bN[nt][dc] = bh[2*H_DIM + c];
        }
    __syncthreads();

    for (int t = 0; t < L_DIM; t++){
        const float* __restrict__ hsrc = dirF ? g_Hf[t & 1] : g_Hb[t & 1];
        float* __restrict__ hdst = dirF ? g_Hf[(t + 1) & 1] : g_Hb[(t + 1) & 1];
        const uint16_t* __restrict__ hsrc16 = dirF ? g_Hfb[t & 1] : g_Hbb[t & 1];
        uint16_t* __restrict__ hdst16 = dirF ? g_Hfb[(t + 1) & 1] : g_Hbb[(t + 1) & 1];

        // stage p: chunk = p>>2 (256 rows), kb = p&3 (64 K-elements)
        auto stage = [&](int p){
            int chunk = p >> 2, kb = p & 3, buf = p & 1;
            const uint16_t* src = hsrc16 + (size_t)(lrow0 + chunk*256)*H_DIM + kb*64;
            uint32_t* dst = As2 + buf*256*36;
            #pragma unroll
            for (int i = tid; i < 2048; i += 512){
                int r = i >> 3, q = i & 7;
                cp16(&dst[r*36 + q*4], src + (size_t)r*H_DIM + q*8);
            }
            cp_commit();
        };

        float acc[3][2][2][4];
        stage(0);
        for (int p = 0; p < 32; p++){
            cp_wait<0>();
            __syncthreads();
            if (p + 1 < 32) stage(p + 1);
            const int kb = p & 3;
            if (kb == 0){
                #pragma unroll
                for (int g = 0; g < 3; g++)
                    #pragma unroll
                    for (int a = 0; a < 2; a++)
                        #pragma unroll
                        for (int b = 0; b < 2; b++)
                            #pragma unroll
                            for (int c = 0; c < 4; c++) acc[g][a][b][c] = 0.f;
            }
            const uint32_t* Ab2 = As2 + (p & 1)*256*36;
            #pragma unroll
            for (int kk = 0; kk < 64; kk += 16){
                uint32_t af[2][4];
                #pragma unroll
                for (int mt = 0; mt < 2; mt++){
                    int r0 = wm*32 + mt*16 + (lane >> 2);
                    int ui = r0*36 + (kk >> 1) + (lane & 3);
                    af[mt][0] = Ab2[ui];
                    af[mt][1] = Ab2[ui + 288];
                    af[mt][2] = Ab2[ui + 4];
                    af[mt][3] = Ab2[ui + 292];
                }
                uint32_t bf[3][2][2];
                #pragma unroll
                for (int g = 0; g < 3; g++)
                    #pragma unroll
                    for (int nt = 0; nt < 2; nt++){
                        int n0 = wn*16 + nt*8 + (lane >> 2);
                        int wi = (g*32 + n0)*132 + kb*32 + (kk >> 1) + (lane & 3);
                        bf[g][nt][0] = Ws2[wi];
                        bf[g][nt][1] = Ws2[wi + 4];
                    }
                #pragma unroll
                for (int g = 0; g < 3; g++)
                    #pragma unroll
                    for (int mt = 0; mt < 2; mt++)
                        #pragma unroll
                        for (int nt = 0; nt < 2; nt++)
                            mma16b(acc[g][mt][nt], af[mt], bf[g][nt]);
            }

            if (kb == 3){
                const int base = lrow0 + (p >> 2)*256;
                #pragma unroll
                for (int mt = 0; mt < 2; mt++){
                    #pragma unroll
                    for (int dr = 0; dr < 2; dr++){
                        int lr = base + wm*32 + mt*16 + (lane >> 2) + dr*8;
                        int iroll = lr >> 10;
                        int nb = lr & (N_DIM - 1);
                        int l = dirF ? ((iroll + t) & 15) : ((iroll + 15 - t) & 15);
                        const float* ge = GIe + __ldg(&lines[nb*L_DIM + l])*100;
                        #pragma unroll
                        for (int nt = 0; nt < 2; nt++){
                            int hcl = wn*16 + nt*8 + (lane & 3)*2;
                            float2 gv0 = *(const float2*)&ge[hcl];
                            float2 gv1 = *(const float2*)&ge[32 + hcl];
                            float2 gv2 = *(const float2*)&ge[64 + hcl];
                            float2 hold = __ldcg((const float2*)&hsrc[(size_t)lr*H_DIM + bcol*32 + hcl]);
                            float2 hout;
                            #pragma unroll
                            for (int dc = 0; dc < 2; dc++){
                                float gr = acc[0][mt][nt][dr*2+dc] + bR[nt][dc];
                                float gz = acc[1][mt][nt][dr*2+dc] + bZ[nt][dc];
                                float gn = acc[2][mt][nt][dr*2+dc] + bN[nt][dc];
                                float r  = sigm((dc ? gv0.y : gv0.x) + gr);
                                float z  = sigm((dc ? gv1.y : gv1.x) + gz);
                                float nn = tanhf((dc ? gv2.y : gv2.x) + r*gn);
                                float ho = dc ? hold.y : hold.x;
                                float hnew = (1.f - z)*nn + z*ho;
                                if (dc) hout.y = hnew; else hout.x = hnew;
                            }
                            __stcg((float2*)&hdst[(size_t)lr*H_DIM + bcol*32 + hcl], hout);
                            __stcg((uint32_t*)(hdst16 + (size_t)lr*H_DIM + bcol*32 + hcl),
                                   packbf(hout.x, hout.y));
                        }
                    }
                }
            }
        }
        slab_sync(slab, 8);
    }
}

// ---------------- bf16 feed-forward GEMM: 128 cols/CTA, m16n8k16 -------------------
// EPI 1: relu + packed bf16 out; EPI 3: +bias, packed bf16 out (GI).
#define FFB_W_U32 (128*132)
#define FFB_A_U32 (2*256*36)
#define FFB_SMEM_BYTES ((FFB_W_U32 + FFB_A_U32)*4)

template<int EPI>
__global__ void __launch_bounds__(512, 1)
gemm_ffb(const uint32_t* __restrict__ A, const float* __restrict__ W,
         const float* __restrict__ bias, uint32_t* __restrict__ outp,
         int out_stride, int nrt)
{
    extern __shared__ uint32_t smu[];
    uint32_t* Ws2 = smu;
    uint32_t* As2 = smu + FFB_W_U32;
    const int tid = threadIdx.x, lane = tid & 31, wid = tid >> 5;
    const int wm = wid >> 1, wn = wid & 1;
    const int bcol = blockIdx.x;

    for (int i = tid; i < 128*128; i += 512){
        int c = i >> 7, kp = i & 127;
        const float* wr = W + (size_t)(bcol*128 + c)*H_DIM + 2*kp;
        Ws2[c*132 + kp] = packbf(wr[0], wr[1]);
    }
    __syncthreads();

    const int nch = (nrt - (int)blockIdx.y + (int)gridDim.y - 1) / (int)gridDim.y;
    if (nch <= 0) return;
    const int total = nch*4;

    auto stage = [&](int p){
        int ci = p >> 2, kb = p & 3, buf = p & 1;
        int rt = blockIdx.y + ci*gridDim.y;
        const uint32_t* src = A + (size_t)rt*256*128 + kb*32;
        uint32_t* dst = As2 + buf*256*36;
        #pragma unroll
        for (int i = tid; i < 2048; i += 512){
            int r = i >> 3, q = i & 7;
            cp16(&dst[r*36 + q*4], src + (size_t)r*128 + q*4);
        }
        cp_commit();
    };

    float acc[2][8][4];
    stage(0);
    for (int p = 0; p < total; p++){
        cp_wait<0>();
        __syncthreads();
        if (p + 1 < total) stage(p + 1);
        const int kb = p & 3;
        if (kb == 0){
            #pragma unroll
            for (int a = 0; a < 2; a++)
                #pragma unroll
                for (int b = 0; b < 8; b++)
                    #pragma unroll
                    for (int c = 0; c < 4; c++) acc[a][b][c] = 0.f;
        }
        const uint32_t* Ab2 = As2 + (p & 1)*256*36;
        #pragma unroll
        for (int kk = 0; kk < 64; kk += 16){
            uint32_t af[2][4];
            #pragma unroll
            for (int mt = 0; mt < 2; mt++){
                int r0 = wm*32 + mt*16 + (lane >> 2);
                int ui = r0*36 + (kk >> 1) + (lane & 3);
                af[mt][0] = Ab2[ui];
                af[mt][1] = Ab2[ui + 288];
                af[mt][2] = Ab2[ui + 4];
                af[mt][3] = Ab2[ui + 292];
            }
            uint32_t bf[8][2];
            #pragma unroll
            for (int nt = 0; nt < 8; nt++){
                int n0 = wn*64 + nt*8 + (lane >> 2);
                int wi = n0*132 + kb*32 + (kk >> 1) + (lane & 3);
                bf[nt][0] = Ws2[wi];
                bf[nt][1] = Ws2[wi + 4];
            }
            #pragma unroll
            for (int mt = 0; mt < 2; mt++)
                #pragma unroll
                for (int nt = 0; nt < 8; nt++)
                    mma16b(acc[mt][nt], af[mt], bf[nt]);
        }

        if (kb == 3){
            int rt = blockIdx.y + (p >> 2)*gridDim.y;
            #pragma unroll
            for (int mt = 0; mt < 2; mt++){
                #pragma unroll
                for (int nt = 0; nt < 8; nt++){
                    #pragma unroll
                    for (int dr = 0; dr < 2; dr++){
                        int rr = rt*256 + wm*32 + mt*16 + (lane >> 2) + dr*8;
                        int cc = bcol*128 + wn*64 + nt*8 + (lane & 3)*2;
                        float v0 = acc[mt][nt][dr*2 + 0] + bias[cc];
                        float v1 = acc[mt][nt][dr*2 + 1] + bias[cc + 1];
                        if (EPI == 1){ v0 = fmaxf(v0, 0.f); v1 = fmaxf(v1, 0.f); }
                        outp[(size_t)rr*out_stride + (cc >> 1)] = packbf(v0, v1);
                    }
                }
            }
        }
    }
}

// ---------------- persistent main GRU v9: bf16 MMA + bf16 gi ----------------------
#define M9_W_U32 (3*32*132)                /* 12672 */
#define M9_A_U32 (64*132)                  /* 8448  */
#define M9_G_U32 (64*52)                   /* 3328  */
#define M9_SMEM_BYTES ((M9_W_U32 + M9_A_U32 + M9_G_U32)*4)

__global__ void __launch_bounds__(256, 1)
main_gru_v9(const float* __restrict__ whh, const float* __restrict__ bhh,
            float* __restrict__ out)
{
    extern __shared__ uint32_t smu[];
    uint32_t* Ws2 = smu;
    uint32_t* As2 = smu + M9_W_U32;
    uint32_t* GIs = smu + M9_W_U32 + M9_A_U32;
    const int tid = threadIdx.x, lane = tid & 31, wid = tid >> 5;
    const int wm = wid >> 1, wn = wid & 1;      // wm 0..3 (16 rows), wn 0..1
    const int bcol = blockIdx.x;                // 0..7 (32 cols)
    const int slab = blockIdx.y;                // 0..15
    const int row0 = slab*64;

    for (int i = tid; i < 3*32*128; i += 256){
        int g = i >> 12, rem = i & 4095;
        int c = rem >> 7, kp = rem & 127;
        const float* wr = whh + (size_t)(g*H_DIM + bcol*32 + c)*H_DIM + 2*kp;
        Ws2[(g*32 + c)*132 + kp] = packbf(wr[0], wr[1]);
    }
    float bR[2][2], bZ[2][2], bN[2][2];
    #pragma unroll
    for (int nt = 0; nt < 2; nt++)
        #pragma unroll
        for (int dc = 0; dc < 2; dc++){
            int c = bcol*32 + nt*8 + wn*16 + (lane & 3)*2 + dc;
            bR[nt][dc] = bhh[c];
            bZ[nt][dc] = bhh[H_DIM + c];
            bN[nt][dc] = bhh[2*H_DIM + c];
        }

    // gi staging: per row 3 gates x 16 u32 (32 bf16 cols)
    auto stage_gi = [&](int tt){
        const uint32_t* gsrc = g_GIb + ((size_t)tt*N_DIM + row0)*(G3/2) + bcol*16;
        #pragma unroll
        for (int i = tid; i < 768; i += 256){
            int r = i / 12, j = i % 12;
            int g = j >> 2, qj = j & 3;
            cp16(&GIs[r*52 + g*16 + qj*4], gsrc + (size_t)r*(G3/2) + g*128 + qj*4);
        }
        cp_commit();
    };

    stage_gi(0);
    slab_sync(slab, 8);

    for (int t = 0; t < T_DIM; t++){
        const float* __restrict__ hsrc = g_hm[t & 1];
        float* __restrict__ hdst = g_hm[(t + 1) & 1];
        const uint16_t* __restrict__ hsrc16 = g_hmb[t & 1];
        uint16_t* __restrict__ hdst16 = g_hmb[(t + 1) & 1];

        // stage bf16 A tile (64 rows x 256 K = 64x128 u32)
        {
            const uint16_t* src = hsrc16 + (size_t)row0*H_DIM;
            #pragma unroll
            for (int i = tid; i < 2048; i += 256){
                int r = i >> 5, q = i & 31;
                cp16(&As2[r*132 + q*4], src + (size_t)r*H_DIM + q*8);
            }
            cp_commit();
        }
        cp_wait<0>();
        __syncthreads();

        float acc[3][2][4];
        #pragma unroll
        for (int g = 0; g < 3; g++)
            #pragma unroll
            for (int n = 0; n < 2; n++)
                #pragma unroll
                for (int c = 0; c < 4; c++) acc[g][n][c] = 0.f;

        #pragma unroll 4
        for (int kk = 0; kk < H_DIM; kk += 16){
            uint32_t af[4];
            {
                int r0 = wm*16 + (lane >> 2);
                int ui = r0*132 + (kk >> 1) + (lane & 3);
                af[0] = As2[ui];
                af[1] = As2[ui + 8*132];
                af[2] = As2[ui + 4];
                af[3] = As2[ui + 8*132 + 4];
            }
            uint32_t bf[3][2][2];
            #pragma unroll
            for (int g = 0; g < 3; g++)
                #pragma unroll
                for (int nt = 0; nt < 2; nt++){
                    int n0 = wn*16 + nt*8 + (lane >> 2);
                    int wi = (g*32 + n0)*132 + (kk >> 1) + (lane & 3);
                    bf[g][nt][0] = Ws2[wi];
                    bf[g][nt][1] = Ws2[wi + 4];
                }
            #pragma unroll
            for (int g = 0; g < 3; g++)
                #pragma unroll
                for (int nt = 0; nt < 2; nt++)
                    mma16b(acc[g][nt], af, bf[g][nt]);
        }

        float* __restrict__ out_t = out + ((size_t)t*N_DIM)*ROW_OUT;
        #pragma unroll
        for (int dr = 0; dr < 2; dr++){
            int rl = wm*16 + (lane >> 2) + dr*8;
            int row = row0 + rl;
            #pragma unroll
            for (int nt = 0; nt < 2; nt++){
                int ccl = wn*16 + nt*8 + (lane & 3)*2;
                float2 gv0 = unpackbf(GIs[rl*52 + (ccl >> 1)]);
                float2 gv1 = unpackbf(GIs[rl*52 + 16 + (ccl >> 1)]);
                float2 gv2 = unpackbf(GIs[rl*52 + 32 + (ccl >> 1)]);
                float2 hold = __ldcg((const float2*)&hsrc[(size_t)row*H_DIM + bcol*32 + ccl]);
                float2 hout;
                #pragma unroll
                for (int dc = 0; dc < 2; dc++){
                    float gr = acc[0][nt][dr*2+dc] + bR[nt][dc];
                    float gz = acc[1][nt][dr*2+dc] + bZ[nt][dc];
                    float gn = acc[2][nt][dr*2+dc] + bN[nt][dc];
                    float r  = sigm((dc ? gv0.y : gv0.x) + gr);
                    float z  = sigm((dc ? gv1.y : gv1.x) + gz);
                    float nn = tanhf((dc ? gv2.y : gv2.x) + r*gn);
                    float ho = dc ? hold.y : hold.x;
                    float hnew = (1.f - z)*nn + z*ho;
                    if (dc) hout.y = hnew; else hout.x = hnew;
                }
                __stcg((float2*)&hdst[(size_t)row*H_DIM + bcol*32 + ccl], hout);
                __stcg((uint32_t*)(hdst16 + (size_t)row*H_DIM + bcol*32 + ccl),
                       packbf(hout.x, hout.y));
                *(float2*)&out_t[(size_t)row*ROW_OUT + 4 + bcol*32 + ccl] = hout;
            }
        }

        __syncthreads();
        if (t + 1 < T_DIM) stage_gi(t + 1);
        slab_sync(slab, 8);
    }
}

// ---------------- heads ----------------
__global__ void __launch_bounds__(256)
heads_kernel(float* __restrict__ out, const int* __restrict__ actions,
             const int* __restrict__ active, const float* __restrict__ p0,
             const float* __restrict__ pp0,
             const float* __restrict__ w_actor, const float* __restrict__ b_actor,
             const float* __restrict__ w_critic, const float* __restrict__ b_critic)
{
    int wid = threadIdx.x >> 5, lane = threadIdx.x & 31;
    size_t row = (size_t)blockIdx.x*8 + wid;
    float* orow = out + row*ROW_OUT;
    float hv[8];
    #pragma unroll
    for (int i = 0; i < 8; i++) hv[i] = orow[4 + lane + 32*i];

    float lg = 0.f;
    #pragma unroll
    for (int a = 0; a < NA_DIM; a++){
        float s = 0.f;
        #pragma unroll
        for (int i = 0; i < 8; i++) s += hv[i]*w_actor[a*H_DIM + lane + 32*i];
        #pragma unroll
        for (int o = 16; o > 0; o >>= 1) s += __shfl_xor_sync(0xffffffffu, s, o);
        if (lane == a) lg = s + b_actor[a];
    }
    float m = (lane < NA_DIM) ? lg : -1e30f;
    #pragma unroll
    for (int o = 16; o > 0; o >>= 1) m = fmaxf(m, __shfl_xor_sync(0xffffffffu, m, o));
    float e = (lane < NA_DIM) ? expf(lg - m) : 0.f;
    float den = e;
    #pragma unroll
    for (int o = 16; o > 0; o >>= 1) den += __shfl_xor_sync(0xffffffffu, den, o);
    if (lane < NA_DIM) orow[260 + lane] = e/den;

    float s = 0.f;
    #pragma unroll
    for (int i = 0; i < 8; i++) s += hv[i]*w_critic[lane + 32*i];
    #pragma unroll
    for (int o = 16; o > 0; o >>= 1) s += __shfl_xor_sync(0xffffffffu, s, o);

    int n = (int)(row & (N_DIM - 1));
    if (lane == 0)  orow[3]   = s + b_critic[0];
    if (lane == 16) orow[0]   = (float)actions[row];
    if (lane == 17) orow[1]   = p0[n];
    if (lane == 18) orow[2]   = (float)active[row];
    if (lane == 19) orow[276] = pp0[n*2];
    if (lane == 20) orow[277] = pp0[n*2 + 1];
}

// ---------------- launch ----------------
extern "C" void kernel_launch(void* const* d_in, const int* in_sizes, int n_in,
                              void* d_out, int out_size)
{
    (void)in_sizes; (void)n_in; (void)out_size;
    const float* condition = (const float*)d_in[0];
    const int*   active    = (const int*)d_in[1];
    const int*   lines     = (const int*)d_in[2];
    const int*   actions   = (const int*)d_in[3];
    const float* h0        = (const float*)d_in[4];
    const float* p0        = (const float*)d_in[5];
    const float* pp0       = (const float*)d_in[6];
    const float* embed     = (const float*)d_in[7];
    const float* wih_f = (const float*)d_in[8],  *whh_f = (const float*)d_in[9];
    const float* bih_f = (const float*)d_in[10], *bhh_f = (const float*)d_in[11];
    const float* wih_b = (const float*)d_in[12], *whh_b = (const float*)d_in[13];
    const float* bih_b = (const float*)d_in[14], *bhh_b = (const float*)d_in[15];
    const float* f_w0 = (const float*)d_in[16], *f_b0 = (const float*)d_in[17];
    const float* f_w1 = (const float*)d_in[18], *f_b1 = (const float*)d_in[19];
    const float* f_w2 = (const float*)d_in[20], *f_b2 = (const float*)d_in[21];
    const float* c_wih = (const float*)d_in[22], *c_whh = (const float*)d_in[23];
    const float* c_bih = (const float*)d_in[24], *c_bhh = (const float*)d_in[25];
    const float* w_critic = (const float*)d_in[26], *b_critic = (const float*)d_in[27];
    const float* w_actor  = (const float*)d_in[28], *b_actor  = (const float*)d_in[29];
    float* out = (float*)d_out;

    float *Rp;
    uint32_t *A0bp, *A1bp, *GIbp;
    cudaGetSymbolAddress((void**)&Rp,  g_Rproj);
    cudaGetSymbolAddress((void**)&A0bp, g_A0b);
    cudaGetSymbolAddress((void**)&A1bp, g_A1b);
    cudaGetSymbolAddress((void**)&GIbp, g_GIb);

    cudaFuncSetAttribute(enc_v7,
                         cudaFuncAttributeMaxDynamicSharedMemorySize, E7_SMEM_BYTES);
    cudaFuncSetAttribute(main_gru_v9,
                         cudaFuncAttributeMaxDynamicSharedMemorySize, M9_SMEM_BYTES);
    cudaFuncSetAttribute(gemm_ffb<1>,
                         cudaFuncAttributeMaxDynamicSharedMemorySize, FFB_SMEM_BYTES);
    cudaFuncSetAttribute(gemm_ffb<3>,
                         cudaFuncAttributeMaxDynamicSharedMemorySize, FFB_SMEM_BYTES);

    // 0) gi tables + state init
    gi_tables<<<(2*NL_DIM*G3 + 255)/256, 256>>>(embed, wih_f, bih_f, wih_b, bih_b);
    init_state<<<4096, 256>>>(h0);

    // 1) persistent bidirectional encoder (bf16, K-chunk 64)
    enc_v7<<<dim3(8, 16), 512, E7_SMEM_BYTES>>>(whh_f, bhh_f, whh_b, bhh_b, lines);

    // 2) Rproj = Hmem @ W0r^T (f32)
    gemm_plain<1, 0><<<dim3(4, 128), 256>>>(nullptr, f_w0 + 64, 576, nullptr, Rp, 512, 256, nullptr);
    // 3) A0 = relu(cond @ W0c^T + Rproj[active] + b0)  -> packed bf16
    gemm_plain<0, 4><<<dim3(4, 2048), 256>>>(condition, f_w0, 576, f_b0, A0bp, 64, 256, active);
    // 4) A1 = relu(A0 @ w1^T + b1); A0'' = relu(A1 @ w2^T + b2)  (bf16 GEMMs)
    gemm_ffb<1><<<dim3(2, 74), 512, FFB_SMEM_BYTES>>>(A0bp, f_w1, f_b1, A1bp, 128, 1024);
    gemm_ffb<1><<<dim3(2, 74), 512, FFB_SMEM_BYTES>>>(A1bp, f_w2, f_b2, A0bp, 128, 1024);
    // 5) GI = A0'' @ c_wih^T + c_bih  -> packed bf16 (halves DRAM round-trip)
    gemm_ffb<3><<<dim3(6, 24), 512, FFB_SMEM_BYTES>>>(A0bp, c_wih, c_bih, GIbp, 384, 1024);

    // 6) persistent main GRU v9 (bf16 MMA + bf16 gi)
    main_gru_v9<<<dim3(8, 16), 256, M9_SMEM_BYTES>>>(c_whh, c_bhh, out);

    // 7) heads + scalar fields
    heads_kernel<<<TN/8, 256>>>(out, actions, active, p0, pp0,
                                w_actor, b_actor, w_critic, b_critic);
}

// round 12
// speedup vs baseline: 3.1089x; 1.0137x over previous
#include <cuda_runtime.h>
#include <math.h>
#include <stdint.h>

#define T_DIM 256
#define N_DIM 1024
#define H_DIM 256
#define L_DIM 16
#define NL_DIM 32
#define C_DIM 64
#define NA_DIM 16
#define ROW_OUT 278
#define G3 768
#define LN (L_DIM*N_DIM)          /* 16384 */
#define TN (T_DIM*N_DIM)          /* 262144 */

// ---------------- scratch ----------------
__device__ float g_giF[NL_DIM*G3];
__device__ float g_giB[NL_DIM*G3];
__device__ float g_Hf[2][(size_t)LN*H_DIM];
__device__ float g_Hb[2][(size_t)LN*H_DIM];
__device__ uint16_t g_Hfb[2][(size_t)LN*H_DIM];   // bf16 shadow of Hf
__device__ uint16_t g_Hbb[2][(size_t)LN*H_DIM];   // bf16 shadow of Hb
__device__ float g_Rproj[(size_t)LN*H_DIM];
__device__ uint32_t g_A0b[(size_t)TN*(H_DIM/2)];  // packed bf16 intermediates
__device__ uint32_t g_A1b[(size_t)TN*(H_DIM/2)];
__device__ uint32_t g_GIb[(size_t)TN*(G3/2)];     // packed bf16 gi
__device__ float g_hall[(size_t)TN*H_DIM];        // compact h history [T][N][H]
__device__ float g_hm0[N_DIM*H_DIM];              // f32 h0 copy
__device__ uint16_t g_hmb[2][N_DIM*H_DIM];        // bf16 shadow of h (double buffer)
__device__ unsigned g_slabc[16][32];
__device__ unsigned g_slabg[16][32];

// ---------------- helpers ----------------
__device__ __forceinline__ uint32_t f2tf(float x){
    uint32_t r; asm("cvt.rna.tf32.f32 %0, %1;" : "=r"(r) : "f"(x)); return r;
}
__device__ __forceinline__ uint32_t packbf(float lo, float hi){
    uint32_t r; asm("cvt.rn.bf16x2.f32 %0, %1, %2;" : "=r"(r) : "f"(hi), "f"(lo)); return r;
}
__device__ __forceinline__ float2 unpackbf(uint32_t u){
    float2 r;
    r.x = __uint_as_float(u << 16);
    r.y = __uint_as_float(u & 0xffff0000u);
    return r;
}
__device__ __forceinline__ void mma8(float* c, const uint32_t* a, const uint32_t* b){
    asm volatile("mma.sync.aligned.m16n8k8.row.col.f32.tf32.tf32.f32 "
        "{%0,%1,%2,%3},{%4,%5,%6,%7},{%8,%9},{%0,%1,%2,%3};"
        : "+f"(c[0]), "+f"(c[1]), "+f"(c[2]), "+f"(c[3])
        : "r"(a[0]), "r"(a[1]), "r"(a[2]), "r"(a[3]), "r"(b[0]), "r"(b[1]));
}
__device__ __forceinline__ void mma16b(float* c, const uint32_t* a, const uint32_t* b){
    asm volatile("mma.sync.aligned.m16n8k16.row.col.f32.bf16.bf16.f32 "
        "{%0,%1,%2,%3},{%4,%5,%6,%7},{%8,%9},{%0,%1,%2,%3};"
        : "+f"(c[0]), "+f"(c[1]), "+f"(c[2]), "+f"(c[3])
        : "r"(a[0]), "r"(a[1]), "r"(a[2]), "r"(a[3]), "r"(b[0]), "r"(b[1]));
}
__device__ __forceinline__ float sigm(float x){ return 1.f/(1.f+expf(-x)); }
__device__ __forceinline__ void cp16(void* smem_dst, const void* gsrc){
    uint32_t s = (uint32_t)__cvta_generic_to_shared(smem_dst);
    asm volatile("cp.async.cg.shared.global [%0], [%1], 16;" :: "r"(s), "l"(gsrc));
}
__device__ __forceinline__ void cp_commit(){ asm volatile("cp.async.commit_group;"); }
template<int N> __device__ __forceinline__ void cp_wait(){
    asm volatile("cp.async.wait_group %0;" :: "n"(N));
}

__device__ __forceinline__ void slab_sync(int slab, unsigned nb){
    __syncthreads();
    if (threadIdx.x == 0){
        volatile unsigned* genp = &g_slabg[slab][0];
        unsigned old = *genp;
        __threadfence();
        if (atomicAdd(&g_slabc[slab][0], 1u) == nb - 1u){
            g_slabc[slab][0] = 0u;
            __threadfence();
            *genp = old + 1u;
        } else {
            while (*genp == old) { }
            __threadfence();
        }
    }
    __syncthreads();
}

// ---------------- gi tables ----------------
__global__ void gi_tables(const float* __restrict__ embed,
                          const float* __restrict__ wihF, const float* __restrict__ bihF,
                          const float* __restrict__ wihB, const float* __restrict__ bihB)
{
    int idx = blockIdx.x*blockDim.x + threadIdx.x;
    if (idx >= 2*NL_DIM*G3) return;
    int dir = idx / (NL_DIM*G3);
    int rem = idx % (NL_DIM*G3);
    int e = rem / G3, j = rem % G3;
    const float* wih = dir ? wihB : wihF;
    const float* bih = dir ? bihB : bihF;
    float s = bih[j];
    const float* em = embed + e*H_DIM;
    const float* w  = wih + (size_t)j*H_DIM;
    #pragma unroll 8
    for (int k = 0; k < H_DIM; k++) s += em[k]*w[k];
    (dir ? g_giB : g_giF)[rem] = s;
}

// ---------------- init ----------------
__global__ void init_state(const float* __restrict__ h0)
{
    size_t stride = (size_t)gridDim.x*blockDim.x;
    size_t i0 = (size_t)blockIdx.x*blockDim.x + threadIdx.x;
    size_t HS = (size_t)LN*H_DIM;
    for (size_t p = i0; p < HS; p += stride){
        g_Hf[0][p] = 0.f; g_Hb[0][p] = 0.f;
        g_Hfb[0][p] = 0;  g_Hbb[0][p] = 0;
    }
    for (size_t p = i0; p < (size_t)N_DIM*H_DIM; p += stride){
        float v = h0[p];
        g_hm0[p] = v;
        g_hmb[0][p] = (uint16_t)(packbf(v, 0.f) & 0xffffu);
    }
}

// ---------------- plain tf32 GEMM: EPI 0 = f32 store (Rproj); EPI 4 = layer0 packed --
template<int ALOAD, int EPI>
__global__ void __launch_bounds__(256)
gemm_plain(const float* __restrict__ A, const float* __restrict__ B, int ldb,
           const float* __restrict__ bias, void* __restrict__ outv,
           int K, int NC, const int* __restrict__ active)
{
    __shared__ float As[128][20];
    __shared__ float Bs[64][20];
    const int tid = threadIdx.x, lane = tid & 31, wid = tid >> 5;
    const int wm = wid >> 1, wn = wid & 1;
    const int brow = blockIdx.y, bcol = blockIdx.x;
    float acc[2][4][4];
    #pragma unroll
    for (int a = 0; a < 2; a++)
        #pragma unroll
        for (int b = 0; b < 4; b++)
            #pragma unroll
            for (int c = 0; c < 4; c++) acc[a][b][c] = 0.f;

    for (int k0 = 0; k0 < K; k0 += 16){
        #pragma unroll
        for (int i = tid; i < 2048; i += 256){
            int r = i >> 4, c = i & 15;
            int row = brow*128 + r; int k = k0 + c;
            float v;
            if (ALOAD == 0) v = A[(size_t)row*K + k];
            else v = (k < H_DIM) ? g_Hf[0][(size_t)row*H_DIM + k]
                                 : g_Hb[0][(size_t)row*H_DIM + (k - H_DIM)];
            As[r][c] = __uint_as_float(f2tf(v));
        }
        #pragma unroll
        for (int i = tid; i < 1024; i += 256){
            int n = i >> 4, c = i & 15;
            Bs[n][c] = __uint_as_float(f2tf(B[(size_t)(bcol*64 + n)*ldb + k0 + c]));
        }
        __syncthreads();
        #pragma unroll
        for (int kk = 0; kk < 16; kk += 8){
            uint32_t af[2][4], bf[4][2];
            #pragma unroll
            for (int mt = 0; mt < 2; mt++){
                int r0 = wm*32 + mt*16 + (lane >> 2);
                int c0 = kk + (lane & 3);
                af[mt][0] = __float_as_uint(As[r0][c0]);
                af[mt][1] = __float_as_uint(As[r0+8][c0]);
                af[mt][2] = __float_as_uint(As[r0][c0+4]);
                af[mt][3] = __float_as_uint(As[r0+8][c0+4]);
            }
            #pragma unroll
            for (int nt = 0; nt < 4; nt++){
                int n0 = wn*32 + nt*8 + (lane >> 2);
                bf[nt][0] = __float_as_uint(Bs[n0][kk + (lane & 3)]);
                bf[nt][1] = __float_as_uint(Bs[n0][kk + 4 + (lane & 3)]);
            }
            #pragma unroll
            for (int mt = 0; mt < 2; mt++)
                #pragma unroll
                for (int nt = 0; nt < 4; nt++)
                    mma8(acc[mt][nt], af[mt], bf[nt]);
        }
        __syncthreads();
    }
    #pragma unroll
    for (int mt = 0; mt < 2; mt++){
        #pragma unroll
        for (int nt = 0; nt < 4; nt++){
            int rbase = brow*128 + wm*32 + mt*16 + (lane >> 2);
            int cbase = bcol*64 + wn*32 + nt*8 + (lane & 3)*2;
            #pragma unroll
            for (int dr = 0; dr < 2; dr++){
                int rr = rbase + dr*8, cc = cbase;
                float v0 = acc[mt][nt][dr*2 + 0];
                float v1 = acc[mt][nt][dr*2 + 1];
                if (EPI == 4){
                    int n = rr & (N_DIM - 1);
                    int w = active[rr];
                    const float* rp = &g_Rproj[(size_t)(w*N_DIM + n)*H_DIM + cc];
                    v0 = fmaxf(v0 + bias[cc]   + rp[0], 0.f);
                    v1 = fmaxf(v1 + bias[cc+1] + rp[1], 0.f);
                    ((uint32_t*)outv)[(size_t)rr*(H_DIM/2) + (cc >> 1)] = packbf(v0, v1);
                } else {
                    float* out = (float*)outv;
                    out[(size_t)rr*NC + cc]     = v0;
                    out[(size_t)rr*NC + cc + 1] = v1;
                }
            }
        }
    }
}

// ---------------- persistent encoder v7: bf16, K-chunk 64 ----------------
#define E7_W_U32 (3*32*132)
#define E7_A_U32 (2*256*36)
#define E7_G_FLOATS (NL_DIM*100)
#define E7_SMEM_BYTES ((E7_W_U32 + E7_A_U32 + E7_G_FLOATS)*4)

__global__ void __launch_bounds__(512, 1)
enc_v7(const float* __restrict__ whF, const float* __restrict__ bhF,
       const float* __restrict__ whB, const float* __restrict__ bhB,
       const int* __restrict__ lines)
{
    extern __shared__ uint32_t smu[];
    uint32_t* Ws2 = smu;
    uint32_t* As2 = smu + E7_W_U32;
    float* GIe = (float*)(smu + E7_W_U32 + E7_A_U32);
    const int tid = threadIdx.x, lane = tid & 31, wid = tid >> 5;
    const int wm = wid >> 1, wn = wid & 1;
    const int bcol = blockIdx.x;
    const int slab = blockIdx.y;
    const bool dirF = (slab < 8);
    const float* __restrict__ W  = dirF ? whF : whB;
    const float* __restrict__ bh = dirF ? bhF : bhB;
    const float* __restrict__ giT = dirF ? g_giF : g_giB;
    const int lrow0 = (dirF ? slab : slab - 8) * 2048;

    for (int i = tid; i < 3*32*128; i += 512){
        int g = i >> 12, rem = i & 4095;
        int c = rem >> 7, kp = rem & 127;
        const float* wr = W + (size_t)(g*H_DIM + bcol*32 + c)*H_DIM + 2*kp;
        Ws2[(g*32 + c)*132 + kp] = packbf(wr[0], wr[1]);
    }
    for (int i = tid; i < NL_DIM*96; i += 512){
        int e = i / 96, j = i % 96;
        int g = j >> 5, c = j & 31;
        GIe[e*100 + j] = __ldg(&giT[e*G3 + g*H_DIM + bcol*32 + c]);
    }
    float bR[2][2], bZ[2][2], bN[2][2];
    #pragma unroll
    for (int nt = 0; nt < 2; nt++)
        #pragma unroll
        for (int dc = 0; dc < 2; dc++){
            int c = bcol*32 + wn*16 + nt*8 + (lane & 3)*2 + dc;
            bR[nt][dc] = bh[c];
            bZ[nt][dc] = bh[H_DIM + c];
            bN[nt][dc] = bh[2*H_DIM + c];
        }
    __syncthreads();

    for (int t = 0; t < L_DIM; t++){
        const float* __restrict__ hsrc = dirF ? g_Hf[t & 1] : g_Hb[t & 1];
        float* __restrict__ hdst = dirF ? g_Hf[(t + 1) & 1] : g_Hb[(t + 1) & 1];
        const uint16_t* __restrict__ hsrc16 = dirF ? g_Hfb[t & 1] : g_Hbb[t & 1];
        uint16_t* __restrict__ hdst16 = dirF ? g_Hfb[(t + 1) & 1] : g_Hbb[(t + 1) & 1];

        auto stage = [&](int p){
            int chunk = p >> 2, kb = p & 3, buf = p & 1;
            const uint16_t* src = hsrc16 + (size_t)(lrow0 + chunk*256)*H_DIM + kb*64;
            uint32_t* dst = As2 + buf*256*36;
            #pragma unroll
            for (int i = tid; i < 2048; i += 512){
                int r = i >> 3, q = i & 7;
                cp16(&dst[r*36 + q*4], src + (size_t)r*H_DIM + q*8);
            }
            cp_commit();
        };

        float acc[3][2][2][4];
        stage(0);
        for (int p = 0; p < 32; p++){
            cp_wait<0>();
            __syncthreads();
            if (p + 1 < 32) stage(p + 1);
            const int kb = p & 3;
            if (kb == 0){
                #pragma unroll
                for (int g = 0; g < 3; g++)
                    #pragma unroll
                    for (int a = 0; a < 2; a++)
                        #pragma unroll
                        for (int b = 0; b < 2; b++)
                            #pragma unroll
                            for (int c = 0; c < 4; c++) acc[g][a][b][c] = 0.f;
            }
            const uint32_t* Ab2 = As2 + (p & 1)*256*36;
            #pragma unroll
            for (int kk = 0; kk < 64; kk += 16){
                uint32_t af[2][4];
                #pragma unroll
                for (int mt = 0; mt < 2; mt++){
                    int r0 = wm*32 + mt*16 + (lane >> 2);
                    int ui = r0*36 + (kk >> 1) + (lane & 3);
                    af[mt][0] = Ab2[ui];
                    af[mt][1] = Ab2[ui + 288];
                    af[mt][2] = Ab2[ui + 4];
                    af[mt][3] = Ab2[ui + 292];
                }
                uint32_t bf[3][2][2];
                #pragma unroll
                for (int g = 0; g < 3; g++)
                    #pragma unroll
                    for (int nt = 0; nt < 2; nt++){
                        int n0 = wn*16 + nt*8 + (lane >> 2);
                        int wi = (g*32 + n0)*132 + kb*32 + (kk >> 1) + (lane & 3);
                        bf[g][nt][0] = Ws2[wi];
                        bf[g][nt][1] = Ws2[wi + 4];
                    }
                #pragma unroll
                for (int g = 0; g < 3; g++)
                    #pragma unroll
                    for (int mt = 0; mt < 2; mt++)
                        #pragma unroll
                        for (int nt = 0; nt < 2; nt++)
                            mma16b(acc[g][mt][nt], af[mt], bf[g][nt]);
            }

            if (kb == 3){
                const int base = lrow0 + (p >> 2)*256;
                #pragma unroll
                for (int mt = 0; mt < 2; mt++){
                    #pragma unroll
                    for (int dr = 0; dr < 2; dr++){
                        int lr = base + wm*32 + mt*16 + (lane >> 2) + dr*8;
                        int iroll = lr >> 10;
                        int nb = lr & (N_DIM - 1);
                        int l = dirF ? ((iroll + t) & 15) : ((iroll + 15 - t) & 15);
                        const float* ge = GIe + __ldg(&lines[nb*L_DIM + l])*100;
                        #pragma unroll
                        for (int nt = 0; nt < 2; nt++){
                            int hcl = wn*16 + nt*8 + (lane & 3)*2;
                            float2 gv0 = *(const float2*)&ge[hcl];
                            float2 gv1 = *(const float2*)&ge[32 + hcl];
                            float2 gv2 = *(const float2*)&ge[64 + hcl];
                            float2 hold = __ldcg((const float2*)&hsrc[(size_t)lr*H_DIM + bcol*32 + hcl]);
                            float2 hout;
                            #pragma unroll
                            for (int dc = 0; dc < 2; dc++){
                                float gr = acc[0][mt][nt][dr*2+dc] + bR[nt][dc];
                                float gz = acc[1][mt][nt][dr*2+dc] + bZ[nt][dc];
                                float gn = acc[2][mt][nt][dr*2+dc] + bN[nt][dc];
                                float r  = sigm((dc ? gv0.y : gv0.x) + gr);
                                float z  = sigm((dc ? gv1.y : gv1.x) + gz);
                                float nn = tanhf((dc ? gv2.y : gv2.x) + r*gn);
                                float ho = dc ? hold.y : hold.x;
                                float hnew = (1.f - z)*nn + z*ho;
                                if (dc) hout.y = hnew; else hout.x = hnew;
                            }
                            __stcg((float2*)&hdst[(size_t)lr*H_DIM + bcol*32 + hcl], hout);
                            __stcg((uint32_t*)(hdst16 + (size_t)lr*H_DIM + bcol*32 + hcl),
                                   packbf(hout.x, hout.y));
                        }
                    }
                }
            }
        }
        slab_sync(slab, 8);
    }
}

// ---------------- bf16 feed-forward GEMM: 128 cols/CTA, m16n8k16 -------------------
#define FFB_W_U32 (128*132)
#define FFB_A_U32 (2*256*36)
#define FFB_SMEM_BYTES ((FFB_W_U32 + FFB_A_U32)*4)

template<int EPI>
__global__ void __launch_bounds__(512, 1)
gemm_ffb(const uint32_t* __restrict__ A, const float* __restrict__ W,
         const float* __restrict__ bias, uint32_t* __restrict__ outp,
         int out_stride, int nrt)
{
    extern __shared__ uint32_t smu[];
    uint32_t* Ws2 = smu;
    uint32_t* As2 = smu + FFB_W_U32;
    const int tid = threadIdx.x, lane = tid & 31, wid = tid >> 5;
    const int wm = wid >> 1, wn = wid & 1;
    const int bcol = blockIdx.x;

    for (int i = tid; i < 128*128; i += 512){
        int c = i >> 7, kp = i & 127;
        const float* wr = W + (size_t)(bcol*128 + c)*H_DIM + 2*kp;
        Ws2[c*132 + kp] = packbf(wr[0], wr[1]);
    }
    __syncthreads();

    const int nch = (nrt - (int)blockIdx.y + (int)gridDim.y - 1) / (int)gridDim.y;
    if (nch <= 0) return;
    const int total = nch*4;

    auto stage = [&](int p){
        int ci = p >> 2, kb = p & 3, buf = p & 1;
        int rt = blockIdx.y + ci*gridDim.y;
        const uint32_t* src = A + (size_t)rt*256*128 + kb*32;
        uint32_t* dst = As2 + buf*256*36;
        #pragma unroll
        for (int i = tid; i < 2048; i += 512){
            int r = i >> 3, q = i & 7;
            cp16(&dst[r*36 + q*4], src + (size_t)r*128 + q*4);
        }
        cp_commit();
    };

    float acc[2][8][4];
    stage(0);
    for (int p = 0; p < total; p++){
        cp_wait<0>();
        __syncthreads();
        if (p + 1 < total) stage(p + 1);
        const int kb = p & 3;
        if (kb == 0){
            #pragma unroll
            for (int a = 0; a < 2; a++)
                #pragma unroll
                for (int b = 0; b < 8; b++)
                    #pragma unroll
                    for (int c = 0; c < 4; c++) acc[a][b][c] = 0.f;
        }
        const uint32_t* Ab2 = As2 + (p & 1)*256*36;
        #pragma unroll
        for (int kk = 0; kk < 64; kk += 16){
            uint32_t af[2][4];
            #pragma unroll
            for (int mt = 0; mt < 2; mt++){
                int r0 = wm*32 + mt*16 + (lane >> 2);
                int ui = r0*36 + (kk >> 1) + (lane & 3);
                af[mt][0] = Ab2[ui];
                af[mt][1] = Ab2[ui + 288];
                af[mt][2] = Ab2[ui + 4];
                af[mt][3] = Ab2[ui + 292];
            }
            uint32_t bf[8][2];
            #pragma unroll
            for (int nt = 0; nt < 8; nt++){
                int n0 = wn*64 + nt*8 + (lane >> 2);
                int wi = n0*132 + kb*32 + (kk >> 1) + (lane & 3);
                bf[nt][0] = Ws2[wi];
                bf[nt][1] = Ws2[wi + 4];
            }
            #pragma unroll
            for (int mt = 0; mt < 2; mt++)
                #pragma unroll
                for (int nt = 0; nt < 8; nt++)
                    mma16b(acc[mt][nt], af[mt], bf[nt]);
        }

        if (kb == 3){
            int rt = blockIdx.y + (p >> 2)*gridDim.y;
            #pragma unroll
            for (int mt = 0; mt < 2; mt++){
                #pragma unroll
                for (int nt = 0; nt < 8; nt++){
                    #pragma unroll
                    for (int dr = 0; dr < 2; dr++){
                        int rr = rt*256 + wm*32 + mt*16 + (lane >> 2) + dr*8;
                        int cc = bcol*128 + wn*64 + nt*8 + (lane & 3)*2;
                        float v0 = acc[mt][nt][dr*2 + 0] + bias[cc];
                        float v1 = acc[mt][nt][dr*2 + 1] + bias[cc + 1];
                        if (EPI == 1){ v0 = fmaxf(v0, 0.f); v1 = fmaxf(v1, 0.f); }
                        outp[(size_t)rr*out_stride + (cc >> 1)] = packbf(v0, v1);
                    }
                }
            }
        }
    }
}

// ---------------- persistent main GRU v10: compact hall history ----------------
#define M9_W_U32 (3*32*132)
#define M9_A_U32 (64*132)
#define M9_G_U32 (64*52)
#define M9_SMEM_BYTES ((M9_W_U32 + M9_A_U32 + M9_G_U32)*4)

__global__ void __launch_bounds__(256, 1)
main_gru_v10(const float* __restrict__ whh, const float* __restrict__ bhh)
{
    extern __shared__ uint32_t smu[];
    uint32_t* Ws2 = smu;
    uint32_t* As2 = smu + M9_W_U32;
    uint32_t* GIs = smu + M9_W_U32 + M9_A_U32;
    const int tid = threadIdx.x, lane = tid & 31, wid = tid >> 5;
    const int wm = wid >> 1, wn = wid & 1;
    const int bcol = blockIdx.x;                // 0..7 (32 cols)
    const int slab = blockIdx.y;                // 0..15
    const int row0 = slab*64;

    for (int i = tid; i < 3*32*128; i += 256){
        int g = i >> 12, rem = i & 4095;
        int c = rem >> 7, kp = rem & 127;
        const float* wr = whh + (size_t)(g*H_DIM + bcol*32 + c)*H_DIM + 2*kp;
        Ws2[(g*32 + c)*132 + kp] = packbf(wr[0], wr[1]);
    }
    float bR[2][2], bZ[2][2], bN[2][2];
    #pragma unroll
    for (int nt = 0; nt < 2; nt++)
        #pragma unroll
        for (int dc = 0; dc < 2; dc++){
            int c = bcol*32 + nt*8 + wn*16 + (lane & 3)*2 + dc;
            bR[nt][dc] = bhh[c];
            bZ[nt][dc] = bhh[H_DIM + c];
            bN[nt][dc] = bhh[2*H_DIM + c];
        }

    auto stage_gi = [&](int tt){
        const uint32_t* gsrc = g_GIb + ((size_t)tt*N_DIM + row0)*(G3/2) + bcol*16;
        #pragma unroll
        for (int i = tid; i < 768; i += 256){
            int r = i / 12, j = i % 12;
            int g = j >> 2, qj = j & 3;
            cp16(&GIs[r*52 + g*16 + qj*4], gsrc + (size_t)r*(G3/2) + g*128 + qj*4);
        }
        cp_commit();
    };

    stage_gi(0);
    slab_sync(slab, 8);

    for (int t = 0; t < T_DIM; t++){
        const float* __restrict__ hsrc = (t == 0) ? g_hm0
                                       : g_hall + (size_t)(t - 1)*N_DIM*H_DIM;
        float* __restrict__ hdst = g_hall + (size_t)t*N_DIM*H_DIM;
        const uint16_t* __restrict__ hsrc16 = g_hmb[t & 1];
        uint16_t* __restrict__ hdst16 = g_hmb[(t + 1) & 1];

        // stage bf16 A tile (64 rows x 256 K = 64x128 u32)
        {
            const uint16_t* src = hsrc16 + (size_t)row0*H_DIM;
            #pragma unroll
            for (int i = tid; i < 2048; i += 256){
                int r = i >> 5, q = i & 31;
                cp16(&As2[r*132 + q*4], src + (size_t)r*H_DIM + q*8);
            }
            cp_commit();
        }
        cp_wait<0>();
        __syncthreads();

        float acc[3][2][4];
        #pragma unroll
        for (int g = 0; g < 3; g++)
            #pragma unroll
            for (int n = 0; n < 2; n++)
                #pragma unroll
                for (int c = 0; c < 4; c++) acc[g][n][c] = 0.f;

        #pragma unroll 4
        for (int kk = 0; kk < H_DIM; kk += 16){
            uint32_t af[4];
            {
                int r0 = wm*16 + (lane >> 2);
                int ui = r0*132 + (kk >> 1) + (lane & 3);
                af[0] = As2[ui];
                af[1] = As2[ui + 8*132];
                af[2] = As2[ui + 4];
                af[3] = As2[ui + 8*132 + 4];
            }
            uint32_t bf[3][2][2];
            #pragma unroll
            for (int g = 0; g < 3; g++)
                #pragma unroll
                for (int nt = 0; nt < 2; nt++){
                    int n0 = wn*16 + nt*8 + (lane >> 2);
                    int wi = (g*32 + n0)*132 + (kk >> 1) + (lane & 3);
                    bf[g][nt][0] = Ws2[wi];
                    bf[g][nt][1] = Ws2[wi + 4];
                }
            #pragma unroll
            for (int g = 0; g < 3; g++)
                #pragma unroll
                for (int nt = 0; nt < 2; nt++)
                    mma16b(acc[g][nt], af, bf[g][nt]);
        }

        #pragma unroll
        for (int dr = 0; dr < 2; dr++){
            int rl = wm*16 + (lane >> 2) + dr*8;
            int row = row0 + rl;
            #pragma unroll
            for (int nt = 0; nt < 2; nt++){
                int ccl = wn*16 + nt*8 + (lane & 3)*2;
                float2 gv0 = unpackbf(GIs[rl*52 + (ccl >> 1)]);
                float2 gv1 = unpackbf(GIs[rl*52 + 16 + (ccl >> 1)]);
                float2 gv2 = unpackbf(GIs[rl*52 + 32 + (ccl >> 1)]);
                float2 hold = __ldcg((const float2*)&hsrc[(size_t)row*H_DIM + bcol*32 + ccl]);
                float2 hout;
                #pragma unroll
                for (int dc = 0; dc < 2; dc++){
                    float gr = acc[0][nt][dr*2+dc] + bR[nt][dc];
                    float gz = acc[1][nt][dr*2+dc] + bZ[nt][dc];
                    float gn = acc[2][nt][dr*2+dc] + bN[nt][dc];
                    float r  = sigm((dc ? gv0.y : gv0.x) + gr);
                    float z  = sigm((dc ? gv1.y : gv1.x) + gz);
                    float nn = tanhf((dc ? gv2.y : gv2.x) + r*gn);
                    float ho = dc ? hold.y : hold.x;
                    float hnew = (1.f - z)*nn + z*ho;
                    if (dc) hout.y = hnew; else hout.x = hnew;
                }
                __stcg((float2*)&hdst[(size_t)row*H_DIM + bcol*32 + ccl], hout);
                __stcg((uint32_t*)(hdst16 + (size_t)row*H_DIM + bcol*32 + ccl),
                       packbf(hout.x, hout.y));
            }
        }

        __syncthreads();
        if (t + 1 < T_DIM) stage_gi(t + 1);
        slab_sync(slab, 8);
    }
}

// ---------------- heads v2: reads compact hall, writes ALL out fields --------------
__global__ void __launch_bounds__(256)
heads_kernel(float* __restrict__ out, const int* __restrict__ actions,
             const int* __restrict__ active, const float* __restrict__ p0,
             const float* __restrict__ pp0,
             const float* __restrict__ w_actor, const float* __restrict__ b_actor,
             const float* __restrict__ w_critic, const float* __restrict__ b_critic)
{
    int wid = threadIdx.x >> 5, lane = threadIdx.x & 31;
    size_t row = (size_t)blockIdx.x*8 + wid;
    const float* hrow = g_hall + row*H_DIM;
    float* orow = out + row*ROW_OUT;
    float hv[8];
    #pragma unroll
    for (int i = 0; i < 8; i++) hv[i] = hrow[lane + 32*i];

    float lg = 0.f;
    #pragma unroll
    for (int a = 0; a < NA_DIM; a++){
        float s = 0.f;
        #pragma unroll
        for (int i = 0; i < 8; i++) s += hv[i]*w_actor[a*H_DIM + lane + 32*i];
        #pragma unroll
        for (int o = 16; o > 0; o >>= 1) s += __shfl_xor_sync(0xffffffffu, s, o);
        if (lane == a) lg = s + b_actor[a];
    }
    float m = (lane < NA_DIM) ? lg : -1e30f;
    #pragma unroll
    for (int o = 16; o > 0; o >>= 1) m = fmaxf(m, __shfl_xor_sync(0xffffffffu, m, o));
    float e = (lane < NA_DIM) ? expf(lg - m) : 0.f;
    float den = e;
    #pragma unroll
    for (int o = 16; o > 0; o >>= 1) den += __shfl_xor_sync(0xffffffffu, den, o);

    // h section (coalesced within the row)
    #pragma unroll
    for (int i = 0; i < 8; i++) orow[4 + lane + 32*i] = hv[i];
    if (lane < NA_DIM) orow[260 + lane] = e/den;

    float s = 0.f;
    #pragma unroll
    for (int i = 0; i < 8; i++) s += hv[i]*w_critic[lane + 32*i];
    #pragma unroll
    for (int o = 16; o > 0; o >>= 1) s += __shfl_xor_sync(0xffffffffu, s, o);

    int n = (int)(row & (N_DIM - 1));
    if (lane == 0)  orow[3]   = s + b_critic[0];
    if (lane == 16) orow[0]   = (float)actions[row];
    if (lane == 17) orow[1]   = p0[n];
    if (lane == 18) orow[2]   = (float)active[row];
    if (lane == 19) orow[276] = pp0[n*2];
    if (lane == 20) orow[277] = pp0[n*2 + 1];
}

// ---------------- launch ----------------
extern "C" void kernel_launch(void* const* d_in, const int* in_sizes, int n_in,
                              void* d_out, int out_size)
{
    (void)in_sizes; (void)n_in; (void)out_size;
    const float* condition = (const float*)d_in[0];
    const int*   active    = (const int*)d_in[1];
    const int*   lines     = (const int*)d_in[2];
    const int*   actions   = (const int*)d_in[3];
    const float* h0        = (const float*)d_in[4];
    const float* p0        = (const float*)d_in[5];
    const float* pp0       = (const float*)d_in[6];
    const float* embed     = (const float*)d_in[7];
    const float* wih_f = (const float*)d_in[8],  *whh_f = (const float*)d_in[9];
    const float* bih_f = (const float*)d_in[10], *bhh_f = (const float*)d_in[11];
    const float* wih_b = (const float*)d_in[12], *whh_b = (const float*)d_in[13];
    const float* bih_b = (const float*)d_in[14], *bhh_b = (const float*)d_in[15];
    const float* f_w0 = (const float*)d_in[16], *f_b0 = (const float*)d_in[17];
    const float* f_w1 = (const float*)d_in[18], *f_b1 = (const float*)d_in[19];
    const float* f_w2 = (const float*)d_in[20], *f_b2 = (const float*)d_in[21];
    const float* c_wih = (const float*)d_in[22], *c_whh = (const float*)d_in[23];
    const float* c_bih = (const float*)d_in[24], *c_bhh = (const float*)d_in[25];
    const float* w_critic = (const float*)d_in[26], *b_critic = (const float*)d_in[27];
    const float* w_actor  = (const float*)d_in[28], *b_actor  = (const float*)d_in[29];
    float* out = (float*)d_out;

    float *Rp;
    uint32_t *A0bp, *A1bp, *GIbp;
    cudaGetSymbolAddress((void**)&Rp,  g_Rproj);
    cudaGetSymbolAddress((void**)&A0bp, g_A0b);
    cudaGetSymbolAddress((void**)&A1bp, g_A1b);
    cudaGetSymbolAddress((void**)&GIbp, g_GIb);

    cudaFuncSetAttribute(enc_v7,
                         cudaFuncAttributeMaxDynamicSharedMemorySize, E7_SMEM_BYTES);
    cudaFuncSetAttribute(main_gru_v10,
                         cudaFuncAttributeMaxDynamicSharedMemorySize, M9_SMEM_BYTES);
    cudaFuncSetAttribute(gemm_ffb<1>,
                         cudaFuncAttributeMaxDynamicSharedMemorySize, FFB_SMEM_BYTES);
    cudaFuncSetAttribute(gemm_ffb<3>,
                         cudaFuncAttributeMaxDynamicSharedMemorySize, FFB_SMEM_BYTES);

    // 0) gi tables + state init
    gi_tables<<<(2*NL_DIM*G3 + 255)/256, 256>>>(embed, wih_f, bih_f, wih_b, bih_b);
    init_state<<<4096, 256>>>(h0);

    // 1) persistent bidirectional encoder (bf16, K-chunk 64)
    enc_v7<<<dim3(8, 16), 512, E7_SMEM_BYTES>>>(whh_f, bhh_f, whh_b, bhh_b, lines);

    // 2) Rproj = Hmem @ W0r^T (f32)
    gemm_plain<1, 0><<<dim3(4, 128), 256>>>(nullptr, f_w0 + 64, 576, nullptr, Rp, 512, 256, nullptr);
    // 3) A0 = relu(cond @ W0c^T + Rproj[active] + b0)  -> packed bf16
    gemm_plain<0, 4><<<dim3(4, 2048), 256>>>(condition, f_w0, 576, f_b0, A0bp, 64, 256, active);
    // 4) A1 = relu(A0 @ w1^T + b1); A0'' = relu(A1 @ w2^T + b2)  (bf16 GEMMs)
    gemm_ffb<1><<<dim3(2, 74), 512, FFB_SMEM_BYTES>>>(A0bp, f_w1, f_b1, A1bp, 128, 1024);
    gemm_ffb<1><<<dim3(2, 74), 512, FFB_SMEM_BYTES>>>(A1bp, f_w2, f_b2, A0bp, 128, 1024);
    // 5) GI = A0'' @ c_wih^T + c_bih  -> packed bf16
    gemm_ffb<3><<<dim3(6, 24), 512, FFB_SMEM_BYTES>>>(A0bp, c_wih, c_bih, GIbp, 384, 1024);

    // 6) persistent main GRU v10 (writes compact g_hall only)
    main_gru_v10<<<dim3(8, 16), 256, M9_SMEM_BYTES>>>(c_whh, c_bhh);

    // 7) heads v2: reads g_hall, writes all out fields
    heads_kernel<<<TN/8, 256>>>(out, actions, active, p0, pp0,
                                w_actor, b_actor, w_critic, b_critic);
}

// round 13
// speedup vs baseline: 3.1972x; 1.0284x over previous
#include <cuda_runtime.h>
#include <math.h>
#include <stdint.h>

#define T_DIM 256
#define N_DIM 1024
#define H_DIM 256
#define L_DIM 16
#define NL_DIM 32
#define C_DIM 64
#define NA_DIM 16
#define ROW_OUT 278
#define G3 768
#define LN (L_DIM*N_DIM)          /* 16384 */
#define TN (T_DIM*N_DIM)          /* 262144 */

// ---------------- scratch ----------------
__device__ float g_giF[NL_DIM*G3];
__device__ float g_giB[NL_DIM*G3];
__device__ float g_Hf[2][(size_t)LN*H_DIM];
__device__ float g_Hb[2][(size_t)LN*H_DIM];
__device__ uint16_t g_Hfb[2][(size_t)LN*H_DIM];
__device__ uint16_t g_Hbb[2][(size_t)LN*H_DIM];
__device__ float g_Rproj[(size_t)LN*H_DIM];
__device__ uint32_t g_A0b[(size_t)TN*(H_DIM/2)];
__device__ uint32_t g_A1b[(size_t)TN*(H_DIM/2)];
__device__ uint32_t g_GIb[(size_t)TN*(G3/2)];
__device__ float g_hall[(size_t)TN*H_DIM];
__device__ float g_hm0[N_DIM*H_DIM];
__device__ uint16_t g_hmb[2][N_DIM*H_DIM];
__device__ unsigned g_slabc[16][32];
__device__ unsigned g_slabg[16][32];

// ---------------- helpers ----------------
__device__ __forceinline__ uint32_t f2tf(float x){
    uint32_t r; asm("cvt.rna.tf32.f32 %0, %1;" : "=r"(r) : "f"(x)); return r;
}
__device__ __forceinline__ uint32_t packbf(float lo, float hi){
    uint32_t r; asm("cvt.rn.bf16x2.f32 %0, %1, %2;" : "=r"(r) : "f"(hi), "f"(lo)); return r;
}
__device__ __forceinline__ float2 unpackbf(uint32_t u){
    float2 r;
    r.x = __uint_as_float(u << 16);
    r.y = __uint_as_float(u & 0xffff0000u);
    return r;
}
__device__ __forceinline__ void mma8(float* c, const uint32_t* a, const uint32_t* b){
    asm volatile("mma.sync.aligned.m16n8k8.row.col.f32.tf32.tf32.f32 "
        "{%0,%1,%2,%3},{%4,%5,%6,%7},{%8,%9},{%0,%1,%2,%3};"
        : "+f"(c[0]), "+f"(c[1]), "+f"(c[2]), "+f"(c[3])
        : "r"(a[0]), "r"(a[1]), "r"(a[2]), "r"(a[3]), "r"(b[0]), "r"(b[1]));
}
__device__ __forceinline__ void mma16b(float* c, const uint32_t* a, const uint32_t* b){
    asm volatile("mma.sync.aligned.m16n8k16.row.col.f32.bf16.bf16.f32 "
        "{%0,%1,%2,%3},{%4,%5,%6,%7},{%8,%9},{%0,%1,%2,%3};"
        : "+f"(c[0]), "+f"(c[1]), "+f"(c[2]), "+f"(c[3])
        : "r"(a[0]), "r"(a[1]), "r"(a[2]), "r"(a[3]), "r"(b[0]), "r"(b[1]));
}
__device__ __forceinline__ void ldsm4(uint32_t* r, uint32_t saddr){
    asm volatile("ldmatrix.sync.aligned.m8n8.x4.shared.b16 {%0,%1,%2,%3}, [%4];"
        : "=r"(r[0]), "=r"(r[1]), "=r"(r[2]), "=r"(r[3]) : "r"(saddr));
}
__device__ __forceinline__ void ldsm2(uint32_t* r, uint32_t saddr){
    asm volatile("ldmatrix.sync.aligned.m8n8.x2.shared.b16 {%0,%1}, [%2];"
        : "=r"(r[0]), "=r"(r[1]) : "r"(saddr));
}
__device__ __forceinline__ uint32_t sptr(const void* p){
    return (uint32_t)__cvta_generic_to_shared(p);
}
__device__ __forceinline__ float sigm(float x){ return 1.f/(1.f+expf(-x)); }
__device__ __forceinline__ void cp16(void* smem_dst, const void* gsrc){
    uint32_t s = (uint32_t)__cvta_generic_to_shared(smem_dst);
    asm volatile("cp.async.cg.shared.global [%0], [%1], 16;" :: "r"(s), "l"(gsrc));
}
__device__ __forceinline__ void cp_commit(){ asm volatile("cp.async.commit_group;"); }
template<int N> __device__ __forceinline__ void cp_wait(){
    asm volatile("cp.async.wait_group %0;" :: "n"(N));
}

__device__ __forceinline__ void slab_sync(int slab, unsigned nb){
    __syncthreads();
    if (threadIdx.x == 0){
        volatile unsigned* genp = &g_slabg[slab][0];
        unsigned old = *genp;
        __threadfence();
        if (atomicAdd(&g_slabc[slab][0], 1u) == nb - 1u){
            g_slabc[slab][0] = 0u;
            __threadfence();
            *genp = old + 1u;
        } else {
            while (*genp == old) { }
            __threadfence();
        }
    }
    __syncthreads();
}

// ---------------- gi tables ----------------
__global__ void gi_tables(const float* __restrict__ embed,
                          const float* __restrict__ wihF, const float* __restrict__ bihF,
                          const float* __restrict__ wihB, const float* __restrict__ bihB)
{
    int idx = blockIdx.x*blockDim.x + threadIdx.x;
    if (idx >= 2*NL_DIM*G3) return;
    int dir = idx / (NL_DIM*G3);
    int rem = idx % (NL_DIM*G3);
    int e = rem / G3, j = rem % G3;
    const float* wih = dir ? wihB : wihF;
    const float* bih = dir ? bihB : bihF;
    float s = bih[j];
    const float* em = embed + e*H_DIM;
    const float* w  = wih + (size_t)j*H_DIM;
    #pragma unroll 8
    for (int k = 0; k < H_DIM; k++) s += em[k]*w[k];
    (dir ? g_giB : g_giF)[rem] = s;
}

// ---------------- init ----------------
__global__ void init_state(const float* __restrict__ h0)
{
    size_t stride = (size_t)gridDim.x*blockDim.x;
    size_t i0 = (size_t)blockIdx.x*blockDim.x + threadIdx.x;
    size_t HS = (size_t)LN*H_DIM;
    for (size_t p = i0; p < HS; p += stride){
        g_Hf[0][p] = 0.f; g_Hb[0][p] = 0.f;
        g_Hfb[0][p] = 0;  g_Hbb[0][p] = 0;
    }
    for (size_t p = i0; p < (size_t)N_DIM*H_DIM; p += stride){
        float v = h0[p];
        g_hm0[p] = v;
        g_hmb[0][p] = (uint16_t)(packbf(v, 0.f) & 0xffffu);
    }
}

// ---------------- plain tf32 GEMM: EPI 0 = f32 (Rproj); EPI 4 = layer0 packed ------
template<int ALOAD, int EPI>
__global__ void __launch_bounds__(256)
gemm_plain(const float* __restrict__ A, const float* __restrict__ B, int ldb,
           const float* __restrict__ bias, void* __restrict__ outv,
           int K, int NC, const int* __restrict__ active)
{
    __shared__ float As[128][20];
    __shared__ float Bs[64][20];
    const int tid = threadIdx.x, lane = tid & 31, wid = tid >> 5;
    const int wm = wid >> 1, wn = wid & 1;
    const int brow = blockIdx.y, bcol = blockIdx.x;
    float acc[2][4][4];
    #pragma unroll
    for (int a = 0; a < 2; a++)
        #pragma unroll
        for (int b = 0; b < 4; b++)
            #pragma unroll
            for (int c = 0; c < 4; c++) acc[a][b][c] = 0.f;

    for (int k0 = 0; k0 < K; k0 += 16){
        #pragma unroll
        for (int i = tid; i < 2048; i += 256){
            int r = i >> 4, c = i & 15;
            int row = brow*128 + r; int k = k0 + c;
            float v;
            if (ALOAD == 0) v = A[(size_t)row*K + k];
            else v = (k < H_DIM) ? g_Hf[0][(size_t)row*H_DIM + k]
                                 : g_Hb[0][(size_t)row*H_DIM + (k - H_DIM)];
            As[r][c] = __uint_as_float(f2tf(v));
        }
        #pragma unroll
        for (int i = tid; i < 1024; i += 256){
            int n = i >> 4, c = i & 15;
            Bs[n][c] = __uint_as_float(f2tf(B[(size_t)(bcol*64 + n)*ldb + k0 + c]));
        }
        __syncthreads();
        #pragma unroll
        for (int kk = 0; kk < 16; kk += 8){
            uint32_t af[2][4], bf[4][2];
            #pragma unroll
            for (int mt = 0; mt < 2; mt++){
                int r0 = wm*32 + mt*16 + (lane >> 2);
                int c0 = kk + (lane & 3);
                af[mt][0] = __float_as_uint(As[r0][c0]);
                af[mt][1] = __float_as_uint(As[r0+8][c0]);
                af[mt][2] = __float_as_uint(As[r0][c0+4]);
                af[mt][3] = __float_as_uint(As[r0+8][c0+4]);
            }
            #pragma unroll
            for (int nt = 0; nt < 4; nt++){
                int n0 = wn*32 + nt*8 + (lane >> 2);
                bf[nt][0] = __float_as_uint(Bs[n0][kk + (lane & 3)]);
                bf[nt][1] = __float_as_uint(Bs[n0][kk + 4 + (lane & 3)]);
            }
            #pragma unroll
            for (int mt = 0; mt < 2; mt++)
                #pragma unroll
                for (int nt = 0; nt < 4; nt++)
                    mma8(acc[mt][nt], af[mt], bf[nt]);
        }
        __syncthreads();
    }
    #pragma unroll
    for (int mt = 0; mt < 2; mt++){
        #pragma unroll
        for (int nt = 0; nt < 4; nt++){
            int rbase = brow*128 + wm*32 + mt*16 + (lane >> 2);
            int cbase = bcol*64 + wn*32 + nt*8 + (lane & 3)*2;
            #pragma unroll
            for (int dr = 0; dr < 2; dr++){
                int rr = rbase + dr*8, cc = cbase;
                float v0 = acc[mt][nt][dr*2 + 0];
                float v1 = acc[mt][nt][dr*2 + 1];
                if (EPI == 4){
                    int n = rr & (N_DIM - 1);
                    int w = active[rr];
                    const float* rp = &g_Rproj[(size_t)(w*N_DIM + n)*H_DIM + cc];
                    v0 = fmaxf(v0 + bias[cc]   + rp[0], 0.f);
                    v1 = fmaxf(v1 + bias[cc+1] + rp[1], 0.f);
                    ((uint32_t*)outv)[(size_t)rr*(H_DIM/2) + (cc >> 1)] = packbf(v0, v1);
                } else {
                    float* out = (float*)outv;
                    out[(size_t)rr*NC + cc]     = v0;
                    out[(size_t)rr*NC + cc + 1] = v1;
                }
            }
        }
    }
}

// ---------------- persistent encoder v8: bf16 K-chunk 64 + ldmatrix ----------------
#define E7_W_U32 (3*32*132)
#define E7_A_U32 (2*256*36)
#define E7_G_FLOATS (NL_DIM*100)
#define E7_SMEM_BYTES ((E7_W_U32 + E7_A_U32 + E7_G_FLOATS)*4)

__global__ void __launch_bounds__(512, 1)
enc_v8(const float* __restrict__ whF, const float* __restrict__ bhF,
       const float* __restrict__ whB, const float* __restrict__ bhB,
       const int* __restrict__ lines)
{
    extern __shared__ uint32_t smu[];
    uint32_t* Ws2 = smu;
    uint32_t* As2 = smu + E7_W_U32;
    float* GIe = (float*)(smu + E7_W_U32 + E7_A_U32);
    const int tid = threadIdx.x, lane = tid & 31, wid = tid >> 5;
    const int wm = wid >> 1, wn = wid & 1;
    const int bcol = blockIdx.x;
    const int slab = blockIdx.y;
    const bool dirF = (slab < 8);
    const float* __restrict__ W  = dirF ? whF : whB;
    const float* __restrict__ bh = dirF ? bhF : bhB;
    const float* __restrict__ giT = dirF ? g_giF : g_giB;
    const int lrow0 = (dirF ? slab : slab - 8) * 2048;

    for (int i = tid; i < 3*32*128; i += 512){
        int g = i >> 12, rem = i & 4095;
        int c = rem >> 7, kp = rem & 127;
        const float* wr = W + (size_t)(g*H_DIM + bcol*32 + c)*H_DIM + 2*kp;
        Ws2[(g*32 + c)*132 + kp] = packbf(wr[0], wr[1]);
    }
    for (int i = tid; i < NL_DIM*96; i += 512){
        int e = i / 96, j = i % 96;
        int g = j >> 5, c = j & 31;
        GIe[e*100 + j] = __ldg(&giT[e*G3 + g*H_DIM + bcol*32 + c]);
    }
    float bR[2][2], bZ[2][2], bN[2][2];
    #pragma unroll
    for (int nt = 0; nt < 2; nt++)
        #pragma unroll
        for (int dc = 0; dc < 2; dc++){
            int c = bcol*32 + wn*16 + nt*8 + (lane & 3)*2 + dc;
            bR[nt][dc] = bh[c];
            bZ[nt][dc] = bh[H_DIM + c];
            bN[nt][dc] = bh[2*H_DIM + c];
        }
    // ldmatrix lane-constant addresses
    const int tA = lane >> 3;               // 0..3
    uint32_t aA[2];
    #pragma unroll
    for (int mt = 0; mt < 2; mt++)
        aA[mt] = sptr(As2) + (uint32_t)(((wm*32 + mt*16 + (tA & 1)*8 + (lane & 7))*36
                                        + (tA >> 1)*4) * 4);
    uint32_t aB[3][2];
    #pragma unroll
    for (int g = 0; g < 3; g++)
        #pragma unroll
        for (int nt = 0; nt < 2; nt++)
            aB[g][nt] = sptr(Ws2) + (uint32_t)(((g*32 + wn*16 + nt*8 + (lane & 7))*132
                                        + ((lane >> 3) & 1)*4) * 4);
    __syncthreads();

    for (int t = 0; t < L_DIM; t++){
        const float* __restrict__ hsrc = dirF ? g_Hf[t & 1] : g_Hb[t & 1];
        float* __restrict__ hdst = dirF ? g_Hf[(t + 1) & 1] : g_Hb[(t + 1) & 1];
        const uint16_t* __restrict__ hsrc16 = dirF ? g_Hfb[t & 1] : g_Hbb[t & 1];
        uint16_t* __restrict__ hdst16 = dirF ? g_Hfb[(t + 1) & 1] : g_Hbb[(t + 1) & 1];

        auto stage = [&](int p){
            int chunk = p >> 2, kb = p & 3, buf = p & 1;
            const uint16_t* src = hsrc16 + (size_t)(lrow0 + chunk*256)*H_DIM + kb*64;
            uint32_t* dst = As2 + buf*256*36;
            #pragma unroll
            for (int i = tid; i < 2048; i += 512){
                int r = i >> 3, q = i & 7;
                cp16(&dst[r*36 + q*4], src + (size_t)r*H_DIM + q*8);
            }
            cp_commit();
        };

        float acc[3][2][2][4];
        stage(0);
        for (int p = 0; p < 32; p++){
            cp_wait<0>();
            __syncthreads();
            if (p + 1 < 32) stage(p + 1);
            const int kb = p & 3;
            if (kb == 0){
                #pragma unroll
                for (int g = 0; g < 3; g++)
                    #pragma unroll
                    for (int a = 0; a < 2; a++)
                        #pragma unroll
                        for (int b = 0; b < 2; b++)
                            #pragma unroll
                            for (int c = 0; c < 4; c++) acc[g][a][b][c] = 0.f;
            }
            const uint32_t abufofs = (uint32_t)((p & 1)*256*36*4);
            const uint32_t bofs = (uint32_t)(kb*128);
            #pragma unroll
            for (int kk = 0; kk < 64; kk += 16){
                uint32_t af[2][4];
                #pragma unroll
                for (int mt = 0; mt < 2; mt++)
                    ldsm4(af[mt], aA[mt] + abufofs + kk*2);
                #pragma unroll
                for (int g = 0; g < 3; g++)
                    #pragma unroll
                    for (int nt = 0; nt < 2; nt++){
                        uint32_t bf[2];
                        ldsm2(bf, aB[g][nt] + bofs + kk*2);
                        #pragma unroll
                        for (int mt = 0; mt < 2; mt++)
                            mma16b(acc[g][mt][nt], af[mt], bf);
                    }
            }

            if (kb == 3){
                const int base = lrow0 + (p >> 2)*256;
                #pragma unroll
                for (int mt = 0; mt < 2; mt++){
                    #pragma unroll
                    for (int dr = 0; dr < 2; dr++){
                        int lr = base + wm*32 + mt*16 + (lane >> 2) + dr*8;
                        int iroll = lr >> 10;
                        int nb = lr & (N_DIM - 1);
                        int l = dirF ? ((iroll + t) & 15) : ((iroll + 15 - t) & 15);
                        const float* ge = GIe + __ldg(&lines[nb*L_DIM + l])*100;
                        #pragma unroll
                        for (int nt = 0; nt < 2; nt++){
                            int hcl = wn*16 + nt*8 + (lane & 3)*2;
                            float2 gv0 = *(const float2*)&ge[hcl];
                            float2 gv1 = *(const float2*)&ge[32 + hcl];
                            float2 gv2 = *(const float2*)&ge[64 + hcl];
                            float2 hold = __ldcg((const float2*)&hsrc[(size_t)lr*H_DIM + bcol*32 + hcl]);
                            float2 hout;
                            #pragma unroll
                            for (int dc = 0; dc < 2; dc++){
                                float gr = acc[0][mt][nt][dr*2+dc] + bR[nt][dc];
                                float gz = acc[1][mt][nt][dr*2+dc] + bZ[nt][dc];
                                float gn = acc[2][mt][nt][dr*2+dc] + bN[nt][dc];
                                float r  = sigm((dc ? gv0.y : gv0.x) + gr);
                                float z  = sigm((dc ? gv1.y : gv1.x) + gz);
                                float nn = tanhf((dc ? gv2.y : gv2.x) + r*gn);
                                float ho = dc ? hold.y : hold.x;
                                float hnew = (1.f - z)*nn + z*ho;
                                if (dc) hout.y = hnew; else hout.x = hnew;
                            }
                            __stcg((float2*)&hdst[(size_t)lr*H_DIM + bcol*32 + hcl], hout);
                            __stcg((uint32_t*)(hdst16 + (size_t)lr*H_DIM + bcol*32 + hcl),
                                   packbf(hout.x, hout.y));
                        }
                    }
                }
            }
        }
        slab_sync(slab, 8);
    }
}

// ---------------- bf16 feed-forward GEMM + ldmatrix -------------------
#define FFB_W_U32 (128*132)
#define FFB_A_U32 (2*256*36)
#define FFB_SMEM_BYTES ((FFB_W_U32 + FFB_A_U32)*4)

template<int EPI>
__global__ void __launch_bounds__(512, 1)
gemm_ffb(const uint32_t* __restrict__ A, const float* __restrict__ W,
         const float* __restrict__ bias, uint32_t* __restrict__ outp,
         int out_stride, int nrt)
{
    extern __shared__ uint32_t smu[];
    uint32_t* Ws2 = smu;
    uint32_t* As2 = smu + FFB_W_U32;
    const int tid = threadIdx.x, lane = tid & 31, wid = tid >> 5;
    const int wm = wid >> 1, wn = wid & 1;
    const int bcol = blockIdx.x;

    for (int i = tid; i < 128*128; i += 512){
        int c = i >> 7, kp = i & 127;
        const float* wr = W + (size_t)(bcol*128 + c)*H_DIM + 2*kp;
        Ws2[c*132 + kp] = packbf(wr[0], wr[1]);
    }
    const int tA = lane >> 3;
    uint32_t aA[2];
    #pragma unroll
    for (int mt = 0; mt < 2; mt++)
        aA[mt] = sptr(As2) + (uint32_t)(((wm*32 + mt*16 + (tA & 1)*8 + (lane & 7))*36
                                        + (tA >> 1)*4) * 4);
    uint32_t aB[8];
    #pragma unroll
    for (int nt = 0; nt < 8; nt++)
        aB[nt] = sptr(Ws2) + (uint32_t)(((wn*64 + nt*8 + (lane & 7))*132
                                        + ((lane >> 3) & 1)*4) * 4);
    __syncthreads();

    const int nch = (nrt - (int)blockIdx.y + (int)gridDim.y - 1) / (int)gridDim.y;
    if (nch <= 0) return;
    const int total = nch*4;

    auto stage = [&](int p){
        int ci = p >> 2, kb = p & 3, buf = p & 1;
        int rt = blockIdx.y + ci*gridDim.y;
        const uint32_t* src = A + (size_t)rt*256*128 + kb*32;
        uint32_t* dst = As2 + buf*256*36;
        #pragma unroll
        for (int i = tid; i < 2048; i += 512){
            int r = i >> 3, q = i & 7;
            cp16(&dst[r*36 + q*4], src + (size_t)r*128 + q*4);
        }
        cp_commit();
    };

    float acc[2][8][4];
    stage(0);
    for (int p = 0; p < total; p++){
        cp_wait<0>();
        __syncthreads();
        if (p + 1 < total) stage(p + 1);
        const int kb = p & 3;
        if (kb == 0){
            #pragma unroll
            for (int a = 0; a < 2; a++)
                #pragma unroll
                for (int b = 0; b < 8; b++)
                    #pragma unroll
                    for (int c = 0; c < 4; c++) acc[a][b][c] = 0.f;
        }
        const uint32_t abufofs = (uint32_t)((p & 1)*256*36*4);
        const uint32_t bofs = (uint32_t)(kb*128);
        #pragma unroll
        for (int kk = 0; kk < 64; kk += 16){
            uint32_t af[2][4];
            #pragma unroll
            for (int mt = 0; mt < 2; mt++)
                ldsm4(af[mt], aA[mt] + abufofs + kk*2);
            #pragma unroll
            for (int nt = 0; nt < 8; nt++){
                uint32_t bf[2];
                ldsm2(bf, aB[nt] + bofs + kk*2);
                #pragma unroll
                for (int mt = 0; mt < 2; mt++)
                    mma16b(acc[mt][nt], af[mt], bf);
            }
        }

        if (kb == 3){
            int rt = blockIdx.y + (p >> 2)*gridDim.y;
            #pragma unroll
            for (int mt = 0; mt < 2; mt++){
                #pragma unroll
                for (int nt = 0; nt < 8; nt++){
                    #pragma unroll
                    for (int dr = 0; dr < 2; dr++){
                        int rr = rt*256 + wm*32 + mt*16 + (lane >> 2) + dr*8;
                        int cc = bcol*128 + wn*64 + nt*8 + (lane & 3)*2;
                        float v0 = acc[mt][nt][dr*2 + 0] + bias[cc];
                        float v1 = acc[mt][nt][dr*2 + 1] + bias[cc + 1];
                        if (EPI == 1){ v0 = fmaxf(v0, 0.f); v1 = fmaxf(v1, 0.f); }
                        outp[(size_t)rr*out_stride + (cc >> 1)] = packbf(v0, v1);
                    }
                }
            }
        }
    }
}

// ---------------- persistent main GRU v11: ldmatrix ----------------
#define M9_W_U32 (3*32*132)
#define M9_A_U32 (64*132)
#define M9_G_U32 (64*52)
#define M9_SMEM_BYTES ((M9_W_U32 + M9_A_U32 + M9_G_U32)*4)

__global__ void __launch_bounds__(256, 1)
main_gru_v11(const float* __restrict__ whh, const float* __restrict__ bhh)
{
    extern __shared__ uint32_t smu[];
    uint32_t* Ws2 = smu;
    uint32_t* As2 = smu + M9_W_U32;
    uint32_t* GIs = smu + M9_W_U32 + M9_A_U32;
    const int tid = threadIdx.x, lane = tid & 31, wid = tid >> 5;
    const int wm = wid >> 1, wn = wid & 1;
    const int bcol = blockIdx.x;
    const int slab = blockIdx.y;
    const int row0 = slab*64;

    for (int i = tid; i < 3*32*128; i += 256){
        int g = i >> 12, rem = i & 4095;
        int c = rem >> 7, kp = rem & 127;
        const float* wr = whh + (size_t)(g*H_DIM + bcol*32 + c)*H_DIM + 2*kp;
        Ws2[(g*32 + c)*132 + kp] = packbf(wr[0], wr[1]);
    }
    float bR[2][2], bZ[2][2], bN[2][2];
    #pragma unroll
    for (int nt = 0; nt < 2; nt++)
        #pragma unroll
        for (int dc = 0; dc < 2; dc++){
            int c = bcol*32 + nt*8 + wn*16 + (lane & 3)*2 + dc;
            bR[nt][dc] = bhh[c];
            bZ[nt][dc] = bhh[H_DIM + c];
            bN[nt][dc] = bhh[2*H_DIM + c];
        }
    const int tA = lane >> 3;
    const uint32_t aA = sptr(As2) + (uint32_t)(((wm*16 + (tA & 1)*8 + (lane & 7))*132
                                        + (tA >> 1)*4) * 4);
    uint32_t aB[3][2];
    #pragma unroll
    for (int g = 0; g < 3; g++)
        #pragma unroll
        for (int nt = 0; nt < 2; nt++)
            aB[g][nt] = sptr(Ws2) + (uint32_t)(((g*32 + wn*16 + nt*8 + (lane & 7))*132
                                        + ((lane >> 3) & 1)*4) * 4);

    auto stage_gi = [&](int tt){
        const uint32_t* gsrc = g_GIb + ((size_t)tt*N_DIM + row0)*(G3/2) + bcol*16;
        #pragma unroll
        for (int i = tid; i < 768; i += 256){
            int r = i / 12, j = i % 12;
            int g = j >> 2, qj = j & 3;
            cp16(&GIs[r*52 + g*16 + qj*4], gsrc + (size_t)r*(G3/2) + g*128 + qj*4);
        }
        cp_commit();
    };

    stage_gi(0);
    slab_sync(slab, 8);

    for (int t = 0; t < T_DIM; t++){
        const float* __restrict__ hsrc = (t == 0) ? g_hm0
                                       : g_hall + (size_t)(t - 1)*N_DIM*H_DIM;
        float* __restrict__ hdst = g_hall + (size_t)t*N_DIM*H_DIM;
        const uint16_t* __restrict__ hsrc16 = g_hmb[t & 1];
        uint16_t* __restrict__ hdst16 = g_hmb[(t + 1) & 1];

        {
            const uint16_t* src = hsrc16 + (size_t)row0*H_DIM;
            #pragma unroll
            for (int i = tid; i < 2048; i += 256){
                int r = i >> 5, q = i & 31;
                cp16(&As2[r*132 + q*4], src + (size_t)r*H_DIM + q*8);
            }
            cp_commit();
        }
        cp_wait<0>();
        __syncthreads();

        float acc[3][2][4];
        #pragma unroll
        for (int g = 0; g < 3; g++)
            #pragma unroll
            for (int n = 0; n < 2; n++)
                #pragma unroll
                for (int c = 0; c < 4; c++) acc[g][n][c] = 0.f;

        #pragma unroll 4
        for (int kk = 0; kk < H_DIM; kk += 16){
            uint32_t af[4];
            ldsm4(af, aA + kk*2);
            #pragma unroll
            for (int g = 0; g < 3; g++)
                #pragma unroll
                for (int nt = 0; nt < 2; nt++){
                    uint32_t bf[2];
                    ldsm2(bf, aB[g][nt] + kk*2);
                    mma16b(acc[g][nt], af, bf);
                }
        }

        #pragma unroll
        for (int dr = 0; dr < 2; dr++){
            int rl = wm*16 + (lane >> 2) + dr*8;
            int row = row0 + rl;
            #pragma unroll
            for (int nt = 0; nt < 2; nt++){
                int ccl = wn*16 + nt*8 + (lane & 3)*2;
                float2 gv0 = unpackbf(GIs[rl*52 + (ccl >> 1)]);
                float2 gv1 = unpackbf(GIs[rl*52 + 16 + (ccl >> 1)]);
                float2 gv2 = unpackbf(GIs[rl*52 + 32 + (ccl >> 1)]);
                float2 hold = __ldcg((const float2*)&hsrc[(size_t)row*H_DIM + bcol*32 + ccl]);
                float2 hout;
                #pragma unroll
                for (int dc = 0; dc < 2; dc++){
                    float gr = acc[0][nt][dr*2+dc] + bR[nt][dc];
                    float gz = acc[1][nt][dr*2+dc] + bZ[nt][dc];
                    float gn = acc[2][nt][dr*2+dc] + bN[nt][dc];
                    float r  = sigm((dc ? gv0.y : gv0.x) + gr);
                    float z  = sigm((dc ? gv1.y : gv1.x) + gz);
                    float nn = tanhf((dc ? gv2.y : gv2.x) + r*gn);
                    float ho = dc ? hold.y : hold.x;
                    float hnew = (1.f - z)*nn + z*ho;
                    if (dc) hout.y = hnew; else hout.x = hnew;
                }
                __stcg((float2*)&hdst[(size_t)row*H_DIM + bcol*32 + ccl], hout);
                __stcg((uint32_t*)(hdst16 + (size_t)row*H_DIM + bcol*32 + ccl),
                       packbf(hout.x, hout.y));
            }
        }

        __syncthreads();
        if (t + 1 < T_DIM) stage_gi(t + 1);
        slab_sync(slab, 8);
    }
}

// ---------------- heads v2 ----------------
__global__ void __launch_bounds__(256)
heads_kernel(float* __restrict__ out, const int* __restrict__ actions,
             const int* __restrict__ active, const float* __restrict__ p0,
             const float* __restrict__ pp0,
             const float* __restrict__ w_actor, const float* __restrict__ b_actor,
             const float* __restrict__ w_critic, const float* __restrict__ b_critic)
{
    int wid = threadIdx.x >> 5, lane = threadIdx.x & 31;
    size_t row = (size_t)blockIdx.x*8 + wid;
    const float* hrow = g_hall + row*H_DIM;
    float* orow = out + row*ROW_OUT;
    float hv[8];
    #pragma unroll
    for (int i = 0; i < 8; i++) hv[i] = hrow[lane + 32*i];

    float lg = 0.f;
    #pragma unroll
    for (int a = 0; a < NA_DIM; a++){
        float s = 0.f;
        #pragma unroll
        for (int i = 0; i < 8; i++) s += hv[i]*w_actor[a*H_DIM + lane + 32*i];
        #pragma unroll
        for (int o = 16; o > 0; o >>= 1) s += __shfl_xor_sync(0xffffffffu, s, o);
        if (lane == a) lg = s + b_actor[a];
    }
    float m = (lane < NA_DIM) ? lg : -1e30f;
    #pragma unroll
    for (int o = 16; o > 0; o >>= 1) m = fmaxf(m, __shfl_xor_sync(0xffffffffu, m, o));
    float e = (lane < NA_DIM) ? expf(lg - m) : 0.f;
    float den = e;
    #pragma unroll
    for (int o = 16; o > 0; o >>= 1) den += __shfl_xor_sync(0xffffffffu, den, o);

    #pragma unroll
    for (int i = 0; i < 8; i++) orow[4 + lane + 32*i] = hv[i];
    if (lane < NA_DIM) orow[260 + lane] = e/den;

    float s = 0.f;
    #pragma unroll
    for (int i = 0; i < 8; i++) s += hv[i]*w_critic[lane + 32*i];
    #pragma unroll
    for (int o = 16; o > 0; o >>= 1) s += __shfl_xor_sync(0xffffffffu, s, o);

    int n = (int)(row & (N_DIM - 1));
    if (lane == 0)  orow[3]   = s + b_critic[0];
    if (lane == 16) orow[0]   = (float)actions[row];
    if (lane == 17) orow[1]   = p0[n];
    if (lane == 18) orow[2]   = (float)active[row];
    if (lane == 19) orow[276] = pp0[n*2];
    if (lane == 20) orow[277] = pp0[n*2 + 1];
}

// ---------------- launch ----------------
extern "C" void kernel_launch(void* const* d_in, const int* in_sizes, int n_in,
                              void* d_out, int out_size)
{
    (void)in_sizes; (void)n_in; (void)out_size;
    const float* condition = (const float*)d_in[0];
    const int*   active    = (const int*)d_in[1];
    const int*   lines     = (const int*)d_in[2];
    const int*   actions   = (const int*)d_in[3];
    const float* h0        = (const float*)d_in[4];
    const float* p0        = (const float*)d_in[5];
    const float* pp0       = (const float*)d_in[6];
    const float* embed     = (const float*)d_in[7];
    const float* wih_f = (const float*)d_in[8],  *whh_f = (const float*)d_in[9];
    const float* bih_f = (const float*)d_in[10], *bhh_f = (const float*)d_in[11];
    const float* wih_b = (const float*)d_in[12], *whh_b = (const float*)d_in[13];
    const float* bih_b = (const float*)d_in[14], *bhh_b = (const float*)d_in[15];
    const float* f_w0 = (const float*)d_in[16], *f_b0 = (const float*)d_in[17];
    const float* f_w1 = (const float*)d_in[18], *f_b1 = (const float*)d_in[19];
    const float* f_w2 = (const float*)d_in[20], *f_b2 = (const float*)d_in[21];
    const float* c_wih = (const float*)d_in[22], *c_whh = (const float*)d_in[23];
    const float* c_bih = (const float*)d_in[24], *c_bhh = (const float*)d_in[25];
    const float* w_critic = (const float*)d_in[26], *b_critic = (const float*)d_in[27];
    const float* w_actor  = (const float*)d_in[28], *b_actor  = (const float*)d_in[29];
    float* out = (float*)d_out;

    float *Rp;
    uint32_t *A0bp, *A1bp, *GIbp;
    cudaGetSymbolAddress((void**)&Rp,  g_Rproj);
    cudaGetSymbolAddress((void**)&A0bp, g_A0b);
    cudaGetSymbolAddress((void**)&A1bp, g_A1b);
    cudaGetSymbolAddress((void**)&GIbp, g_GIb);

    cudaFuncSetAttribute(enc_v8,
                         cudaFuncAttributeMaxDynamicSharedMemorySize, E7_SMEM_BYTES);
    cudaFuncSetAttribute(main_gru_v11,
                         cudaFuncAttributeMaxDynamicSharedMemorySize, M9_SMEM_BYTES);
    cudaFuncSetAttribute(gemm_ffb<1>,
                         cudaFuncAttributeMaxDynamicSharedMemorySize, FFB_SMEM_BYTES);
    cudaFuncSetAttribute(gemm_ffb<3>,
                         cudaFuncAttributeMaxDynamicSharedMemorySize, FFB_SMEM_BYTES);

    // 0) gi tables + state init
    gi_tables<<<(2*NL_DIM*G3 + 255)/256, 256>>>(embed, wih_f, bih_f, wih_b, bih_b);
    init_state<<<4096, 256>>>(h0);

    // 1) persistent bidirectional encoder (bf16 + ldmatrix)
    enc_v8<<<dim3(8, 16), 512, E7_SMEM_BYTES>>>(whh_f, bhh_f, whh_b, bhh_b, lines);

    // 2) Rproj = Hmem @ W0r^T (f32)
    gemm_plain<1, 0><<<dim3(4, 128), 256>>>(nullptr, f_w0 + 64, 576, nullptr, Rp, 512, 256, nullptr);
    // 3) A0 = relu(cond @ W0c^T + Rproj[active] + b0)  -> packed bf16
    gemm_plain<0, 4><<<dim3(4, 2048), 256>>>(condition, f_w0, 576, f_b0, A0bp, 64, 256, active);
    // 4) A1 = relu(A0 @ w1^T + b1); A0'' = relu(A1 @ w2^T + b2)  (bf16 + ldmatrix)
    gemm_ffb<1><<<dim3(2, 74), 512, FFB_SMEM_BYTES>>>(A0bp, f_w1, f_b1, A1bp, 128, 1024);
    gemm_ffb<1><<<dim3(2, 74), 512, FFB_SMEM_BYTES>>>(A1bp, f_w2, f_b2, A0bp, 128, 1024);
    // 5) GI = A0'' @ c_wih^T + c_bih  -> packed bf16
    gemm_ffb<3><<<dim3(6, 24), 512, FFB_SMEM_BYTES>>>(A0bp, c_wih, c_bih, GIbp, 384, 1024);

    // 6) persistent main GRU v11 (bf16 + ldmatrix, compact hall)
    main_gru_v11<<<dim3(8, 16), 256, M9_SMEM_BYTES>>>(c_whh, c_bhh);

    // 7) heads v2
    heads_kernel<<<TN/8, 256>>>(out, actions, active, p0, pp0,
                                w_actor, b_actor, w_critic, b_critic);
}

// round 14
// speedup vs baseline: 3.3948x; 1.0618x over previous
#include <cuda_runtime.h>
#include <math.h>
#include <stdint.h>

#define T_DIM 256
#define N_DIM 1024
#define H_DIM 256
#define L_DIM 16
#define NL_DIM 32
#define C_DIM 64
#define NA_DIM 16
#define ROW_OUT 278
#define G3 768
#define LN (L_DIM*N_DIM)          /* 16384 */
#define TN (T_DIM*N_DIM)          /* 262144 */

// ---------------- scratch ----------------
__device__ float g_giF[NL_DIM*G3];
__device__ float g_giB[NL_DIM*G3];
__device__ float g_Hf[2][(size_t)LN*H_DIM];
__device__ float g_Hb[2][(size_t)LN*H_DIM];
__device__ uint16_t g_Hfb[2][(size_t)LN*H_DIM];
__device__ uint16_t g_Hbb[2][(size_t)LN*H_DIM];
__device__ float g_Rproj[(size_t)LN*H_DIM];
__device__ uint32_t g_A0b[(size_t)TN*(H_DIM/2)];
__device__ uint32_t g_A1b[(size_t)TN*(H_DIM/2)];
__device__ uint32_t g_GIb[(size_t)TN*(G3/2)];
__device__ float g_hall[(size_t)TN*H_DIM];
__device__ float g_hm0[N_DIM*H_DIM];
__device__ uint16_t g_hmb[2][N_DIM*H_DIM];
__device__ unsigned g_slabc[16][32];
__device__ unsigned g_slabg[16][32];
__device__ unsigned g_pflag[64][2][32];     // pair flags (monotonic per launch)

// ---------------- helpers ----------------
__device__ __forceinline__ uint32_t f2tf(float x){
    uint32_t r; asm("cvt.rna.tf32.f32 %0, %1;" : "=r"(r) : "f"(x)); return r;
}
__device__ __forceinline__ uint32_t packbf(float lo, float hi){
    uint32_t r; asm("cvt.rn.bf16x2.f32 %0, %1, %2;" : "=r"(r) : "f"(hi), "f"(lo)); return r;
}
__device__ __forceinline__ float2 unpackbf(uint32_t u){
    float2 r;
    r.x = __uint_as_float(u << 16);
    r.y = __uint_as_float(u & 0xffff0000u);
    return r;
}
__device__ __forceinline__ void mma8(float* c, const uint32_t* a, const uint32_t* b){
    asm volatile("mma.sync.aligned.m16n8k8.row.col.f32.tf32.tf32.f32 "
        "{%0,%1,%2,%3},{%4,%5,%6,%7},{%8,%9},{%0,%1,%2,%3};"
        : "+f"(c[0]), "+f"(c[1]), "+f"(c[2]), "+f"(c[3])
        : "r"(a[0]), "r"(a[1]), "r"(a[2]), "r"(a[3]), "r"(b[0]), "r"(b[1]));
}
__device__ __forceinline__ void mma16b(float* c, const uint32_t* a, const uint32_t* b){
    asm volatile("mma.sync.aligned.m16n8k16.row.col.f32.bf16.bf16.f32 "
        "{%0,%1,%2,%3},{%4,%5,%6,%7},{%8,%9},{%0,%1,%2,%3};"
        : "+f"(c[0]), "+f"(c[1]), "+f"(c[2]), "+f"(c[3])
        : "r"(a[0]), "r"(a[1]), "r"(a[2]), "r"(a[3]), "r"(b[0]), "r"(b[1]));
}
__device__ __forceinline__ void ldsm4(uint32_t* r, uint32_t saddr){
    asm volatile("ldmatrix.sync.aligned.m8n8.x4.shared.b16 {%0,%1,%2,%3}, [%4];"
        : "=r"(r[0]), "=r"(r[1]), "=r"(r[2]), "=r"(r[3]) : "r"(saddr));
}
__device__ __forceinline__ void ldsm2(uint32_t* r, uint32_t saddr){
    asm volatile("ldmatrix.sync.aligned.m8n8.x2.shared.b16 {%0,%1}, [%2];"
        : "=r"(r[0]), "=r"(r[1]) : "r"(saddr));
}
__device__ __forceinline__ uint32_t sptr(const void* p){
    return (uint32_t)__cvta_generic_to_shared(p);
}
__device__ __forceinline__ float sigm(float x){ return 1.f/(1.f+expf(-x)); }
__device__ __forceinline__ void cp16(void* smem_dst, const void* gsrc){
    uint32_t s = (uint32_t)__cvta_generic_to_shared(smem_dst);
    asm volatile("cp.async.cg.shared.global [%0], [%1], 16;" :: "r"(s), "l"(gsrc));
}
__device__ __forceinline__ void cp_commit(){ asm volatile("cp.async.commit_group;"); }
template<int N> __device__ __forceinline__ void cp_wait(){
    asm volatile("cp.async.wait_group %0;" :: "n"(N));
}

__device__ __forceinline__ void slab_sync(int slab, unsigned nb){
    __syncthreads();
    if (threadIdx.x == 0){
        volatile unsigned* genp = &g_slabg[slab][0];
        unsigned old = *genp;
        __threadfence();
        if (atomicAdd(&g_slabc[slab][0], 1u) == nb - 1u){
            g_slabc[slab][0] = 0u;
            __threadfence();
            *genp = old + 1u;
        } else {
            while (*genp == old) { }
            __threadfence();
        }
    }
    __syncthreads();
}

// ---------------- gi tables ----------------
__global__ void gi_tables(const float* __restrict__ embed,
                          const float* __restrict__ wihF, const float* __restrict__ bihF,
                          const float* __restrict__ wihB, const float* __restrict__ bihB)
{
    int idx = blockIdx.x*blockDim.x + threadIdx.x;
    if (idx >= 2*NL_DIM*G3) return;
    int dir = idx / (NL_DIM*G3);
    int rem = idx % (NL_DIM*G3);
    int e = rem / G3, j = rem % G3;
    const float* wih = dir ? wihB : wihF;
    const float* bih = dir ? bihB : bihF;
    float s = bih[j];
    const float* em = embed + e*H_DIM;
    const float* w  = wih + (size_t)j*H_DIM;
    #pragma unroll 8
    for (int k = 0; k < H_DIM; k++) s += em[k]*w[k];
    (dir ? g_giB : g_giF)[rem] = s;
}

// ---------------- init ----------------
__global__ void init_state(const float* __restrict__ h0)
{
    size_t stride = (size_t)gridDim.x*blockDim.x;
    size_t i0 = (size_t)blockIdx.x*blockDim.x + threadIdx.x;
    size_t HS = (size_t)LN*H_DIM;
    for (size_t p = i0; p < HS; p += stride){
        g_Hf[0][p] = 0.f; g_Hb[0][p] = 0.f;
        g_Hfb[0][p] = 0;  g_Hbb[0][p] = 0;
    }
    for (size_t p = i0; p < (size_t)N_DIM*H_DIM; p += stride){
        float v = h0[p];
        g_hm0[p] = v;
        g_hmb[0][p] = (uint16_t)(packbf(v, 0.f) & 0xffffu);
    }
    for (size_t p = i0; p < 64*2*32; p += stride)
        ((unsigned*)g_pflag)[p] = 0u;
}

// ---------------- plain tf32 GEMM: EPI 0 = f32 (Rproj); EPI 4 = layer0 packed ------
template<int ALOAD, int EPI>
__global__ void __launch_bounds__(256)
gemm_plain(const float* __restrict__ A, const float* __restrict__ B, int ldb,
           const float* __restrict__ bias, void* __restrict__ outv,
           int K, int NC, const int* __restrict__ active)
{
    __shared__ float As[128][20];
    __shared__ float Bs[64][20];
    const int tid = threadIdx.x, lane = tid & 31, wid = tid >> 5;
    const int wm = wid >> 1, wn = wid & 1;
    const int brow = blockIdx.y, bcol = blockIdx.x;
    float acc[2][4][4];
    #pragma unroll
    for (int a = 0; a < 2; a++)
        #pragma unroll
        for (int b = 0; b < 4; b++)
            #pragma unroll
            for (int c = 0; c < 4; c++) acc[a][b][c] = 0.f;

    for (int k0 = 0; k0 < K; k0 += 16){
        #pragma unroll
        for (int i = tid; i < 2048; i += 256){
            int r = i >> 4, c = i & 15;
            int row = brow*128 + r; int k = k0 + c;
            float v;
            if (ALOAD == 0) v = A[(size_t)row*K + k];
            else v = (k < H_DIM) ? g_Hf[0][(size_t)row*H_DIM + k]
                                 : g_Hb[0][(size_t)row*H_DIM + (k - H_DIM)];
            As[r][c] = __uint_as_float(f2tf(v));
        }
        #pragma unroll
        for (int i = tid; i < 1024; i += 256){
            int n = i >> 4, c = i & 15;
            Bs[n][c] = __uint_as_float(f2tf(B[(size_t)(bcol*64 + n)*ldb + k0 + c]));
        }
        __syncthreads();
        #pragma unroll
        for (int kk = 0; kk < 16; kk += 8){
            uint32_t af[2][4], bf[4][2];
            #pragma unroll
            for (int mt = 0; mt < 2; mt++){
                int r0 = wm*32 + mt*16 + (lane >> 2);
                int c0 = kk + (lane & 3);
                af[mt][0] = __float_as_uint(As[r0][c0]);
                af[mt][1] = __float_as_uint(As[r0+8][c0]);
                af[mt][2] = __float_as_uint(As[r0][c0+4]);
                af[mt][3] = __float_as_uint(As[r0+8][c0+4]);
            }
            #pragma unroll
            for (int nt = 0; nt < 4; nt++){
                int n0 = wn*32 + nt*8 + (lane >> 2);
                bf[nt][0] = __float_as_uint(Bs[n0][kk + (lane & 3)]);
                bf[nt][1] = __float_as_uint(Bs[n0][kk + 4 + (lane & 3)]);
            }
            #pragma unroll
            for (int mt = 0; mt < 2; mt++)
                #pragma unroll
                for (int nt = 0; nt < 4; nt++)
                    mma8(acc[mt][nt], af[mt], bf[nt]);
        }
        __syncthreads();
    }
    #pragma unroll
    for (int mt = 0; mt < 2; mt++){
        #pragma unroll
        for (int nt = 0; nt < 4; nt++){
            int rbase = brow*128 + wm*32 + mt*16 + (lane >> 2);
            int cbase = bcol*64 + wn*32 + nt*8 + (lane & 3)*2;
            #pragma unroll
            for (int dr = 0; dr < 2; dr++){
                int rr = rbase + dr*8, cc = cbase;
                float v0 = acc[mt][nt][dr*2 + 0];
                float v1 = acc[mt][nt][dr*2 + 1];
                if (EPI == 4){
                    int n = rr & (N_DIM - 1);
                    int w = active[rr];
                    const float* rp = &g_Rproj[(size_t)(w*N_DIM + n)*H_DIM + cc];
                    v0 = fmaxf(v0 + bias[cc]   + rp[0], 0.f);
                    v1 = fmaxf(v1 + bias[cc+1] + rp[1], 0.f);
                    ((uint32_t*)outv)[(size_t)rr*(H_DIM/2) + (cc >> 1)] = packbf(v0, v1);
                } else {
                    float* out = (float*)outv;
                    out[(size_t)rr*NC + cc]     = v0;
                    out[(size_t)rr*NC + cc + 1] = v1;
                }
            }
        }
    }
}

// ---------------- persistent encoder v8: bf16 K-chunk 64 + ldmatrix ----------------
#define E7_W_U32 (3*32*132)
#define E7_A_U32 (2*256*36)
#define E7_G_FLOATS (NL_DIM*100)
#define E7_SMEM_BYTES ((E7_W_U32 + E7_A_U32 + E7_G_FLOATS)*4)

__global__ void __launch_bounds__(512, 1)
enc_v8(const float* __restrict__ whF, const float* __restrict__ bhF,
       const float* __restrict__ whB, const float* __restrict__ bhB,
       const int* __restrict__ lines)
{
    extern __shared__ uint32_t smu[];
    uint32_t* Ws2 = smu;
    uint32_t* As2 = smu + E7_W_U32;
    float* GIe = (float*)(smu + E7_W_U32 + E7_A_U32);
    const int tid = threadIdx.x, lane = tid & 31, wid = tid >> 5;
    const int wm = wid >> 1, wn = wid & 1;
    const int bcol = blockIdx.x;
    const int slab = blockIdx.y;
    const bool dirF = (slab < 8);
    const float* __restrict__ W  = dirF ? whF : whB;
    const float* __restrict__ bh = dirF ? bhF : bhB;
    const float* __restrict__ giT = dirF ? g_giF : g_giB;
    const int lrow0 = (dirF ? slab : slab - 8) * 2048;

    for (int i = tid; i < 3*32*128; i += 512){
        int g = i >> 12, rem = i & 4095;
        int c = rem >> 7, kp = rem & 127;
        const float* wr = W + (size_t)(g*H_DIM + bcol*32 + c)*H_DIM + 2*kp;
        Ws2[(g*32 + c)*132 + kp] = packbf(wr[0], wr[1]);
    }
    for (int i = tid; i < NL_DIM*96; i += 512){
        int e = i / 96, j = i % 96;
        int g = j >> 5, c = j & 31;
        GIe[e*100 + j] = __ldg(&giT[e*G3 + g*H_DIM + bcol*32 + c]);
    }
    float bR[2][2], bZ[2][2], bN[2][2];
    #pragma unroll
    for (int nt = 0; nt < 2; nt++)
        #pragma unroll
        for (int dc = 0; dc < 2; dc++){
            int c = bcol*32 + wn*16 + nt*8 + (lane & 3)*2 + dc;
            bR[nt][dc] = bh[c];
            bZ[nt][dc] = bh[H_DIM + c];
            bN[nt][dc] = bh[2*H_DIM + c];
        }
    const int tA = lane >> 3;
    uint32_t aA[2];
    #pragma unroll
    for (int mt = 0; mt < 2; mt++)
        aA[mt] = sptr(As2) + (uint32_t)(((wm*32 + mt*16 + (tA & 1)*8 + (lane & 7))*36
                                        + (tA >> 1)*4) * 4);
    uint32_t aB[3][2];
    #pragma unroll
    for (int g = 0; g < 3; g++)
        #pragma unroll
        for (int nt = 0; nt < 2; nt++)
            aB[g][nt] = sptr(Ws2) + (uint32_t)(((g*32 + wn*16 + nt*8 + (lane & 7))*132
                                        + ((lane >> 3) & 1)*4) * 4);
    __syncthreads();

    for (int t = 0; t < L_DIM; t++){
        const float* __restrict__ hsrc = dirF ? g_Hf[t & 1] : g_Hb[t & 1];
        float* __restrict__ hdst = dirF ? g_Hf[(t + 1) & 1] : g_Hb[(t + 1) & 1];
        const uint16_t* __restrict__ hsrc16 = dirF ? g_Hfb[t & 1] : g_Hbb[t & 1];
        uint16_t* __restrict__ hdst16 = dirF ? g_Hfb[(t + 1) & 1] : g_Hbb[(t + 1) & 1];

        auto stage = [&](int p){
            int chunk = p >> 2, kb = p & 3, buf = p & 1;
            const uint16_t* src = hsrc16 + (size_t)(lrow0 + chunk*256)*H_DIM + kb*64;
            uint32_t* dst = As2 + buf*256*36;
            #pragma unroll
            for (int i = tid; i < 2048; i += 512){
                int r = i >> 3, q = i & 7;
                cp16(&dst[r*36 + q*4], src + (size_t)r*H_DIM + q*8);
            }
            cp_commit();
        };

        float acc[3][2][2][4];
        stage(0);
        for (int p = 0; p < 32; p++){
            cp_wait<0>();
            __syncthreads();
            if (p + 1 < 32) stage(p + 1);
            const int kb = p & 3;
            if (kb == 0){
                #pragma unroll
                for (int g = 0; g < 3; g++)
                    #pragma unroll
                    for (int a = 0; a < 2; a++)
                        #pragma unroll
                        for (int b = 0; b < 2; b++)
                            #pragma unroll
                            for (int c = 0; c < 4; c++) acc[g][a][b][c] = 0.f;
            }
            const uint32_t abufofs = (uint32_t)((p & 1)*256*36*4);
            const uint32_t bofs = (uint32_t)(kb*128);
            #pragma unroll
            for (int kk = 0; kk < 64; kk += 16){
                uint32_t af[2][4];
                #pragma unroll
                for (int mt = 0; mt < 2; mt++)
                    ldsm4(af[mt], aA[mt] + abufofs + kk*2);
                #pragma unroll
                for (int g = 0; g < 3; g++)
                    #pragma unroll
                    for (int nt = 0; nt < 2; nt++){
                        uint32_t bf[2];
                        ldsm2(bf, aB[g][nt] + bofs + kk*2);
                        #pragma unroll
                        for (int mt = 0; mt < 2; mt++)
                            mma16b(acc[g][mt][nt], af[mt], bf);
                    }
            }

            if (kb == 3){
                const int base = lrow0 + (p >> 2)*256;
                #pragma unroll
                for (int mt = 0; mt < 2; mt++){
                    #pragma unroll
                    for (int dr = 0; dr < 2; dr++){
                        int lr = base + wm*32 + mt*16 + (lane >> 2) + dr*8;
                        int iroll = lr >> 10;
                        int nb = lr & (N_DIM - 1);
                        int l = dirF ? ((iroll + t) & 15) : ((iroll + 15 - t) & 15);
                        const float* ge = GIe + __ldg(&lines[nb*L_DIM + l])*100;
                        #pragma unroll
                        for (int nt = 0; nt < 2; nt++){
                            int hcl = wn*16 + nt*8 + (lane & 3)*2;
                            float2 gv0 = *(const float2*)&ge[hcl];
                            float2 gv1 = *(const float2*)&ge[32 + hcl];
                            float2 gv2 = *(const float2*)&ge[64 + hcl];
                            float2 hold = __ldcg((const float2*)&hsrc[(size_t)lr*H_DIM + bcol*32 + hcl]);
                            float2 hout;
                            #pragma unroll
                            for (int dc = 0; dc < 2; dc++){
                                float gr = acc[0][mt][nt][dr*2+dc] + bR[nt][dc];
                                float gz = acc[1][mt][nt][dr*2+dc] + bZ[nt][dc];
                                float gn = acc[2][mt][nt][dr*2+dc] + bN[nt][dc];
                                float r  = sigm((dc ? gv0.y : gv0.x) + gr);
                                float z  = sigm((dc ? gv1.y : gv1.x) + gz);
                                float nn = tanhf((dc ? gv2.y : gv2.x) + r*gn);
                                float ho = dc ? hold.y : hold.x;
                                float hnew = (1.f - z)*nn + z*ho;
                                if (dc) hout.y = hnew; else hout.x = hnew;
                            }
                            __stcg((float2*)&hdst[(size_t)lr*H_DIM + bcol*32 + hcl], hout);
                            __stcg((uint32_t*)(hdst16 + (size_t)lr*H_DIM + bcol*32 + hcl),
                                   packbf(hout.x, hout.y));
                        }
                    }
                }
            }
        }
        slab_sync(slab, 8);
    }
}

// ---------------- bf16 feed-forward GEMM + ldmatrix -------------------
#define FFB_W_U32 (128*132)
#define FFB_A_U32 (2*256*36)
#define FFB_SMEM_BYTES ((FFB_W_U32 + FFB_A_U32)*4)

template<int EPI>
__global__ void __launch_bounds__(512, 1)
gemm_ffb(const uint32_t* __restrict__ A, const float* __restrict__ W,
         const float* __restrict__ bias, uint32_t* __restrict__ outp,
         int out_stride, int nrt)
{
    extern __shared__ uint32_t smu[];
    uint32_t* Ws2 = smu;
    uint32_t* As2 = smu + FFB_W_U32;
    const int tid = threadIdx.x, lane = tid & 31, wid = tid >> 5;
    const int wm = wid >> 1, wn = wid & 1;
    const int bcol = blockIdx.x;

    for (int i = tid; i < 128*128; i += 512){
        int c = i >> 7, kp = i & 127;
        const float* wr = W + (size_t)(bcol*128 + c)*H_DIM + 2*kp;
        Ws2[c*132 + kp] = packbf(wr[0], wr[1]);
    }
    const int tA = lane >> 3;
    uint32_t aA[2];
    #pragma unroll
    for (int mt = 0; mt < 2; mt++)
        aA[mt] = sptr(As2) + (uint32_t)(((wm*32 + mt*16 + (tA & 1)*8 + (lane & 7))*36
                                        + (tA >> 1)*4) * 4);
    uint32_t aB[8];
    #pragma unroll
    for (int nt = 0; nt < 8; nt++)
        aB[nt] = sptr(Ws2) + (uint32_t)(((wn*64 + nt*8 + (lane & 7))*132
                                        + ((lane >> 3) & 1)*4) * 4);
    __syncthreads();

    const int nch = (nrt - (int)blockIdx.y + (int)gridDim.y - 1) / (int)gridDim.y;
    if (nch <= 0) return;
    const int total = nch*4;

    auto stage = [&](int p){
        int ci = p >> 2, kb = p & 3, buf = p & 1;
        int rt = blockIdx.y + ci*gridDim.y;
        const uint32_t* src = A + (size_t)rt*256*128 + kb*32;
        uint32_t* dst = As2 + buf*256*36;
        #pragma unroll
        for (int i = tid; i < 2048; i += 512){
            int r = i >> 3, q = i & 7;
            cp16(&dst[r*36 + q*4], src + (size_t)r*128 + q*4);
        }
        cp_commit();
    };

    float acc[2][8][4];
    stage(0);
    for (int p = 0; p < total; p++){
        cp_wait<0>();
        __syncthreads();
        if (p + 1 < total) stage(p + 1);
        const int kb = p & 3;
        if (kb == 0){
            #pragma unroll
            for (int a = 0; a < 2; a++)
                #pragma unroll
                for (int b = 0; b < 8; b++)
                    #pragma unroll
                    for (int c = 0; c < 4; c++) acc[a][b][c] = 0.f;
        }
        const uint32_t abufofs = (uint32_t)((p & 1)*256*36*4);
        const uint32_t bofs = (uint32_t)(kb*128);
        #pragma unroll
        for (int kk = 0; kk < 64; kk += 16){
            uint32_t af[2][4];
            #pragma unroll
            for (int mt = 0; mt < 2; mt++)
                ldsm4(af[mt], aA[mt] + abufofs + kk*2);
            #pragma unroll
            for (int nt = 0; nt < 8; nt++){
                uint32_t bf[2];
                ldsm2(bf, aB[nt] + bofs + kk*2);
                #pragma unroll
                for (int mt = 0; mt < 2; mt++)
                    mma16b(acc[mt][nt], af[mt], bf);
            }
        }

        if (kb == 3){
            int rt = blockIdx.y + (p >> 2)*gridDim.y;
            #pragma unroll
            for (int mt = 0; mt < 2; mt++){
                #pragma unroll
                for (int nt = 0; nt < 8; nt++){
                    #pragma unroll
                    for (int dr = 0; dr < 2; dr++){
                        int rr = rt*256 + wm*32 + mt*16 + (lane >> 2) + dr*8;
                        int cc = bcol*128 + wn*64 + nt*8 + (lane & 3)*2;
                        float v0 = acc[mt][nt][dr*2 + 0] + bias[cc];
                        float v1 = acc[mt][nt][dr*2 + 1] + bias[cc + 1];
                        if (EPI == 1){ v0 = fmaxf(v0, 0.f); v1 = fmaxf(v1, 0.f); }
                        outp[(size_t)rr*out_stride + (cc >> 1)] = packbf(v0, v1);
                    }
                }
            }
        }
    }
}

// ---------------- main GRU v12: 16 rows x 128 cols, pair-flag barrier --------------
#define M12_W_U32 (384*132)                /* 50688 */
#define M12_A_U32 (16*132)                 /* 2112  */
#define M12_G_U32 (16*200)                 /* 3200  */
#define M12_SMEM_BYTES ((M12_W_U32 + M12_A_U32 + M12_G_U32)*4)   /* 224000 */

__global__ void __launch_bounds__(256, 1)
main_gru_v12(const float* __restrict__ whh, const float* __restrict__ bhh)
{
    extern __shared__ uint32_t smu[];
    uint32_t* Ws2 = smu;
    uint32_t* As2 = smu + M12_W_U32;
    uint32_t* GIs = smu + M12_W_U32 + M12_A_U32;
    const int tid = threadIdx.x, lane = tid & 31, w = tid >> 5;   // w 0..7
    const int me = blockIdx.x;            // 0..1 (col half)
    const int rg = blockIdx.y;            // 0..63 (row group)
    const int row0 = rg*16;

    // weights: 3 gates x 128 cols x 256 K (bf16 pairs), rows = g*128 + cl
    for (int i = tid; i < 384*128; i += 256){
        int row = i >> 7, kp = i & 127;
        int g = row >> 7, cl = row & 127;
        const float* wr = whh + (size_t)(g*H_DIM + me*128 + cl)*H_DIM + 2*kp;
        Ws2[row*132 + kp] = packbf(wr[0], wr[1]);
    }
    // bias regs: warp covers cols me*128 + w*16 + ct*8 + (lane&3)*2 + dc
    float bR[2][2], bZ[2][2], bN[2][2];
    #pragma unroll
    for (int ct = 0; ct < 2; ct++)
        #pragma unroll
        for (int dc = 0; dc < 2; dc++){
            int c = me*128 + w*16 + ct*8 + (lane & 3)*2 + dc;
            bR[ct][dc] = bhh[c];
            bZ[ct][dc] = bhh[H_DIM + c];
            bN[ct][dc] = bhh[2*H_DIM + c];
        }
    const int tA = lane >> 3;
    const uint32_t aA = sptr(As2) + (uint32_t)((((tA & 1)*8 + (lane & 7))*132
                                        + (tA >> 1)*4) * 4);
    uint32_t aB[6];
    #pragma unroll
    for (int nt = 0; nt < 6; nt++){
        int g = nt >> 1, ct = nt & 1;
        aB[nt] = sptr(Ws2) + (uint32_t)(((g*128 + w*16 + ct*8 + (lane & 7))*132
                                        + ((lane >> 3) & 1)*4) * 4);
    }

    auto stage_gi = [&](int tt){
        const uint32_t* gsrc = g_GIb + ((size_t)tt*N_DIM + row0)*(G3/2) + me*64;
        #pragma unroll
        for (int i = tid; i < 768; i += 256){
            int r = i / 48, j = i % 48;
            int g = j >> 4, q = j & 15;
            cp16(&GIs[r*200 + g*64 + q*4], gsrc + (size_t)r*(G3/2) + g*128 + q*4);
        }
        cp_commit();
    };

    stage_gi(0);
    __syncthreads();

    for (int t = 0; t < T_DIM; t++){
        const uint16_t* __restrict__ hsrc16 = g_hmb[t & 1];
        uint16_t* __restrict__ hdst16 = g_hmb[(t + 1) & 1];
        const float* __restrict__ hsrcf = (t == 0) ? g_hm0
                                        : g_hall + (size_t)(t - 1)*N_DIM*H_DIM;
        float* __restrict__ hdstf = g_hall + (size_t)t*N_DIM*H_DIM;

        // stage A: 16 rows x 256 K (bf16) = 16x128 u32
        {
            const uint16_t* src = hsrc16 + (size_t)row0*H_DIM;
            #pragma unroll
            for (int i = tid; i < 512; i += 256){
                int r = i >> 5, q = i & 31;
                cp16(&As2[r*132 + q*4], src + (size_t)r*H_DIM + q*8);
            }
            cp_commit();
        }
        cp_wait<0>();
        __syncthreads();

        float acc[6][4];
        #pragma unroll
        for (int n = 0; n < 6; n++)
            #pragma unroll
            for (int c = 0; c < 4; c++) acc[n][c] = 0.f;

        #pragma unroll 4
        for (int kk = 0; kk < H_DIM; kk += 16){
            uint32_t af[4];
            ldsm4(af, aA + kk*2);
            #pragma unroll
            for (int nt = 0; nt < 6; nt++){
                uint32_t bf[2];
                ldsm2(bf, aB[nt] + kk*2);
                mma16b(acc[nt], af, bf);
            }
        }

        // epilogue
        #pragma unroll
        for (int dr = 0; dr < 2; dr++){
            int r = (lane >> 2) + dr*8;
            int row = row0 + r;
            #pragma unroll
            for (int ct = 0; ct < 2; ct++){
                int cl = w*16 + ct*8 + (lane & 3)*2;        // local col in half
                int gcol = me*128 + cl;
                float2 gv0 = unpackbf(GIs[r*200 +       (cl >> 1)]);
                float2 gv1 = unpackbf(GIs[r*200 +  64 + (cl >> 1)]);
                float2 gv2 = unpackbf(GIs[r*200 + 128 + (cl >> 1)]);
                float2 hold = __ldcg((const float2*)&hsrcf[(size_t)row*H_DIM + gcol]);
                float2 hout;
                #pragma unroll
                for (int dc = 0; dc < 2; dc++){
                    float gr = acc[0*2 + ct][dr*2+dc] + bR[ct][dc];
                    float gz = acc[1*2 + ct][dr*2+dc] + bZ[ct][dc];
                    float gn = acc[2*2 + ct][dr*2+dc] + bN[ct][dc];
                    float rr = sigm((dc ? gv0.y : gv0.x) + gr);
                    float zz = sigm((dc ? gv1.y : gv1.x) + gz);
                    float nn = tanhf((dc ? gv2.y : gv2.x) + rr*gn);
                    float ho = dc ? hold.y : hold.x;
                    float hnew = (1.f - zz)*nn + zz*ho;
                    if (dc) hout.y = hnew; else hout.x = hnew;
                }
                __stcg((float2*)&hdstf[(size_t)row*H_DIM + gcol], hout);
                __stcg((uint32_t*)(hdst16 + (size_t)row*H_DIM + gcol),
                       packbf(hout.x, hout.y));
            }
        }

        __syncthreads();                   // protect GIs before overwrite
        if (t + 1 < T_DIM) stage_gi(t + 1);

        // pair barrier: own flag store + partner poll (monotonic gen = t+1)
        if (tid == 0){
            __threadfence();
            *(volatile unsigned*)&g_pflag[rg][me][0] = (unsigned)(t + 1);
        }
        if (tid == 32){
            while (*(volatile unsigned*)&g_pflag[rg][me ^ 1][0] < (unsigned)(t + 1)) { }
            __threadfence();
        }
        __syncthreads();
    }
}

// ---------------- heads v2 ----------------
__global__ void __launch_bounds__(256)
heads_kernel(float* __restrict__ out, const int* __restrict__ actions,
             const int* __restrict__ active, const float* __restrict__ p0,
             const float* __restrict__ pp0,
             const float* __restrict__ w_actor, const float* __restrict__ b_actor,
             const float* __restrict__ w_critic, const float* __restrict__ b_critic)
{
    int wid = threadIdx.x >> 5, lane = threadIdx.x & 31;
    size_t row = (size_t)blockIdx.x*8 + wid;
    const float* hrow = g_hall + row*H_DIM;
    float* orow = out + row*ROW_OUT;
    float hv[8];
    #pragma unroll
    for (int i = 0; i < 8; i++) hv[i] = hrow[lane + 32*i];

    float lg = 0.f;
    #pragma unroll
    for (int a = 0; a < NA_DIM; a++){
        float s = 0.f;
        #pragma unroll
        for (int i = 0; i < 8; i++) s += hv[i]*w_actor[a*H_DIM + lane + 32*i];
        #pragma unroll
        for (int o = 16; o > 0; o >>= 1) s += __shfl_xor_sync(0xffffffffu, s, o);
        if (lane == a) lg = s + b_actor[a];
    }
    float m = (lane < NA_DIM) ? lg : -1e30f;
    #pragma unroll
    for (int o = 16; o > 0; o >>= 1) m = fmaxf(m, __shfl_xor_sync(0xffffffffu, m, o));
    float e = (lane < NA_DIM) ? expf(lg - m) : 0.f;
    float den = e;
    #pragma unroll
    for (int o = 16; o > 0; o >>= 1) den += __shfl_xor_sync(0xffffffffu, den, o);

    #pragma unroll
    for (int i = 0; i < 8; i++) orow[4 + lane + 32*i] = hv[i];
    if (lane < NA_DIM) orow[260 + lane] = e/den;

    float s = 0.f;
    #pragma unroll
    for (int i = 0; i < 8; i++) s += hv[i]*w_critic[lane + 32*i];
    #pragma unroll
    for (int o = 16; o > 0; o >>= 1) s += __shfl_xor_sync(0xffffffffu, s, o);

    int n = (int)(row & (N_DIM - 1));
    if (lane == 0)  orow[3]   = s + b_critic[0];
    if (lane == 16) orow[0]   = (float)actions[row];
    if (lane == 17) orow[1]   = p0[n];
    if (lane == 18) orow[2]   = (float)active[row];
    if (lane == 19) orow[276] = pp0[n*2];
    if (lane == 20) orow[277] = pp0[n*2 + 1];
}

// ---------------- launch ----------------
extern "C" void kernel_launch(void* const* d_in, const int* in_sizes, int n_in,
                              void* d_out, int out_size)
{
    (void)in_sizes; (void)n_in; (void)out_size;
    const float* condition = (const float*)d_in[0];
    const int*   active    = (const int*)d_in[1];
    const int*   lines     = (const int*)d_in[2];
    const int*   actions   = (const int*)d_in[3];
    const float* h0        = (const float*)d_in[4];
    const float* p0        = (const float*)d_in[5];
    const float* pp0       = (const float*)d_in[6];
    const float* embed     = (const float*)d_in[7];
    const float* wih_f = (const float*)d_in[8],  *whh_f = (const float*)d_in[9];
    const float* bih_f = (const float*)d_in[10], *bhh_f = (const float*)d_in[11];
    const float* wih_b = (const float*)d_in[12], *whh_b = (const float*)d_in[13];
    const float* bih_b = (const float*)d_in[14], *bhh_b = (const float*)d_in[15];
    const float* f_w0 = (const float*)d_in[16], *f_b0 = (const float*)d_in[17];
    const float* f_w1 = (const float*)d_in[18], *f_b1 = (const float*)d_in[19];
    const float* f_w2 = (const float*)d_in[20], *f_b2 = (const float*)d_in[21];
    const float* c_wih = (const float*)d_in[22], *c_whh = (const float*)d_in[23];
    const float* c_bih = (const float*)d_in[24], *c_bhh = (const float*)d_in[25];
    const float* w_critic = (const float*)d_in[26], *b_critic = (const float*)d_in[27];
    const float* w_actor  = (const float*)d_in[28], *b_actor  = (const float*)d_in[29];
    float* out = (float*)d_out;

    float *Rp;
    uint32_t *A0bp, *A1bp, *GIbp;
    cudaGetSymbolAddress((void**)&Rp,  g_Rproj);
    cudaGetSymbolAddress((void**)&A0bp, g_A0b);
    cudaGetSymbolAddress((void**)&A1bp, g_A1b);
    cudaGetSymbolAddress((void**)&GIbp, g_GIb);

    cudaFuncSetAttribute(enc_v8,
                         cudaFuncAttributeMaxDynamicSharedMemorySize, E7_SMEM_BYTES);
    cudaFuncSetAttribute(main_gru_v12,
                         cudaFuncAttributeMaxDynamicSharedMemorySize, M12_SMEM_BYTES);
    cudaFuncSetAttribute(gemm_ffb<1>,
                         cudaFuncAttributeMaxDynamicSharedMemorySize, FFB_SMEM_BYTES);
    cudaFuncSetAttribute(gemm_ffb<3>,
                         cudaFuncAttributeMaxDynamicSharedMemorySize, FFB_SMEM_BYTES);

    // 0) gi tables + state init (also resets pair flags)
    gi_tables<<<(2*NL_DIM*G3 + 255)/256, 256>>>(embed, wih_f, bih_f, wih_b, bih_b);
    init_state<<<4096, 256>>>(h0);

    // 1) persistent bidirectional encoder (bf16 + ldmatrix)
    enc_v8<<<dim3(8, 16), 512, E7_SMEM_BYTES>>>(whh_f, bhh_f, whh_b, bhh_b, lines);

    // 2) Rproj = Hmem @ W0r^T (f32)
    gemm_plain<1, 0><<<dim3(4, 128), 256>>>(nullptr, f_w0 + 64, 576, nullptr, Rp, 512, 256, nullptr);
    // 3) A0 = relu(cond @ W0c^T + Rproj[active] + b0)  -> packed bf16
    gemm_plain<0, 4><<<dim3(4, 2048), 256>>>(condition, f_w0, 576, f_b0, A0bp, 64, 256, active);
    // 4) A1 = relu(A0 @ w1^T + b1); A0'' = relu(A1 @ w2^T + b2)  (bf16 + ldmatrix)
    gemm_ffb<1><<<dim3(2, 74), 512, FFB_SMEM_BYTES>>>(A0bp, f_w1, f_b1, A1bp, 128, 1024);
    gemm_ffb<1><<<dim3(2, 74), 512, FFB_SMEM_BYTES>>>(A1bp, f_w2, f_b2, A0bp, 128, 1024);
    // 5) GI = A0'' @ c_wih^T + c_bih  -> packed bf16
    gemm_ffb<3><<<dim3(6, 24), 512, FFB_SMEM_BYTES>>>(A0bp, c_wih, c_bih, GIbp, 384, 1024);

    // 6) main GRU v12: 64 independent row-groups x 2-CTA pairs, flag barrier
    main_gru_v12<<<dim3(2, 64), 256, M12_SMEM_BYTES>>>(c_whh, c_bhh);

    // 7) heads v2
    heads_kernel<<<TN/8, 256>>>(out, actions, active, p0, pp0,
                                w_actor, b_actor, w_critic, b_critic);
}

// round 15
// speedup vs baseline: 3.4994x; 1.0308x over previous
#include <cuda_runtime.h>
#include <math.h>
#include <stdint.h>

#define T_DIM 256
#define N_DIM 1024
#define H_DIM 256
#define L_DIM 16
#define NL_DIM 32
#define C_DIM 64
#define NA_DIM 16
#define ROW_OUT 278
#define G3 768
#define LN (L_DIM*N_DIM)          /* 16384 */
#define TN (T_DIM*N_DIM)          /* 262144 */

// ---------------- scratch ----------------
__device__ float g_giF[NL_DIM*G3];
__device__ float g_giB[NL_DIM*G3];
__device__ float g_Hf[2][(size_t)LN*H_DIM];
__device__ float g_Hb[2][(size_t)LN*H_DIM];
__device__ uint16_t g_Hfb[2][(size_t)LN*H_DIM];
__device__ uint16_t g_Hbb[2][(size_t)LN*H_DIM];
__device__ float g_Rproj[(size_t)LN*H_DIM];
__device__ uint32_t g_A0b[(size_t)TN*(H_DIM/2)];
__device__ uint32_t g_A1b[(size_t)TN*(H_DIM/2)];
__device__ uint32_t g_GIb[(size_t)TN*(G3/2)];
__device__ float g_hall[(size_t)TN*H_DIM];
__device__ float g_hm0[N_DIM*H_DIM];
__device__ uint16_t g_hmb[2][N_DIM*H_DIM];
__device__ unsigned g_slabc[16][32];
__device__ unsigned g_slabg[16][32];
__device__ unsigned g_pflag[64][2][32];

// ---------------- helpers ----------------
__device__ __forceinline__ uint32_t packbf(float lo, float hi){
    uint32_t r; asm("cvt.rn.bf16x2.f32 %0, %1, %2;" : "=r"(r) : "f"(hi), "f"(lo)); return r;
}
__device__ __forceinline__ float2 unpackbf(uint32_t u){
    float2 r;
    r.x = __uint_as_float(u << 16);
    r.y = __uint_as_float(u & 0xffff0000u);
    return r;
}
__device__ __forceinline__ void mma16b(float* c, const uint32_t* a, const uint32_t* b){
    asm volatile("mma.sync.aligned.m16n8k16.row.col.f32.bf16.bf16.f32 "
        "{%0,%1,%2,%3},{%4,%5,%6,%7},{%8,%9},{%0,%1,%2,%3};"
        : "+f"(c[0]), "+f"(c[1]), "+f"(c[2]), "+f"(c[3])
        : "r"(a[0]), "r"(a[1]), "r"(a[2]), "r"(a[3]), "r"(b[0]), "r"(b[1]));
}
__device__ __forceinline__ void ldsm4(uint32_t* r, uint32_t saddr){
    asm volatile("ldmatrix.sync.aligned.m8n8.x4.shared.b16 {%0,%1,%2,%3}, [%4];"
        : "=r"(r[0]), "=r"(r[1]), "=r"(r[2]), "=r"(r[3]) : "r"(saddr));
}
__device__ __forceinline__ void ldsm2(uint32_t* r, uint32_t saddr){
    asm volatile("ldmatrix.sync.aligned.m8n8.x2.shared.b16 {%0,%1}, [%2];"
        : "=r"(r[0]), "=r"(r[1]) : "r"(saddr));
}
__device__ __forceinline__ uint32_t sptr(const void* p){
    return (uint32_t)__cvta_generic_to_shared(p);
}
__device__ __forceinline__ float sigm(float x){ return 1.f/(1.f+expf(-x)); }
__device__ __forceinline__ void cp16(void* smem_dst, const void* gsrc){
    uint32_t s = (uint32_t)__cvta_generic_to_shared(smem_dst);
    asm volatile("cp.async.cg.shared.global [%0], [%1], 16;" :: "r"(s), "l"(gsrc));
}
__device__ __forceinline__ void cp_commit(){ asm volatile("cp.async.commit_group;"); }
template<int N> __device__ __forceinline__ void cp_wait(){
    asm volatile("cp.async.wait_group %0;" :: "n"(N));
}

__device__ __forceinline__ void slab_sync(int slab, unsigned nb){
    __syncthreads();
    if (threadIdx.x == 0){
        volatile unsigned* genp = &g_slabg[slab][0];
        unsigned old = *genp;
        __threadfence();
        if (atomicAdd(&g_slabc[slab][0], 1u) == nb - 1u){
            g_slabc[slab][0] = 0u;
            __threadfence();
            *genp = old + 1u;
        } else {
            while (*genp == old) { }
            __threadfence();
        }
    }
    __syncthreads();
}

// ---------------- gi tables ----------------
__global__ void gi_tables(const float* __restrict__ embed,
                          const float* __restrict__ wihF, const float* __restrict__ bihF,
                          const float* __restrict__ wihB, const float* __restrict__ bihB)
{
    int idx = blockIdx.x*blockDim.x + threadIdx.x;
    if (idx >= 2*NL_DIM*G3) return;
    int dir = idx / (NL_DIM*G3);
    int rem = idx % (NL_DIM*G3);
    int e = rem / G3, j = rem % G3;
    const float* wih = dir ? wihB : wihF;
    const float* bih = dir ? bihB : bihF;
    float s = bih[j];
    const float* em = embed + e*H_DIM;
    const float* w  = wih + (size_t)j*H_DIM;
    #pragma unroll 8
    for (int k = 0; k < H_DIM; k++) s += em[k]*w[k];
    (dir ? g_giB : g_giF)[rem] = s;
}

// ---------------- init ----------------
__global__ void init_state(const float* __restrict__ h0)
{
    size_t stride = (size_t)gridDim.x*blockDim.x;
    size_t i0 = (size_t)blockIdx.x*blockDim.x + threadIdx.x;
    size_t HS = (size_t)LN*H_DIM;
    for (size_t p = i0; p < HS; p += stride){
        g_Hf[0][p] = 0.f; g_Hb[0][p] = 0.f;
        g_Hfb[0][p] = 0;  g_Hbb[0][p] = 0;
    }
    for (size_t p = i0; p < (size_t)N_DIM*H_DIM; p += stride){
        float v = h0[p];
        g_hm0[p] = v;
        g_hmb[0][p] = (uint16_t)(packbf(v, 0.f) & 0xffffu);
    }
    for (size_t p = i0; p < 64*2*32; p += stride)
        ((unsigned*)g_pflag)[p] = 0u;
}

// ---------------- persistent encoder v8: bf16 K-chunk 64 + ldmatrix ----------------
#define E7_W_U32 (3*32*132)
#define E7_A_U32 (2*256*36)
#define E7_G_FLOATS (NL_DIM*100)
#define E7_SMEM_BYTES ((E7_W_U32 + E7_A_U32 + E7_G_FLOATS)*4)

__global__ void __launch_bounds__(512, 1)
enc_v8(const float* __restrict__ whF, const float* __restrict__ bhF,
       const float* __restrict__ whB, const float* __restrict__ bhB,
       const int* __restrict__ lines)
{
    extern __shared__ uint32_t smu[];
    uint32_t* Ws2 = smu;
    uint32_t* As2 = smu + E7_W_U32;
    float* GIe = (float*)(smu + E7_W_U32 + E7_A_U32);
    const int tid = threadIdx.x, lane = tid & 31, wid = tid >> 5;
    const int wm = wid >> 1, wn = wid & 1;
    const int bcol = blockIdx.x;
    const int slab = blockIdx.y;
    const bool dirF = (slab < 8);
    const float* __restrict__ W  = dirF ? whF : whB;
    const float* __restrict__ bh = dirF ? bhF : bhB;
    const float* __restrict__ giT = dirF ? g_giF : g_giB;
    const int lrow0 = (dirF ? slab : slab - 8) * 2048;

    for (int i = tid; i < 3*32*128; i += 512){
        int g = i >> 12, rem = i & 4095;
        int c = rem >> 7, kp = rem & 127;
        const float* wr = W + (size_t)(g*H_DIM + bcol*32 + c)*H_DIM + 2*kp;
        Ws2[(g*32 + c)*132 + kp] = packbf(wr[0], wr[1]);
    }
    for (int i = tid; i < NL_DIM*96; i += 512){
        int e = i / 96, j = i % 96;
        int g = j >> 5, c = j & 31;
        GIe[e*100 + j] = __ldg(&giT[e*G3 + g*H_DIM + bcol*32 + c]);
    }
    float bR[2][2], bZ[2][2], bN[2][2];
    #pragma unroll
    for (int nt = 0; nt < 2; nt++)
        #pragma unroll
        for (int dc = 0; dc < 2; dc++){
            int c = bcol*32 + wn*16 + nt*8 + (lane & 3)*2 + dc;
            bR[nt][dc] = bh[c];
            bZ[nt][dc] = bh[H_DIM + c];
            bN[nt][dc] = bh[2*H_DIM + c];
        }
    const int tA = lane >> 3;
    uint32_t aA[2];
    #pragma unroll
    for (int mt = 0; mt < 2; mt++)
        aA[mt] = sptr(As2) + (uint32_t)(((wm*32 + mt*16 + (tA & 1)*8 + (lane & 7))*36
                                        + (tA >> 1)*4) * 4);
    uint32_t aB[3][2];
    #pragma unroll
    for (int g = 0; g < 3; g++)
        #pragma unroll
        for (int nt = 0; nt < 2; nt++)
            aB[g][nt] = sptr(Ws2) + (uint32_t)(((g*32 + wn*16 + nt*8 + (lane & 7))*132
                                        + ((lane >> 3) & 1)*4) * 4);
    __syncthreads();

    for (int t = 0; t < L_DIM; t++){
        const float* __restrict__ hsrc = dirF ? g_Hf[t & 1] : g_Hb[t & 1];
        float* __restrict__ hdst = dirF ? g_Hf[(t + 1) & 1] : g_Hb[(t + 1) & 1];
        const uint16_t* __restrict__ hsrc16 = dirF ? g_Hfb[t & 1] : g_Hbb[t & 1];
        uint16_t* __restrict__ hdst16 = dirF ? g_Hfb[(t + 1) & 1] : g_Hbb[(t + 1) & 1];

        auto stage = [&](int p){
            int chunk = p >> 2, kb = p & 3, buf = p & 1;
            const uint16_t* src = hsrc16 + (size_t)(lrow0 + chunk*256)*H_DIM + kb*64;
            uint32_t* dst = As2 + buf*256*36;
            #pragma unroll
            for (int i = tid; i < 2048; i += 512){
                int r = i >> 3, q = i & 7;
                cp16(&dst[r*36 + q*4], src + (size_t)r*H_DIM + q*8);
            }
            cp_commit();
        };

        float acc[3][2][2][4];
        stage(0);
        for (int p = 0; p < 32; p++){
            cp_wait<0>();
            __syncthreads();
            if (p + 1 < 32) stage(p + 1);
            const int kb = p & 3;
            if (kb == 0){
                #pragma unroll
                for (int g = 0; g < 3; g++)
                    #pragma unroll
                    for (int a = 0; a < 2; a++)
                        #pragma unroll
                        for (int b = 0; b < 2; b++)
                            #pragma unroll
                            for (int c = 0; c < 4; c++) acc[g][a][b][c] = 0.f;
            }
            const uint32_t abufofs = (uint32_t)((p & 1)*256*36*4);
            const uint32_t bofs = (uint32_t)(kb*128);
            #pragma unroll
            for (int kk = 0; kk < 64; kk += 16){
                uint32_t af[2][4];
                #pragma unroll
                for (int mt = 0; mt < 2; mt++)
                    ldsm4(af[mt], aA[mt] + abufofs + kk*2);
                #pragma unroll
                for (int g = 0; g < 3; g++)
                    #pragma unroll
                    for (int nt = 0; nt < 2; nt++){
                        uint32_t bf[2];
                        ldsm2(bf, aB[g][nt] + bofs + kk*2);
                        #pragma unroll
                        for (int mt = 0; mt < 2; mt++)
                            mma16b(acc[g][mt][nt], af[mt], bf);
                    }
            }

            if (kb == 3){
                const int base = lrow0 + (p >> 2)*256;
                #pragma unroll
                for (int mt = 0; mt < 2; mt++){
                    #pragma unroll
                    for (int dr = 0; dr < 2; dr++){
                        int lr = base + wm*32 + mt*16 + (lane >> 2) + dr*8;
                        int iroll = lr >> 10;
                        int nb = lr & (N_DIM - 1);
                        int l = dirF ? ((iroll + t) & 15) : ((iroll + 15 - t) & 15);
                        const float* ge = GIe + __ldg(&lines[nb*L_DIM + l])*100;
                        #pragma unroll
                        for (int nt = 0; nt < 2; nt++){
                            int hcl = wn*16 + nt*8 + (lane & 3)*2;
                            float2 gv0 = *(const float2*)&ge[hcl];
                            float2 gv1 = *(const float2*)&ge[32 + hcl];
                            float2 gv2 = *(const float2*)&ge[64 + hcl];
                            float2 hold = __ldcg((const float2*)&hsrc[(size_t)lr*H_DIM + bcol*32 + hcl]);
                            float2 hout;
                            #pragma unroll
                            for (int dc = 0; dc < 2; dc++){
                                float gr = acc[0][mt][nt][dr*2+dc] + bR[nt][dc];
                                float gz = acc[1][mt][nt][dr*2+dc] + bZ[nt][dc];
                                float gn = acc[2][mt][nt][dr*2+dc] + bN[nt][dc];
                                float r  = sigm((dc ? gv0.y : gv0.x) + gr);
                                float z  = sigm((dc ? gv1.y : gv1.x) + gz);
                                float nn = tanhf((dc ? gv2.y : gv2.x) + r*gn);
                                float ho = dc ? hold.y : hold.x;
                                float hnew = (1.f - z)*nn + z*ho;
                                if (dc) hout.y = hnew; else hout.x = hnew;
                            }
                            __stcg((float2*)&hdst[(size_t)lr*H_DIM + bcol*32 + hcl], hout);
                            __stcg((uint32_t*)(hdst16 + (size_t)lr*H_DIM + bcol*32 + hcl),
                                   packbf(hout.x, hout.y));
                        }
                    }
                }
            }
        }
        slab_sync(slab, 8);
    }
}

// ---------------- Rproj bf16: Hmem(bf16 shadows) @ W0r^T, f32 out -----------------
// grid (2, 64), 512 thr. K=512 (Hf 256 | Hb 256), 8 staged chunks of 64.
#define RPB_W_U32 (128*260)                /* 33280 */
#define RPB_A_U32 (2*256*36)               /* 18432 */
#define RPB_SMEM_BYTES ((RPB_W_U32 + RPB_A_U32)*4)

__global__ void __launch_bounds__(512, 1)
rproj_b(const float* __restrict__ f_w0)
{
    extern __shared__ uint32_t smu[];
    uint32_t* Ws2 = smu;
    uint32_t* As2 = smu + RPB_W_U32;
    const int tid = threadIdx.x, lane = tid & 31, wid = tid >> 5;
    const int wm = wid >> 1, wn = wid & 1;
    const int bcol = blockIdx.x;            // 0..1 (128 out cols)
    const int rt = blockIdx.y;              // 0..63 (256-row tile)

    // pack W0r: 128 cols x 512 K -> bf16 pairs (kp 0..255)
    for (int i = tid; i < 128*256; i += 512){
        int c = i >> 8, kp = i & 255;
        const float* wr = f_w0 + (size_t)(bcol*128 + c)*576 + 64 + 2*kp;
        Ws2[c*260 + kp] = packbf(wr[0], wr[1]);
    }
    const int tA = lane >> 3;
    uint32_t aA[2];
    #pragma unroll
    for (int mt = 0; mt < 2; mt++)
        aA[mt] = sptr(As2) + (uint32_t)(((wm*32 + mt*16 + (tA & 1)*8 + (lane & 7))*36
                                        + (tA >> 1)*4) * 4);
    uint32_t aB[8];
    #pragma unroll
    for (int nt = 0; nt < 8; nt++)
        aB[nt] = sptr(Ws2) + (uint32_t)(((wn*64 + nt*8 + (lane & 7))*260
                                        + ((lane >> 3) & 1)*4) * 4);
    __syncthreads();

    auto stage = [&](int p){
        int kb = p, buf = p & 1;
        const uint32_t* src = (kb < 4)
            ? (const uint32_t*)g_Hfb[0] + (size_t)(rt*256)*128 + kb*32
            : (const uint32_t*)g_Hbb[0] + (size_t)(rt*256)*128 + (kb - 4)*32;
        uint32_t* dst = As2 + buf*256*36;
        #pragma unroll
        for (int i = tid; i < 2048; i += 512){
            int r = i >> 3, q = i & 7;
            cp16(&dst[r*36 + q*4], src + (size_t)r*128 + q*4);
        }
        cp_commit();
    };

    float acc[2][8][4];
    #pragma unroll
    for (int a = 0; a < 2; a++)
        #pragma unroll
        for (int b = 0; b < 8; b++)
            #pragma unroll
            for (int c = 0; c < 4; c++) acc[a][b][c] = 0.f;

    stage(0);
    for (int p = 0; p < 8; p++){
        cp_wait<0>();
        __syncthreads();
        if (p + 1 < 8) stage(p + 1);
        const uint32_t abufofs = (uint32_t)((p & 1)*256*36*4);
        const uint32_t bofs = (uint32_t)(p*128);
        #pragma unroll
        for (int kk = 0; kk < 64; kk += 16){
            uint32_t af[2][4];
            #pragma unroll
            for (int mt = 0; mt < 2; mt++)
                ldsm4(af[mt], aA[mt] + abufofs + kk*2);
            #pragma unroll
            for (int nt = 0; nt < 8; nt++){
                uint32_t bf[2];
                ldsm2(bf, aB[nt] + bofs + kk*2);
                #pragma unroll
                for (int mt = 0; mt < 2; mt++)
                    mma16b(acc[mt][nt], af[mt], bf);
            }
        }
        __syncthreads();
    }

    #pragma unroll
    for (int mt = 0; mt < 2; mt++){
        #pragma unroll
        for (int nt = 0; nt < 8; nt++){
            #pragma unroll
            for (int dr = 0; dr < 2; dr++){
                int rr = rt*256 + wm*32 + mt*16 + (lane >> 2) + dr*8;
                int cc = bcol*128 + wn*64 + nt*8 + (lane & 3)*2;
                float2 v; v.x = acc[mt][nt][dr*2 + 0]; v.y = acc[mt][nt][dr*2 + 1];
                *(float2*)&g_Rproj[(size_t)rr*H_DIM + cc] = v;
            }
        }
    }
}

// ---------------- layer0 bf16: A0 = relu(cond @ W0c^T + Rproj[active] + b0) -------
// grid (2, 74), 512 thr, loops 256-row tiles. K=64.
#define L0B_W_U32 (128*36)                 /* 4608  */
#define L0B_A_U32 (256*36)                 /* 9216  */
#define L0B_SMEM_BYTES ((L0B_W_U32 + L0B_A_U32)*4)

__global__ void __launch_bounds__(512, 1)
l0_b(const float* __restrict__ cond, const float* __restrict__ f_w0,
     const float* __restrict__ f_b0, const int* __restrict__ active)
{
    extern __shared__ uint32_t smu[];
    uint32_t* Ws2 = smu;
    uint32_t* As2 = smu + L0B_W_U32;
    const int tid = threadIdx.x, lane = tid & 31, wid = tid >> 5;
    const int wm = wid >> 1, wn = wid & 1;
    const int bcol = blockIdx.x;            // 0..1

    for (int i = tid; i < 128*32; i += 512){
        int c = i >> 5, kp = i & 31;
        const float* wr = f_w0 + (size_t)(bcol*128 + c)*576 + 2*kp;
        Ws2[c*36 + kp] = packbf(wr[0], wr[1]);
    }
    const int tA = lane >> 3;
    uint32_t aA[2];
    #pragma unroll
    for (int mt = 0; mt < 2; mt++)
        aA[mt] = sptr(As2) + (uint32_t)(((wm*32 + mt*16 + (tA & 1)*8 + (lane & 7))*36
                                        + (tA >> 1)*4) * 4);
    uint32_t aB[8];
    #pragma unroll
    for (int nt = 0; nt < 8; nt++)
        aB[nt] = sptr(Ws2) + (uint32_t)(((wn*64 + nt*8 + (lane & 7))*36
                                        + ((lane >> 3) & 1)*4) * 4);
    float bias[8][2];
    #pragma unroll
    for (int nt = 0; nt < 8; nt++){
        int cc = bcol*128 + wn*64 + nt*8 + (lane & 3)*2;
        bias[nt][0] = f_b0[cc];
        bias[nt][1] = f_b0[cc + 1];
    }
    __syncthreads();

    for (int rt = blockIdx.y; rt < TN/256; rt += gridDim.y){
        // load cond f32 (float4) and pack bf16 into SMEM
        const float4* src = (const float4*)(cond + (size_t)rt*256*C_DIM);
        #pragma unroll
        for (int i = tid; i < 4096; i += 512){
            int r = i >> 4, q = i & 15;
            float4 v = __ldg(&src[r*16 + q]);
            uint32_t* dst = &As2[r*36 + q*2];
            dst[0] = packbf(v.x, v.y);
            dst[1] = packbf(v.z, v.w);
        }
        __syncthreads();

        float acc[2][8][4];
        #pragma unroll
        for (int a = 0; a < 2; a++)
            #pragma unroll
            for (int b = 0; b < 8; b++)
                #pragma unroll
                for (int c = 0; c < 4; c++) acc[a][b][c] = 0.f;

        #pragma unroll
        for (int kk = 0; kk < 64; kk += 16){
            uint32_t af[2][4];
            #pragma unroll
            for (int mt = 0; mt < 2; mt++)
                ldsm4(af[mt], aA[mt] + kk*2);
            #pragma unroll
            for (int nt = 0; nt < 8; nt++){
                uint32_t bf[2];
                ldsm2(bf, aB[nt] + kk*2);
                #pragma unroll
                for (int mt = 0; mt < 2; mt++)
                    mma16b(acc[mt][nt], af[mt], bf);
            }
        }

        #pragma unroll
        for (int mt = 0; mt < 2; mt++){
            #pragma unroll
            for (int dr = 0; dr < 2; dr++){
                int rr = rt*256 + wm*32 + mt*16 + (lane >> 2) + dr*8;
                int n = rr & (N_DIM - 1);
                int w = __ldg(&active[rr]);
                const float* rp = g_Rproj + (size_t)(w*N_DIM + n)*H_DIM;
                #pragma unroll
                for (int nt = 0; nt < 8; nt++){
                    int cc = bcol*128 + wn*64 + nt*8 + (lane & 3)*2;
                    float2 rv = __ldg((const float2*)&rp[cc]);
                    float v0 = fmaxf(acc[mt][nt][dr*2 + 0] + bias[nt][0] + rv.x, 0.f);
                    float v1 = fmaxf(acc[mt][nt][dr*2 + 1] + bias[nt][1] + rv.y, 0.f);
                    g_A0b[(size_t)rr*(H_DIM/2) + (cc >> 1)] = packbf(v0, v1);
                }
            }
        }
        __syncthreads();
    }
}

// ---------------- bf16 feed-forward GEMM + ldmatrix -------------------
#define FFB_W_U32 (128*132)
#define FFB_A_U32 (2*256*36)
#define FFB_SMEM_BYTES ((FFB_W_U32 + FFB_A_U32)*4)

template<int EPI>
__global__ void __launch_bounds__(512, 1)
gemm_ffb(const uint32_t* __restrict__ A, const float* __restrict__ W,
         const float* __restrict__ bias, uint32_t* __restrict__ outp,
         int out_stride, int nrt)
{
    extern __shared__ uint32_t smu[];
    uint32_t* Ws2 = smu;
    uint32_t* As2 = smu + FFB_W_U32;
    const int tid = threadIdx.x, lane = tid & 31, wid = tid >> 5;
    const int wm = wid >> 1, wn = wid & 1;
    const int bcol = blockIdx.x;

    for (int i = tid; i < 128*128; i += 512){
        int c = i >> 7, kp = i & 127;
        const float* wr = W + (size_t)(bcol*128 + c)*H_DIM + 2*kp;
        Ws2[c*132 + kp] = packbf(wr[0], wr[1]);
    }
    const int tA = lane >> 3;
    uint32_t aA[2];
    #pragma unroll
    for (int mt = 0; mt < 2; mt++)
        aA[mt] = sptr(As2) + (uint32_t)(((wm*32 + mt*16 + (tA & 1)*8 + (lane & 7))*36
                                        + (tA >> 1)*4) * 4);
    uint32_t aB[8];
    #pragma unroll
    for (int nt = 0; nt < 8; nt++)
        aB[nt] = sptr(Ws2) + (uint32_t)(((wn*64 + nt*8 + (lane & 7))*132
                                        + ((lane >> 3) & 1)*4) * 4);
    __syncthreads();

    const int nch = (nrt - (int)blockIdx.y + (int)gridDim.y - 1) / (int)gridDim.y;
    if (nch <= 0) return;
    const int total = nch*4;

    auto stage = [&](int p){
        int ci = p >> 2, kb = p & 3, buf = p & 1;
        int rt = blockIdx.y + ci*gridDim.y;
        const uint32_t* src = A + (size_t)rt*256*128 + kb*32;
        uint32_t* dst = As2 + buf*256*36;
        #pragma unroll
        for (int i = tid; i < 2048; i += 512){
            int r = i >> 3, q = i & 7;
            cp16(&dst[r*36 + q*4], src + (size_t)r*128 + q*4);
        }
        cp_commit();
    };

    float acc[2][8][4];
    stage(0);
    for (int p = 0; p < total; p++){
        cp_wait<0>();
        __syncthreads();
        if (p + 1 < total) stage(p + 1);
        const int kb = p & 3;
        if (kb == 0){
            #pragma unroll
            for (int a = 0; a < 2; a++)
                #pragma unroll
                for (int b = 0; b < 8; b++)
                    #pragma unroll
                    for (int c = 0; c < 4; c++) acc[a][b][c] = 0.f;
        }
        const uint32_t abufofs = (uint32_t)((p & 1)*256*36*4);
        const uint32_t bofs = (uint32_t)(kb*128);
        #pragma unroll
        for (int kk = 0; kk < 64; kk += 16){
            uint32_t af[2][4];
            #pragma unroll
            for (int mt = 0; mt < 2; mt++)
                ldsm4(af[mt], aA[mt] + abufofs + kk*2);
            #pragma unroll
            for (int nt = 0; nt < 8; nt++){
                uint32_t bf[2];
                ldsm2(bf, aB[nt] + bofs + kk*2);
                #pragma unroll
                for (int mt = 0; mt < 2; mt++)
                    mma16b(acc[mt][nt], af[mt], bf);
            }
        }

        if (kb == 3){
            int rt = blockIdx.y + (p >> 2)*gridDim.y;
            #pragma unroll
            for (int mt = 0; mt < 2; mt++){
                #pragma unroll
                for (int nt = 0; nt < 8; nt++){
                    #pragma unroll
                    for (int dr = 0; dr < 2; dr++){
                        int rr = rt*256 + wm*32 + mt*16 + (lane >> 2) + dr*8;
                        int cc = bcol*128 + wn*64 + nt*8 + (lane & 3)*2;
                        float v0 = acc[mt][nt][dr*2 + 0] + bias[cc];
                        float v1 = acc[mt][nt][dr*2 + 1] + bias[cc + 1];
                        if (EPI == 1){ v0 = fmaxf(v0, 0.f); v1 = fmaxf(v1, 0.f); }
                        outp[(size_t)rr*out_stride + (cc >> 1)] = packbf(v0, v1);
                    }
                }
            }
        }
    }
}

// ---------------- main GRU v12: 16 rows x 128 cols, pair-flag barrier --------------
#define M12_W_U32 (384*132)
#define M12_A_U32 (16*132)
#define M12_G_U32 (16*200)
#define M12_SMEM_BYTES ((M12_W_U32 + M12_A_U32 + M12_G_U32)*4)

__global__ void __launch_bounds__(256, 1)
main_gru_v12(const float* __restrict__ whh, const float* __restrict__ bhh)
{
    extern __shared__ uint32_t smu[];
    uint32_t* Ws2 = smu;
    uint32_t* As2 = smu + M12_W_U32;
    uint32_t* GIs = smu + M12_W_U32 + M12_A_U32;
    const int tid = threadIdx.x, lane = tid & 31, w = tid >> 5;
    const int me = blockIdx.x;
    const int rg = blockIdx.y;
    const int row0 = rg*16;

    for (int i = tid; i < 384*128; i += 256){
        int row = i >> 7, kp = i & 127;
        int g = row >> 7, cl = row & 127;
        const float* wr = whh + (size_t)(g*H_DIM + me*128 + cl)*H_DIM + 2*kp;
        Ws2[row*132 + kp] = packbf(wr[0], wr[1]);
    }
    float bR[2][2], bZ[2][2], bN[2][2];
    #pragma unroll
    for (int ct = 0; ct < 2; ct++)
        #pragma unroll
        for (int dc = 0; dc < 2; dc++){
            int c = me*128 + w*16 + ct*8 + (lane & 3)*2 + dc;
            bR[ct][dc] = bhh[c];
            bZ[ct][dc] = bhh[H_DIM + c];
            bN[ct][dc] = bhh[2*H_DIM + c];
        }
    const int tA = lane >> 3;
    const uint32_t aA = sptr(As2) + (uint32_t)((((tA & 1)*8 + (lane & 7))*132
                                        + (tA >> 1)*4) * 4);
    uint32_t aB[6];
    #pragma unroll
    for (int nt = 0; nt < 6; nt++){
        int g = nt >> 1, ct = nt & 1;
        aB[nt] = sptr(Ws2) + (uint32_t)(((g*128 + w*16 + ct*8 + (lane & 7))*132
                                        + ((lane >> 3) & 1)*4) * 4);
    }

    auto stage_gi = [&](int tt){
        const uint32_t* gsrc = g_GIb + ((size_t)tt*N_DIM + row0)*(G3/2) + me*64;
        #pragma unroll
        for (int i = tid; i < 768; i += 256){
            int r = i / 48, j = i % 48;
            int g = j >> 4, q = j & 15;
            cp16(&GIs[r*200 + g*64 + q*4], gsrc + (size_t)r*(G3/2) + g*128 + q*4);
        }
        cp_commit();
    };

    stage_gi(0);
    __syncthreads();

    for (int t = 0; t < T_DIM; t++){
        const uint16_t* __restrict__ hsrc16 = g_hmb[t & 1];
        uint16_t* __restrict__ hdst16 = g_hmb[(t + 1) & 1];
        const float* __restrict__ hsrcf = (t == 0) ? g_hm0
                                        : g_hall + (size_t)(t - 1)*N_DIM*H_DIM;
        float* __restrict__ hdstf = g_hall + (size_t)t*N_DIM*H_DIM;

        {
            const uint16_t* src = hsrc16 + (size_t)row0*H_DIM;
            #pragma unroll
            for (int i = tid; i < 512; i += 256){
                int r = i >> 5, q = i & 31;
                cp16(&As2[r*132 + q*4], src + (size_t)r*H_DIM + q*8);
            }
            cp_commit();
        }
        cp_wait<0>();
        __syncthreads();

        float acc[6][4];
        #pragma unroll
        for (int n = 0; n < 6; n++)
            #pragma unroll
            for (int c = 0; c < 4; c++) acc[n][c] = 0.f;

        #pragma unroll 4
        for (int kk = 0; kk < H_DIM; kk += 16){
            uint32_t af[4];
            ldsm4(af, aA + kk*2);
            #pragma unroll
            for (int nt = 0; nt < 6; nt++){
                uint32_t bf[2];
                ldsm2(bf, aB[nt] + kk*2);
                mma16b(acc[nt], af, bf);
            }
        }

        #pragma unroll
        for (int dr = 0; dr < 2; dr++){
            int r = (lane >> 2) + dr*8;
            int row = row0 + r;
            #pragma unroll
            for (int ct = 0; ct < 2; ct++){
                int cl = w*16 + ct*8 + (lane & 3)*2;
                int gcol = me*128 + cl;
                float2 gv0 = unpackbf(GIs[r*200 +       (cl >> 1)]);
                float2 gv1 = unpackbf(GIs[r*200 +  64 + (cl >> 1)]);
                float2 gv2 = unpackbf(GIs[r*200 + 128 + (cl >> 1)]);
                float2 hold = __ldcg((const float2*)&hsrcf[(size_t)row*H_DIM + gcol]);
                float2 hout;
                #pragma unroll
                for (int dc = 0; dc < 2; dc++){
                    float gr = acc[0*2 + ct][dr*2+dc] + bR[ct][dc];
                    float gz = acc[1*2 + ct][dr*2+dc] + bZ[ct][dc];
                    float gn = acc[2*2 + ct][dr*2+dc] + bN[ct][dc];
                    float rr = sigm((dc ? gv0.y : gv0.x) + gr);
                    float zz = sigm((dc ? gv1.y : gv1.x) + gz);
                    float nn = tanhf((dc ? gv2.y : gv2.x) + rr*gn);
                    float ho = dc ? hold.y : hold.x;
                    float hnew = (1.f - zz)*nn + zz*ho;
                    if (dc) hout.y = hnew; else hout.x = hnew;
                }
                __stcg((float2*)&hdstf[(size_t)row*H_DIM + gcol], hout);
                __stcg((uint32_t*)(hdst16 + (size_t)row*H_DIM + gcol),
                       packbf(hout.x, hout.y));
            }
        }

        __syncthreads();
        if (t + 1 < T_DIM) stage_gi(t + 1);

        if (tid == 0){
            __threadfence();
            *(volatile unsigned*)&g_pflag[rg][me][0] = (unsigned)(t + 1);
        }
        if (tid == 32){
            while (*(volatile unsigned*)&g_pflag[rg][me ^ 1][0] < (unsigned)(t + 1)) { }
            __threadfence();
        }
        __syncthreads();
    }
}

// ---------------- heads v2 ----------------
__global__ void __launch_bounds__(256)
heads_kernel(float* __restrict__ out, const int* __restrict__ actions,
             const int* __restrict__ active, const float* __restrict__ p0,
             const float* __restrict__ pp0,
             const float* __restrict__ w_actor, const float* __restrict__ b_actor,
             const float* __restrict__ w_critic, const float* __restrict__ b_critic)
{
    int wid = threadIdx.x >> 5, lane = threadIdx.x & 31;
    size_t row = (size_t)blockIdx.x*8 + wid;
    const float* hrow = g_hall + row*H_DIM;
    float* orow = out + row*ROW_OUT;
    float hv[8];
    #pragma unroll
    for (int i = 0; i < 8; i++) hv[i] = hrow[lane + 32*i];

    float lg = 0.f;
    #pragma unroll
    for (int a = 0; a < NA_DIM; a++){
        float s = 0.f;
        #pragma unroll
        for (int i = 0; i < 8; i++) s += hv[i]*w_actor[a*H_DIM + lane + 32*i];
        #pragma unroll
        for (int o = 16; o > 0; o >>= 1) s += __shfl_xor_sync(0xffffffffu, s, o);
        if (lane == a) lg = s + b_actor[a];
    }
    float m = (lane < NA_DIM) ? lg : -1e30f;
    #pragma unroll
    for (int o = 16; o > 0; o >>= 1) m = fmaxf(m, __shfl_xor_sync(0xffffffffu, m, o));
    float e = (lane < NA_DIM) ? expf(lg - m) : 0.f;
    float den = e;
    #pragma unroll
    for (int o = 16; o > 0; o >>= 1) den += __shfl_xor_sync(0xffffffffu, den, o);

    #pragma unroll
    for (int i = 0; i < 8; i++) orow[4 + lane + 32*i] = hv[i];
    if (lane < NA_DIM) orow[260 + lane] = e/den;

    float s = 0.f;
    #pragma unroll
    for (int i = 0; i < 8; i++) s += hv[i]*w_critic[lane + 32*i];
    #pragma unroll
    for (int o = 16; o > 0; o >>= 1) s += __shfl_xor_sync(0xffffffffu, s, o);

    int n = (int)(row & (N_DIM - 1));
    if (lane == 0)  orow[3]   = s + b_critic[0];
    if (lane == 16) orow[0]   = (float)actions[row];
    if (lane == 17) orow[1]   = p0[n];
    if (lane == 18) orow[2]   = (float)active[row];
    if (lane == 19) orow[276] = pp0[n*2];
    if (lane == 20) orow[277] = pp0[n*2 + 1];
}

// ---------------- launch ----------------
extern "C" void kernel_launch(void* const* d_in, const int* in_sizes, int n_in,
                              void* d_out, int out_size)
{
    (void)in_sizes; (void)n_in; (void)out_size;
    const float* condition = (const float*)d_in[0];
    const int*   active    = (const int*)d_in[1];
    const int*   lines     = (const int*)d_in[2];
    const int*   actions   = (const int*)d_in[3];
    const float* h0        = (const float*)d_in[4];
    const float* p0        = (const float*)d_in[5];
    const float* pp0       = (const float*)d_in[6];
    const float* embed     = (const float*)d_in[7];
    const float* wih_f = (const float*)d_in[8],  *whh_f = (const float*)d_in[9];
    const float* bih_f = (const float*)d_in[10], *bhh_f = (const float*)d_in[11];
    const float* wih_b = (const float*)d_in[12], *whh_b = (const float*)d_in[13];
    const float* bih_b = (const float*)d_in[14], *bhh_b = (const float*)d_in[15];
    const float* f_w0 = (const float*)d_in[16], *f_b0 = (const float*)d_in[17];
    const float* f_w1 = (const float*)d_in[18], *f_b1 = (const float*)d_in[19];
    const float* f_w2 = (const float*)d_in[20], *f_b2 = (const float*)d_in[21];
    const float* c_wih = (const float*)d_in[22], *c_whh = (const float*)d_in[23];
    const float* c_bih = (const float*)d_in[24], *c_bhh = (const float*)d_in[25];
    const float* w_critic = (const float*)d_in[26], *b_critic = (const float*)d_in[27];
    const float* w_actor  = (const float*)d_in[28], *b_actor  = (const float*)d_in[29];
    float* out = (float*)d_out;

    uint32_t *A0bp, *A1bp, *GIbp;
    cudaGetSymbolAddress((void**)&A0bp, g_A0b);
    cudaGetSymbolAddress((void**)&A1bp, g_A1b);
    cudaGetSymbolAddress((void**)&GIbp, g_GIb);

    cudaFuncSetAttribute(enc_v8,
                         cudaFuncAttributeMaxDynamicSharedMemorySize, E7_SMEM_BYTES);
    cudaFuncSetAttribute(main_gru_v12,
                         cudaFuncAttributeMaxDynamicSharedMemorySize, M12_SMEM_BYTES);
    cudaFuncSetAttribute(rproj_b,
                         cudaFuncAttributeMaxDynamicSharedMemorySize, RPB_SMEM_BYTES);
    cudaFuncSetAttribute(l0_b,
                         cudaFuncAttributeMaxDynamicSharedMemorySize, L0B_SMEM_BYTES);
    cudaFuncSetAttribute(gemm_ffb<1>,
                         cudaFuncAttributeMaxDynamicSharedMemorySize, FFB_SMEM_BYTES);
    cudaFuncSetAttribute(gemm_ffb<3>,
                         cudaFuncAttributeMaxDynamicSharedMemorySize, FFB_SMEM_BYTES);

    // 0) gi tables + state init
    gi_tables<<<(2*NL_DIM*G3 + 255)/256, 256>>>(embed, wih_f, bih_f, wih_b, bih_b);
    init_state<<<4096, 256>>>(h0);

    // 1) persistent bidirectional encoder (bf16 + ldmatrix)
    enc_v8<<<dim3(8, 16), 512, E7_SMEM_BYTES>>>(whh_f, bhh_f, whh_b, bhh_b, lines);

    // 2) Rproj = Hmem @ W0r^T  (bf16 + ldmatrix, f32 out)
    rproj_b<<<dim3(2, 64), 512, RPB_SMEM_BYTES>>>(f_w0);
    // 3) A0 = relu(cond @ W0c^T + Rproj[active] + b0)  (bf16 + ldmatrix)
    l0_b<<<dim3(2, 74), 512, L0B_SMEM_BYTES>>>(condition, f_w0, f_b0, active);
    // 4) A1 = relu(A0 @ w1^T + b1); A0'' = relu(A1 @ w2^T + b2)
    gemm_ffb<1><<<dim3(2, 74), 512, FFB_SMEM_BYTES>>>(A0bp, f_w1, f_b1, A1bp, 128, 1024);
    gemm_ffb<1><<<dim3(2, 74), 512, FFB_SMEM_BYTES>>>(A1bp, f_w2, f_b2, A0bp, 128, 1024);
    // 5) GI = A0'' @ c_wih^T + c_bih  -> packed bf16
    gemm_ffb<3><<<dim3(6, 24), 512, FFB_SMEM_BYTES>>>(A0bp, c_wih, c_bih, GIbp, 384, 1024);

    // 6) main GRU v12: 64 independent row-group pairs, flag barrier
    main_gru_v12<<<dim3(2, 64), 256, M12_SMEM_BYTES>>>(c_whh, c_bhh);

    // 7) heads v2
    heads_kernel<<<TN/8, 256>>>(out, actions, active, p0, pp0,
                                w_actor, b_actor, w_critic, b_critic);
}

// round 16
// speedup vs baseline: 3.5995x; 1.0286x over previous
#include <cuda_runtime.h>
#include <math.h>
#include <stdint.h>

#define T_DIM 256
#define N_DIM 1024
#define H_DIM 256
#define L_DIM 16
#define NL_DIM 32
#define C_DIM 64
#define NA_DIM 16
#define ROW_OUT 278
#define G3 768
#define LN (L_DIM*N_DIM)          /* 16384 */
#define TN (T_DIM*N_DIM)          /* 262144 */

// ---------------- scratch ----------------
__device__ float g_giF[NL_DIM*G3];
__device__ float g_giB[NL_DIM*G3];
__device__ uint16_t g_Hfb[2][(size_t)LN*H_DIM];   // bf16 encoder h (fwd)
__device__ uint16_t g_Hbb[2][(size_t)LN*H_DIM];   // bf16 encoder h (bwd)
__device__ float g_Rproj[(size_t)LN*H_DIM];
__device__ uint32_t g_A0b[(size_t)TN*(H_DIM/2)];
__device__ uint32_t g_A1b[(size_t)TN*(H_DIM/2)];
__device__ uint32_t g_GIb[(size_t)TN*(G3/2)];
__device__ float g_hall[(size_t)TN*H_DIM];
__device__ float g_hm0[N_DIM*H_DIM];
__device__ uint16_t g_hmb[2][N_DIM*H_DIM];
__device__ unsigned g_pflag[64][2][32];
__device__ unsigned g_eflag[16][8][32];

// ---------------- helpers ----------------
__device__ __forceinline__ uint32_t packbf(float lo, float hi){
    uint32_t r; asm("cvt.rn.bf16x2.f32 %0, %1, %2;" : "=r"(r) : "f"(hi), "f"(lo)); return r;
}
__device__ __forceinline__ float2 unpackbf(uint32_t u){
    float2 r;
    r.x = __uint_as_float(u << 16);
    r.y = __uint_as_float(u & 0xffff0000u);
    return r;
}
__device__ __forceinline__ void mma16b(float* c, const uint32_t* a, const uint32_t* b){
    asm volatile("mma.sync.aligned.m16n8k16.row.col.f32.bf16.bf16.f32 "
        "{%0,%1,%2,%3},{%4,%5,%6,%7},{%8,%9},{%0,%1,%2,%3};"
        : "+f"(c[0]), "+f"(c[1]), "+f"(c[2]), "+f"(c[3])
        : "r"(a[0]), "r"(a[1]), "r"(a[2]), "r"(a[3]), "r"(b[0]), "r"(b[1]));
}
__device__ __forceinline__ void ldsm4(uint32_t* r, uint32_t saddr){
    asm volatile("ldmatrix.sync.aligned.m8n8.x4.shared.b16 {%0,%1,%2,%3}, [%4];"
        : "=r"(r[0]), "=r"(r[1]), "=r"(r[2]), "=r"(r[3]) : "r"(saddr));
}
__device__ __forceinline__ void ldsm2(uint32_t* r, uint32_t saddr){
    asm volatile("ldmatrix.sync.aligned.m8n8.x2.shared.b16 {%0,%1}, [%2];"
        : "=r"(r[0]), "=r"(r[1]) : "r"(saddr));
}
__device__ __forceinline__ uint32_t sptr(const void* p){
    return (uint32_t)__cvta_generic_to_shared(p);
}
__device__ __forceinline__ float sigm(float x){ return 1.f/(1.f+expf(-x)); }
__device__ __forceinline__ void cp16(void* smem_dst, const void* gsrc){
    uint32_t s = (uint32_t)__cvta_generic_to_shared(smem_dst);
    asm volatile("cp.async.cg.shared.global [%0], [%1], 16;" :: "r"(s), "l"(gsrc));
}
__device__ __forceinline__ void cp_commit(){ asm volatile("cp.async.commit_group;"); }
template<int N> __device__ __forceinline__ void cp_wait(){
    asm volatile("cp.async.wait_group %0;" :: "n"(N));
}

// ---------------- gi tables ----------------
__global__ void gi_tables(const float* __restrict__ embed,
                          const float* __restrict__ wihF, const float* __restrict__ bihF,
                          const float* __restrict__ wihB, const float* __restrict__ bihB)
{
    int idx = blockIdx.x*blockDim.x + threadIdx.x;
    if (idx >= 2*NL_DIM*G3) return;
    int dir = idx / (NL_DIM*G3);
    int rem = idx % (NL_DIM*G3);
    int e = rem / G3, j = rem % G3;
    const float* wih = dir ? wihB : wihF;
    const float* bih = dir ? bihB : bihF;
    float s = bih[j];
    const float* em = embed + e*H_DIM;
    const float* w  = wih + (size_t)j*H_DIM;
    #pragma unroll 8
    for (int k = 0; k < H_DIM; k++) s += em[k]*w[k];
    (dir ? g_giB : g_giF)[rem] = s;
}

// ---------------- init ----------------
__global__ void init_state(const float* __restrict__ h0)
{
    size_t stride = (size_t)gridDim.x*blockDim.x;
    size_t i0 = (size_t)blockIdx.x*blockDim.x + threadIdx.x;
    size_t HS = (size_t)LN*H_DIM;
    for (size_t p = i0; p < HS; p += stride){
        g_Hfb[0][p] = 0;  g_Hbb[0][p] = 0;
    }
    for (size_t p = i0; p < (size_t)N_DIM*H_DIM; p += stride){
        float v = h0[p];
        g_hm0[p] = v;
        g_hmb[0][p] = (uint16_t)(packbf(v, 0.f) & 0xffffu);
    }
    for (size_t p = i0; p < 64*2*32; p += stride)
        ((unsigned*)g_pflag)[p] = 0u;
    for (size_t p = i0; p < 16*8*32; p += stride)
        ((unsigned*)g_eflag)[p] = 0u;
}

// ---------------- persistent encoder v9: bf16-only h, flag barrier ----------------
#define E7_W_U32 (3*32*132)
#define E7_A_U32 (2*256*36)
#define E7_G_FLOATS (NL_DIM*100)
#define E7_SMEM_BYTES ((E7_W_U32 + E7_A_U32 + E7_G_FLOATS)*4)

__global__ void __launch_bounds__(512, 1)
enc_v9(const float* __restrict__ whF, const float* __restrict__ bhF,
       const float* __restrict__ whB, const float* __restrict__ bhB,
       const int* __restrict__ lines)
{
    extern __shared__ uint32_t smu[];
    uint32_t* Ws2 = smu;
    uint32_t* As2 = smu + E7_W_U32;
    float* GIe = (float*)(smu + E7_W_U32 + E7_A_U32);
    const int tid = threadIdx.x, lane = tid & 31, wid = tid >> 5;
    const int wm = wid >> 1, wn = wid & 1;
    const int bcol = blockIdx.x;
    const int slab = blockIdx.y;
    const bool dirF = (slab < 8);
    const float* __restrict__ W  = dirF ? whF : whB;
    const float* __restrict__ bh = dirF ? bhF : bhB;
    const float* __restrict__ giT = dirF ? g_giF : g_giB;
    const int lrow0 = (dirF ? slab : slab - 8) * 2048;

    for (int i = tid; i < 3*32*128; i += 512){
        int g = i >> 12, rem = i & 4095;
        int c = rem >> 7, kp = rem & 127;
        const float* wr = W + (size_t)(g*H_DIM + bcol*32 + c)*H_DIM + 2*kp;
        Ws2[(g*32 + c)*132 + kp] = packbf(wr[0], wr[1]);
    }
    for (int i = tid; i < NL_DIM*96; i += 512){
        int e = i / 96, j = i % 96;
        int g = j >> 5, c = j & 31;
        GIe[e*100 + j] = __ldg(&giT[e*G3 + g*H_DIM + bcol*32 + c]);
    }
    float bR[2][2], bZ[2][2], bN[2][2];
    #pragma unroll
    for (int nt = 0; nt < 2; nt++)
        #pragma unroll
        for (int dc = 0; dc < 2; dc++){
            int c = bcol*32 + wn*16 + nt*8 + (lane & 3)*2 + dc;
            bR[nt][dc] = bh[c];
            bZ[nt][dc] = bh[H_DIM + c];
            bN[nt][dc] = bh[2*H_DIM + c];
        }
    const int tA = lane >> 3;
    uint32_t aA[2];
    #pragma unroll
    for (int mt = 0; mt < 2; mt++)
        aA[mt] = sptr(As2) + (uint32_t)(((wm*32 + mt*16 + (tA & 1)*8 + (lane & 7))*36
                                        + (tA >> 1)*4) * 4);
    uint32_t aB[3][2];
    #pragma unroll
    for (int g = 0; g < 3; g++)
        #pragma unroll
        for (int nt = 0; nt < 2; nt++)
            aB[g][nt] = sptr(Ws2) + (uint32_t)(((g*32 + wn*16 + nt*8 + (lane & 7))*132
                                        + ((lane >> 3) & 1)*4) * 4);
    __syncthreads();

    for (int t = 0; t < L_DIM; t++){
        const uint16_t* __restrict__ hsrc16 = dirF ? g_Hfb[t & 1] : g_Hbb[t & 1];
        uint16_t* __restrict__ hdst16 = dirF ? g_Hfb[(t + 1) & 1] : g_Hbb[(t + 1) & 1];

        auto stage = [&](int p){
            int chunk = p >> 2, kb = p & 3, buf = p & 1;
            const uint16_t* src = hsrc16 + (size_t)(lrow0 + chunk*256)*H_DIM + kb*64;
            uint32_t* dst = As2 + buf*256*36;
            #pragma unroll
            for (int i = tid; i < 2048; i += 512){
                int r = i >> 3, q = i & 7;
                cp16(&dst[r*36 + q*4], src + (size_t)r*H_DIM + q*8);
            }
            cp_commit();
        };

        float acc[3][2][2][4];
        stage(0);
        for (int p = 0; p < 32; p++){
            cp_wait<0>();
            __syncthreads();
            if (p + 1 < 32) stage(p + 1);
            const int kb = p & 3;
            if (kb == 0){
                #pragma unroll
                for (int g = 0; g < 3; g++)
                    #pragma unroll
                    for (int a = 0; a < 2; a++)
                        #pragma unroll
                        for (int b = 0; b < 2; b++)
                            #pragma unroll
                            for (int c = 0; c < 4; c++) acc[g][a][b][c] = 0.f;
            }
            const uint32_t abufofs = (uint32_t)((p & 1)*256*36*4);
            const uint32_t bofs = (uint32_t)(kb*128);
            #pragma unroll
            for (int kk = 0; kk < 64; kk += 16){
                uint32_t af[2][4];
                #pragma unroll
                for (int mt = 0; mt < 2; mt++)
                    ldsm4(af[mt], aA[mt] + abufofs + kk*2);
                #pragma unroll
                for (int g = 0; g < 3; g++)
                    #pragma unroll
                    for (int nt = 0; nt < 2; nt++){
                        uint32_t bf[2];
                        ldsm2(bf, aB[g][nt] + bofs + kk*2);
                        #pragma unroll
                        for (int mt = 0; mt < 2; mt++)
                            mma16b(acc[g][mt][nt], af[mt], bf);
                    }
            }

            if (kb == 3){
                const int base = lrow0 + (p >> 2)*256;
                #pragma unroll
                for (int mt = 0; mt < 2; mt++){
                    #pragma unroll
                    for (int dr = 0; dr < 2; dr++){
                        int lr = base + wm*32 + mt*16 + (lane >> 2) + dr*8;
                        int iroll = lr >> 10;
                        int nb = lr & (N_DIM - 1);
                        int l = dirF ? ((iroll + t) & 15) : ((iroll + 15 - t) & 15);
                        const float* ge = GIe + __ldg(&lines[nb*L_DIM + l])*100;
                        #pragma unroll
                        for (int nt = 0; nt < 2; nt++){
                            int hcl = wn*16 + nt*8 + (lane & 3)*2;
                            float2 gv0 = *(const float2*)&ge[hcl];
                            float2 gv1 = *(const float2*)&ge[32 + hcl];
                            float2 gv2 = *(const float2*)&ge[64 + hcl];
                            float2 hold = unpackbf(__ldcg(
                                (const uint32_t*)(hsrc16 + (size_t)lr*H_DIM + bcol*32 + hcl)));
                            float2 hout;
                            #pragma unroll
                            for (int dc = 0; dc < 2; dc++){
                                float gr = acc[0][mt][nt][dr*2+dc] + bR[nt][dc];
                                float gz = acc[1][mt][nt][dr*2+dc] + bZ[nt][dc];
                                float gn = acc[2][mt][nt][dr*2+dc] + bN[nt][dc];
                                float r  = sigm((dc ? gv0.y : gv0.x) + gr);
                                float z  = sigm((dc ? gv1.y : gv1.x) + gz);
                                float nn = tanhf((dc ? gv2.y : gv2.x) + r*gn);
                                float ho = dc ? hold.y : hold.x;
                                float hnew = (1.f - z)*nn + z*ho;
                                if (dc) hout.y = hnew; else hout.x = hnew;
                            }
                            __stcg((uint32_t*)(hdst16 + (size_t)lr*H_DIM + bcol*32 + hcl),
                                   packbf(hout.x, hout.y));
                        }
                    }
                }
            }
        }
        // flag barrier over the 8 slab CTAs (own store + parallel poll)
        __syncthreads();
        if (tid == 0){
            __threadfence();
            *(volatile unsigned*)&g_eflag[slab][bcol][0] = (unsigned)(t + 1);
        }
        if (wid == 1 && lane < 8){
            while (*(volatile unsigned*)&g_eflag[slab][lane][0] < (unsigned)(t + 1)) { }
            __threadfence();
        }
        __syncthreads();
    }
}

// ---------------- Rproj bf16: Hmem(bf16) @ W0r^T, f32 out -----------------
#define RPB_W_U32 (128*260)
#define RPB_A_U32 (2*256*36)
#define RPB_SMEM_BYTES ((RPB_W_U32 + RPB_A_U32)*4)

__global__ void __launch_bounds__(512, 1)
rproj_b(const float* __restrict__ f_w0)
{
    extern __shared__ uint32_t smu[];
    uint32_t* Ws2 = smu;
    uint32_t* As2 = smu + RPB_W_U32;
    const int tid = threadIdx.x, lane = tid & 31, wid = tid >> 5;
    const int wm = wid >> 1, wn = wid & 1;
    const int bcol = blockIdx.x;
    const int rt = blockIdx.y;

    for (int i = tid; i < 128*256; i += 512){
        int c = i >> 8, kp = i & 255;
        const float* wr = f_w0 + (size_t)(bcol*128 + c)*576 + 64 + 2*kp;
        Ws2[c*260 + kp] = packbf(wr[0], wr[1]);
    }
    const int tA = lane >> 3;
    uint32_t aA[2];
    #pragma unroll
    for (int mt = 0; mt < 2; mt++)
        aA[mt] = sptr(As2) + (uint32_t)(((wm*32 + mt*16 + (tA & 1)*8 + (lane & 7))*36
                                        + (tA >> 1)*4) * 4);
    uint32_t aB[8];
    #pragma unroll
    for (int nt = 0; nt < 8; nt++)
        aB[nt] = sptr(Ws2) + (uint32_t)(((wn*64 + nt*8 + (lane & 7))*260
                                        + ((lane >> 3) & 1)*4) * 4);
    __syncthreads();

    auto stage = [&](int p){
        int kb = p, buf = p & 1;
        const uint32_t* src = (kb < 4)
            ? (const uint32_t*)g_Hfb[0] + (size_t)(rt*256)*128 + kb*32
            : (const uint32_t*)g_Hbb[0] + (size_t)(rt*256)*128 + (kb - 4)*32;
        uint32_t* dst = As2 + buf*256*36;
        #pragma unroll
        for (int i = tid; i < 2048; i += 512){
            int r = i >> 3, q = i & 7;
            cp16(&dst[r*36 + q*4], src + (size_t)r*128 + q*4);
        }
        cp_commit();
    };

    float acc[2][8][4];
    #pragma unroll
    for (int a = 0; a < 2; a++)
        #pragma unroll
        for (int b = 0; b < 8; b++)
            #pragma unroll
            for (int c = 0; c < 4; c++) acc[a][b][c] = 0.f;

    stage(0);
    for (int p = 0; p < 8; p++){
        cp_wait<0>();
        __syncthreads();
        if (p + 1 < 8) stage(p + 1);
        const uint32_t abufofs = (uint32_t)((p & 1)*256*36*4);
        const uint32_t bofs = (uint32_t)(p*128);
        #pragma unroll
        for (int kk = 0; kk < 64; kk += 16){
            uint32_t af[2][4];
            #pragma unroll
            for (int mt = 0; mt < 2; mt++)
                ldsm4(af[mt], aA[mt] + abufofs + kk*2);
            #pragma unroll
            for (int nt = 0; nt < 8; nt++){
                uint32_t bf[2];
                ldsm2(bf, aB[nt] + bofs + kk*2);
                #pragma unroll
                for (int mt = 0; mt < 2; mt++)
                    mma16b(acc[mt][nt], af[mt], bf);
            }
        }
        __syncthreads();
    }

    #pragma unroll
    for (int mt = 0; mt < 2; mt++){
        #pragma unroll
        for (int nt = 0; nt < 8; nt++){
            #pragma unroll
            for (int dr = 0; dr < 2; dr++){
                int rr = rt*256 + wm*32 + mt*16 + (lane >> 2) + dr*8;
                int cc = bcol*128 + wn*64 + nt*8 + (lane & 3)*2;
                float2 v; v.x = acc[mt][nt][dr*2 + 0]; v.y = acc[mt][nt][dr*2 + 1];
                *(float2*)&g_Rproj[(size_t)rr*H_DIM + cc] = v;
            }
        }
    }
}

// ---------------- layer0 bf16 ----------------
#define L0B_W_U32 (128*36)
#define L0B_A_U32 (256*36)
#define L0B_SMEM_BYTES ((L0B_W_U32 + L0B_A_U32)*4)

__global__ void __launch_bounds__(512, 1)
l0_b(const float* __restrict__ cond, const float* __restrict__ f_w0,
     const float* __restrict__ f_b0, const int* __restrict__ active)
{
    extern __shared__ uint32_t smu[];
    uint32_t* Ws2 = smu;
    uint32_t* As2 = smu + L0B_W_U32;
    const int tid = threadIdx.x, lane = tid & 31, wid = tid >> 5;
    const int wm = wid >> 1, wn = wid & 1;
    const int bcol = blockIdx.x;

    for (int i = tid; i < 128*32; i += 512){
        int c = i >> 5, kp = i & 31;
        const float* wr = f_w0 + (size_t)(bcol*128 + c)*576 + 2*kp;
        Ws2[c*36 + kp] = packbf(wr[0], wr[1]);
    }
    const int tA = lane >> 3;
    uint32_t aA[2];
    #pragma unroll
    for (int mt = 0; mt < 2; mt++)
        aA[mt] = sptr(As2) + (uint32_t)(((wm*32 + mt*16 + (tA & 1)*8 + (lane & 7))*36
                                        + (tA >> 1)*4) * 4);
    uint32_t aB[8];
    #pragma unroll
    for (int nt = 0; nt < 8; nt++)
        aB[nt] = sptr(Ws2) + (uint32_t)(((wn*64 + nt*8 + (lane & 7))*36
                                        + ((lane >> 3) & 1)*4) * 4);
    float bias[8][2];
    #pragma unroll
    for (int nt = 0; nt < 8; nt++){
        int cc = bcol*128 + wn*64 + nt*8 + (lane & 3)*2;
        bias[nt][0] = f_b0[cc];
        bias[nt][1] = f_b0[cc + 1];
    }
    __syncthreads();

    for (int rt = blockIdx.y; rt < TN/256; rt += gridDim.y){
        const float4* src = (const float4*)(cond + (size_t)rt*256*C_DIM);
        #pragma unroll
        for (int i = tid; i < 4096; i += 512){
            int r = i >> 4, q = i & 15;
            float4 v = __ldg(&src[r*16 + q]);
            uint32_t* dst = &As2[r*36 + q*2];
            dst[0] = packbf(v.x, v.y);
            dst[1] = packbf(v.z, v.w);
        }
        __syncthreads();

        float acc[2][8][4];
        #pragma unroll
        for (int a = 0; a < 2; a++)
            #pragma unroll
            for (int b = 0; b < 8; b++)
                #pragma unroll
                for (int c = 0; c < 4; c++) acc[a][b][c] = 0.f;

        #pragma unroll
        for (int kk = 0; kk < 64; kk += 16){
            uint32_t af[2][4];
            #pragma unroll
            for (int mt = 0; mt < 2; mt++)
                ldsm4(af[mt], aA[mt] + kk*2);
            #pragma unroll
            for (int nt = 0; nt < 8; nt++){
                uint32_t bf[2];
                ldsm2(bf, aB[nt] + kk*2);
                #pragma unroll
                for (int mt = 0; mt < 2; mt++)
                    mma16b(acc[mt][nt], af[mt], bf);
            }
        }

        #pragma unroll
        for (int mt = 0; mt < 2; mt++){
            #pragma unroll
            for (int dr = 0; dr < 2; dr++){
                int rr = rt*256 + wm*32 + mt*16 + (lane >> 2) + dr*8;
                int n = rr & (N_DIM - 1);
                int w = __ldg(&active[rr]);
                const float* rp = g_Rproj + (size_t)(w*N_DIM + n)*H_DIM;
                #pragma unroll
                for (int nt = 0; nt < 8; nt++){
                    int cc = bcol*128 + wn*64 + nt*8 + (lane & 3)*2;
                    float2 rv = __ldg((const float2*)&rp[cc]);
                    float v0 = fmaxf(acc[mt][nt][dr*2 + 0] + bias[nt][0] + rv.x, 0.f);
                    float v1 = fmaxf(acc[mt][nt][dr*2 + 1] + bias[nt][1] + rv.y, 0.f);
                    g_A0b[(size_t)rr*(H_DIM/2) + (cc >> 1)] = packbf(v0, v1);
                }
            }
        }
        __syncthreads();
    }
}

// ---------------- bf16 feed-forward GEMM + ldmatrix -------------------
#define FFB_W_U32 (128*132)
#define FFB_A_U32 (2*256*36)
#define FFB_SMEM_BYTES ((FFB_W_U32 + FFB_A_U32)*4)

template<int EPI>
__global__ void __launch_bounds__(512, 1)
gemm_ffb(const uint32_t* __restrict__ A, const float* __restrict__ W,
         const float* __restrict__ bias, uint32_t* __restrict__ outp,
         int out_stride, int nrt)
{
    extern __shared__ uint32_t smu[];
    uint32_t* Ws2 = smu;
    uint32_t* As2 = smu + FFB_W_U32;
    const int tid = threadIdx.x, lane = tid & 31, wid = tid >> 5;
    const int wm = wid >> 1, wn = wid & 1;
    const int bcol = blockIdx.x;

    for (int i = tid; i < 128*128; i += 512){
        int c = i >> 7, kp = i & 127;
        const float* wr = W + (size_t)(bcol*128 + c)*H_DIM + 2*kp;
        Ws2[c*132 + kp] = packbf(wr[0], wr[1]);
    }
    const int tA = lane >> 3;
    uint32_t aA[2];
    #pragma unroll
    for (int mt = 0; mt < 2; mt++)
        aA[mt] = sptr(As2) + (uint32_t)(((wm*32 + mt*16 + (tA & 1)*8 + (lane & 7))*36
                                        + (tA >> 1)*4) * 4);
    uint32_t aB[8];
    #pragma unroll
    for (int nt = 0; nt < 8; nt++)
        aB[nt] = sptr(Ws2) + (uint32_t)(((wn*64 + nt*8 + (lane & 7))*132
                                        + ((lane >> 3) & 1)*4) * 4);
    __syncthreads();

    const int nch = (nrt - (int)blockIdx.y + (int)gridDim.y - 1) / (int)gridDim.y;
    if (nch <= 0) return;
    const int total = nch*4;

    auto stage = [&](int p){
        int ci = p >> 2, kb = p & 3, buf = p & 1;
        int rt = blockIdx.y + ci*gridDim.y;
        const uint32_t* src = A + (size_t)rt*256*128 + kb*32;
        uint32_t* dst = As2 + buf*256*36;
        #pragma unroll
        for (int i = tid; i < 2048; i += 512){
            int r = i >> 3, q = i & 7;
            cp16(&dst[r*36 + q*4], src + (size_t)r*128 + q*4);
        }
        cp_commit();
    };

    float acc[2][8][4];
    stage(0);
    for (int p = 0; p < total; p++){
        cp_wait<0>();
        __syncthreads();
        if (p + 1 < total) stage(p + 1);
        const int kb = p & 3;
        if (kb == 0){
            #pragma unroll
            for (int a = 0; a < 2; a++)
                #pragma unroll
                for (int b = 0; b < 8; b++)
                    #pragma unroll
                    for (int c = 0; c < 4; c++) acc[a][b][c] = 0.f;
        }
        const uint32_t abufofs = (uint32_t)((p & 1)*256*36*4);
        const uint32_t bofs = (uint32_t)(kb*128);
        #pragma unroll
        for (int kk = 0; kk < 64; kk += 16){
            uint32_t af[2][4];
            #pragma unroll
            for (int mt = 0; mt < 2; mt++)
                ldsm4(af[mt], aA[mt] + abufofs + kk*2);
            #pragma unroll
            for (int nt = 0; nt < 8; nt++){
                uint32_t bf[2];
                ldsm2(bf, aB[nt] + bofs + kk*2);
                #pragma unroll
                for (int mt = 0; mt < 2; mt++)
                    mma16b(acc[mt][nt], af[mt], bf);
            }
        }

        if (kb == 3){
            int rt = blockIdx.y + (p >> 2)*gridDim.y;
            #pragma unroll
            for (int mt = 0; mt < 2; mt++){
                #pragma unroll
                for (int nt = 0; nt < 8; nt++){
                    #pragma unroll
                    for (int dr = 0; dr < 2; dr++){
                        int rr = rt*256 + wm*32 + mt*16 + (lane >> 2) + dr*8;
                        int cc = bcol*128 + wn*64 + nt*8 + (lane & 3)*2;
                        float v0 = acc[mt][nt][dr*2 + 0] + bias[cc];
                        float v1 = acc[mt][nt][dr*2 + 1] + bias[cc + 1];
                        if (EPI == 1){ v0 = fmaxf(v0, 0.f); v1 = fmaxf(v1, 0.f); }
                        outp[(size_t)rr*out_stride + (cc >> 1)] = packbf(v0, v1);
                    }
                }
            }
        }
    }
}

// ---------------- main GRU v12: 16 rows x 128 cols, pair-flag barrier --------------
#define M12_W_U32 (384*132)
#define M12_A_U32 (16*132)
#define M12_G_U32 (16*200)
#define M12_SMEM_BYTES ((M12_W_U32 + M12_A_U32 + M12_G_U32)*4)

__global__ void __launch_bounds__(256, 1)
main_gru_v12(const float* __restrict__ whh, const float* __restrict__ bhh)
{
    extern __shared__ uint32_t smu[];
    uint32_t* Ws2 = smu;
    uint32_t* As2 = smu + M12_W_U32;
    uint32_t* GIs = smu + M12_W_U32 + M12_A_U32;
    const int tid = threadIdx.x, lane = tid & 31, w = tid >> 5;
    const int me = blockIdx.x;
    const int rg = blockIdx.y;
    const int row0 = rg*16;

    for (int i = tid; i < 384*128; i += 256){
        int row = i >> 7, kp = i & 127;
        int g = row >> 7, cl = row & 127;
        const float* wr = whh + (size_t)(g*H_DIM + me*128 + cl)*H_DIM + 2*kp;
        Ws2[row*132 + kp] = packbf(wr[0], wr[1]);
    }
    float bR[2][2], bZ[2][2], bN[2][2];
    #pragma unroll
    for (int ct = 0; ct < 2; ct++)
        #pragma unroll
        for (int dc = 0; dc < 2; dc++){
            int c = me*128 + w*16 + ct*8 + (lane & 3)*2 + dc;
            bR[ct][dc] = bhh[c];
            bZ[ct][dc] = bhh[H_DIM + c];
            bN[ct][dc] = bhh[2*H_DIM + c];
        }
    const int tA = lane >> 3;
    const uint32_t aA = sptr(As2) + (uint32_t)((((tA & 1)*8 + (lane & 7))*132
                                        + (tA >> 1)*4) * 4);
    uint32_t aB[6];
    #pragma unroll
    for (int nt = 0; nt < 6; nt++){
        int g = nt >> 1, ct = nt & 1;
        aB[nt] = sptr(Ws2) + (uint32_t)(((g*128 + w*16 + ct*8 + (lane & 7))*132
                                        + ((lane >> 3) & 1)*4) * 4);
    }

    auto stage_gi = [&](int tt){
        const uint32_t* gsrc = g_GIb + ((size_t)tt*N_DIM + row0)*(G3/2) + me*64;
        #pragma unroll
        for (int i = tid; i < 768; i += 256){
            int r = i / 48, j = i % 48;
            int g = j >> 4, q = j & 15;
            cp16(&GIs[r*200 + g*64 + q*4], gsrc + (size_t)r*(G3/2) + g*128 + q*4);
        }
        cp_commit();
    };

    stage_gi(0);
    __syncthreads();

    for (int t = 0; t < T_DIM; t++){
        const uint16_t* __restrict__ hsrc16 = g_hmb[t & 1];
        uint16_t* __restrict__ hdst16 = g_hmb[(t + 1) & 1];
        const float* __restrict__ hsrcf = (t == 0) ? g_hm0
                                        : g_hall + (size_t)(t - 1)*N_DIM*H_DIM;
        float* __restrict__ hdstf = g_hall + (size_t)t*N_DIM*H_DIM;

        {
            const uint16_t* src = hsrc16 + (size_t)row0*H_DIM;
            #pragma unroll
            for (int i = tid; i < 512; i += 256){
                int r = i >> 5, q = i & 31;
                cp16(&As2[r*132 + q*4], src + (size_t)r*H_DIM + q*8);
            }
            cp_commit();
        }
        cp_wait<0>();
        __syncthreads();

        float acc[6][4];
        #pragma unroll
        for (int n = 0; n < 6; n++)
            #pragma unroll
            for (int c = 0; c < 4; c++) acc[n][c] = 0.f;

        #pragma unroll 4
        for (int kk = 0; kk < H_DIM; kk += 16){
            uint32_t af[4];
            ldsm4(af, aA + kk*2);
            #pragma unroll
            for (int nt = 0; nt < 6; nt++){
                uint32_t bf[2];
                ldsm2(bf, aB[nt] + kk*2);
                mma16b(acc[nt], af, bf);
            }
        }

        #pragma unroll
        for (int dr = 0; dr < 2; dr++){
            int r = (lane >> 2) + dr*8;
            int row = row0 + r;
            #pragma unroll
            for (int ct = 0; ct < 2; ct++){
                int cl = w*16 + ct*8 + (lane & 3)*2;
                int gcol = me*128 + cl;
                float2 gv0 = unpackbf(GIs[r*200 +       (cl >> 1)]);
                float2 gv1 = unpackbf(GIs[r*200 +  64 + (cl >> 1)]);
                float2 gv2 = unpackbf(GIs[r*200 + 128 + (cl >> 1)]);
                float2 hold = __ldcg((const float2*)&hsrcf[(size_t)row*H_DIM + gcol]);
                float2 hout;
                #pragma unroll
                for (int dc = 0; dc < 2; dc++){
                    float gr = acc[0*2 + ct][dr*2+dc] + bR[ct][dc];
                    float gz = acc[1*2 + ct][dr*2+dc] + bZ[ct][dc];
                    float gn = acc[2*2 + ct][dr*2+dc] + bN[ct][dc];
                    float rr = sigm((dc ? gv0.y : gv0.x) + gr);
                    float zz = sigm((dc ? gv1.y : gv1.x) + gz);
                    float nn = tanhf((dc ? gv2.y : gv2.x) + rr*gn);
                    float ho = dc ? hold.y : hold.x;
                    float hnew = (1.f - zz)*nn + zz*ho;
                    if (dc) hout.y = hnew; else hout.x = hnew;
                }
                __stcg((float2*)&hdstf[(size_t)row*H_DIM + gcol], hout);
                __stcg((uint32_t*)(hdst16 + (size_t)row*H_DIM + gcol),
                       packbf(hout.x, hout.y));
            }
        }

        __syncthreads();
        if (t + 1 < T_DIM) stage_gi(t + 1);

        if (tid == 0){
            __threadfence();
            *(volatile unsigned*)&g_pflag[rg][me][0] = (unsigned)(t + 1);
        }
        if (tid == 32){
            while (*(volatile unsigned*)&g_pflag[rg][me ^ 1][0] < (unsigned)(t + 1)) { }
            __threadfence();
        }
        __syncthreads();
    }
}

// ---------------- heads v2 ----------------
__global__ void __launch_bounds__(256)
heads_kernel(float* __restrict__ out, const int* __restrict__ actions,
             const int* __restrict__ active, const float* __restrict__ p0,
             const float* __restrict__ pp0,
             const float* __restrict__ w_actor, const float* __restrict__ b_actor,
             const float* __restrict__ w_critic, const float* __restrict__ b_critic)
{
    int wid = threadIdx.x >> 5, lane = threadIdx.x & 31;
    size_t row = (size_t)blockIdx.x*8 + wid;
    const float* hrow = g_hall + row*H_DIM;
    float* orow = out + row*ROW_OUT;
    float hv[8];
    #pragma unroll
    for (int i = 0; i < 8; i++) hv[i] = hrow[lane + 32*i];

    float lg = 0.f;
    #pragma unroll
    for (int a = 0; a < NA_DIM; a++){
        float s = 0.f;
        #pragma unroll
        for (int i = 0; i < 8; i++) s += hv[i]*w_actor[a*H_DIM + lane + 32*i];
        #pragma unroll
        for (int o = 16; o > 0; o >>= 1) s += __shfl_xor_sync(0xffffffffu, s, o);
        if (lane == a) lg = s + b_actor[a];
    }
    float m = (lane < NA_DIM) ? lg : -1e30f;
    #pragma unroll
    for (int o = 16; o > 0; o >>= 1) m = fmaxf(m, __shfl_xor_sync(0xffffffffu, m, o));
    float e = (lane < NA_DIM) ? expf(lg - m) : 0.f;
    float den = e;
    #pragma unroll
    for (int o = 16; o > 0; o >>= 1) den += __shfl_xor_sync(0xffffffffu, den, o);

    #pragma unroll
    for (int i = 0; i < 8; i++) orow[4 + lane + 32*i] = hv[i];
    if (lane < NA_DIM) orow[260 + lane] = e/den;

    float s = 0.f;
    #pragma unroll
    for (int i = 0; i < 8; i++) s += hv[i]*w_critic[lane + 32*i];
    #pragma unroll
    for (int o = 16; o > 0; o >>= 1) s += __shfl_xor_sync(0xffffffffu, s, o);

    int n = (int)(row & (N_DIM - 1));
    if (lane == 0)  orow[3]   = s + b_critic[0];
    if (lane == 16) orow[0]   = (float)actions[row];
    if (lane == 17) orow[1]   = p0[n];
    if (lane == 18) orow[2]   = (float)active[row];
    if (lane == 19) orow[276] = pp0[n*2];
    if (lane == 20) orow[277] = pp0[n*2 + 1];
}

// ---------------- launch ----------------
extern "C" void kernel_launch(void* const* d_in, const int* in_sizes, int n_in,
                              void* d_out, int out_size)
{
    (void)in_sizes; (void)n_in; (void)out_size;
    const float* condition = (const float*)d_in[0];
    const int*   active    = (const int*)d_in[1];
    const int*   lines     = (const int*)d_in[2];
    const int*   actions   = (const int*)d_in[3];
    const float* h0        = (const float*)d_in[4];
    const float* p0        = (const float*)d_in[5];
    const float* pp0       = (const float*)d_in[6];
    const float* embed     = (const float*)d_in[7];
    const float* wih_f = (const float*)d_in[8],  *whh_f = (const float*)d_in[9];
    const float* bih_f = (const float*)d_in[10], *bhh_f = (const float*)d_in[11];
    const float* wih_b = (const float*)d_in[12], *whh_b = (const float*)d_in[13];
    const float* bih_b = (const float*)d_in[14], *bhh_b = (const float*)d_in[15];
    const float* f_w0 = (const float*)d_in[16], *f_b0 = (const float*)d_in[17];
    const float* f_w1 = (const float*)d_in[18], *f_b1 = (const float*)d_in[19];
    const float* f_w2 = (const float*)d_in[20], *f_b2 = (const float*)d_in[21];
    const float* c_wih = (const float*)d_in[22], *c_whh = (const float*)d_in[23];
    const float* c_bih = (const float*)d_in[24], *c_bhh = (const float*)d_in[25];
    const float* w_critic = (const float*)d_in[26], *b_critic = (const float*)d_in[27];
    const float* w_actor  = (const float*)d_in[28], *b_actor  = (const float*)d_in[29];
    float* out = (float*)d_out;

    uint32_t *A0bp, *A1bp, *GIbp;
    cudaGetSymbolAddress((void**)&A0bp, g_A0b);
    cudaGetSymbolAddress((void**)&A1bp, g_A1b);
    cudaGetSymbolAddress((void**)&GIbp, g_GIb);

    cudaFuncSetAttribute(enc_v9,
                         cudaFuncAttributeMaxDynamicSharedMemorySize, E7_SMEM_BYTES);
    cudaFuncSetAttribute(main_gru_v12,
                         cudaFuncAttributeMaxDynamicSharedMemorySize, M12_SMEM_BYTES);
    cudaFuncSetAttribute(rproj_b,
                         cudaFuncAttributeMaxDynamicSharedMemorySize, RPB_SMEM_BYTES);
    cudaFuncSetAttribute(l0_b,
                         cudaFuncAttributeMaxDynamicSharedMemorySize, L0B_SMEM_BYTES);
    cudaFuncSetAttribute(gemm_ffb<1>,
                         cudaFuncAttributeMaxDynamicSharedMemorySize, FFB_SMEM_BYTES);
    cudaFuncSetAttribute(gemm_ffb<3>,
                         cudaFuncAttributeMaxDynamicSharedMemorySize, FFB_SMEM_BYTES);

    // 0) gi tables + state init (also resets flags)
    gi_tables<<<(2*NL_DIM*G3 + 255)/256, 256>>>(embed, wih_f, bih_f, wih_b, bih_b);
    init_state<<<4096, 256>>>(h0);

    // 1) persistent bidirectional encoder (bf16-only h, flag barrier)
    enc_v9<<<dim3(8, 16), 512, E7_SMEM_BYTES>>>(whh_f, bhh_f, whh_b, bhh_b, lines);

    // 2) Rproj = Hmem @ W0r^T  (bf16 + ldmatrix, f32 out)
    rproj_b<<<dim3(2, 64), 512, RPB_SMEM_BYTES>>>(f_w0);
    // 3) A0 = relu(cond @ W0c^T + Rproj[active] + b0)
    l0_b<<<dim3(2, 74), 512, L0B_SMEM_BYTES>>>(condition, f_w0, f_b0, active);
    // 4) A1 = relu(A0 @ w1^T + b1); A0'' = relu(A1 @ w2^T + b2)
    gemm_ffb<1><<<dim3(2, 74), 512, FFB_SMEM_BYTES>>>(A0bp, f_w1, f_b1, A1bp, 128, 1024);
    gemm_ffb<1><<<dim3(2, 74), 512, FFB_SMEM_BYTES>>>(A1bp, f_w2, f_b2, A0bp, 128, 1024);
    // 5) GI = A0'' @ c_wih^T + c_bih  -> packed bf16
    gemm_ffb<3><<<dim3(6, 24), 512, FFB_SMEM_BYTES>>>(A0bp, c_wih, c_bih, GIbp, 384, 1024);

    // 6) main GRU v12: pair-flag barrier
    main_gru_v12<<<dim3(2, 64), 256, M12_SMEM_BYTES>>>(c_whh, c_bhh);

    // 7) heads v2
    heads_kernel<<<TN/8, 256>>>(out, actions, active, p0, pp0,
                                w_actor, b_actor, w_critic, b_critic);
}

// round 17
// speedup vs baseline: 3.6628x; 1.0176x over previous
#include <cuda_runtime.h>
#include <math.h>
#include <stdint.h>

#define T_DIM 256
#define N_DIM 1024
#define H_DIM 256
#define L_DIM 16
#define NL_DIM 32
#define C_DIM 64
#define NA_DIM 16
#define ROW_OUT 278
#define G3 768
#define LN (L_DIM*N_DIM)          /* 16384 */
#define TN (T_DIM*N_DIM)          /* 262144 */

// ---------------- scratch ----------------
__device__ float g_giF[NL_DIM*G3];
__device__ float g_giB[NL_DIM*G3];
__device__ uint16_t g_Hfb[2][(size_t)LN*H_DIM];
__device__ uint16_t g_Hbb[2][(size_t)LN*H_DIM];
__device__ float g_Rproj[(size_t)LN*H_DIM];
__device__ uint32_t g_A0b[(size_t)TN*(H_DIM/2)];
__device__ uint32_t g_A1b[(size_t)TN*(H_DIM/2)];
__device__ uint32_t g_GIb[(size_t)TN*(G3/2)];
__device__ float g_hall[(size_t)TN*H_DIM];
__device__ float g_hm0[N_DIM*H_DIM];
__device__ uint16_t g_hmb[2][N_DIM*H_DIM];
__device__ unsigned g_pflag[64][2][32];
__device__ unsigned g_eflag[16][8][32];

// ---------------- helpers ----------------
__device__ __forceinline__ uint32_t packbf(float lo, float hi){
    uint32_t r; asm("cvt.rn.bf16x2.f32 %0, %1, %2;" : "=r"(r) : "f"(hi), "f"(lo)); return r;
}
__device__ __forceinline__ float2 unpackbf(uint32_t u){
    float2 r;
    r.x = __uint_as_float(u << 16);
    r.y = __uint_as_float(u & 0xffff0000u);
    return r;
}
__device__ __forceinline__ void mma16b(float* c, const uint32_t* a, const uint32_t* b){
    asm volatile("mma.sync.aligned.m16n8k16.row.col.f32.bf16.bf16.f32 "
        "{%0,%1,%2,%3},{%4,%5,%6,%7},{%8,%9},{%0,%1,%2,%3};"
        : "+f"(c[0]), "+f"(c[1]), "+f"(c[2]), "+f"(c[3])
        : "r"(a[0]), "r"(a[1]), "r"(a[2]), "r"(a[3]), "r"(b[0]), "r"(b[1]));
}
__device__ __forceinline__ void ldsm4(uint32_t* r, uint32_t saddr){
    asm volatile("ldmatrix.sync.aligned.m8n8.x4.shared.b16 {%0,%1,%2,%3}, [%4];"
        : "=r"(r[0]), "=r"(r[1]), "=r"(r[2]), "=r"(r[3]) : "r"(saddr));
}
__device__ __forceinline__ void ldsm2(uint32_t* r, uint32_t saddr){
    asm volatile("ldmatrix.sync.aligned.m8n8.x2.shared.b16 {%0,%1}, [%2];"
        : "=r"(r[0]), "=r"(r[1]) : "r"(saddr));
}
__device__ __forceinline__ uint32_t sptr(const void* p){
    return (uint32_t)__cvta_generic_to_shared(p);
}
__device__ __forceinline__ float sigm(float x){ return 1.f/(1.f+expf(-x)); }
__device__ __forceinline__ void cp16(void* smem_dst, const void* gsrc){
    uint32_t s = (uint32_t)__cvta_generic_to_shared(smem_dst);
    asm volatile("cp.async.cg.shared.global [%0], [%1], 16;" :: "r"(s), "l"(gsrc));
}
__device__ __forceinline__ void cp_commit(){ asm volatile("cp.async.commit_group;"); }
template<int N> __device__ __forceinline__ void cp_wait(){
    asm volatile("cp.async.wait_group %0;" :: "n"(N));
}

// ---------------- gi tables ----------------
__global__ void gi_tables(const float* __restrict__ embed,
                          const float* __restrict__ wihF, const float* __restrict__ bihF,
                          const float* __restrict__ wihB, const float* __restrict__ bihB)
{
    int idx = blockIdx.x*blockDim.x + threadIdx.x;
    if (idx >= 2*NL_DIM*G3) return;
    int dir = idx / (NL_DIM*G3);
    int rem = idx % (NL_DIM*G3);
    int e = rem / G3, j = rem % G3;
    const float* wih = dir ? wihB : wihF;
    const float* bih = dir ? bihB : bihF;
    float s = bih[j];
    const float* em = embed + e*H_DIM;
    const float* w  = wih + (size_t)j*H_DIM;
    #pragma unroll 8
    for (int k = 0; k < H_DIM; k++) s += em[k]*w[k];
    (dir ? g_giB : g_giF)[rem] = s;
}

// ---------------- init ----------------
__global__ void init_state(const float* __restrict__ h0)
{
    size_t stride = (size_t)gridDim.x*blockDim.x;
    size_t i0 = (size_t)blockIdx.x*blockDim.x + threadIdx.x;
    size_t HS = (size_t)LN*H_DIM;
    for (size_t p = i0; p < HS; p += stride){
        g_Hfb[0][p] = 0;  g_Hbb[0][p] = 0;
    }
    for (size_t p = i0; p < (size_t)N_DIM*H_DIM; p += stride){
        float v = h0[p];
        g_hm0[p] = v;
        g_hmb[0][p] = (uint16_t)(packbf(v, 0.f) & 0xffffu);
    }
    for (size_t p = i0; p < 64*2*32; p += stride)
        ((unsigned*)g_pflag)[p] = 0u;
    for (size_t p = i0; p < 16*8*32; p += stride)
        ((unsigned*)g_eflag)[p] = 0u;
}

// ---------------- persistent encoder v10: K-chunk 128 (16 stages/step) -------------
#define E10_W_U32 (3*32*132)               /* 12672 */
#define E10_A_U32 (2*256*68)               /* 34816 */
#define E10_G_FLOATS (NL_DIM*100)          /* 3200  */
#define E10_SMEM_BYTES ((E10_W_U32 + E10_A_U32 + E10_G_FLOATS)*4)

__global__ void __launch_bounds__(512, 1)
enc_v10(const float* __restrict__ whF, const float* __restrict__ bhF,
        const float* __restrict__ whB, const float* __restrict__ bhB,
        const int* __restrict__ lines)
{
    extern __shared__ uint32_t smu[];
    uint32_t* Ws2 = smu;
    uint32_t* As2 = smu + E10_W_U32;
    float* GIe = (float*)(smu + E10_W_U32 + E10_A_U32);
    const int tid = threadIdx.x, lane = tid & 31, wid = tid >> 5;
    const int wm = wid >> 1, wn = wid & 1;
    const int bcol = blockIdx.x;
    const int slab = blockIdx.y;
    const bool dirF = (slab < 8);
    const float* __restrict__ W  = dirF ? whF : whB;
    const float* __restrict__ bh = dirF ? bhF : bhB;
    const float* __restrict__ giT = dirF ? g_giF : g_giB;
    const int lrow0 = (dirF ? slab : slab - 8) * 2048;

    for (int i = tid; i < 3*32*128; i += 512){
        int g = i >> 12, rem = i & 4095;
        int c = rem >> 7, kp = rem & 127;
        const float* wr = W + (size_t)(g*H_DIM + bcol*32 + c)*H_DIM + 2*kp;
        Ws2[(g*32 + c)*132 + kp] = packbf(wr[0], wr[1]);
    }
    for (int i = tid; i < NL_DIM*96; i += 512){
        int e = i / 96, j = i % 96;
        int g = j >> 5, c = j & 31;
        GIe[e*100 + j] = __ldg(&giT[e*G3 + g*H_DIM + bcol*32 + c]);
    }
    float bR[2][2], bZ[2][2], bN[2][2];
    #pragma unroll
    for (int nt = 0; nt < 2; nt++)
        #pragma unroll
        for (int dc = 0; dc < 2; dc++){
            int c = bcol*32 + wn*16 + nt*8 + (lane & 3)*2 + dc;
            bR[nt][dc] = bh[c];
            bZ[nt][dc] = bh[H_DIM + c];
            bN[nt][dc] = bh[2*H_DIM + c];
        }
    const int tA = lane >> 3;
    uint32_t aA[2];
    #pragma unroll
    for (int mt = 0; mt < 2; mt++)
        aA[mt] = sptr(As2) + (uint32_t)(((wm*32 + mt*16 + (tA & 1)*8 + (lane & 7))*68
                                        + (tA >> 1)*4) * 4);
    uint32_t aB[3][2];
    #pragma unroll
    for (int g = 0; g < 3; g++)
        #pragma unroll
        for (int nt = 0; nt < 2; nt++)
            aB[g][nt] = sptr(Ws2) + (uint32_t)(((g*32 + wn*16 + nt*8 + (lane & 7))*132
                                        + ((lane >> 3) & 1)*4) * 4);
    __syncthreads();

    for (int t = 0; t < L_DIM; t++){
        const uint16_t* __restrict__ hsrc16 = dirF ? g_Hfb[t & 1] : g_Hbb[t & 1];
        uint16_t* __restrict__ hdst16 = dirF ? g_Hfb[(t + 1) & 1] : g_Hbb[(t + 1) & 1];

        // stage p: chunk = p>>1 (256 rows), kb = p&1 (128 K-elements)
        auto stage = [&](int p){
            int chunk = p >> 1, kb = p & 1, buf = p & 1;
            const uint16_t* src = hsrc16 + (size_t)(lrow0 + chunk*256)*H_DIM + kb*128;
            uint32_t* dst = As2 + buf*256*68;
            #pragma unroll
            for (int i = tid; i < 4096; i += 512){
                int r = i >> 4, q = i & 15;
                cp16(&dst[r*68 + q*4], src + (size_t)r*H_DIM + q*8);
            }
            cp_commit();
        };

        float acc[3][2][2][4];
        stage(0);
        for (int p = 0; p < 16; p++){
            cp_wait<0>();
            __syncthreads();
            if (p + 1 < 16) stage(p + 1);
            const int kb = p & 1;
            if (kb == 0){
                #pragma unroll
                for (int g = 0; g < 3; g++)
                    #pragma unroll
                    for (int a = 0; a < 2; a++)
                        #pragma unroll
                        for (int b = 0; b < 2; b++)
                            #pragma unroll
                            for (int c = 0; c < 4; c++) acc[g][a][b][c] = 0.f;
            }
            const uint32_t abufofs = (uint32_t)((p & 1)*256*68*4);
            const uint32_t bofs = (uint32_t)(kb*256);
            #pragma unroll
            for (int kk = 0; kk < 128; kk += 16){
                uint32_t af[2][4];
                #pragma unroll
                for (int mt = 0; mt < 2; mt++)
                    ldsm4(af[mt], aA[mt] + abufofs + kk*2);
                #pragma unroll
                for (int g = 0; g < 3; g++)
                    #pragma unroll
                    for (int nt = 0; nt < 2; nt++){
                        uint32_t bf[2];
                        ldsm2(bf, aB[g][nt] + bofs + kk*2);
                        #pragma unroll
                        for (int mt = 0; mt < 2; mt++)
                            mma16b(acc[g][mt][nt], af[mt], bf);
                    }
            }

            if (kb == 1){
                const int base = lrow0 + (p >> 1)*256;
                #pragma unroll
                for (int mt = 0; mt < 2; mt++){
                    #pragma unroll
                    for (int dr = 0; dr < 2; dr++){
                        int lr = base + wm*32 + mt*16 + (lane >> 2) + dr*8;
                        int iroll = lr >> 10;
                        int nb = lr & (N_DIM - 1);
                        int l = dirF ? ((iroll + t) & 15) : ((iroll + 15 - t) & 15);
                        const float* ge = GIe + __ldg(&lines[nb*L_DIM + l])*100;
                        #pragma unroll
                        for (int nt = 0; nt < 2; nt++){
                            int hcl = wn*16 + nt*8 + (lane & 3)*2;
                            float2 gv0 = *(const float2*)&ge[hcl];
                            float2 gv1 = *(const float2*)&ge[32 + hcl];
                            float2 gv2 = *(const float2*)&ge[64 + hcl];
                            float2 hold = unpackbf(__ldcg(
                                (const uint32_t*)(hsrc16 + (size_t)lr*H_DIM + bcol*32 + hcl)));
                            float2 hout;
                            #pragma unroll
                            for (int dc = 0; dc < 2; dc++){
                                float gr = acc[0][mt][nt][dr*2+dc] + bR[nt][dc];
                                float gz = acc[1][mt][nt][dr*2+dc] + bZ[nt][dc];
                                float gn = acc[2][mt][nt][dr*2+dc] + bN[nt][dc];
                                float r  = sigm((dc ? gv0.y : gv0.x) + gr);
                                float z  = sigm((dc ? gv1.y : gv1.x) + gz);
                                float nn = tanhf((dc ? gv2.y : gv2.x) + r*gn);
                                float ho = dc ? hold.y : hold.x;
                                float hnew = (1.f - z)*nn + z*ho;
                                if (dc) hout.y = hnew; else hout.x = hnew;
                            }
                            __stcg((uint32_t*)(hdst16 + (size_t)lr*H_DIM + bcol*32 + hcl),
                                   packbf(hout.x, hout.y));
                        }
                    }
                }
            }
        }
        __syncthreads();
        if (tid == 0){
            __threadfence();
            *(volatile unsigned*)&g_eflag[slab][bcol][0] = (unsigned)(t + 1);
        }
        if (wid == 1 && lane < 8){
            while (*(volatile unsigned*)&g_eflag[slab][lane][0] < (unsigned)(t + 1)) { }
            __threadfence();
        }
        __syncthreads();
    }
}

// ---------------- Rproj bf16 ----------------
#define RPB_W_U32 (128*260)
#define RPB_A_U32 (2*256*36)
#define RPB_SMEM_BYTES ((RPB_W_U32 + RPB_A_U32)*4)

__global__ void __launch_bounds__(512, 1)
rproj_b(const float* __restrict__ f_w0)
{
    extern __shared__ uint32_t smu[];
    uint32_t* Ws2 = smu;
    uint32_t* As2 = smu + RPB_W_U32;
    const int tid = threadIdx.x, lane = tid & 31, wid = tid >> 5;
    const int wm = wid >> 1, wn = wid & 1;
    const int bcol = blockIdx.x;
    const int rt = blockIdx.y;

    for (int i = tid; i < 128*256; i += 512){
        int c = i >> 8, kp = i & 255;
        const float* wr = f_w0 + (size_t)(bcol*128 + c)*576 + 64 + 2*kp;
        Ws2[c*260 + kp] = packbf(wr[0], wr[1]);
    }
    const int tA = lane >> 3;
    uint32_t aA[2];
    #pragma unroll
    for (int mt = 0; mt < 2; mt++)
        aA[mt] = sptr(As2) + (uint32_t)(((wm*32 + mt*16 + (tA & 1)*8 + (lane & 7))*36
                                        + (tA >> 1)*4) * 4);
    uint32_t aB[8];
    #pragma unroll
    for (int nt = 0; nt < 8; nt++)
        aB[nt] = sptr(Ws2) + (uint32_t)(((wn*64 + nt*8 + (lane & 7))*260
                                        + ((lane >> 3) & 1)*4) * 4);
    __syncthreads();

    auto stage = [&](int p){
        int kb = p, buf = p & 1;
        const uint32_t* src = (kb < 4)
            ? (const uint32_t*)g_Hfb[0] + (size_t)(rt*256)*128 + kb*32
            : (const uint32_t*)g_Hbb[0] + (size_t)(rt*256)*128 + (kb - 4)*32;
        uint32_t* dst = As2 + buf*256*36;
        #pragma unroll
        for (int i = tid; i < 2048; i += 512){
            int r = i >> 3, q = i & 7;
            cp16(&dst[r*36 + q*4], src + (size_t)r*128 + q*4);
        }
        cp_commit();
    };

    float acc[2][8][4];
    #pragma unroll
    for (int a = 0; a < 2; a++)
        #pragma unroll
        for (int b = 0; b < 8; b++)
            #pragma unroll
            for (int c = 0; c < 4; c++) acc[a][b][c] = 0.f;

    stage(0);
    for (int p = 0; p < 8; p++){
        cp_wait<0>();
        __syncthreads();
        if (p + 1 < 8) stage(p + 1);
        const uint32_t abufofs = (uint32_t)((p & 1)*256*36*4);
        const uint32_t bofs = (uint32_t)(p*128);
        #pragma unroll
        for (int kk = 0; kk < 64; kk += 16){
            uint32_t af[2][4];
            #pragma unroll
            for (int mt = 0; mt < 2; mt++)
                ldsm4(af[mt], aA[mt] + abufofs + kk*2);
            #pragma unroll
            for (int nt = 0; nt < 8; nt++){
                uint32_t bf[2];
                ldsm2(bf, aB[nt] + bofs + kk*2);
                #pragma unroll
                for (int mt = 0; mt < 2; mt++)
                    mma16b(acc[mt][nt], af[mt], bf);
            }
        }
        __syncthreads();
    }

    #pragma unroll
    for (int mt = 0; mt < 2; mt++){
        #pragma unroll
        for (int nt = 0; nt < 8; nt++){
            #pragma unroll
            for (int dr = 0; dr < 2; dr++){
                int rr = rt*256 + wm*32 + mt*16 + (lane >> 2) + dr*8;
                int cc = bcol*128 + wn*64 + nt*8 + (lane & 3)*2;
                float2 v; v.x = acc[mt][nt][dr*2 + 0]; v.y = acc[mt][nt][dr*2 + 1];
                *(float2*)&g_Rproj[(size_t)rr*H_DIM + cc] = v;
            }
        }
    }
}

// ---------------- layer0 bf16 ----------------
#define L0B_W_U32 (128*36)
#define L0B_A_U32 (256*36)
#define L0B_SMEM_BYTES ((L0B_W_U32 + L0B_A_U32)*4)

__global__ void __launch_bounds__(512, 1)
l0_b(const float* __restrict__ cond, const float* __restrict__ f_w0,
     const float* __restrict__ f_b0, const int* __restrict__ active)
{
    extern __shared__ uint32_t smu[];
    uint32_t* Ws2 = smu;
    uint32_t* As2 = smu + L0B_W_U32;
    const int tid = threadIdx.x, lane = tid & 31, wid = tid >> 5;
    const int wm = wid >> 1, wn = wid & 1;
    const int bcol = blockIdx.x;

    for (int i = tid; i < 128*32; i += 512){
        int c = i >> 5, kp = i & 31;
        const float* wr = f_w0 + (size_t)(bcol*128 + c)*576 + 2*kp;
        Ws2[c*36 + kp] = packbf(wr[0], wr[1]);
    }
    const int tA = lane >> 3;
    uint32_t aA[2];
    #pragma unroll
    for (int mt = 0; mt < 2; mt++)
        aA[mt] = sptr(As2) + (uint32_t)(((wm*32 + mt*16 + (tA & 1)*8 + (lane & 7))*36
                                        + (tA >> 1)*4) * 4);
    uint32_t aB[8];
    #pragma unroll
    for (int nt = 0; nt < 8; nt++)
        aB[nt] = sptr(Ws2) + (uint32_t)(((wn*64 + nt*8 + (lane & 7))*36
                                        + ((lane >> 3) & 1)*4) * 4);
    float bias[8][2];
    #pragma unroll
    for (int nt = 0; nt < 8; nt++){
        int cc = bcol*128 + wn*64 + nt*8 + (lane & 3)*2;
        bias[nt][0] = f_b0[cc];
        bias[nt][1] = f_b0[cc + 1];
    }
    __syncthreads();

    for (int rt = blockIdx.y; rt < TN/256; rt += gridDim.y){
        const float4* src = (const float4*)(cond + (size_t)rt*256*C_DIM);
        #pragma unroll
        for (int i = tid; i < 4096; i += 512){
            int r = i >> 4, q = i & 15;
            float4 v = __ldg(&src[r*16 + q]);
            uint32_t* dst = &As2[r*36 + q*2];
            dst[0] = packbf(v.x, v.y);
            dst[1] = packbf(v.z, v.w);
        }
        __syncthreads();

        float acc[2][8][4];
        #pragma unroll
        for (int a = 0; a < 2; a++)
            #pragma unroll
            for (int b = 0; b < 8; b++)
                #pragma unroll
                for (int c = 0; c < 4; c++) acc[a][b][c] = 0.f;

        #pragma unroll
        for (int kk = 0; kk < 64; kk += 16){
            uint32_t af[2][4];
            #pragma unroll
            for (int mt = 0; mt < 2; mt++)
                ldsm4(af[mt], aA[mt] + kk*2);
            #pragma unroll
            for (int nt = 0; nt < 8; nt++){
                uint32_t bf[2];
                ldsm2(bf, aB[nt] + kk*2);
                #pragma unroll
                for (int mt = 0; mt < 2; mt++)
                    mma16b(acc[mt][nt], af[mt], bf);
            }
        }

        #pragma unroll
        for (int mt = 0; mt < 2; mt++){
            #pragma unroll
            for (int dr = 0; dr < 2; dr++){
                int rr = rt*256 + wm*32 + mt*16 + (lane >> 2) + dr*8;
                int n = rr & (N_DIM - 1);
                int w = __ldg(&active[rr]);
                const float* rp = g_Rproj + (size_t)(w*N_DIM + n)*H_DIM;
                #pragma unroll
                for (int nt = 0; nt < 8; nt++){
                    int cc = bcol*128 + wn*64 + nt*8 + (lane & 3)*2;
                    float2 rv = __ldg((const float2*)&rp[cc]);
                    float v0 = fmaxf(acc[mt][nt][dr*2 + 0] + bias[nt][0] + rv.x, 0.f);
                    float v1 = fmaxf(acc[mt][nt][dr*2 + 1] + bias[nt][1] + rv.y, 0.f);
                    g_A0b[(size_t)rr*(H_DIM/2) + (cc >> 1)] = packbf(v0, v1);
                }
            }
        }
        __syncthreads();
    }
}

// ---------------- bf16 feed-forward GEMM + ldmatrix -------------------
#define FFB_W_U32 (128*132)
#define FFB_A_U32 (2*256*36)
#define FFB_SMEM_BYTES ((FFB_W_U32 + FFB_A_U32)*4)

template<int EPI>
__global__ void __launch_bounds__(512, 1)
gemm_ffb(const uint32_t* __restrict__ A, const float* __restrict__ W,
         const float* __restrict__ bias, uint32_t* __restrict__ outp,
         int out_stride, int nrt)
{
    extern __shared__ uint32_t smu[];
    uint32_t* Ws2 = smu;
    uint32_t* As2 = smu + FFB_W_U32;
    const int tid = threadIdx.x, lane = tid & 31, wid = tid >> 5;
    const int wm = wid >> 1, wn = wid & 1;
    const int bcol = blockIdx.x;

    for (int i = tid; i < 128*128; i += 512){
        int c = i >> 7, kp = i & 127;
        const float* wr = W + (size_t)(bcol*128 + c)*H_DIM + 2*kp;
        Ws2[c*132 + kp] = packbf(wr[0], wr[1]);
    }
    const int tA = lane >> 3;
    uint32_t aA[2];
    #pragma unroll
    for (int mt = 0; mt < 2; mt++)
        aA[mt] = sptr(As2) + (uint32_t)(((wm*32 + mt*16 + (tA & 1)*8 + (lane & 7))*36
                                        + (tA >> 1)*4) * 4);
    uint32_t aB[8];
    #pragma unroll
    for (int nt = 0; nt < 8; nt++)
        aB[nt] = sptr(Ws2) + (uint32_t)(((wn*64 + nt*8 + (lane & 7))*132
                                        + ((lane >> 3) & 1)*4) * 4);
    __syncthreads();

    const int nch = (nrt - (int)blockIdx.y + (int)gridDim.y - 1) / (int)gridDim.y;
    if (nch <= 0) return;
    const int total = nch*4;

    auto stage = [&](int p){
        int ci = p >> 2, kb = p & 3, buf = p & 1;
        int rt = blockIdx.y + ci*gridDim.y;
        const uint32_t* src = A + (size_t)rt*256*128 + kb*32;
        uint32_t* dst = As2 + buf*256*36;
        #pragma unroll
        for (int i = tid; i < 2048; i += 512){
            int r = i >> 3, q = i & 7;
            cp16(&dst[r*36 + q*4], src + (size_t)r*128 + q*4);
        }
        cp_commit();
    };

    float acc[2][8][4];
    stage(0);
    for (int p = 0; p < total; p++){
        cp_wait<0>();
        __syncthreads();
        if (p + 1 < total) stage(p + 1);
        const int kb = p & 3;
        if (kb == 0){
            #pragma unroll
            for (int a = 0; a < 2; a++)
                #pragma unroll
                for (int b = 0; b < 8; b++)
                    #pragma unroll
                    for (int c = 0; c < 4; c++) acc[a][b][c] = 0.f;
        }
        const uint32_t abufofs = (uint32_t)((p & 1)*256*36*4);
        const uint32_t bofs = (uint32_t)(kb*128);
        #pragma unroll
        for (int kk = 0; kk < 64; kk += 16){
            uint32_t af[2][4];
            #pragma unroll
            for (int mt = 0; mt < 2; mt++)
                ldsm4(af[mt], aA[mt] + abufofs + kk*2);
            #pragma unroll
            for (int nt = 0; nt < 8; nt++){
                uint32_t bf[2];
                ldsm2(bf, aB[nt] + bofs + kk*2);
                #pragma unroll
                for (int mt = 0; mt < 2; mt++)
                    mma16b(acc[mt][nt], af[mt], bf);
            }
        }

        if (kb == 3){
            int rt = blockIdx.y + (p >> 2)*gridDim.y;
            #pragma unroll
            for (int mt = 0; mt < 2; mt++){
                #pragma unroll
                for (int nt = 0; nt < 8; nt++){
                    #pragma unroll
                    for (int dr = 0; dr < 2; dr++){
                        int rr = rt*256 + wm*32 + mt*16 + (lane >> 2) + dr*8;
                        int cc = bcol*128 + wn*64 + nt*8 + (lane & 3)*2;
                        float v0 = acc[mt][nt][dr*2 + 0] + bias[cc];
                        float v1 = acc[mt][nt][dr*2 + 1] + bias[cc + 1];
                        if (EPI == 1){ v0 = fmaxf(v0, 0.f); v1 = fmaxf(v1, 0.f); }
                        outp[(size_t)rr*out_stride + (cc >> 1)] = packbf(v0, v1);
                    }
                }
            }
        }
    }
}

// ---------------- main GRU v13: split A staging across pair barrier ----------------
#define M12_W_U32 (384*132)
#define M12_A_U32 (16*132)
#define M12_G_U32 (16*200)
#define M12_SMEM_BYTES ((M12_W_U32 + M12_A_U32 + M12_G_U32)*4)

__global__ void __launch_bounds__(256, 1)
main_gru_v13(const float* __restrict__ whh, const float* __restrict__ bhh)
{
    extern __shared__ uint32_t smu[];
    uint32_t* Ws2 = smu;
    uint32_t* As2 = smu + M12_W_U32;
    uint32_t* GIs = smu + M12_W_U32 + M12_A_U32;
    const int tid = threadIdx.x, lane = tid & 31, w = tid >> 5;
    const int me = blockIdx.x;
    const int rg = blockIdx.y;
    const int row0 = rg*16;

    for (int i = tid; i < 384*128; i += 256){
        int row = i >> 7, kp = i & 127;
        int g = row >> 7, cl = row & 127;
        const float* wr = whh + (size_t)(g*H_DIM + me*128 + cl)*H_DIM + 2*kp;
        Ws2[row*132 + kp] = packbf(wr[0], wr[1]);
    }
    float bR[2][2], bZ[2][2], bN[2][2];
    #pragma unroll
    for (int ct = 0; ct < 2; ct++)
        #pragma unroll
        for (int dc = 0; dc < 2; dc++){
            int c = me*128 + w*16 + ct*8 + (lane & 3)*2 + dc;
            bR[ct][dc] = bhh[c];
            bZ[ct][dc] = bhh[H_DIM + c];
            bN[ct][dc] = bhh[2*H_DIM + c];
        }
    const int tA = lane >> 3;
    const uint32_t aA = sptr(As2) + (uint32_t)((((tA & 1)*8 + (lane & 7))*132
                                        + (tA >> 1)*4) * 4);
    uint32_t aB[6];
    #pragma unroll
    for (int nt = 0; nt < 6; nt++){
        int g = nt >> 1, ct = nt & 1;
        aB[nt] = sptr(Ws2) + (uint32_t)(((g*128 + w*16 + ct*8 + (lane & 7))*132
                                        + ((lane >> 3) & 1)*4) * 4);
    }

    auto stage_gi = [&](int tt){
        const uint32_t* gsrc = g_GIb + ((size_t)tt*N_DIM + row0)*(G3/2) + me*64;
        #pragma unroll
        for (int i = tid; i < 768; i += 256){
            int r = i / 48, j = i % 48;
            int g = j >> 4, q = j & 15;
            cp16(&GIs[r*200 + g*64 + q*4], gsrc + (size_t)r*(G3/2) + g*128 + q*4);
        }
        cp_commit();
    };
    // stage one 128-col half (hc = 0 or 1) of A(t) from g_hmb[tt&1]
    auto stage_A_half = [&](int hc, int tt){
        const uint16_t* src = g_hmb[tt & 1] + (size_t)row0*H_DIM + hc*128;
        if (tid < 256){
            int r = tid >> 4, q = tid & 15;
            cp16(&As2[r*132 + hc*64 + q*4], src + (size_t)r*H_DIM + q*8);
        }
        cp_commit();
    };

    stage_gi(0);
    stage_A_half(0, 0);
    stage_A_half(1, 0);

    for (int t = 0; t < T_DIM; t++){
        const float* __restrict__ hsrcf = (t == 0) ? g_hm0
                                        : g_hall + (size_t)(t - 1)*N_DIM*H_DIM;
        float* __restrict__ hdstf = g_hall + (size_t)t*N_DIM*H_DIM;
        uint16_t* __restrict__ hdst16 = g_hmb[(t + 1) & 1];

        cp_wait<0>();
        __syncthreads();

        float acc[6][4];
        #pragma unroll
        for (int n = 0; n < 6; n++)
            #pragma unroll
            for (int c = 0; c < 4; c++) acc[n][c] = 0.f;

        #pragma unroll 4
        for (int kk = 0; kk < H_DIM; kk += 16){
            uint32_t af[4];
            ldsm4(af, aA + kk*2);
            #pragma unroll
            for (int nt = 0; nt < 6; nt++){
                uint32_t bf[2];
                ldsm2(bf, aB[nt] + kk*2);
                mma16b(acc[nt], af, bf);
            }
        }

        #pragma unroll
        for (int dr = 0; dr < 2; dr++){
            int r = (lane >> 2) + dr*8;
            int row = row0 + r;
            #pragma unroll
            for (int ct = 0; ct < 2; ct++){
                int cl = w*16 + ct*8 + (lane & 3)*2;
                int gcol = me*128 + cl;
                float2 gv0 = unpackbf(GIs[r*200 +       (cl >> 1)]);
                float2 gv1 = unpackbf(GIs[r*200 +  64 + (cl >> 1)]);
                float2 gv2 = unpackbf(GIs[r*200 + 128 + (cl >> 1)]);
                float2 hold = __ldcg((const float2*)&hsrcf[(size_t)row*H_DIM + gcol]);
                float2 hout;
                #pragma unroll
                for (int dc = 0; dc < 2; dc++){
                    float gr = acc[0*2 + ct][dr*2+dc] + bR[ct][dc];
                    float gz = acc[1*2 + ct][dr*2+dc] + bZ[ct][dc];
                    float gn = acc[2*2 + ct][dr*2+dc] + bN[ct][dc];
                    float rr = sigm((dc ? gv0.y : gv0.x) + gr);
                    float zz = sigm((dc ? gv1.y : gv1.x) + gz);
                    float nn = tanhf((dc ? gv2.y : gv2.x) + rr*gn);
                    float ho = dc ? hold.y : hold.x;
                    float hnew = (1.f - zz)*nn + zz*ho;
                    if (dc) hout.y = hnew; else hout.x = hnew;
                }
                __stcg((float2*)&hdstf[(size_t)row*H_DIM + gcol], hout);
                __stcg((uint32_t*)(hdst16 + (size_t)row*H_DIM + gcol),
                       packbf(hout.x, hout.y));
            }
        }

        __syncthreads();                 // GIs/As2 consumed; own h(t) stores CTA-visible
        if (t + 1 < T_DIM){
            stage_gi(t + 1);
            stage_A_half(me, t + 1);     // own half of next A (our own stores)
        }

        if (tid == 0){
            __threadfence();
            *(volatile unsigned*)&g_pflag[rg][me][0] = (unsigned)(t + 1);
        }
        if (tid == 32){
            while (*(volatile unsigned*)&g_pflag[rg][me ^ 1][0] < (unsigned)(t + 1)) { }
            __threadfence();
        }
        __syncthreads();
        if (t + 1 < T_DIM)
            stage_A_half(me ^ 1, t + 1); // partner half after its flag
    }
}

// ---------------- heads v2 ----------------
__global__ void __launch_bounds__(256)
heads_kernel(float* __restrict__ out, const int* __restrict__ actions,
             const int* __restrict__ active, const float* __restrict__ p0,
             const float* __restrict__ pp0,
             const float* __restrict__ w_actor, const float* __restrict__ b_actor,
             const float* __restrict__ w_critic, const float* __restrict__ b_critic)
{
    int wid = threadIdx.x >> 5, lane = threadIdx.x & 31;
    size_t row = (size_t)blockIdx.x*8 + wid;
    const float* hrow = g_hall + row*H_DIM;
    float* orow = out + row*ROW_OUT;
    float hv[8];
    #pragma unroll
    for (int i = 0; i < 8; i++) hv[i] = hrow[lane + 32*i];

    float lg = 0.f;
    #pragma unroll
    for (int a = 0; a < NA_DIM; a++){
        float s = 0.f;
        #pragma unroll
        for (int i = 0; i < 8; i++) s += hv[i]*w_actor[a*H_DIM + lane + 32*i];
        #pragma unroll
        for (int o = 16; o > 0; o >>= 1) s += __shfl_xor_sync(0xffffffffu, s, o);
        if (lane == a) lg = s + b_actor[a];
    }
    float m = (lane < NA_DIM) ? lg : -1e30f;
    #pragma unroll
    for (int o = 16; o > 0; o >>= 1) m = fmaxf(m, __shfl_xor_sync(0xffffffffu, m, o));
    float e = (lane < NA_DIM) ? expf(lg - m) : 0.f;
    float den = e;
    #pragma unroll
    for (int o = 16; o > 0; o >>= 1) den += __shfl_xor_sync(0xffffffffu, den, o);

    #pragma unroll
    for (int i = 0; i < 8; i++) orow[4 + lane + 32*i] = hv[i];
    if (lane < NA_DIM) orow[260 + lane] = e/den;

    float s = 0.f;
    #pragma unroll
    for (int i = 0; i < 8; i++) s += hv[i]*w_critic[lane + 32*i];
    #pragma unroll
    for (int o = 16; o > 0; o >>= 1) s += __shfl_xor_sync(0xffffffffu, s, o);

    int n = (int)(row & (N_DIM - 1));
    if (lane == 0)  orow[3]   = s + b_critic[0];
    if (lane == 16) orow[0]   = (float)actions[row];
    if (lane == 17) orow[1]   = p0[n];
    if (lane == 18) orow[2]   = (float)active[row];
    if (lane == 19) orow[276] = pp0[n*2];
    if (lane == 20) orow[277] = pp0[n*2 + 1];
}

// ---------------- launch ----------------
extern "C" void kernel_launch(void* const* d_in, const int* in_sizes, int n_in,
                              void* d_out, int out_size)
{
    (void)in_sizes; (void)n_in; (void)out_size;
    const float* condition = (const float*)d_in[0];
    const int*   active    = (const int*)d_in[1];
    const int*   lines     = (const int*)d_in[2];
    const int*   actions   = (const int*)d_in[3];
    const float* h0        = (const float*)d_in[4];
    const float* p0        = (const float*)d_in[5];
    const float* pp0       = (const float*)d_in[6];
    const float* embed     = (const float*)d_in[7];
    const float* wih_f = (const float*)d_in[8],  *whh_f = (const float*)d_in[9];
    const float* bih_f = (const float*)d_in[10], *bhh_f = (const float*)d_in[11];
    const float* wih_b = (const float*)d_in[12], *whh_b = (const float*)d_in[13];
    const float* bih_b = (const float*)d_in[14], *bhh_b = (const float*)d_in[15];
    const float* f_w0 = (const float*)d_in[16], *f_b0 = (const float*)d_in[17];
    const float* f_w1 = (const float*)d_in[18], *f_b1 = (const float*)d_in[19];
    const float* f_w2 = (const float*)d_in[20], *f_b2 = (const float*)d_in[21];
    const float* c_wih = (const float*)d_in[22], *c_whh = (const float*)d_in[23];
    const float* c_bih = (const float*)d_in[24], *c_bhh = (const float*)d_in[25];
    const float* w_critic = (const float*)d_in[26], *b_critic = (const float*)d_in[27];
    const float* w_actor  = (const float*)d_in[28], *b_actor  = (const float*)d_in[29];
    float* out = (float*)d_out;

    uint32_t *A0bp, *A1bp, *GIbp;
    cudaGetSymbolAddress((void**)&A0bp, g_A0b);
    cudaGetSymbolAddress((void**)&A1bp, g_A1b);
    cudaGetSymbolAddress((void**)&GIbp, g_GIb);

    cudaFuncSetAttribute(enc_v10,
                         cudaFuncAttributeMaxDynamicSharedMemorySize, E10_SMEM_BYTES);
    cudaFuncSetAttribute(main_gru_v13,
                         cudaFuncAttributeMaxDynamicSharedMemorySize, M12_SMEM_BYTES);
    cudaFuncSetAttribute(rproj_b,
                         cudaFuncAttributeMaxDynamicSharedMemorySize, RPB_SMEM_BYTES);
    cudaFuncSetAttribute(l0_b,
                         cudaFuncAttributeMaxDynamicSharedMemorySize, L0B_SMEM_BYTES);
    cudaFuncSetAttribute(gemm_ffb<1>,
                         cudaFuncAttributeMaxDynamicSharedMemorySize, FFB_SMEM_BYTES);
    cudaFuncSetAttribute(gemm_ffb<3>,
                         cudaFuncAttributeMaxDynamicSharedMemorySize, FFB_SMEM_BYTES);

    // 0) gi tables + state init (also resets flags)
    gi_tables<<<(2*NL_DIM*G3 + 255)/256, 256>>>(embed, wih_f, bih_f, wih_b, bih_b);
    init_state<<<4096, 256>>>(h0);

    // 1) persistent bidirectional encoder (K-chunk 128, flag barrier)
    enc_v10<<<dim3(8, 16), 512, E10_SMEM_BYTES>>>(whh_f, bhh_f, whh_b, bhh_b, lines);

    // 2) Rproj = Hmem @ W0r^T
    rproj_b<<<dim3(2, 64), 512, RPB_SMEM_BYTES>>>(f_w0);
    // 3) A0 = relu(cond @ W0c^T + Rproj[active] + b0)
    l0_b<<<dim3(2, 74), 512, L0B_SMEM_BYTES>>>(condition, f_w0, f_b0, active);
    // 4) A1 = relu(A0 @ w1^T + b1); A0'' = relu(A1 @ w2^T + b2)
    gemm_ffb<1><<<dim3(2, 74), 512, FFB_SMEM_BYTES>>>(A0bp, f_w1, f_b1, A1bp, 128, 1024);
    gemm_ffb<1><<<dim3(2, 74), 512, FFB_SMEM_BYTES>>>(A1bp, f_w2, f_b2, A0bp, 128, 1024);
    // 5) GI = A0'' @ c_wih^T + c_bih  -> packed bf16
    gemm_ffb<3><<<dim3(6, 24), 512, FFB_SMEM_BYTES>>>(A0bp, c_wih, c_bih, GIbp, 384, 1024);

    // 6) main GRU v13: split A staging across pair barrier
    main_gru_v13<<<dim3(2, 64), 256, M12_SMEM_BYTES>>>(c_whh, c_bhh);

    // 7) heads v2
    heads_kernel<<<TN/8, 256>>>(out, actions, active, p0, pp0,
                                w_actor, b_actor, w_critic, b_critic);
}